// round 1
// baseline (speedup 1.0000x reference)
#include <cuda_runtime.h>
#include <cuda_bf16.h>
#include <math.h>

// ---------------- problem constants ----------------
#define S        2048
#define HID      4096
#define H        32
#define Q_LORA   1536
#define KV_LORA  512
#define NOPE     128
#define ROPE     64
#define VDIM     128
#define A_COLS   (Q_LORA + KV_LORA + ROPE)   // 2112
#define QDIM     (NOPE + ROPE)               // 192
#define Q_COLS   (H * QDIM)                  // 6144
#define KV_COLS  (H * 2 * NOPE)              // 8192
#define O_COLS   (H * VDIM)                  // 4096
#define ATT_SCALE 0.07216878364870322992f    // 1/sqrt(192)

// ---------------- scratch (no allocation allowed) ----------------
__device__ float g_a[S * A_COLS];      // fused-A output, rmsnormed in place
__device__ float g_kpe[S * ROPE];      // rotated k_pe
__device__ float g_q[S * Q_COLS];      // q (rope applied in place on pe part)
__device__ float g_kv[S * KV_COLS];    // k_nope | v interleaved per head
__device__ float g_attn[S * O_COLS];   // attention output

// ================= SGEMM: C[M,N] = A[M,K] * B[N,K]^T =================
// A row-major (lda), B row-major (ldb, N rows of K), C row-major (ldc).
// BM=BN=128, BK=16, 256 threads, 8x8 microtile. M,K assumed multiples of tile;
// N guarded (needed for N=2112).
#define BM 128
#define BN 128
#define BK 16

__global__ __launch_bounds__(256) void sgemm_nt(
    const float* __restrict__ A, int lda,
    const float* __restrict__ B, int ldb,
    float* __restrict__ C, int ldc,
    int N, int K)
{
    __shared__ float As[BK][BM];
    __shared__ float Bs[BK][BN];

    const int row0 = blockIdx.y * BM;
    const int col0 = blockIdx.x * BN;
    const int tid  = threadIdx.x;
    const int tx   = tid & 15;     // 0..15 -> n
    const int ty   = tid >> 4;     // 0..15 -> m

    float acc[8][8];
    #pragma unroll
    for (int i = 0; i < 8; i++)
        #pragma unroll
        for (int j = 0; j < 8; j++) acc[i][j] = 0.f;

    for (int k0 = 0; k0 < K; k0 += BK) {
        // load A tile (transpose-on-store)
        #pragma unroll
        for (int l = 0; l < 2; l++) {
            int v  = tid + l * 256;          // 0..511 float4 slots
            int r  = v >> 2;                  // 0..127
            int kc = (v & 3) << 2;            // 0,4,8,12
            float4 f = *(const float4*)&A[(size_t)(row0 + r) * lda + k0 + kc];
            As[kc + 0][r] = f.x; As[kc + 1][r] = f.y;
            As[kc + 2][r] = f.z; As[kc + 3][r] = f.w;
        }
        // load B tile (transpose-on-store), guard N
        #pragma unroll
        for (int l = 0; l < 2; l++) {
            int v  = tid + l * 256;
            int r  = v >> 2;
            int kc = (v & 3) << 2;
            float4 f = make_float4(0.f, 0.f, 0.f, 0.f);
            if (col0 + r < N)
                f = *(const float4*)&B[(size_t)(col0 + r) * ldb + k0 + kc];
            Bs[kc + 0][r] = f.x; Bs[kc + 1][r] = f.y;
            Bs[kc + 2][r] = f.z; Bs[kc + 3][r] = f.w;
        }
        __syncthreads();

        #pragma unroll
        for (int k = 0; k < BK; k++) {
            float ra[8], rb[8];
            *(float4*)&ra[0] = *(float4*)&As[k][ty * 8 + 0];
            *(float4*)&ra[4] = *(float4*)&As[k][ty * 8 + 4];
            *(float4*)&rb[0] = *(float4*)&Bs[k][tx * 8 + 0];
            *(float4*)&rb[4] = *(float4*)&Bs[k][tx * 8 + 4];
            #pragma unroll
            for (int i = 0; i < 8; i++)
                #pragma unroll
                for (int j = 0; j < 8; j++)
                    acc[i][j] += ra[i] * rb[j];
        }
        __syncthreads();
    }

    #pragma unroll
    for (int i = 0; i < 8; i++) {
        int r = row0 + ty * 8 + i;
        #pragma unroll
        for (int j = 0; j < 8; j += 4) {
            int c = col0 + tx * 8 + j;
            if (c < N)
                *(float4*)&C[(size_t)r * ldc + c] = *(float4*)&acc[i][j];
        }
    }
}

// ================= RMSNorm (q + kv segments, in place) + k_pe RoPE =========
__global__ __launch_bounds__(256) void rmsnorm_rope_kernel(
    float* __restrict__ a,            // [S, A_COLS]
    float* __restrict__ kpe_out,      // [S, ROPE]
    const float* __restrict__ wq,
    const float* __restrict__ wkv,
    const int* __restrict__ pos_ids)
{
    const int s   = blockIdx.x;
    const int tid = threadIdx.x;
    float* row = a + (size_t)s * A_COLS;
    __shared__ float red[8];

    // --- q segment (1536) ---
    float ss = 0.f;
    for (int i = tid; i < Q_LORA; i += 256) { float v = row[i]; ss += v * v; }
    #pragma unroll
    for (int o = 16; o; o >>= 1) ss += __shfl_xor_sync(0xffffffffu, ss, o);
    if ((tid & 31) == 0) red[tid >> 5] = ss;
    __syncthreads();
    float tot = 0.f;
    #pragma unroll
    for (int w = 0; w < 8; w++) tot += red[w];
    float inv = rsqrtf(tot / (float)Q_LORA + 1e-6f);
    for (int i = tid; i < Q_LORA; i += 256) row[i] = row[i] * inv * wq[i];
    __syncthreads();

    // --- kv segment (512) ---
    float* row2 = row + Q_LORA;
    ss = 0.f;
    for (int i = tid; i < KV_LORA; i += 256) { float v = row2[i]; ss += v * v; }
    #pragma unroll
    for (int o = 16; o; o >>= 1) ss += __shfl_xor_sync(0xffffffffu, ss, o);
    if ((tid & 31) == 0) red[tid >> 5] = ss;
    __syncthreads();
    tot = 0.f;
    #pragma unroll
    for (int w = 0; w < 8; w++) tot += red[w];
    inv = rsqrtf(tot / (float)KV_LORA + 1e-6f);
    for (int i = tid; i < KV_LORA; i += 256) row2[i] = row2[i] * inv * wkv[i];

    // --- k_pe rope (64 dims, threads 0..31) ---
    if (tid < 32) {
        int p = pos_ids[s];
        float inv_freq = 1.0f / powf(10000.0f, (float)tid / 32.0f);
        float ang = (float)p * inv_freq;
        float c = cosf(ang), sn = sinf(ang);
        float x1 = row[Q_LORA + KV_LORA + tid];
        float x2 = row[Q_LORA + KV_LORA + 32 + tid];
        kpe_out[(size_t)s * ROPE + tid]      = x1 * c - x2 * sn;
        kpe_out[(size_t)s * ROPE + 32 + tid] = x2 * c + x1 * sn;
    }
}

// ================= q_pe RoPE (in place on g_q) =================
__global__ __launch_bounds__(256) void rope_q_kernel(
    float* __restrict__ q, const int* __restrict__ pos_ids)
{
    const int s = blockIdx.x;
    const int p = pos_ids[s];
    for (int idx = threadIdx.x; idx < H * 32; idx += 256) {
        int h = idx >> 5, i = idx & 31;
        float inv_freq = 1.0f / powf(10000.0f, (float)i / 32.0f);
        float ang = (float)p * inv_freq;
        float c = cosf(ang), sn = sinf(ang);
        float* base = q + (size_t)s * Q_COLS + h * QDIM + NOPE;
        float x1 = base[i], x2 = base[i + 32];
        base[i]      = x1 * c - x2 * sn;
        base[i + 32] = x2 * c + x1 * sn;
    }
}

// ================= causal flash attention =================
// grid (S/64, H), 256 threads. 4 threads per query row:
// each owns 48 of 192 QK dims (shfl-reduced) and 32 of 128 V dims.
#define FA_BM 64
#define FA_BN 32

__global__ __launch_bounds__(256) void flash_kernel(
    const float* __restrict__ Q,     // [S, Q_COLS]
    const float* __restrict__ KV,    // [S, KV_COLS]
    const float* __restrict__ KPE,   // [S, ROPE]
    float* __restrict__ O)           // [S, O_COLS]
{
    const int qt  = blockIdx.x;
    const int h   = blockIdx.y;
    const int qm0 = qt * FA_BM;
    const int tid = threadIdx.x;
    const int m    = tid >> 2;
    const int part = tid & 3;
    const int qrow = qm0 + m;

    __shared__ float Ks[FA_BN][QDIM];
    __shared__ float Vs[FA_BN][VDIM];

    float qreg[48];
    {
        const float* qp = Q + (size_t)qrow * Q_COLS + h * QDIM + part * 48;
        #pragma unroll
        for (int i = 0; i < 48; i += 4)
            *(float4*)&qreg[i] = *(const float4*)&qp[i];
    }

    float acc[32];
    #pragma unroll
    for (int j = 0; j < 32; j++) acc[j] = 0.f;
    float mi = -INFINITY, li = 0.f;

    for (int n0 = 0; n0 < qm0 + FA_BM; n0 += FA_BN) {
        __syncthreads();
        // K tile: 32 x 192 floats = 1536 float4, 6 per thread
        #pragma unroll
        for (int l = 0; l < 6; l++) {
            int v  = tid + l * 256;
            int n  = v / 48;
            int d  = (v % 48) * 4;
            float4 f;
            if (d < NOPE)
                f = *(const float4*)&KV[(size_t)(n0 + n) * KV_COLS + h * 2 * NOPE + d];
            else
                f = *(const float4*)&KPE[(size_t)(n0 + n) * ROPE + (d - NOPE)];
            *(float4*)&Ks[n][d] = f;
        }
        // V tile: 32 x 128 floats = 1024 float4, 4 per thread
        #pragma unroll
        for (int l = 0; l < 4; l++) {
            int v = tid + l * 256;
            int n = v >> 5;
            int d = (v & 31) * 4;
            *(float4*)&Vs[n][d] =
                *(const float4*)&KV[(size_t)(n0 + n) * KV_COLS + h * 2 * NOPE + NOPE + d];
        }
        __syncthreads();

        float sc[FA_BN];
        #pragma unroll
        for (int n = 0; n < FA_BN; n++) {
            float sv = 0.f;
            const float* kp = &Ks[n][part * 48];
            #pragma unroll
            for (int i = 0; i < 48; i++) sv += qreg[i] * kp[i];
            sv += __shfl_xor_sync(0xffffffffu, sv, 1);
            sv += __shfl_xor_sync(0xffffffffu, sv, 2);
            sv *= ATT_SCALE;
            if (n0 + n > qrow) sv = -INFINITY;
            sc[n] = sv;
        }

        float tmax = sc[0];
        #pragma unroll
        for (int n = 1; n < FA_BN; n++) tmax = fmaxf(tmax, sc[n]);
        float newm = fmaxf(mi, tmax);
        float corr = __expf(mi - newm);
        li *= corr;
        #pragma unroll
        for (int j = 0; j < 32; j++) acc[j] *= corr;

        #pragma unroll
        for (int n = 0; n < FA_BN; n++) {
            float p = __expf(sc[n] - newm);
            li += p;
            const float* vp = &Vs[n][part * 32];
            #pragma unroll
            for (int j = 0; j < 32; j++) acc[j] += p * vp[j];
        }
        mi = newm;
    }

    float invl = 1.f / li;
    float* op = O + (size_t)qrow * O_COLS + h * VDIM + part * 32;
    #pragma unroll
    for (int j = 0; j < 32; j++) op[j] = acc[j] * invl;
}

// ================= launch =================
extern "C" void kernel_launch(void* const* d_in, const int* in_sizes, int n_in,
                              void* d_out, int out_size)
{
    const int*   pos   = (const int*)  d_in[0];
    const float* hid   = (const float*)d_in[1];
    const float* w_a   = (const float*)d_in[2];
    const float* wq_ln = (const float*)d_in[3];
    const float* wkv_ln= (const float*)d_in[4];
    const float* w_q_b = (const float*)d_in[5];
    const float* w_kv_b= (const float*)d_in[6];
    const float* w_o   = (const float*)d_in[7];
    float* out = (float*)d_out;

    float *a, *kpe, *q, *kv, *attn;
    cudaGetSymbolAddress((void**)&a,    g_a);
    cudaGetSymbolAddress((void**)&kpe,  g_kpe);
    cudaGetSymbolAddress((void**)&q,    g_q);
    cudaGetSymbolAddress((void**)&kv,   g_kv);
    cudaGetSymbolAddress((void**)&attn, g_attn);

    // 1) fused-A GEMM: [S,HID] x [A_COLS,HID]^T -> [S,A_COLS]
    sgemm_nt<<<dim3((A_COLS + BN - 1) / BN, S / BM), 256>>>(
        hid, HID, w_a, HID, a, A_COLS, A_COLS, HID);

    // 2) RMSNorm both segments (in place) + k_pe rope
    rmsnorm_rope_kernel<<<S, 256>>>(a, kpe, wq_ln, wkv_ln, pos);

    // 3) q = cq @ w_q_b^T : [S,Q_LORA(lda=A_COLS)] x [Q_COLS,Q_LORA]^T
    sgemm_nt<<<dim3(Q_COLS / BN, S / BM), 256>>>(
        a, A_COLS, w_q_b, Q_LORA, q, Q_COLS, Q_COLS, Q_LORA);

    // 4) kv = ckv @ w_kv_b^T : [S,KV_LORA] x [KV_COLS,KV_LORA]^T
    sgemm_nt<<<dim3(KV_COLS / BN, S / BM), 256>>>(
        a + Q_LORA, A_COLS, w_kv_b, KV_LORA, kv, KV_COLS, KV_COLS, KV_LORA);

    // 5) rope on q_pe (in place)
    rope_q_kernel<<<S, 256>>>(q, pos);

    // 6) causal flash attention -> attn [S, H*VDIM]
    flash_kernel<<<dim3(S / FA_BM, H), 256>>>(q, kv, kpe, attn);

    // 7) out = attn @ w_o^T : [S,O_COLS] x [HID,O_COLS]^T -> [S,HID]
    sgemm_nt<<<dim3(HID / BN, S / BM), 256>>>(
        attn, O_COLS, w_o, O_COLS, out, HID, HID, O_COLS);
}

// round 3
// speedup vs baseline: 1.2435x; 1.2435x over previous
#include <cuda_runtime.h>
#include <cuda_bf16.h>
#include <math.h>
#include <stdint.h>

// ---------------- problem constants ----------------
#define S        2048
#define HID      4096
#define H        32
#define Q_LORA   1536
#define KV_LORA  512
#define NOPE     128
#define ROPE     64
#define VDIM     128
#define A_COLS   (Q_LORA + KV_LORA + ROPE)   // 2112
#define A_COLS_P 2176                        // padded to 128-mult
#define QDIM     (NOPE + ROPE)               // 192
#define Q_COLS   (H * QDIM)                  // 6144
#define KV_COLS  (H * 2 * NOPE)              // 8192
#define O_COLS   (H * VDIM)                  // 4096
#define ATT_SCALE 0.07216878364870322992f    // 1/sqrt(192)

// ---------------- scratch (no allocation allowed) ----------------
__device__ __align__(256) float g_a[S * A_COLS];
__device__ __align__(256) float g_kpe[S * ROPE];
__device__ __align__(256) float g_q[S * Q_COLS];
__device__ __align__(256) float g_kv[S * KV_COLS];
__device__ __align__(256) float g_attn[S * O_COLS];

__device__ __align__(256) __nv_bfloat16 g_h_hi[S * HID],       g_h_lo[S * HID];
__device__ __align__(256) __nv_bfloat16 g_cq_hi[S * Q_LORA],   g_cq_lo[S * Q_LORA];
__device__ __align__(256) __nv_bfloat16 g_ckv_hi[S * KV_LORA], g_ckv_lo[S * KV_LORA];
__device__ __align__(256) __nv_bfloat16 g_at_hi[S * O_COLS],   g_at_lo[S * O_COLS];
__device__ __align__(256) __nv_bfloat16 g_wa_hi[A_COLS_P * HID],   g_wa_lo[A_COLS_P * HID];
__device__ __align__(256) __nv_bfloat16 g_wqb_hi[Q_COLS * Q_LORA], g_wqb_lo[Q_COLS * Q_LORA];
__device__ __align__(256) __nv_bfloat16 g_wkvb_hi[KV_COLS * KV_LORA], g_wkvb_lo[KV_COLS * KV_LORA];
__device__ __align__(256) __nv_bfloat16 g_wo_hi[HID * O_COLS], g_wo_lo[HID * O_COLS];

// ================= portable PTX helpers =================
__device__ __forceinline__ uint32_t smem_u32(const void* p) {
    uint32_t a;
    asm("{ .reg .u64 t; cvta.to.shared.u64 t, %1; cvt.u32.u64 %0, t; }"
        : "=r"(a) : "l"(p));
    return a;
}
__device__ __forceinline__ void cp16(uint32_t dst, const void* src) {
    asm volatile("cp.async.cg.shared.global [%0], [%1], 16;" :: "r"(dst), "l"(src));
}
#define CP_COMMIT() asm volatile("cp.async.commit_group;" ::: "memory")
#define CP_WAIT0()  asm volatile("cp.async.wait_group 0;"  ::: "memory")

__device__ __forceinline__ void ldmx4(uint32_t* r, uint32_t addr) {
    asm volatile("ldmatrix.sync.aligned.m8n8.x4.shared.b16 {%0,%1,%2,%3}, [%4];"
                 : "=r"(r[0]), "=r"(r[1]), "=r"(r[2]), "=r"(r[3]) : "r"(addr));
}
__device__ __forceinline__ void ldmx2(uint32_t* r, uint32_t addr) {
    asm volatile("ldmatrix.sync.aligned.m8n8.x2.shared.b16 {%0,%1}, [%2];"
                 : "=r"(r[0]), "=r"(r[1]) : "r"(addr));
}
__device__ __forceinline__ void mma16816(float* c, const uint32_t* a, const uint32_t* b) {
    asm volatile(
        "mma.sync.aligned.m16n8k16.row.col.f32.bf16.bf16.f32 "
        "{%0,%1,%2,%3},{%4,%5,%6,%7},{%8,%9},{%0,%1,%2,%3};"
        : "+f"(c[0]), "+f"(c[1]), "+f"(c[2]), "+f"(c[3])
        : "r"(a[0]), "r"(a[1]), "r"(a[2]), "r"(a[3]), "r"(b[0]), "r"(b[1]));
}

// ================= fp32 -> bf16 hi/lo split =================
__global__ __launch_bounds__(256) void cvt_split(
    const float* __restrict__ src,
    __nv_bfloat16* __restrict__ hi, __nv_bfloat16* __restrict__ lo,
    int total4, int cols, int rows)
{
    for (int i = blockIdx.x * 256 + threadIdx.x; i < total4; i += gridDim.x * 256) {
        int e = i * 4;
        int r = e / cols;
        float4 f = make_float4(0.f, 0.f, 0.f, 0.f);
        if (r < rows) f = *(const float4*)(src + (size_t)e);
        __nv_bfloat16 h0 = __float2bfloat16(f.x);
        __nv_bfloat16 h1 = __float2bfloat16(f.y);
        __nv_bfloat16 h2 = __float2bfloat16(f.z);
        __nv_bfloat16 h3 = __float2bfloat16(f.w);
        __nv_bfloat16 l0 = __float2bfloat16(f.x - __bfloat162float(h0));
        __nv_bfloat16 l1 = __float2bfloat16(f.y - __bfloat162float(h1));
        __nv_bfloat16 l2 = __float2bfloat16(f.z - __bfloat162float(h2));
        __nv_bfloat16 l3 = __float2bfloat16(f.w - __bfloat162float(h3));
        *(__nv_bfloat162*)(hi + (size_t)e)     = __nv_bfloat162(h0, h1);
        *(__nv_bfloat162*)(hi + (size_t)e + 2) = __nv_bfloat162(h2, h3);
        *(__nv_bfloat162*)(lo + (size_t)e)     = __nv_bfloat162(l0, l1);
        *(__nv_bfloat162*)(lo + (size_t)e + 2) = __nv_bfloat162(l2, l3);
    }
}

// ================= split-bf16 HMMA GEMM =================
// C[M,N] = A[M,K]*B[N,K]^T via Ah*Bh + Al*Bh + Ah*Bl, fp32 accum.
// CTA 128x128, BK=32, 8 warps (2x4), warp tile 64x32, cp.async double buffer.
#define BKC   32
#define ROWB  80                       // 32 bf16 = 64B padded to 80B (conflict-free)
#define TILEB (128 * ROWB)             // 10240 B
#define STG   (4 * TILEB)              // 40960 B per stage
#define GSMEM (2 * STG)                // 81920 B

__device__ __forceinline__ void issue_stage(
    const __nv_bfloat16* __restrict__ Ah, const __nv_bfloat16* __restrict__ Al,
    const __nv_bfloat16* __restrict__ Bh, const __nv_bfloat16* __restrict__ Bl,
    int row0, int col0, int K, int c, uint32_t sbase, int s, int tid)
{
    uint32_t st = sbase + s * STG;
    #pragma unroll
    for (int l = 0; l < 2; ++l) {
        int v = tid + l * 256;        // 0..511
        int r = v >> 2;               // 0..127
        int j = v & 3;                // 16B chunk
        size_t goffA = (size_t)(row0 + r) * K + c * BKC + j * 8;
        size_t goffB = (size_t)(col0 + r) * K + c * BKC + j * 8;
        uint32_t so = r * ROWB + j * 16;
        cp16(st + 0 * TILEB + so, Ah + goffA);
        cp16(st + 1 * TILEB + so, Al + goffA);
        cp16(st + 2 * TILEB + so, Bh + goffB);
        cp16(st + 3 * TILEB + so, Bl + goffB);
    }
}

__global__ __launch_bounds__(256, 1) void mma_gemm(
    const __nv_bfloat16* __restrict__ Ah, const __nv_bfloat16* __restrict__ Al,
    const __nv_bfloat16* __restrict__ Bh, const __nv_bfloat16* __restrict__ Bl,
    float* __restrict__ C, int ldc, int N, int K)
{
    extern __shared__ char sm[];
    uint32_t sbase = smem_u32(sm);
    const int tid    = threadIdx.x;
    const int lane   = tid & 31;
    const int warp   = tid >> 5;
    const int warp_m = warp >> 2;       // 0..1
    const int warp_n = warp & 3;        // 0..3
    const int row0 = blockIdx.y * 128;
    const int col0 = blockIdx.x * 128;

    float acc[4][4][4];
    #pragma unroll
    for (int mi = 0; mi < 4; ++mi)
        #pragma unroll
        for (int ni = 0; ni < 4; ++ni)
            #pragma unroll
            for (int e = 0; e < 4; ++e) acc[mi][ni][e] = 0.f;

    const int nch = K / BKC;

    issue_stage(Ah, Al, Bh, Bl, row0, col0, K, 0, sbase, 0, tid);
    CP_COMMIT();

    // ldmatrix lane addressing (byte offsets within tile)
    const uint32_t a_l = (uint32_t)((warp_m * 64 + (lane & 15)) * ROWB + (lane >> 4) * 16);
    const uint32_t b_l = (uint32_t)((warp_n * 32 + (lane & 7)) * ROWB + ((lane >> 3) & 1) * 16);

    for (int c = 0; c < nch; ++c) {
        CP_WAIT0();
        __syncthreads();
        if (c + 1 < nch) {
            issue_stage(Ah, Al, Bh, Bl, row0, col0, K, c + 1, sbase, (c + 1) & 1, tid);
            CP_COMMIT();
        }
        uint32_t st = sbase + (c & 1) * STG;

        #pragma unroll
        for (int ki = 0; ki < 2; ++ki) {
            uint32_t ah[4][4], al[4][4], bh[4][2], bl[4][2];
            #pragma unroll
            for (int mi = 0; mi < 4; ++mi) {
                uint32_t ad = st + a_l + mi * (16 * ROWB) + ki * 32;
                ldmx4(ah[mi], ad + 0 * TILEB);
                ldmx4(al[mi], ad + 1 * TILEB);
            }
            #pragma unroll
            for (int ni = 0; ni < 4; ++ni) {
                uint32_t bd = st + b_l + ni * (8 * ROWB) + ki * 32;
                ldmx2(bh[ni], bd + 2 * TILEB);
                ldmx2(bl[ni], bd + 3 * TILEB);
            }
            #pragma unroll
            for (int mi = 0; mi < 4; ++mi)
                #pragma unroll
                for (int ni = 0; ni < 4; ++ni) {
                    mma16816(acc[mi][ni], ah[mi], bh[ni]);
                    mma16816(acc[mi][ni], al[mi], bh[ni]);
                    mma16816(acc[mi][ni], ah[mi], bl[ni]);
                }
        }
        __syncthreads();
    }

    // epilogue
    #pragma unroll
    for (int mi = 0; mi < 4; ++mi) {
        int row = row0 + warp_m * 64 + mi * 16 + (lane >> 2);
        #pragma unroll
        for (int ni = 0; ni < 4; ++ni) {
            int col = col0 + warp_n * 32 + ni * 8 + (lane & 3) * 2;
            if (col < N) {
                *(float2*)&C[(size_t)row * ldc + col] =
                    make_float2(acc[mi][ni][0], acc[mi][ni][1]);
                *(float2*)&C[(size_t)(row + 8) * ldc + col] =
                    make_float2(acc[mi][ni][2], acc[mi][ni][3]);
            }
        }
    }
}

// ================= RMSNorm (emits bf16 hi/lo) + k_pe RoPE =================
__global__ __launch_bounds__(256) void rmsnorm_rope_kernel(
    const float* __restrict__ a,
    float* __restrict__ kpe_out,
    __nv_bfloat16* __restrict__ cqh, __nv_bfloat16* __restrict__ cql,
    __nv_bfloat16* __restrict__ ckvh, __nv_bfloat16* __restrict__ ckvl,
    const float* __restrict__ wq,
    const float* __restrict__ wkv,
    const int* __restrict__ pos_ids)
{
    const int s   = blockIdx.x;
    const int tid = threadIdx.x;
    const float* row = a + (size_t)s * A_COLS;
    __shared__ float red[8];

    float ss = 0.f;
    for (int i = tid; i < Q_LORA; i += 256) { float v = row[i]; ss += v * v; }
    #pragma unroll
    for (int o = 16; o; o >>= 1) ss += __shfl_xor_sync(0xffffffffu, ss, o);
    if ((tid & 31) == 0) red[tid >> 5] = ss;
    __syncthreads();
    float tot = 0.f;
    #pragma unroll
    for (int w = 0; w < 8; w++) tot += red[w];
    float inv = rsqrtf(tot / (float)Q_LORA + 1e-6f);
    for (int i = tid; i < Q_LORA; i += 256) {
        float v = row[i] * inv * wq[i];
        __nv_bfloat16 h = __float2bfloat16(v);
        cqh[(size_t)s * Q_LORA + i] = h;
        cql[(size_t)s * Q_LORA + i] = __float2bfloat16(v - __bfloat162float(h));
    }
    __syncthreads();

    const float* row2 = row + Q_LORA;
    ss = 0.f;
    for (int i = tid; i < KV_LORA; i += 256) { float v = row2[i]; ss += v * v; }
    #pragma unroll
    for (int o = 16; o; o >>= 1) ss += __shfl_xor_sync(0xffffffffu, ss, o);
    if ((tid & 31) == 0) red[tid >> 5] = ss;
    __syncthreads();
    tot = 0.f;
    #pragma unroll
    for (int w = 0; w < 8; w++) tot += red[w];
    inv = rsqrtf(tot / (float)KV_LORA + 1e-6f);
    for (int i = tid; i < KV_LORA; i += 256) {
        float v = row2[i] * inv * wkv[i];
        __nv_bfloat16 h = __float2bfloat16(v);
        ckvh[(size_t)s * KV_LORA + i] = h;
        ckvl[(size_t)s * KV_LORA + i] = __float2bfloat16(v - __bfloat162float(h));
    }

    if (tid < 32) {
        int p = pos_ids[s];
        float inv_freq = 1.0f / powf(10000.0f, (float)tid / 32.0f);
        float ang = (float)p * inv_freq;
        float c = cosf(ang), sn = sinf(ang);
        float x1 = row[Q_LORA + KV_LORA + tid];
        float x2 = row[Q_LORA + KV_LORA + 32 + tid];
        kpe_out[(size_t)s * ROPE + tid]      = x1 * c - x2 * sn;
        kpe_out[(size_t)s * ROPE + 32 + tid] = x2 * c + x1 * sn;
    }
}

// ================= q_pe RoPE =================
__global__ __launch_bounds__(256) void rope_q_kernel(
    float* __restrict__ q, const int* __restrict__ pos_ids)
{
    const int s = blockIdx.x;
    const int p = pos_ids[s];
    for (int idx = threadIdx.x; idx < H * 32; idx += 256) {
        int h = idx >> 5, i = idx & 31;
        float inv_freq = 1.0f / powf(10000.0f, (float)i / 32.0f);
        float ang = (float)p * inv_freq;
        float c = cosf(ang), sn = sinf(ang);
        float* base = q + (size_t)s * Q_COLS + h * QDIM + NOPE;
        float x1 = base[i], x2 = base[i + 32];
        base[i]      = x1 * c - x2 * sn;
        base[i + 32] = x2 * c + x1 * sn;
    }
}

// ================= causal flash attention (fp32 SIMT) =================
#define FA_BM 64
#define FA_BN 32

__global__ __launch_bounds__(256) void flash_kernel(
    const float* __restrict__ Q,
    const float* __restrict__ KV,
    const float* __restrict__ KPE,
    float* __restrict__ O)
{
    const int qt  = blockIdx.x;
    const int h   = blockIdx.y;
    const int qm0 = qt * FA_BM;
    const int tid = threadIdx.x;
    const int m    = tid >> 2;
    const int part = tid & 3;
    const int qrow = qm0 + m;

    __shared__ float Ks[FA_BN][QDIM];
    __shared__ float Vs[FA_BN][VDIM];

    float qreg[48];
    {
        const float* qp = Q + (size_t)qrow * Q_COLS + h * QDIM + part * 48;
        #pragma unroll
        for (int i = 0; i < 48; i += 4)
            *(float4*)&qreg[i] = *(const float4*)&qp[i];
    }

    float acc[32];
    #pragma unroll
    for (int j = 0; j < 32; j++) acc[j] = 0.f;
    float mi = -INFINITY, li = 0.f;

    for (int n0 = 0; n0 < qm0 + FA_BM; n0 += FA_BN) {
        __syncthreads();
        #pragma unroll
        for (int l = 0; l < 6; l++) {
            int v  = tid + l * 256;
            int n  = v / 48;
            int d  = (v % 48) * 4;
            float4 f;
            if (d < NOPE)
                f = *(const float4*)&KV[(size_t)(n0 + n) * KV_COLS + h * 2 * NOPE + d];
            else
                f = *(const float4*)&KPE[(size_t)(n0 + n) * ROPE + (d - NOPE)];
            *(float4*)&Ks[n][d] = f;
        }
        #pragma unroll
        for (int l = 0; l < 4; l++) {
            int v = tid + l * 256;
            int n = v >> 5;
            int d = (v & 31) * 4;
            *(float4*)&Vs[n][d] =
                *(const float4*)&KV[(size_t)(n0 + n) * KV_COLS + h * 2 * NOPE + NOPE + d];
        }
        __syncthreads();

        float sc[FA_BN];
        #pragma unroll
        for (int n = 0; n < FA_BN; n++) {
            float sv = 0.f;
            const float* kp = &Ks[n][part * 48];
            #pragma unroll
            for (int i = 0; i < 48; i++) sv += qreg[i] * kp[i];
            sv += __shfl_xor_sync(0xffffffffu, sv, 1);
            sv += __shfl_xor_sync(0xffffffffu, sv, 2);
            sv *= ATT_SCALE;
            if (n0 + n > qrow) sv = -INFINITY;
            sc[n] = sv;
        }

        float tmax = sc[0];
        #pragma unroll
        for (int n = 1; n < FA_BN; n++) tmax = fmaxf(tmax, sc[n]);
        float newm = fmaxf(mi, tmax);
        float corr = __expf(mi - newm);
        li *= corr;
        #pragma unroll
        for (int j = 0; j < 32; j++) acc[j] *= corr;

        #pragma unroll
        for (int n = 0; n < FA_BN; n++) {
            float p = __expf(sc[n] - newm);
            li += p;
            const float* vp = &Vs[n][part * 32];
            #pragma unroll
            for (int j = 0; j < 32; j++) acc[j] += p * vp[j];
        }
        mi = newm;
    }

    float invl = 1.f / li;
    float* op = O + (size_t)qrow * O_COLS + h * VDIM + part * 32;
    #pragma unroll
    for (int j = 0; j < 32; j++) op[j] = acc[j] * invl;
}

// ================= launch =================
extern "C" void kernel_launch(void* const* d_in, const int* in_sizes, int n_in,
                              void* d_out, int out_size)
{
    const int*   pos   = (const int*)  d_in[0];
    const float* hid   = (const float*)d_in[1];
    const float* w_a   = (const float*)d_in[2];
    const float* wq_ln = (const float*)d_in[3];
    const float* wkv_ln= (const float*)d_in[4];
    const float* w_q_b = (const float*)d_in[5];
    const float* w_kv_b= (const float*)d_in[6];
    const float* w_o   = (const float*)d_in[7];
    float* out = (float*)d_out;

    float *a, *kpe, *q, *kv, *attn;
    cudaGetSymbolAddress((void**)&a,    g_a);
    cudaGetSymbolAddress((void**)&kpe,  g_kpe);
    cudaGetSymbolAddress((void**)&q,    g_q);
    cudaGetSymbolAddress((void**)&kv,   g_kv);
    cudaGetSymbolAddress((void**)&attn, g_attn);

    __nv_bfloat16 *h_hi, *h_lo, *cq_hi, *cq_lo, *ckv_hi, *ckv_lo, *at_hi, *at_lo;
    __nv_bfloat16 *wa_hi, *wa_lo, *wqb_hi, *wqb_lo, *wkvb_hi, *wkvb_lo, *wo_hi, *wo_lo;
    cudaGetSymbolAddress((void**)&h_hi,   g_h_hi);   cudaGetSymbolAddress((void**)&h_lo,   g_h_lo);
    cudaGetSymbolAddress((void**)&cq_hi,  g_cq_hi);  cudaGetSymbolAddress((void**)&cq_lo,  g_cq_lo);
    cudaGetSymbolAddress((void**)&ckv_hi, g_ckv_hi); cudaGetSymbolAddress((void**)&ckv_lo, g_ckv_lo);
    cudaGetSymbolAddress((void**)&at_hi,  g_at_hi);  cudaGetSymbolAddress((void**)&at_lo,  g_at_lo);
    cudaGetSymbolAddress((void**)&wa_hi,  g_wa_hi);  cudaGetSymbolAddress((void**)&wa_lo,  g_wa_lo);
    cudaGetSymbolAddress((void**)&wqb_hi, g_wqb_hi); cudaGetSymbolAddress((void**)&wqb_lo, g_wqb_lo);
    cudaGetSymbolAddress((void**)&wkvb_hi,g_wkvb_hi);cudaGetSymbolAddress((void**)&wkvb_lo,g_wkvb_lo);
    cudaGetSymbolAddress((void**)&wo_hi,  g_wo_hi);  cudaGetSymbolAddress((void**)&wo_lo,  g_wo_lo);

    cudaFuncSetAttribute(mma_gemm, cudaFuncAttributeMaxDynamicSharedMemorySize, GSMEM);

    // conversions (bf16 hi/lo split)
    cvt_split<<<4096, 256>>>(w_a,   wa_hi,  wa_lo,  A_COLS_P * HID / 4, HID,    A_COLS);
    cvt_split<<<4096, 256>>>(w_q_b, wqb_hi, wqb_lo, Q_COLS * Q_LORA / 4, Q_LORA, Q_COLS);
    cvt_split<<<4096, 256>>>(w_kv_b,wkvb_hi,wkvb_lo,KV_COLS * KV_LORA / 4, KV_LORA, KV_COLS);
    cvt_split<<<4096, 256>>>(w_o,   wo_hi,  wo_lo,  HID * O_COLS / 4, O_COLS, HID);
    cvt_split<<<4096, 256>>>(hid,   h_hi,   h_lo,   S * HID / 4, HID, S);

    // 1) fused-A GEMM -> g_a (fp32)
    mma_gemm<<<dim3(A_COLS_P / 128, S / 128), 256, GSMEM>>>(
        h_hi, h_lo, wa_hi, wa_lo, a, A_COLS, A_COLS, HID);

    // 2) RMSNorm -> bf16 hi/lo + k_pe rope
    rmsnorm_rope_kernel<<<S, 256>>>(a, kpe, cq_hi, cq_lo, ckv_hi, ckv_lo,
                                    wq_ln, wkv_ln, pos);

    // 3) q GEMM
    mma_gemm<<<dim3(Q_COLS / 128, S / 128), 256, GSMEM>>>(
        cq_hi, cq_lo, wqb_hi, wqb_lo, q, Q_COLS, Q_COLS, Q_LORA);

    // 4) kv GEMM
    mma_gemm<<<dim3(KV_COLS / 128, S / 128), 256, GSMEM>>>(
        ckv_hi, ckv_lo, wkvb_hi, wkvb_lo, kv, KV_COLS, KV_COLS, KV_LORA);

    // 5) rope on q_pe
    rope_q_kernel<<<S, 256>>>(q, pos);

    // 6) flash attention
    flash_kernel<<<dim3(S / FA_BM, H), 256>>>(q, kv, kpe, attn);

    // 7) attn split + output GEMM
    cvt_split<<<4096, 256>>>(attn, at_hi, at_lo, S * O_COLS / 4, O_COLS, S);
    mma_gemm<<<dim3(HID / 128, S / 128), 256, GSMEM>>>(
        at_hi, at_lo, wo_hi, wo_lo, out, HID, HID, O_COLS);
}

// round 4
// speedup vs baseline: 2.5031x; 2.0130x over previous
#include <cuda_runtime.h>
#include <cuda_bf16.h>
#include <math.h>
#include <stdint.h>

// ---------------- problem constants ----------------
#define S        2048
#define HID      4096
#define H        32
#define Q_LORA   1536
#define KV_LORA  512
#define NOPE     128
#define ROPE     64
#define VDIM     128
#define A_COLS   (Q_LORA + KV_LORA + ROPE)   // 2112
#define A_COLS_P 2176                        // padded to 128-mult
#define QDIM     (NOPE + ROPE)               // 192
#define Q_COLS   (H * QDIM)                  // 6144
#define KV_COLS  (H * 2 * NOPE)              // 8192
#define O_COLS   (H * VDIM)                  // 4096
#define ATT_SCALE 0.07216878364870322992f    // 1/sqrt(192)

// ---------------- scratch (no allocation allowed) ----------------
__device__ __align__(256) float g_a[S * A_COLS];
__device__ __align__(256) float g_kpe[S * ROPE];
__device__ __align__(256) float g_q[S * Q_COLS];
__device__ __align__(256) float g_kv[S * KV_COLS];
__device__ __align__(256) float g_attn[S * O_COLS];

__device__ __align__(256) __nv_bfloat16 g_h_hi[S * HID],       g_h_lo[S * HID];
__device__ __align__(256) __nv_bfloat16 g_cq_hi[S * Q_LORA],   g_cq_lo[S * Q_LORA];
__device__ __align__(256) __nv_bfloat16 g_ckv_hi[S * KV_LORA], g_ckv_lo[S * KV_LORA];
__device__ __align__(256) __nv_bfloat16 g_at_hi[S * O_COLS],   g_at_lo[S * O_COLS];
__device__ __align__(256) __nv_bfloat16 g_wa_hi[A_COLS_P * HID],   g_wa_lo[A_COLS_P * HID];
__device__ __align__(256) __nv_bfloat16 g_wqb_hi[Q_COLS * Q_LORA], g_wqb_lo[Q_COLS * Q_LORA];
__device__ __align__(256) __nv_bfloat16 g_wkvb_hi[KV_COLS * KV_LORA], g_wkvb_lo[KV_COLS * KV_LORA];
__device__ __align__(256) __nv_bfloat16 g_wo_hi[HID * O_COLS], g_wo_lo[HID * O_COLS];

// ================= portable PTX helpers =================
__device__ __forceinline__ uint32_t smem_u32(const void* p) {
    uint32_t a;
    asm("{ .reg .u64 t; cvta.to.shared.u64 t, %1; cvt.u32.u64 %0, t; }"
        : "=r"(a) : "l"(p));
    return a;
}
__device__ __forceinline__ void cp16(uint32_t dst, const void* src) {
    asm volatile("cp.async.cg.shared.global [%0], [%1], 16;" :: "r"(dst), "l"(src));
}
#define CP_COMMIT()  asm volatile("cp.async.commit_group;" ::: "memory")
#define CP_WAIT(n)   asm volatile("cp.async.wait_group %0;" :: "n"(n) : "memory")

__device__ __forceinline__ void ldmx4(uint32_t* r, uint32_t addr) {
    asm volatile("ldmatrix.sync.aligned.m8n8.x4.shared.b16 {%0,%1,%2,%3}, [%4];"
                 : "=r"(r[0]), "=r"(r[1]), "=r"(r[2]), "=r"(r[3]) : "r"(addr));
}
__device__ __forceinline__ void ldmx2(uint32_t* r, uint32_t addr) {
    asm volatile("ldmatrix.sync.aligned.m8n8.x2.shared.b16 {%0,%1}, [%2];"
                 : "=r"(r[0]), "=r"(r[1]) : "r"(addr));
}
__device__ __forceinline__ void mma16816(float* c, const uint32_t* a, const uint32_t* b) {
    asm volatile(
        "mma.sync.aligned.m16n8k16.row.col.f32.bf16.bf16.f32 "
        "{%0,%1,%2,%3},{%4,%5,%6,%7},{%8,%9},{%0,%1,%2,%3};"
        : "+f"(c[0]), "+f"(c[1]), "+f"(c[2]), "+f"(c[3])
        : "r"(a[0]), "r"(a[1]), "r"(a[2]), "r"(a[3]), "r"(b[0]), "r"(b[1]));
}

// ================= fp32 -> bf16 hi/lo split =================
__global__ __launch_bounds__(256) void cvt_split(
    const float* __restrict__ src,
    __nv_bfloat16* __restrict__ hi, __nv_bfloat16* __restrict__ lo,
    int total4, int cols, int rows)
{
    for (int i = blockIdx.x * 256 + threadIdx.x; i < total4; i += gridDim.x * 256) {
        int e = i * 4;
        int r = e / cols;
        float4 f = make_float4(0.f, 0.f, 0.f, 0.f);
        if (r < rows) f = *(const float4*)(src + (size_t)e);
        __nv_bfloat16 h0 = __float2bfloat16(f.x);
        __nv_bfloat16 h1 = __float2bfloat16(f.y);
        __nv_bfloat16 h2 = __float2bfloat16(f.z);
        __nv_bfloat16 h3 = __float2bfloat16(f.w);
        __nv_bfloat16 l0 = __float2bfloat16(f.x - __bfloat162float(h0));
        __nv_bfloat16 l1 = __float2bfloat16(f.y - __bfloat162float(h1));
        __nv_bfloat16 l2 = __float2bfloat16(f.z - __bfloat162float(h2));
        __nv_bfloat16 l3 = __float2bfloat16(f.w - __bfloat162float(h3));
        *(__nv_bfloat162*)(hi + (size_t)e)     = __nv_bfloat162(h0, h1);
        *(__nv_bfloat162*)(hi + (size_t)e + 2) = __nv_bfloat162(h2, h3);
        *(__nv_bfloat162*)(lo + (size_t)e)     = __nv_bfloat162(l0, l1);
        *(__nv_bfloat162*)(lo + (size_t)e + 2) = __nv_bfloat162(l2, l3);
    }
}

// ================= split-bf16 HMMA GEMM (4-stage cp.async ring) ==========
// C[M,N] = A[M,K]*B[N,K]^T via Ah*Bh + Al*Bh + Ah*Bl, fp32 accum.
// CTA 128x128, BK=32, 8 warps (2x4), warp tile 64x32.
#define BKC   32
#define ROWB  80                       // 64B row padded to 80B (conflict-free)
#define TILEB (128 * ROWB)             // 10240 B
#define STG   (4 * TILEB)              // 40960 B per stage
#define NS    4
#define GSMEM (NS * STG)               // 163840 B

__device__ __forceinline__ void issue_stage(
    const __nv_bfloat16* __restrict__ Ah, const __nv_bfloat16* __restrict__ Al,
    const __nv_bfloat16* __restrict__ Bh, const __nv_bfloat16* __restrict__ Bl,
    int row0, int col0, int K, int c, uint32_t sbase, int slot, int tid)
{
    uint32_t st = sbase + slot * STG;
    #pragma unroll
    for (int l = 0; l < 2; ++l) {
        int v = tid + l * 256;        // 0..511
        int r = v >> 2;               // 0..127
        int j = v & 3;                // 16B chunk
        size_t goffA = (size_t)(row0 + r) * K + c * BKC + j * 8;
        size_t goffB = (size_t)(col0 + r) * K + c * BKC + j * 8;
        uint32_t so = r * ROWB + j * 16;
        cp16(st + 0 * TILEB + so, Ah + goffA);
        cp16(st + 1 * TILEB + so, Al + goffA);
        cp16(st + 2 * TILEB + so, Bh + goffB);
        cp16(st + 3 * TILEB + so, Bl + goffB);
    }
}

__global__ __launch_bounds__(256, 1) void mma_gemm(
    const __nv_bfloat16* __restrict__ Ah, const __nv_bfloat16* __restrict__ Al,
    const __nv_bfloat16* __restrict__ Bh, const __nv_bfloat16* __restrict__ Bl,
    float* __restrict__ C, int ldc, int N, int K)
{
    extern __shared__ char sm[];
    uint32_t sbase = smem_u32(sm);
    const int tid    = threadIdx.x;
    const int lane   = tid & 31;
    const int warp   = tid >> 5;
    const int warp_m = warp >> 2;       // 0..1
    const int warp_n = warp & 3;        // 0..3
    const int row0 = blockIdx.y * 128;
    const int col0 = blockIdx.x * 128;

    float acc[4][4][4];
    #pragma unroll
    for (int mi = 0; mi < 4; ++mi)
        #pragma unroll
        for (int ni = 0; ni < 4; ++ni)
            #pragma unroll
            for (int e = 0; e < 4; ++e) acc[mi][ni][e] = 0.f;

    const int nch = K / BKC;

    // prologue: prefetch NS-1 stages
    #pragma unroll
    for (int p = 0; p < NS - 1; ++p) {
        if (p < nch) issue_stage(Ah, Al, Bh, Bl, row0, col0, K, p, sbase, p, tid);
        CP_COMMIT();
    }

    const uint32_t a_l = (uint32_t)((warp_m * 64 + (lane & 15)) * ROWB + (lane >> 4) * 16);
    const uint32_t b_l = (uint32_t)((warp_n * 32 + (lane & 7)) * ROWB + ((lane >> 3) & 1) * 16);

    for (int c = 0; c < nch; ++c) {
        CP_WAIT(NS - 2);         // stage c resident
        __syncthreads();         // all warps done with slot being refilled below
        int np = c + NS - 1;
        if (np < nch)
            issue_stage(Ah, Al, Bh, Bl, row0, col0, K, np, sbase, np & (NS - 1), tid);
        CP_COMMIT();             // unconditional: keeps group accounting exact

        uint32_t st = sbase + (c & (NS - 1)) * STG;

        #pragma unroll
        for (int ki = 0; ki < 2; ++ki) {
            uint32_t ah[4][4], al[4][4], bh[4][2], bl[4][2];
            #pragma unroll
            for (int mi = 0; mi < 4; ++mi) {
                uint32_t ad = st + a_l + mi * (16 * ROWB) + ki * 32;
                ldmx4(ah[mi], ad + 0 * TILEB);
                ldmx4(al[mi], ad + 1 * TILEB);
            }
            #pragma unroll
            for (int ni = 0; ni < 4; ++ni) {
                uint32_t bd = st + b_l + ni * (8 * ROWB) + ki * 32;
                ldmx2(bh[ni], bd + 2 * TILEB);
                ldmx2(bl[ni], bd + 3 * TILEB);
            }
            #pragma unroll
            for (int mi = 0; mi < 4; ++mi)
                #pragma unroll
                for (int ni = 0; ni < 4; ++ni) {
                    mma16816(acc[mi][ni], ah[mi], bh[ni]);
                    mma16816(acc[mi][ni], al[mi], bh[ni]);
                    mma16816(acc[mi][ni], ah[mi], bl[ni]);
                }
        }
    }

    // epilogue
    #pragma unroll
    for (int mi = 0; mi < 4; ++mi) {
        int row = row0 + warp_m * 64 + mi * 16 + (lane >> 2);
        #pragma unroll
        for (int ni = 0; ni < 4; ++ni) {
            int col = col0 + warp_n * 32 + ni * 8 + (lane & 3) * 2;
            if (col < N) {
                *(float2*)&C[(size_t)row * ldc + col] =
                    make_float2(acc[mi][ni][0], acc[mi][ni][1]);
                *(float2*)&C[(size_t)(row + 8) * ldc + col] =
                    make_float2(acc[mi][ni][2], acc[mi][ni][3]);
            }
        }
    }
}

// ================= RMSNorm (emits bf16 hi/lo) + k_pe RoPE =================
__global__ __launch_bounds__(256) void rmsnorm_rope_kernel(
    const float* __restrict__ a,
    float* __restrict__ kpe_out,
    __nv_bfloat16* __restrict__ cqh, __nv_bfloat16* __restrict__ cql,
    __nv_bfloat16* __restrict__ ckvh, __nv_bfloat16* __restrict__ ckvl,
    const float* __restrict__ wq,
    const float* __restrict__ wkv,
    const int* __restrict__ pos_ids)
{
    const int s   = blockIdx.x;
    const int tid = threadIdx.x;
    const float* row = a + (size_t)s * A_COLS;
    __shared__ float red[8];

    float ss = 0.f;
    for (int i = tid; i < Q_LORA; i += 256) { float v = row[i]; ss += v * v; }
    #pragma unroll
    for (int o = 16; o; o >>= 1) ss += __shfl_xor_sync(0xffffffffu, ss, o);
    if ((tid & 31) == 0) red[tid >> 5] = ss;
    __syncthreads();
    float tot = 0.f;
    #pragma unroll
    for (int w = 0; w < 8; w++) tot += red[w];
    float inv = rsqrtf(tot / (float)Q_LORA + 1e-6f);
    for (int i = tid; i < Q_LORA; i += 256) {
        float v = row[i] * inv * wq[i];
        __nv_bfloat16 h = __float2bfloat16(v);
        cqh[(size_t)s * Q_LORA + i] = h;
        cql[(size_t)s * Q_LORA + i] = __float2bfloat16(v - __bfloat162float(h));
    }
    __syncthreads();

    const float* row2 = row + Q_LORA;
    ss = 0.f;
    for (int i = tid; i < KV_LORA; i += 256) { float v = row2[i]; ss += v * v; }
    #pragma unroll
    for (int o = 16; o; o >>= 1) ss += __shfl_xor_sync(0xffffffffu, ss, o);
    if ((tid & 31) == 0) red[tid >> 5] = ss;
    __syncthreads();
    tot = 0.f;
    #pragma unroll
    for (int w = 0; w < 8; w++) tot += red[w];
    inv = rsqrtf(tot / (float)KV_LORA + 1e-6f);
    for (int i = tid; i < KV_LORA; i += 256) {
        float v = row2[i] * inv * wkv[i];
        __nv_bfloat16 h = __float2bfloat16(v);
        ckvh[(size_t)s * KV_LORA + i] = h;
        ckvl[(size_t)s * KV_LORA + i] = __float2bfloat16(v - __bfloat162float(h));
    }

    if (tid < 32) {
        int p = pos_ids[s];
        // inv_freq = 10000^(-tid/32) = exp2(-tid/32 * log2(10000))
        float inv_freq = exp2f(-(float)tid * (13.287712379549449f / 32.0f));
        float ang = (float)p * inv_freq;
        float c, sn;
        __sincosf(ang, &sn, &c);
        float x1 = row[Q_LORA + KV_LORA + tid];
        float x2 = row[Q_LORA + KV_LORA + 32 + tid];
        kpe_out[(size_t)s * ROPE + tid]      = x1 * c - x2 * sn;
        kpe_out[(size_t)s * ROPE + 32 + tid] = x2 * c + x1 * sn;
    }
}

// ================= q_pe RoPE =================
__global__ __launch_bounds__(256) void rope_q_kernel(
    float* __restrict__ q, const int* __restrict__ pos_ids)
{
    const int s = blockIdx.x;
    const int p = pos_ids[s];
    for (int idx = threadIdx.x; idx < H * 32; idx += 256) {
        int h = idx >> 5, i = idx & 31;
        float inv_freq = exp2f(-(float)i * (13.287712379549449f / 32.0f));
        float ang = (float)p * inv_freq;
        float c, sn;
        __sincosf(ang, &sn, &c);
        float* base = q + (size_t)s * Q_COLS + h * QDIM + NOPE;
        float x1 = base[i], x2 = base[i + 32];
        base[i]      = x1 * c - x2 * sn;
        base[i + 32] = x2 * c + x1 * sn;
    }
}

// ================= causal flash attention (fp32, conflict-free smem) ======
#define FA_BM 64
#define FA_BN 32
#define KSEG  52            // 48 floats + 4 pad per part segment
#define VSEG  36            // 32 floats + 4 pad per part segment

__global__ __launch_bounds__(256) void flash_kernel(
    const float* __restrict__ Q,
    const float* __restrict__ KV,
    const float* __restrict__ KPE,
    float* __restrict__ O)
{
    const int qt  = blockIdx.x;
    const int h   = blockIdx.y;
    const int qm0 = qt * FA_BM;
    const int tid = threadIdx.x;
    const int m    = tid >> 2;
    const int part = tid & 3;
    const int qrow = qm0 + m;

    __shared__ float Ks[FA_BN][4 * KSEG];   // 832B/row, part offsets {0,80,32,112} mod128
    __shared__ float Vs[FA_BN][4 * VSEG];   // 576B/row, part offsets {0,16,32,48} mod128

    float qreg[48];
    {
        const float* qp = Q + (size_t)qrow * Q_COLS + h * QDIM + part * 48;
        #pragma unroll
        for (int i = 0; i < 48; i += 4)
            *(float4*)&qreg[i] = *(const float4*)&qp[i];
    }

    float acc[32];
    #pragma unroll
    for (int j = 0; j < 32; j++) acc[j] = 0.f;
    float mi = -INFINITY, li = 0.f;

    for (int n0 = 0; n0 < qm0 + FA_BM; n0 += FA_BN) {
        __syncthreads();
        // K tile: 1536 float4 slots
        #pragma unroll
        for (int l = 0; l < 6; l++) {
            int v  = tid + l * 256;
            int n  = v / 48;
            int d  = (v % 48) * 4;          // float offset 0..188
            float4 f;
            if (d < NOPE)
                f = *(const float4*)&KV[(size_t)(n0 + n) * KV_COLS + h * 2 * NOPE + d];
            else
                f = *(const float4*)&KPE[(size_t)(n0 + n) * ROPE + (d - NOPE)];
            int p = d / 48, o = d % 48;
            *(float4*)&Ks[n][p * KSEG + o] = f;
        }
        // V tile: 1024 float4 slots
        #pragma unroll
        for (int l = 0; l < 4; l++) {
            int v = tid + l * 256;
            int n = v >> 5;
            int d = (v & 31) * 4;           // 0..124
            int p = d / 32, o = d % 32;
            *(float4*)&Vs[n][p * VSEG + o] =
                *(const float4*)&KV[(size_t)(n0 + n) * KV_COLS + h * 2 * NOPE + NOPE + d];
        }
        __syncthreads();

        float sc[FA_BN];
        #pragma unroll
        for (int n = 0; n < FA_BN; n++) {
            float sv = 0.f;
            const float* kp = &Ks[n][part * KSEG];
            #pragma unroll
            for (int i = 0; i < 48; i++) sv += qreg[i] * kp[i];
            sv += __shfl_xor_sync(0xffffffffu, sv, 1);
            sv += __shfl_xor_sync(0xffffffffu, sv, 2);
            sv *= ATT_SCALE;
            if (n0 + n > qrow) sv = -INFINITY;
            sc[n] = sv;
        }

        float tmax = sc[0];
        #pragma unroll
        for (int n = 1; n < FA_BN; n++) tmax = fmaxf(tmax, sc[n]);
        float newm = fmaxf(mi, tmax);
        float corr = __expf(mi - newm);
        li *= corr;
        #pragma unroll
        for (int j = 0; j < 32; j++) acc[j] *= corr;

        #pragma unroll
        for (int n = 0; n < FA_BN; n++) {
            float p = __expf(sc[n] - newm);
            li += p;
            const float* vp = &Vs[n][part * VSEG];
            #pragma unroll
            for (int j = 0; j < 32; j++) acc[j] += p * vp[j];
        }
        mi = newm;
    }

    float invl = 1.f / li;
    float* op = O + (size_t)qrow * O_COLS + h * VDIM + part * 32;
    #pragma unroll
    for (int j = 0; j < 32; j++) op[j] = acc[j] * invl;
}

// ================= launch =================
extern "C" void kernel_launch(void* const* d_in, const int* in_sizes, int n_in,
                              void* d_out, int out_size)
{
    const int*   pos   = (const int*)  d_in[0];
    const float* hid   = (const float*)d_in[1];
    const float* w_a   = (const float*)d_in[2];
    const float* wq_ln = (const float*)d_in[3];
    const float* wkv_ln= (const float*)d_in[4];
    const float* w_q_b = (const float*)d_in[5];
    const float* w_kv_b= (const float*)d_in[6];
    const float* w_o   = (const float*)d_in[7];
    float* out = (float*)d_out;

    float *a, *kpe, *q, *kv, *attn;
    cudaGetSymbolAddress((void**)&a,    g_a);
    cudaGetSymbolAddress((void**)&kpe,  g_kpe);
    cudaGetSymbolAddress((void**)&q,    g_q);
    cudaGetSymbolAddress((void**)&kv,   g_kv);
    cudaGetSymbolAddress((void**)&attn, g_attn);

    __nv_bfloat16 *h_hi, *h_lo, *cq_hi, *cq_lo, *ckv_hi, *ckv_lo, *at_hi, *at_lo;
    __nv_bfloat16 *wa_hi, *wa_lo, *wqb_hi, *wqb_lo, *wkvb_hi, *wkvb_lo, *wo_hi, *wo_lo;
    cudaGetSymbolAddress((void**)&h_hi,   g_h_hi);   cudaGetSymbolAddress((void**)&h_lo,   g_h_lo);
    cudaGetSymbolAddress((void**)&cq_hi,  g_cq_hi);  cudaGetSymbolAddress((void**)&cq_lo,  g_cq_lo);
    cudaGetSymbolAddress((void**)&ckv_hi, g_ckv_hi); cudaGetSymbolAddress((void**)&ckv_lo, g_ckv_lo);
    cudaGetSymbolAddress((void**)&at_hi,  g_at_hi);  cudaGetSymbolAddress((void**)&at_lo,  g_at_lo);
    cudaGetSymbolAddress((void**)&wa_hi,  g_wa_hi);  cudaGetSymbolAddress((void**)&wa_lo,  g_wa_lo);
    cudaGetSymbolAddress((void**)&wqb_hi, g_wqb_hi); cudaGetSymbolAddress((void**)&wqb_lo, g_wqb_lo);
    cudaGetSymbolAddress((void**)&wkvb_hi,g_wkvb_hi);cudaGetSymbolAddress((void**)&wkvb_lo,g_wkvb_lo);
    cudaGetSymbolAddress((void**)&wo_hi,  g_wo_hi);  cudaGetSymbolAddress((void**)&wo_lo,  g_wo_lo);

    cudaFuncSetAttribute(mma_gemm, cudaFuncAttributeMaxDynamicSharedMemorySize, GSMEM);

    // conversions (bf16 hi/lo split)
    cvt_split<<<4096, 256>>>(w_a,   wa_hi,  wa_lo,  A_COLS_P * HID / 4, HID,    A_COLS);
    cvt_split<<<4096, 256>>>(w_q_b, wqb_hi, wqb_lo, Q_COLS * Q_LORA / 4, Q_LORA, Q_COLS);
    cvt_split<<<4096, 256>>>(w_kv_b,wkvb_hi,wkvb_lo,KV_COLS * KV_LORA / 4, KV_LORA, KV_COLS);
    cvt_split<<<4096, 256>>>(w_o,   wo_hi,  wo_lo,  HID * O_COLS / 4, O_COLS, HID);
    cvt_split<<<4096, 256>>>(hid,   h_hi,   h_lo,   S * HID / 4, HID, S);

    // 1) fused-A GEMM -> g_a (fp32)
    mma_gemm<<<dim3(A_COLS_P / 128, S / 128), 256, GSMEM>>>(
        h_hi, h_lo, wa_hi, wa_lo, a, A_COLS, A_COLS, HID);

    // 2) RMSNorm -> bf16 hi/lo + k_pe rope
    rmsnorm_rope_kernel<<<S, 256>>>(a, kpe, cq_hi, cq_lo, ckv_hi, ckv_lo,
                                    wq_ln, wkv_ln, pos);

    // 3) q GEMM
    mma_gemm<<<dim3(Q_COLS / 128, S / 128), 256, GSMEM>>>(
        cq_hi, cq_lo, wqb_hi, wqb_lo, q, Q_COLS, Q_COLS, Q_LORA);

    // 4) kv GEMM
    mma_gemm<<<dim3(KV_COLS / 128, S / 128), 256, GSMEM>>>(
        ckv_hi, ckv_lo, wkvb_hi, wkvb_lo, kv, KV_COLS, KV_COLS, KV_LORA);

    // 5) rope on q_pe
    rope_q_kernel<<<S, 256>>>(q, pos);

    // 6) flash attention
    flash_kernel<<<dim3(S / FA_BM, H), 256>>>(q, kv, kpe, attn);

    // 7) attn split + output GEMM
    cvt_split<<<4096, 256>>>(attn, at_hi, at_lo, S * O_COLS / 4, O_COLS, S);
    mma_gemm<<<dim3(HID / 128, S / 128), 256, GSMEM>>>(
        at_hi, at_lo, wo_hi, wo_lo, out, HID, HID, O_COLS);
}

// round 5
// speedup vs baseline: 5.2947x; 2.1152x over previous
#include <cuda_runtime.h>
#include <cuda_bf16.h>
#include <math.h>
#include <stdint.h>

// ---------------- problem constants ----------------
#define S        2048
#define HID      4096
#define H        32
#define Q_LORA   1536
#define KV_LORA  512
#define NOPE     128
#define ROPE     64
#define VDIM     128
#define A_COLS   (Q_LORA + KV_LORA + ROPE)   // 2112
#define A_COLS_P 2176
#define QDIM     (NOPE + ROPE)               // 192
#define Q_COLS   (H * QDIM)                  // 6144
#define KV_COLS  (H * 2 * NOPE)              // 8192
#define O_COLS   (H * VDIM)                  // 4096
#define ATT_SCALE 0.07216878364870322992f    // 1/sqrt(192)

// ---------------- scratch ----------------
__device__ __align__(256) float g_a[S * A_COLS];
__device__ __align__(256) float g_kpe[S * ROPE];
__device__ __align__(256) float g_q[S * Q_COLS];
__device__ __align__(256) float g_kv[S * KV_COLS];
__device__ __align__(256) float g_attn[S * O_COLS];

__device__ __align__(256) __nv_bfloat16 g_h_hi[S * HID],       g_h_lo[S * HID];
__device__ __align__(256) __nv_bfloat16 g_cq_hi[S * Q_LORA],   g_cq_lo[S * Q_LORA];
__device__ __align__(256) __nv_bfloat16 g_ckv_hi[S * KV_LORA], g_ckv_lo[S * KV_LORA];
__device__ __align__(256) __nv_bfloat16 g_at_hi[S * O_COLS],   g_at_lo[S * O_COLS];
__device__ __align__(256) __nv_bfloat16 g_wa_hi[A_COLS_P * HID],   g_wa_lo[A_COLS_P * HID];
__device__ __align__(256) __nv_bfloat16 g_wqb_hi[Q_COLS * Q_LORA], g_wqb_lo[Q_COLS * Q_LORA];
__device__ __align__(256) __nv_bfloat16 g_wkvb_hi[KV_COLS * KV_LORA], g_wkvb_lo[KV_COLS * KV_LORA];
__device__ __align__(256) __nv_bfloat16 g_wo_hi[HID * O_COLS], g_wo_lo[HID * O_COLS];
// flash operands (bf16 hi/lo)
__device__ __align__(256) __nv_bfloat16 g_qs_hi[S * Q_COLS],  g_qs_lo[S * Q_COLS];
__device__ __align__(256) __nv_bfloat16 g_kvh[S * KV_COLS],   g_kvl[S * KV_COLS];
__device__ __align__(256) __nv_bfloat16 g_kpeh[S * ROPE],     g_kpel[S * ROPE];

// ================= portable PTX helpers =================
__device__ __forceinline__ uint32_t smem_u32(const void* p) {
    uint32_t a;
    asm("{ .reg .u64 t; cvta.to.shared.u64 t, %1; cvt.u32.u64 %0, t; }"
        : "=r"(a) : "l"(p));
    return a;
}
__device__ __forceinline__ void cp16(uint32_t dst, const void* src) {
    asm volatile("cp.async.cg.shared.global [%0], [%1], 16;" :: "r"(dst), "l"(src));
}
#define CP_COMMIT()  asm volatile("cp.async.commit_group;" ::: "memory")
#define CP_WAIT(n)   asm volatile("cp.async.wait_group %0;" :: "n"(n) : "memory")

__device__ __forceinline__ void ldmx4(uint32_t* r, uint32_t addr) {
    asm volatile("ldmatrix.sync.aligned.m8n8.x4.shared.b16 {%0,%1,%2,%3}, [%4];"
                 : "=r"(r[0]), "=r"(r[1]), "=r"(r[2]), "=r"(r[3]) : "r"(addr));
}
__device__ __forceinline__ void ldmx2(uint32_t* r, uint32_t addr) {
    asm volatile("ldmatrix.sync.aligned.m8n8.x2.shared.b16 {%0,%1}, [%2];"
                 : "=r"(r[0]), "=r"(r[1]) : "r"(addr));
}
__device__ __forceinline__ void ldmx4t(uint32_t* r, uint32_t addr) {
    asm volatile("ldmatrix.sync.aligned.m8n8.x4.trans.shared.b16 {%0,%1,%2,%3}, [%4];"
                 : "=r"(r[0]), "=r"(r[1]), "=r"(r[2]), "=r"(r[3]) : "r"(addr));
}
__device__ __forceinline__ void mma16816(float* c, const uint32_t* a, const uint32_t* b) {
    asm volatile(
        "mma.sync.aligned.m16n8k16.row.col.f32.bf16.bf16.f32 "
        "{%0,%1,%2,%3},{%4,%5,%6,%7},{%8,%9},{%0,%1,%2,%3};"
        : "+f"(c[0]), "+f"(c[1]), "+f"(c[2]), "+f"(c[3])
        : "r"(a[0]), "r"(a[1]), "r"(a[2]), "r"(a[3]), "r"(b[0]), "r"(b[1]));
}
__device__ __forceinline__ uint32_t packbf2(float x, float y) {
    __nv_bfloat162 b = __floats2bfloat162_rn(x, y);
    return *(uint32_t*)&b;
}

// ================= fp32 -> bf16 hi/lo split (optional scale) ==============
__global__ __launch_bounds__(256) void cvt_split(
    const float* __restrict__ src,
    __nv_bfloat16* __restrict__ hi, __nv_bfloat16* __restrict__ lo,
    int total4, int cols, int rows, float scale)
{
    for (int i = blockIdx.x * 256 + threadIdx.x; i < total4; i += gridDim.x * 256) {
        int e = i * 4;
        int r = e / cols;
        float4 f = make_float4(0.f, 0.f, 0.f, 0.f);
        if (r < rows) f = *(const float4*)(src + (size_t)e);
        f.x *= scale; f.y *= scale; f.z *= scale; f.w *= scale;
        __nv_bfloat16 h0 = __float2bfloat16(f.x);
        __nv_bfloat16 h1 = __float2bfloat16(f.y);
        __nv_bfloat16 h2 = __float2bfloat16(f.z);
        __nv_bfloat16 h3 = __float2bfloat16(f.w);
        __nv_bfloat16 l0 = __float2bfloat16(f.x - __bfloat162float(h0));
        __nv_bfloat16 l1 = __float2bfloat16(f.y - __bfloat162float(h1));
        __nv_bfloat16 l2 = __float2bfloat16(f.z - __bfloat162float(h2));
        __nv_bfloat16 l3 = __float2bfloat16(f.w - __bfloat162float(h3));
        *(__nv_bfloat162*)(hi + (size_t)e)     = __nv_bfloat162(h0, h1);
        *(__nv_bfloat162*)(hi + (size_t)e + 2) = __nv_bfloat162(h2, h3);
        *(__nv_bfloat162*)(lo + (size_t)e)     = __nv_bfloat162(l0, l1);
        *(__nv_bfloat162*)(lo + (size_t)e + 2) = __nv_bfloat162(l2, l3);
    }
}

// ================= split-bf16 HMMA GEMM (4-stage cp.async ring) ==========
#define BKC   32
#define ROWB  80
#define TILEB (128 * ROWB)
#define STG   (4 * TILEB)
#define NS    4
#define GSMEM (NS * STG)

__device__ __forceinline__ void issue_stage(
    const __nv_bfloat16* __restrict__ Ah, const __nv_bfloat16* __restrict__ Al,
    const __nv_bfloat16* __restrict__ Bh, const __nv_bfloat16* __restrict__ Bl,
    int row0, int col0, int K, int c, uint32_t sbase, int slot, int tid)
{
    uint32_t st = sbase + slot * STG;
    #pragma unroll
    for (int l = 0; l < 2; ++l) {
        int v = tid + l * 256;
        int r = v >> 2;
        int j = v & 3;
        size_t goffA = (size_t)(row0 + r) * K + c * BKC + j * 8;
        size_t goffB = (size_t)(col0 + r) * K + c * BKC + j * 8;
        uint32_t so = r * ROWB + j * 16;
        cp16(st + 0 * TILEB + so, Ah + goffA);
        cp16(st + 1 * TILEB + so, Al + goffA);
        cp16(st + 2 * TILEB + so, Bh + goffB);
        cp16(st + 3 * TILEB + so, Bl + goffB);
    }
}

__global__ __launch_bounds__(256, 1) void mma_gemm(
    const __nv_bfloat16* __restrict__ Ah, const __nv_bfloat16* __restrict__ Al,
    const __nv_bfloat16* __restrict__ Bh, const __nv_bfloat16* __restrict__ Bl,
    float* __restrict__ C, int ldc, int N, int K)
{
    extern __shared__ char sm[];
    uint32_t sbase = smem_u32(sm);
    const int tid    = threadIdx.x;
    const int lane   = tid & 31;
    const int warp   = tid >> 5;
    const int warp_m = warp >> 2;
    const int warp_n = warp & 3;
    const int row0 = blockIdx.y * 128;
    const int col0 = blockIdx.x * 128;

    float acc[4][4][4];
    #pragma unroll
    for (int mi = 0; mi < 4; ++mi)
        #pragma unroll
        for (int ni = 0; ni < 4; ++ni)
            #pragma unroll
            for (int e = 0; e < 4; ++e) acc[mi][ni][e] = 0.f;

    const int nch = K / BKC;

    #pragma unroll
    for (int p = 0; p < NS - 1; ++p) {
        if (p < nch) issue_stage(Ah, Al, Bh, Bl, row0, col0, K, p, sbase, p, tid);
        CP_COMMIT();
    }

    const uint32_t a_l = (uint32_t)((warp_m * 64 + (lane & 15)) * ROWB + (lane >> 4) * 16);
    const uint32_t b_l = (uint32_t)((warp_n * 32 + (lane & 7)) * ROWB + ((lane >> 3) & 1) * 16);

    for (int c = 0; c < nch; ++c) {
        CP_WAIT(NS - 2);
        __syncthreads();
        int np = c + NS - 1;
        if (np < nch)
            issue_stage(Ah, Al, Bh, Bl, row0, col0, K, np, sbase, np & (NS - 1), tid);
        CP_COMMIT();

        uint32_t st = sbase + (c & (NS - 1)) * STG;

        #pragma unroll
        for (int ki = 0; ki < 2; ++ki) {
            uint32_t ah[4][4], al[4][4], bh[4][2], bl[4][2];
            #pragma unroll
            for (int mi = 0; mi < 4; ++mi) {
                uint32_t ad = st + a_l + mi * (16 * ROWB) + ki * 32;
                ldmx4(ah[mi], ad + 0 * TILEB);
                ldmx4(al[mi], ad + 1 * TILEB);
            }
            #pragma unroll
            for (int ni = 0; ni < 4; ++ni) {
                uint32_t bd = st + b_l + ni * (8 * ROWB) + ki * 32;
                ldmx2(bh[ni], bd + 2 * TILEB);
                ldmx2(bl[ni], bd + 3 * TILEB);
            }
            #pragma unroll
            for (int mi = 0; mi < 4; ++mi)
                #pragma unroll
                for (int ni = 0; ni < 4; ++ni) {
                    mma16816(acc[mi][ni], ah[mi], bh[ni]);
                    mma16816(acc[mi][ni], al[mi], bh[ni]);
                    mma16816(acc[mi][ni], ah[mi], bl[ni]);
                }
        }
    }

    #pragma unroll
    for (int mi = 0; mi < 4; ++mi) {
        int row = row0 + warp_m * 64 + mi * 16 + (lane >> 2);
        #pragma unroll
        for (int ni = 0; ni < 4; ++ni) {
            int col = col0 + warp_n * 32 + ni * 8 + (lane & 3) * 2;
            if (col < N) {
                *(float2*)&C[(size_t)row * ldc + col] =
                    make_float2(acc[mi][ni][0], acc[mi][ni][1]);
                *(float2*)&C[(size_t)(row + 8) * ldc + col] =
                    make_float2(acc[mi][ni][2], acc[mi][ni][3]);
            }
        }
    }
}

// ================= RMSNorm (emits bf16 hi/lo) + k_pe RoPE =================
__global__ __launch_bounds__(256) void rmsnorm_rope_kernel(
    const float* __restrict__ a,
    float* __restrict__ kpe_out,
    __nv_bfloat16* __restrict__ cqh, __nv_bfloat16* __restrict__ cql,
    __nv_bfloat16* __restrict__ ckvh, __nv_bfloat16* __restrict__ ckvl,
    const float* __restrict__ wq,
    const float* __restrict__ wkv,
    const int* __restrict__ pos_ids)
{
    const int s   = blockIdx.x;
    const int tid = threadIdx.x;
    const float* row = a + (size_t)s * A_COLS;
    __shared__ float red[8];

    float ss = 0.f;
    for (int i = tid; i < Q_LORA; i += 256) { float v = row[i]; ss += v * v; }
    #pragma unroll
    for (int o = 16; o; o >>= 1) ss += __shfl_xor_sync(0xffffffffu, ss, o);
    if ((tid & 31) == 0) red[tid >> 5] = ss;
    __syncthreads();
    float tot = 0.f;
    #pragma unroll
    for (int w = 0; w < 8; w++) tot += red[w];
    float inv = rsqrtf(tot / (float)Q_LORA + 1e-6f);
    for (int i = tid; i < Q_LORA; i += 256) {
        float v = row[i] * inv * wq[i];
        __nv_bfloat16 h = __float2bfloat16(v);
        cqh[(size_t)s * Q_LORA + i] = h;
        cql[(size_t)s * Q_LORA + i] = __float2bfloat16(v - __bfloat162float(h));
    }
    __syncthreads();

    const float* row2 = row + Q_LORA;
    ss = 0.f;
    for (int i = tid; i < KV_LORA; i += 256) { float v = row2[i]; ss += v * v; }
    #pragma unroll
    for (int o = 16; o; o >>= 1) ss += __shfl_xor_sync(0xffffffffu, ss, o);
    if ((tid & 31) == 0) red[tid >> 5] = ss;
    __syncthreads();
    tot = 0.f;
    #pragma unroll
    for (int w = 0; w < 8; w++) tot += red[w];
    inv = rsqrtf(tot / (float)KV_LORA + 1e-6f);
    for (int i = tid; i < KV_LORA; i += 256) {
        float v = row2[i] * inv * wkv[i];
        __nv_bfloat16 h = __float2bfloat16(v);
        ckvh[(size_t)s * KV_LORA + i] = h;
        ckvl[(size_t)s * KV_LORA + i] = __float2bfloat16(v - __bfloat162float(h));
    }

    if (tid < 32) {
        int p = pos_ids[s];
        float inv_freq = exp2f(-(float)tid * (13.287712379549449f / 32.0f));
        float ang = (float)p * inv_freq;
        float c, sn;
        __sincosf(ang, &sn, &c);
        float x1 = row[Q_LORA + KV_LORA + tid];
        float x2 = row[Q_LORA + KV_LORA + 32 + tid];
        kpe_out[(size_t)s * ROPE + tid]      = x1 * c - x2 * sn;
        kpe_out[(size_t)s * ROPE + 32 + tid] = x2 * c + x1 * sn;
    }
}

// ================= q_pe RoPE =================
__global__ __launch_bounds__(256) void rope_q_kernel(
    float* __restrict__ q, const int* __restrict__ pos_ids)
{
    const int s = blockIdx.x;
    const int p = pos_ids[s];
    for (int idx = threadIdx.x; idx < H * 32; idx += 256) {
        int h = idx >> 5, i = idx & 31;
        float inv_freq = exp2f(-(float)i * (13.287712379549449f / 32.0f));
        float ang = (float)p * inv_freq;
        float c, sn;
        __sincosf(ang, &sn, &c);
        float* base = q + (size_t)s * Q_COLS + h * QDIM + NOPE;
        float x1 = base[i], x2 = base[i + 32];
        base[i]      = x1 * c - x2 * sn;
        base[i + 32] = x2 * c + x1 * sn;
    }
}

// ================= HMMA flash attention ==================================
// CTA: 64 queries x 64-key tiles, 128 threads (4 warps x 16 rows).
// smem: Q hi/lo resident (400B rows), 2-stage K(400B)/V(272B) ring.
#define QSTR   400
#define VSTR   272
#define SM_QH  0
#define SM_QL  25600
#define SM_ST0 51200
#define KLOFF  25600          // KL offset within stage
#define VHOFF  51200          // VH offset within stage
#define VLOFF  68608
#define STGSZ  86016
#define FSMEM  (SM_ST0 + 2 * STGSZ)   // 223232

__device__ __forceinline__ void issue_kv(
    const __nv_bfloat16* __restrict__ KVh, const __nv_bfloat16* __restrict__ KVl,
    const __nv_bfloat16* __restrict__ KPh, const __nv_bfloat16* __restrict__ KPl,
    int n0, int h, uint32_t stg, int tid)
{
    #pragma unroll
    for (int l = 0; l < 12; ++l) {                // 64*24 / 128
        int i = tid + l * 128;
        int r = i / 24, j = i % 24;
        uint32_t dst = stg + r * QSTR + j * 16;
        if (j < 16) {
            size_t off = (size_t)(n0 + r) * KV_COLS + h * 2 * NOPE + j * 8;
            cp16(dst,         KVh + off);
            cp16(dst + KLOFF, KVl + off);
        } else {
            size_t off = (size_t)(n0 + r) * ROPE + (j - 16) * 8;
            cp16(dst,         KPh + off);
            cp16(dst + KLOFF, KPl + off);
        }
    }
    #pragma unroll
    for (int l = 0; l < 8; ++l) {                 // 64*16 / 128
        int i = tid + l * 128;
        int r = i / 16, j = i % 16;
        size_t off = (size_t)(n0 + r) * KV_COLS + h * 2 * NOPE + NOPE + j * 8;
        uint32_t dst = stg + VHOFF + r * VSTR + j * 16;
        cp16(dst, KVh + off);
        cp16(dst + (VLOFF - VHOFF), KVl + off);
    }
}

__global__ __launch_bounds__(128, 1) void flash_mma(
    const __nv_bfloat16* __restrict__ Qh, const __nv_bfloat16* __restrict__ Ql,
    const __nv_bfloat16* __restrict__ KVh, const __nv_bfloat16* __restrict__ KVl,
    const __nv_bfloat16* __restrict__ KPh, const __nv_bfloat16* __restrict__ KPl,
    float* __restrict__ O)
{
    extern __shared__ char sm[];
    uint32_t sb = smem_u32(sm);
    const int qt = blockIdx.x, h = blockIdx.y;
    const int qm0 = qt * 64;
    const int tid = threadIdx.x, lane = tid & 31, warp = tid >> 5;

    // Q tile (hi+lo) load
    #pragma unroll
    for (int l = 0; l < 12; ++l) {
        int i = tid + l * 128;
        int r = i / 24, j = i % 24;
        size_t off = (size_t)(qm0 + r) * Q_COLS + h * QDIM + j * 8;
        cp16(sb + SM_QH + r * QSTR + j * 16, Qh + off);
        cp16(sb + SM_QL + r * QSTR + j * 16, Ql + off);
    }
    issue_kv(KVh, KVl, KPh, KPl, 0, h, sb + SM_ST0, tid);
    CP_COMMIT();

    float acc[16][4];
    #pragma unroll
    for (int vt = 0; vt < 16; ++vt)
        #pragma unroll
        for (int e = 0; e < 4; ++e) acc[vt][e] = 0.f;
    float miA = -1e30f, miB = -1e30f, liA = 0.f, liB = 0.f;

    const int T = qt + 1;
    const int rA = qm0 + warp * 16 + (lane >> 2);

    for (int t = 0; t < T; ++t) {
        if (t + 1 < T) {
            issue_kv(KVh, KVl, KPh, KPl, (t + 1) * 64, h,
                     sb + SM_ST0 + ((t + 1) & 1) * STGSZ, tid);
            CP_COMMIT();
            CP_WAIT(1);
        } else {
            CP_WAIT(0);
        }
        __syncthreads();
        uint32_t stg = sb + SM_ST0 + (t & 1) * STGSZ;

        // ---- scores: S = Q K^T (3-term split) ----
        float sc[8][4];
        #pragma unroll
        for (int nt = 0; nt < 8; ++nt)
            #pragma unroll
            for (int e = 0; e < 4; ++e) sc[nt][e] = 0.f;

        const uint32_t qa = sb + (warp * 16 + (lane & 15)) * QSTR + (lane >> 4) * 16;
        #pragma unroll
        for (int kk = 0; kk < 12; ++kk) {
            uint32_t aH[4], aL[4];
            ldmx4(aH, qa + SM_QH + kk * 32);
            ldmx4(aL, qa + SM_QL + kk * 32);
            #pragma unroll
            for (int np = 0; np < 4; ++np) {
                uint32_t bH[4], bL[4];
                uint32_t ba = stg + ((np * 2 + (lane >> 4)) * 8 + (lane & 7)) * QSTR
                              + ((lane >> 3) & 1) * 16 + kk * 32;
                ldmx4(bH, ba);
                ldmx4(bL, ba + KLOFF);
                mma16816(sc[np * 2],     aH, bH);
                mma16816(sc[np * 2],     aL, bH);
                mma16816(sc[np * 2],     aH, bL);
                mma16816(sc[np * 2 + 1], aH, bH + 2);
                mma16816(sc[np * 2 + 1], aL, bH + 2);
                mma16816(sc[np * 2 + 1], aH, bL + 2);
            }
        }

        // ---- causal mask (only diagonal tile) ----
        if (t == qt) {
            #pragma unroll
            for (int nt = 0; nt < 8; ++nt) {
                int c0 = qm0 + nt * 8 + (lane & 3) * 2;
                if (c0     > rA)     sc[nt][0] = -1e30f;
                if (c0 + 1 > rA)     sc[nt][1] = -1e30f;
                if (c0     > rA + 8) sc[nt][2] = -1e30f;
                if (c0 + 1 > rA + 8) sc[nt][3] = -1e30f;
            }
        }

        // ---- online softmax ----
        float mA = -1e30f, mB = -1e30f;
        #pragma unroll
        for (int nt = 0; nt < 8; ++nt) {
            mA = fmaxf(mA, fmaxf(sc[nt][0], sc[nt][1]));
            mB = fmaxf(mB, fmaxf(sc[nt][2], sc[nt][3]));
        }
        mA = fmaxf(mA, __shfl_xor_sync(0xffffffffu, mA, 1));
        mA = fmaxf(mA, __shfl_xor_sync(0xffffffffu, mA, 2));
        mB = fmaxf(mB, __shfl_xor_sync(0xffffffffu, mB, 1));
        mB = fmaxf(mB, __shfl_xor_sync(0xffffffffu, mB, 2));
        float nmA = fmaxf(miA, mA), nmB = fmaxf(miB, mB);
        float cA = __expf(miA - nmA), cB = __expf(miB - nmB);
        miA = nmA; miB = nmB;

        float sA = 0.f, sB = 0.f;
        #pragma unroll
        for (int nt = 0; nt < 8; ++nt) {
            sc[nt][0] = __expf(sc[nt][0] - nmA); sA += sc[nt][0];
            sc[nt][1] = __expf(sc[nt][1] - nmA); sA += sc[nt][1];
            sc[nt][2] = __expf(sc[nt][2] - nmB); sB += sc[nt][2];
            sc[nt][3] = __expf(sc[nt][3] - nmB); sB += sc[nt][3];
        }
        sA += __shfl_xor_sync(0xffffffffu, sA, 1);
        sA += __shfl_xor_sync(0xffffffffu, sA, 2);
        sB += __shfl_xor_sync(0xffffffffu, sB, 1);
        sB += __shfl_xor_sync(0xffffffffu, sB, 2);
        liA = liA * cA + sA;
        liB = liB * cB + sB;
        #pragma unroll
        for (int vt = 0; vt < 16; ++vt) {
            acc[vt][0] *= cA; acc[vt][1] *= cA;
            acc[vt][2] *= cB; acc[vt][3] *= cB;
        }

        // ---- attn += P V (3-term split) ----
        #pragma unroll
        for (int kp = 0; kp < 4; ++kp) {
            uint32_t aPh[4], aPl[4];
            #pragma unroll
            for (int q2 = 0; q2 < 2; ++q2) {       // q2=0: nt=2kp, q2=1: nt=2kp+1
                const float* s0 = sc[2 * kp + q2];
                aPh[q2 * 2 + 0] = packbf2(s0[0], s0[1]);
                aPh[q2 * 2 + 1] = packbf2(s0[2], s0[3]);
                float2 hA = __bfloat1622float2(*(__nv_bfloat162*)&aPh[q2 * 2 + 0]);
                float2 hB = __bfloat1622float2(*(__nv_bfloat162*)&aPh[q2 * 2 + 1]);
                aPl[q2 * 2 + 0] = packbf2(s0[0] - hA.x, s0[1] - hA.y);
                aPl[q2 * 2 + 1] = packbf2(s0[2] - hB.x, s0[3] - hB.y);
            }
            // a-frag order: {rowsA k0-7, rowsB k0-7, rowsA k8-15, rowsB k8-15}
            uint32_t aH[4] = { aPh[0], aPh[1], aPh[2], aPh[3] };
            uint32_t aL[4] = { aPl[0], aPl[1], aPl[2], aPl[3] };
            #pragma unroll
            for (int vp = 0; vp < 8; ++vp) {
                uint32_t bH[4], bL[4];
                uint32_t va = stg + VHOFF + (kp * 16 + (lane & 15)) * VSTR
                              + (vp * 2 + (lane >> 4)) * 16;
                ldmx4t(bH, va);
                ldmx4t(bL, va + (VLOFF - VHOFF));
                mma16816(acc[vp * 2],     aH, bH);
                mma16816(acc[vp * 2],     aL, bH);
                mma16816(acc[vp * 2],     aH, bL);
                mma16816(acc[vp * 2 + 1], aH, bH + 2);
                mma16816(acc[vp * 2 + 1], aL, bH + 2);
                mma16816(acc[vp * 2 + 1], aH, bL + 2);
            }
        }
        __syncthreads();
    }

    float rlA = 1.f / liA, rlB = 1.f / liB;
    #pragma unroll
    for (int vt = 0; vt < 16; ++vt) {
        int col = h * VDIM + vt * 8 + (lane & 3) * 2;
        *(float2*)&O[(size_t)rA * O_COLS + col] =
            make_float2(acc[vt][0] * rlA, acc[vt][1] * rlA);
        *(float2*)&O[(size_t)(rA + 8) * O_COLS + col] =
            make_float2(acc[vt][2] * rlB, acc[vt][3] * rlB);
    }
}

// ================= launch =================
extern "C" void kernel_launch(void* const* d_in, const int* in_sizes, int n_in,
                              void* d_out, int out_size)
{
    const int*   pos   = (const int*)  d_in[0];
    const float* hid   = (const float*)d_in[1];
    const float* w_a   = (const float*)d_in[2];
    const float* wq_ln = (const float*)d_in[3];
    const float* wkv_ln= (const float*)d_in[4];
    const float* w_q_b = (const float*)d_in[5];
    const float* w_kv_b= (const float*)d_in[6];
    const float* w_o   = (const float*)d_in[7];
    float* out = (float*)d_out;

    float *a, *kpe, *q, *kv, *attn;
    cudaGetSymbolAddress((void**)&a,    g_a);
    cudaGetSymbolAddress((void**)&kpe,  g_kpe);
    cudaGetSymbolAddress((void**)&q,    g_q);
    cudaGetSymbolAddress((void**)&kv,   g_kv);
    cudaGetSymbolAddress((void**)&attn, g_attn);

    __nv_bfloat16 *h_hi, *h_lo, *cq_hi, *cq_lo, *ckv_hi, *ckv_lo, *at_hi, *at_lo;
    __nv_bfloat16 *wa_hi, *wa_lo, *wqb_hi, *wqb_lo, *wkvb_hi, *wkvb_lo, *wo_hi, *wo_lo;
    __nv_bfloat16 *qs_hi, *qs_lo, *kvh, *kvl, *kpeh, *kpel;
    cudaGetSymbolAddress((void**)&h_hi,   g_h_hi);   cudaGetSymbolAddress((void**)&h_lo,   g_h_lo);
    cudaGetSymbolAddress((void**)&cq_hi,  g_cq_hi);  cudaGetSymbolAddress((void**)&cq_lo,  g_cq_lo);
    cudaGetSymbolAddress((void**)&ckv_hi, g_ckv_hi); cudaGetSymbolAddress((void**)&ckv_lo, g_ckv_lo);
    cudaGetSymbolAddress((void**)&at_hi,  g_at_hi);  cudaGetSymbolAddress((void**)&at_lo,  g_at_lo);
    cudaGetSymbolAddress((void**)&wa_hi,  g_wa_hi);  cudaGetSymbolAddress((void**)&wa_lo,  g_wa_lo);
    cudaGetSymbolAddress((void**)&wqb_hi, g_wqb_hi); cudaGetSymbolAddress((void**)&wqb_lo, g_wqb_lo);
    cudaGetSymbolAddress((void**)&wkvb_hi,g_wkvb_hi);cudaGetSymbolAddress((void**)&wkvb_lo,g_wkvb_lo);
    cudaGetSymbolAddress((void**)&wo_hi,  g_wo_hi);  cudaGetSymbolAddress((void**)&wo_lo,  g_wo_lo);
    cudaGetSymbolAddress((void**)&qs_hi,  g_qs_hi);  cudaGetSymbolAddress((void**)&qs_lo,  g_qs_lo);
    cudaGetSymbolAddress((void**)&kvh,    g_kvh);    cudaGetSymbolAddress((void**)&kvl,    g_kvl);
    cudaGetSymbolAddress((void**)&kpeh,   g_kpeh);   cudaGetSymbolAddress((void**)&kpel,   g_kpel);

    cudaFuncSetAttribute(mma_gemm, cudaFuncAttributeMaxDynamicSharedMemorySize, GSMEM);
    cudaFuncSetAttribute(flash_mma, cudaFuncAttributeMaxDynamicSharedMemorySize, FSMEM);

    // weight + hidden conversions
    cvt_split<<<4096, 256>>>(w_a,   wa_hi,  wa_lo,  A_COLS_P * HID / 4, HID,    A_COLS, 1.f);
    cvt_split<<<4096, 256>>>(w_q_b, wqb_hi, wqb_lo, Q_COLS * Q_LORA / 4, Q_LORA, Q_COLS, 1.f);
    cvt_split<<<4096, 256>>>(w_kv_b,wkvb_hi,wkvb_lo,KV_COLS * KV_LORA / 4, KV_LORA, KV_COLS, 1.f);
    cvt_split<<<4096, 256>>>(w_o,   wo_hi,  wo_lo,  HID * O_COLS / 4, O_COLS, HID, 1.f);
    cvt_split<<<4096, 256>>>(hid,   h_hi,   h_lo,   S * HID / 4, HID, S, 1.f);

    // 1) fused-A GEMM
    mma_gemm<<<dim3(A_COLS_P / 128, S / 128), 256, GSMEM>>>(
        h_hi, h_lo, wa_hi, wa_lo, a, A_COLS, A_COLS, HID);

    // 2) RMSNorm + k_pe rope
    rmsnorm_rope_kernel<<<S, 256>>>(a, kpe, cq_hi, cq_lo, ckv_hi, ckv_lo,
                                    wq_ln, wkv_ln, pos);

    // 3) q GEMM
    mma_gemm<<<dim3(Q_COLS / 128, S / 128), 256, GSMEM>>>(
        cq_hi, cq_lo, wqb_hi, wqb_lo, q, Q_COLS, Q_COLS, Q_LORA);

    // 4) kv GEMM
    mma_gemm<<<dim3(KV_COLS / 128, S / 128), 256, GSMEM>>>(
        ckv_hi, ckv_lo, wkvb_hi, wkvb_lo, kv, KV_COLS, KV_COLS, KV_LORA);

    // 5) rope on q_pe, then flash-operand conversions
    rope_q_kernel<<<S, 256>>>(q, pos);
    cvt_split<<<4096, 256>>>(q,   qs_hi, qs_lo, S * Q_COLS / 4,  Q_COLS,  S, ATT_SCALE);
    cvt_split<<<4096, 256>>>(kv,  kvh,   kvl,   S * KV_COLS / 4, KV_COLS, S, 1.f);
    cvt_split<<<256, 256>>>(kpe,  kpeh,  kpel,  S * ROPE / 4,    ROPE,    S, 1.f);

    // 6) HMMA flash attention
    flash_mma<<<dim3(S / 64, H), 128, FSMEM>>>(qs_hi, qs_lo, kvh, kvl, kpeh, kpel, attn);

    // 7) attn split + output GEMM
    cvt_split<<<4096, 256>>>(attn, at_hi, at_lo, S * O_COLS / 4, O_COLS, S, 1.f);
    mma_gemm<<<dim3(HID / 128, S / 128), 256, GSMEM>>>(
        at_hi, at_lo, wo_hi, wo_lo, out, HID, HID, O_COLS);
}

// round 6
// speedup vs baseline: 7.3353x; 1.3854x over previous
#include <cuda_runtime.h>
#include <cuda_fp16.h>
#include <math.h>
#include <stdint.h>

// ---------------- problem constants ----------------
#define S        2048
#define HID      4096
#define H        32
#define Q_LORA   1536
#define KV_LORA  512
#define NOPE     128
#define ROPE     64
#define VDIM     128
#define A_COLS   (Q_LORA + KV_LORA + ROPE)   // 2112
#define A_COLS_P 2176
#define QDIM     (NOPE + ROPE)               // 192
#define Q_COLS   (H * QDIM)                  // 6144
#define KV_COLS  (H * 2 * NOPE)              // 8192
#define O_COLS   (H * VDIM)                  // 4096
#define ATT_SCALE 0.07216878364870322992f    // 1/sqrt(192)

// ---------------- scratch ----------------
__device__ __align__(256) float g_a[S * A_COLS];
__device__ __align__(256) float g_q[S * Q_COLS];

// fp16 operands
__device__ __align__(256) __half g_h_hi[S * HID],     g_h_lo[S * HID];
__device__ __align__(256) __half g_cq_hi[S * Q_LORA], g_cq_lo[S * Q_LORA];
__device__ __align__(256) __half g_ckv_hi[S * KV_LORA], g_ckv_lo[S * KV_LORA];
__device__ __align__(256) __half g_at_hi[S * O_COLS], g_at_lo[S * O_COLS];
__device__ __align__(256) __half g_qs_hi[S * Q_COLS], g_qs_lo[S * Q_COLS];
__device__ __align__(256) __half g_kvh[S * KV_COLS];          // K-nope|V, fp16 hi
__device__ __align__(256) __half g_kpeh[S * ROPE];            // rotated k_pe fp16
// weights: fp16 hi only (B-side operand)
__device__ __align__(256) __half g_wa_h[A_COLS_P * HID];
__device__ __align__(256) __half g_wqb_h[Q_COLS * Q_LORA];
__device__ __align__(256) __half g_wkvb_h[KV_COLS * KV_LORA];
__device__ __align__(256) __half g_wo_h[HID * O_COLS];

// ================= portable PTX helpers =================
__device__ __forceinline__ uint32_t smem_u32(const void* p) {
    uint32_t a;
    asm("{ .reg .u64 t; cvta.to.shared.u64 t, %1; cvt.u32.u64 %0, t; }"
        : "=r"(a) : "l"(p));
    return a;
}
__device__ __forceinline__ void cp16(uint32_t dst, const void* src) {
    asm volatile("cp.async.cg.shared.global [%0], [%1], 16;" :: "r"(dst), "l"(src));
}
#define CP_COMMIT()  asm volatile("cp.async.commit_group;" ::: "memory")
#define CP_WAIT(n)   asm volatile("cp.async.wait_group %0;" :: "n"(n) : "memory")

__device__ __forceinline__ void ldmx4(uint32_t* r, uint32_t addr) {
    asm volatile("ldmatrix.sync.aligned.m8n8.x4.shared.b16 {%0,%1,%2,%3}, [%4];"
                 : "=r"(r[0]), "=r"(r[1]), "=r"(r[2]), "=r"(r[3]) : "r"(addr));
}
__device__ __forceinline__ void ldmx2(uint32_t* r, uint32_t addr) {
    asm volatile("ldmatrix.sync.aligned.m8n8.x2.shared.b16 {%0,%1}, [%2];"
                 : "=r"(r[0]), "=r"(r[1]) : "r"(addr));
}
__device__ __forceinline__ void ldmx4t(uint32_t* r, uint32_t addr) {
    asm volatile("ldmatrix.sync.aligned.m8n8.x4.trans.shared.b16 {%0,%1,%2,%3}, [%4];"
                 : "=r"(r[0]), "=r"(r[1]), "=r"(r[2]), "=r"(r[3]) : "r"(addr));
}
__device__ __forceinline__ void mma16816(float* c, const uint32_t* a, const uint32_t* b) {
    asm volatile(
        "mma.sync.aligned.m16n8k16.row.col.f32.f16.f16.f32 "
        "{%0,%1,%2,%3},{%4,%5,%6,%7},{%8,%9},{%0,%1,%2,%3};"
        : "+f"(c[0]), "+f"(c[1]), "+f"(c[2]), "+f"(c[3])
        : "r"(a[0]), "r"(a[1]), "r"(a[2]), "r"(a[3]), "r"(b[0]), "r"(b[1]));
}
__device__ __forceinline__ uint32_t packh2(float x, float y) {
    __half2 h = __floats2half2_rn(x, y);
    return *(uint32_t*)&h;
}

// ================= fp32 -> fp16 hi/lo split (activations) =================
__global__ __launch_bounds__(256) void cvt_split(
    const float* __restrict__ src,
    __half* __restrict__ hi, __half* __restrict__ lo,
    int total4, float scale)
{
    for (int i = blockIdx.x * 256 + threadIdx.x; i < total4; i += gridDim.x * 256) {
        int e = i * 4;
        float4 f = *(const float4*)(src + (size_t)e);
        f.x *= scale; f.y *= scale; f.z *= scale; f.w *= scale;
        __half2 h01 = __floats2half2_rn(f.x, f.y);
        __half2 h23 = __floats2half2_rn(f.z, f.w);
        float2 b01 = __half22float2(h01), b23 = __half22float2(h23);
        *(__half2*)(hi + (size_t)e)     = h01;
        *(__half2*)(hi + (size_t)e + 2) = h23;
        *(__half2*)(lo + (size_t)e)     = __floats2half2_rn(f.x - b01.x, f.y - b01.y);
        *(__half2*)(lo + (size_t)e + 2) = __floats2half2_rn(f.z - b23.x, f.w - b23.y);
    }
}

// ================= fp32 -> fp16 hi only (weights, padded rows) ============
__global__ __launch_bounds__(256) void cvt_hi(
    const float* __restrict__ src, __half* __restrict__ hi,
    int total4, int cols, int rows)
{
    for (int i = blockIdx.x * 256 + threadIdx.x; i < total4; i += gridDim.x * 256) {
        int e = i * 4;
        int r = e / cols;
        float4 f = make_float4(0.f, 0.f, 0.f, 0.f);
        if (r < rows) f = *(const float4*)(src + (size_t)e);
        *(__half2*)(hi + (size_t)e)     = __floats2half2_rn(f.x, f.y);
        *(__half2*)(hi + (size_t)e + 2) = __floats2half2_rn(f.z, f.w);
    }
}

// ================= 2-term fp16 HMMA GEMM (4-stage cp.async ring) ==========
// C[M,N] = (Ah+Al)[M,K] * Bh[N,K]^T, fp32 accum.
#define BKC   32
#define ROWB  80
#define TILEB (128 * ROWB)
#define STG   (3 * TILEB)              // Ah, Al, Bh
#define NS    4
#define GSMEM (NS * STG)               // 122880

__device__ __forceinline__ void issue_stage(
    const __half* __restrict__ Ah, const __half* __restrict__ Al,
    const __half* __restrict__ Bh,
    int row0, int col0, int K, int c, uint32_t sbase, int slot, int tid)
{
    uint32_t st = sbase + slot * STG;
    #pragma unroll
    for (int l = 0; l < 2; ++l) {
        int v = tid + l * 256;
        int r = v >> 2;
        int j = v & 3;
        size_t goffA = (size_t)(row0 + r) * K + c * BKC + j * 8;
        size_t goffB = (size_t)(col0 + r) * K + c * BKC + j * 8;
        uint32_t so = r * ROWB + j * 16;
        cp16(st + 0 * TILEB + so, Ah + goffA);
        cp16(st + 1 * TILEB + so, Al + goffA);
        cp16(st + 2 * TILEB + so, Bh + goffB);
    }
}

__global__ __launch_bounds__(256, 1) void mma_gemm(
    const __half* __restrict__ Ah, const __half* __restrict__ Al,
    const __half* __restrict__ Bh,
    float* __restrict__ C, __half* __restrict__ Ch,
    int ldc, int N, int K, int half_out)
{
    extern __shared__ char sm[];
    uint32_t sbase = smem_u32(sm);
    const int tid    = threadIdx.x;
    const int lane   = tid & 31;
    const int warp   = tid >> 5;
    const int warp_m = warp >> 2;
    const int warp_n = warp & 3;
    const int row0 = blockIdx.y * 128;
    const int col0 = blockIdx.x * 128;

    float acc[4][4][4];
    #pragma unroll
    for (int mi = 0; mi < 4; ++mi)
        #pragma unroll
        for (int ni = 0; ni < 4; ++ni)
            #pragma unroll
            for (int e = 0; e < 4; ++e) acc[mi][ni][e] = 0.f;

    const int nch = K / BKC;

    #pragma unroll
    for (int p = 0; p < NS - 1; ++p) {
        if (p < nch) issue_stage(Ah, Al, Bh, row0, col0, K, p, sbase, p, tid);
        CP_COMMIT();
    }

    const uint32_t a_l = (uint32_t)((warp_m * 64 + (lane & 15)) * ROWB + (lane >> 4) * 16);
    const uint32_t b_l = (uint32_t)((warp_n * 32 + (lane & 7)) * ROWB + ((lane >> 3) & 1) * 16);

    for (int c = 0; c < nch; ++c) {
        CP_WAIT(NS - 2);
        __syncthreads();
        int np = c + NS - 1;
        if (np < nch)
            issue_stage(Ah, Al, Bh, row0, col0, K, np, sbase, np & (NS - 1), tid);
        CP_COMMIT();

        uint32_t st = sbase + (c & (NS - 1)) * STG;

        #pragma unroll
        for (int ki = 0; ki < 2; ++ki) {
            uint32_t ah[4][4], al[4][4], bh[4][2];
            #pragma unroll
            for (int mi = 0; mi < 4; ++mi) {
                uint32_t ad = st + a_l + mi * (16 * ROWB) + ki * 32;
                ldmx4(ah[mi], ad + 0 * TILEB);
                ldmx4(al[mi], ad + 1 * TILEB);
            }
            #pragma unroll
            for (int ni = 0; ni < 4; ++ni)
                ldmx2(bh[ni], st + b_l + ni * (8 * ROWB) + ki * 32 + 2 * TILEB);
            #pragma unroll
            for (int mi = 0; mi < 4; ++mi)
                #pragma unroll
                for (int ni = 0; ni < 4; ++ni) {
                    mma16816(acc[mi][ni], ah[mi], bh[ni]);
                    mma16816(acc[mi][ni], al[mi], bh[ni]);
                }
        }
    }

    if (half_out) {
        #pragma unroll
        for (int mi = 0; mi < 4; ++mi) {
            int row = row0 + warp_m * 64 + mi * 16 + (lane >> 2);
            #pragma unroll
            for (int ni = 0; ni < 4; ++ni) {
                int col = col0 + warp_n * 32 + ni * 8 + (lane & 3) * 2;
                *(__half2*)&Ch[(size_t)row * ldc + col] =
                    __floats2half2_rn(acc[mi][ni][0], acc[mi][ni][1]);
                *(__half2*)&Ch[(size_t)(row + 8) * ldc + col] =
                    __floats2half2_rn(acc[mi][ni][2], acc[mi][ni][3]);
            }
        }
    } else {
        #pragma unroll
        for (int mi = 0; mi < 4; ++mi) {
            int row = row0 + warp_m * 64 + mi * 16 + (lane >> 2);
            #pragma unroll
            for (int ni = 0; ni < 4; ++ni) {
                int col = col0 + warp_n * 32 + ni * 8 + (lane & 3) * 2;
                if (col < N) {
                    *(float2*)&C[(size_t)row * ldc + col] =
                        make_float2(acc[mi][ni][0], acc[mi][ni][1]);
                    *(float2*)&C[(size_t)(row + 8) * ldc + col] =
                        make_float2(acc[mi][ni][2], acc[mi][ni][3]);
                }
            }
        }
    }
}

// ================= RMSNorm (fp16 hi/lo out) + k_pe RoPE (fp16) ============
__global__ __launch_bounds__(256) void rmsnorm_rope_kernel(
    const float* __restrict__ a,
    __half* __restrict__ kpeh,
    __half* __restrict__ cqh, __half* __restrict__ cql,
    __half* __restrict__ ckvh, __half* __restrict__ ckvl,
    const float* __restrict__ wq,
    const float* __restrict__ wkv,
    const int* __restrict__ pos_ids)
{
    const int s   = blockIdx.x;
    const int tid = threadIdx.x;
    const float* row = a + (size_t)s * A_COLS;
    __shared__ float red[8];

    float ss = 0.f;
    for (int i = tid; i < Q_LORA; i += 256) { float v = row[i]; ss += v * v; }
    #pragma unroll
    for (int o = 16; o; o >>= 1) ss += __shfl_xor_sync(0xffffffffu, ss, o);
    if ((tid & 31) == 0) red[tid >> 5] = ss;
    __syncthreads();
    float tot = 0.f;
    #pragma unroll
    for (int w = 0; w < 8; w++) tot += red[w];
    float inv = rsqrtf(tot / (float)Q_LORA + 1e-6f);
    for (int i = tid; i < Q_LORA; i += 256) {
        float v = row[i] * inv * wq[i];
        __half h = __float2half_rn(v);
        cqh[(size_t)s * Q_LORA + i] = h;
        cql[(size_t)s * Q_LORA + i] = __float2half_rn(v - __half2float(h));
    }
    __syncthreads();

    const float* row2 = row + Q_LORA;
    ss = 0.f;
    for (int i = tid; i < KV_LORA; i += 256) { float v = row2[i]; ss += v * v; }
    #pragma unroll
    for (int o = 16; o; o >>= 1) ss += __shfl_xor_sync(0xffffffffu, ss, o);
    if ((tid & 31) == 0) red[tid >> 5] = ss;
    __syncthreads();
    tot = 0.f;
    #pragma unroll
    for (int w = 0; w < 8; w++) tot += red[w];
    inv = rsqrtf(tot / (float)KV_LORA + 1e-6f);
    for (int i = tid; i < KV_LORA; i += 256) {
        float v = row2[i] * inv * wkv[i];
        __half h = __float2half_rn(v);
        ckvh[(size_t)s * KV_LORA + i] = h;
        ckvl[(size_t)s * KV_LORA + i] = __float2half_rn(v - __half2float(h));
    }

    if (tid < 32) {
        int p = pos_ids[s];
        float inv_freq = exp2f(-(float)tid * (13.287712379549449f / 32.0f));
        float ang = (float)p * inv_freq;
        float c, sn;
        __sincosf(ang, &sn, &c);
        float x1 = row[Q_LORA + KV_LORA + tid];
        float x2 = row[Q_LORA + KV_LORA + 32 + tid];
        kpeh[(size_t)s * ROPE + tid]      = __float2half_rn(x1 * c - x2 * sn);
        kpeh[(size_t)s * ROPE + 32 + tid] = __float2half_rn(x2 * c + x1 * sn);
    }
}

// ================= q: rope + scale + fp16 hi/lo split (one pass) ==========
__global__ __launch_bounds__(256) void rope_split_q(
    const float* __restrict__ q,
    __half* __restrict__ qh, __half* __restrict__ ql,
    const int* __restrict__ pos_ids)
{
    const int s = blockIdx.x;
    const int p = pos_ids[s];
    const float* row = q + (size_t)s * Q_COLS;
    #pragma unroll
    for (int l = 0; l < Q_COLS / 256; ++l) {
        int idx = threadIdx.x + l * 256;
        int d = idx % QDIM;
        float val;
        if (d < NOPE) {
            val = row[idx];
        } else if (d < NOPE + 32) {
            int i = d - NOPE;
            float inv_freq = exp2f(-(float)i * (13.287712379549449f / 32.0f));
            float c, sn; __sincosf((float)p * inv_freq, &sn, &c);
            val = row[idx] * c - row[idx + 32] * sn;
        } else {
            int i = d - NOPE - 32;
            float inv_freq = exp2f(-(float)i * (13.287712379549449f / 32.0f));
            float c, sn; __sincosf((float)p * inv_freq, &sn, &c);
            val = row[idx] * c + row[idx - 32] * sn;
        }
        val *= ATT_SCALE;
        __half h = __float2half_rn(val);
        qh[(size_t)s * Q_COLS + idx] = h;
        ql[(size_t)s * Q_COLS + idx] = __float2half_rn(val - __half2float(h));
    }
}

// ================= HMMA flash attention (2-term fp16) =====================
// CTA: 64 queries x 64-key tiles, 128 threads.
#define QSTR   400
#define VSTR   272
#define SM_QH  0
#define SM_QL  25600
#define SM_ST0 51200
#define VHOFF  25600                    // V offset within stage (K = 64*400)
#define STGSZ  43008                    // 25600 + 64*272
#define FSMEM  (SM_ST0 + 2 * STGSZ)     // 137216

__device__ __forceinline__ void issue_kv(
    const __half* __restrict__ KVh, const __half* __restrict__ KPh,
    int n0, int h, uint32_t stg, int tid)
{
    #pragma unroll
    for (int l = 0; l < 12; ++l) {                // 64*24 / 128
        int i = tid + l * 128;
        int r = i / 24, j = i % 24;
        uint32_t dst = stg + r * QSTR + j * 16;
        if (j < 16)
            cp16(dst, KVh + (size_t)(n0 + r) * KV_COLS + h * 2 * NOPE + j * 8);
        else
            cp16(dst, KPh + (size_t)(n0 + r) * ROPE + (j - 16) * 8);
    }
    #pragma unroll
    for (int l = 0; l < 8; ++l) {                 // 64*16 / 128
        int i = tid + l * 128;
        int r = i / 16, j = i % 16;
        cp16(stg + VHOFF + r * VSTR + j * 16,
             KVh + (size_t)(n0 + r) * KV_COLS + h * 2 * NOPE + NOPE + j * 8);
    }
}

__global__ __launch_bounds__(128, 1) void flash_mma(
    const __half* __restrict__ Qh, const __half* __restrict__ Ql,
    const __half* __restrict__ KVh, const __half* __restrict__ KPh,
    __half* __restrict__ Oh, __half* __restrict__ Ol)
{
    extern __shared__ char sm[];
    uint32_t sb = smem_u32(sm);
    const int qt = (int)gridDim.x - 1 - (int)blockIdx.x;   // longest CTAs first
    const int h = blockIdx.y;
    const int qm0 = qt * 64;
    const int tid = threadIdx.x, lane = tid & 31, warp = tid >> 5;

    #pragma unroll
    for (int l = 0; l < 12; ++l) {
        int i = tid + l * 128;
        int r = i / 24, j = i % 24;
        size_t off = (size_t)(qm0 + r) * Q_COLS + h * QDIM + j * 8;
        cp16(sb + SM_QH + r * QSTR + j * 16, Qh + off);
        cp16(sb + SM_QL + r * QSTR + j * 16, Ql + off);
    }
    issue_kv(KVh, KPh, 0, h, sb + SM_ST0, tid);
    CP_COMMIT();

    float acc[16][4];
    #pragma unroll
    for (int vt = 0; vt < 16; ++vt)
        #pragma unroll
        for (int e = 0; e < 4; ++e) acc[vt][e] = 0.f;
    float miA = -1e30f, miB = -1e30f, liA = 0.f, liB = 0.f;

    const int T = qt + 1;
    const int rA = qm0 + warp * 16 + (lane >> 2);

    for (int t = 0; t < T; ++t) {
        if (t + 1 < T) {
            issue_kv(KVh, KPh, (t + 1) * 64, h, sb + SM_ST0 + ((t + 1) & 1) * STGSZ, tid);
            CP_COMMIT();
            CP_WAIT(1);
        } else {
            CP_WAIT(0);
        }
        __syncthreads();
        uint32_t stg = sb + SM_ST0 + (t & 1) * STGSZ;

        // ---- S = Q K^T (2-term) ----
        float sc[8][4];
        #pragma unroll
        for (int nt = 0; nt < 8; ++nt)
            #pragma unroll
            for (int e = 0; e < 4; ++e) sc[nt][e] = 0.f;

        const uint32_t qa = sb + (warp * 16 + (lane & 15)) * QSTR + (lane >> 4) * 16;
        #pragma unroll
        for (int kk = 0; kk < 12; ++kk) {
            uint32_t aH[4], aL[4];
            ldmx4(aH, qa + SM_QH + kk * 32);
            ldmx4(aL, qa + SM_QL + kk * 32);
            #pragma unroll
            for (int np = 0; np < 4; ++np) {
                uint32_t bH[4];
                uint32_t ba = stg + ((np * 2 + (lane >> 4)) * 8 + (lane & 7)) * QSTR
                              + ((lane >> 3) & 1) * 16 + kk * 32;
                ldmx4(bH, ba);
                mma16816(sc[np * 2],     aH, bH);
                mma16816(sc[np * 2],     aL, bH);
                mma16816(sc[np * 2 + 1], aH, bH + 2);
                mma16816(sc[np * 2 + 1], aL, bH + 2);
            }
        }

        if (t == qt) {
            #pragma unroll
            for (int nt = 0; nt < 8; ++nt) {
                int c0 = qm0 + nt * 8 + (lane & 3) * 2;
                if (c0     > rA)     sc[nt][0] = -1e30f;
                if (c0 + 1 > rA)     sc[nt][1] = -1e30f;
                if (c0     > rA + 8) sc[nt][2] = -1e30f;
                if (c0 + 1 > rA + 8) sc[nt][3] = -1e30f;
            }
        }

        float mA = -1e30f, mB = -1e30f;
        #pragma unroll
        for (int nt = 0; nt < 8; ++nt) {
            mA = fmaxf(mA, fmaxf(sc[nt][0], sc[nt][1]));
            mB = fmaxf(mB, fmaxf(sc[nt][2], sc[nt][3]));
        }
        mA = fmaxf(mA, __shfl_xor_sync(0xffffffffu, mA, 1));
        mA = fmaxf(mA, __shfl_xor_sync(0xffffffffu, mA, 2));
        mB = fmaxf(mB, __shfl_xor_sync(0xffffffffu, mB, 1));
        mB = fmaxf(mB, __shfl_xor_sync(0xffffffffu, mB, 2));
        float nmA = fmaxf(miA, mA), nmB = fmaxf(miB, mB);
        float cA = __expf(miA - nmA), cB = __expf(miB - nmB);
        miA = nmA; miB = nmB;

        float sA = 0.f, sB = 0.f;
        #pragma unroll
        for (int nt = 0; nt < 8; ++nt) {
            sc[nt][0] = __expf(sc[nt][0] - nmA); sA += sc[nt][0];
            sc[nt][1] = __expf(sc[nt][1] - nmA); sA += sc[nt][1];
            sc[nt][2] = __expf(sc[nt][2] - nmB); sB += sc[nt][2];
            sc[nt][3] = __expf(sc[nt][3] - nmB); sB += sc[nt][3];
        }
        sA += __shfl_xor_sync(0xffffffffu, sA, 1);
        sA += __shfl_xor_sync(0xffffffffu, sA, 2);
        sB += __shfl_xor_sync(0xffffffffu, sB, 1);
        sB += __shfl_xor_sync(0xffffffffu, sB, 2);
        liA = liA * cA + sA;
        liB = liB * cB + sB;
        #pragma unroll
        for (int vt = 0; vt < 16; ++vt) {
            acc[vt][0] *= cA; acc[vt][1] *= cA;
            acc[vt][2] *= cB; acc[vt][3] *= cB;
        }

        // ---- attn += P V (2-term: Ph,Pl x Vh) ----
        #pragma unroll
        for (int kp = 0; kp < 4; ++kp) {
            uint32_t aH[4], aL[4];
            #pragma unroll
            for (int q2 = 0; q2 < 2; ++q2) {
                const float* s0 = sc[2 * kp + q2];
                uint32_t h0 = packh2(s0[0], s0[1]);
                uint32_t h1 = packh2(s0[2], s0[3]);
                float2 f0 = __half22float2(*(__half2*)&h0);
                float2 f1 = __half22float2(*(__half2*)&h1);
                aH[q2 * 2 + 0] = h0;
                aH[q2 * 2 + 1] = h1;
                aL[q2 * 2 + 0] = packh2(s0[0] - f0.x, s0[1] - f0.y);
                aL[q2 * 2 + 1] = packh2(s0[2] - f1.x, s0[3] - f1.y);
            }
            #pragma unroll
            for (int vp = 0; vp < 8; ++vp) {
                uint32_t bH[4];
                uint32_t va = stg + VHOFF + (kp * 16 + (lane & 15)) * VSTR
                              + (vp * 2 + (lane >> 4)) * 16;
                ldmx4t(bH, va);
                mma16816(acc[vp * 2],     aH, bH);
                mma16816(acc[vp * 2],     aL, bH);
                mma16816(acc[vp * 2 + 1], aH, bH + 2);
                mma16816(acc[vp * 2 + 1], aL, bH + 2);
            }
        }
        __syncthreads();
    }

    float rlA = 1.f / liA, rlB = 1.f / liB;
    #pragma unroll
    for (int vt = 0; vt < 16; ++vt) {
        int col = h * VDIM + vt * 8 + (lane & 3) * 2;
        float a0 = acc[vt][0] * rlA, a1 = acc[vt][1] * rlA;
        float a2 = acc[vt][2] * rlB, a3 = acc[vt][3] * rlB;
        __half2 h0 = __floats2half2_rn(a0, a1);
        __half2 h1 = __floats2half2_rn(a2, a3);
        float2 f0 = __half22float2(h0), f1 = __half22float2(h1);
        *(__half2*)&Oh[(size_t)rA * O_COLS + col]       = h0;
        *(__half2*)&Oh[(size_t)(rA + 8) * O_COLS + col] = h1;
        *(__half2*)&Ol[(size_t)rA * O_COLS + col]       = __floats2half2_rn(a0 - f0.x, a1 - f0.y);
        *(__half2*)&Ol[(size_t)(rA + 8) * O_COLS + col] = __floats2half2_rn(a2 - f1.x, a3 - f1.y);
    }
}

// ================= launch =================
extern "C" void kernel_launch(void* const* d_in, const int* in_sizes, int n_in,
                              void* d_out, int out_size)
{
    const int*   pos   = (const int*)  d_in[0];
    const float* hid   = (const float*)d_in[1];
    const float* w_a   = (const float*)d_in[2];
    const float* wq_ln = (const float*)d_in[3];
    const float* wkv_ln= (const float*)d_in[4];
    const float* w_q_b = (const float*)d_in[5];
    const float* w_kv_b= (const float*)d_in[6];
    const float* w_o   = (const float*)d_in[7];
    float* out = (float*)d_out;

    float *a, *q;
    cudaGetSymbolAddress((void**)&a, g_a);
    cudaGetSymbolAddress((void**)&q, g_q);

    __half *h_hi, *h_lo, *cq_hi, *cq_lo, *ckv_hi, *ckv_lo, *at_hi, *at_lo;
    __half *qs_hi, *qs_lo, *kvh, *kpeh, *wa_h, *wqb_h, *wkvb_h, *wo_h;
    cudaGetSymbolAddress((void**)&h_hi,   g_h_hi);   cudaGetSymbolAddress((void**)&h_lo,   g_h_lo);
    cudaGetSymbolAddress((void**)&cq_hi,  g_cq_hi);  cudaGetSymbolAddress((void**)&cq_lo,  g_cq_lo);
    cudaGetSymbolAddress((void**)&ckv_hi, g_ckv_hi); cudaGetSymbolAddress((void**)&ckv_lo, g_ckv_lo);
    cudaGetSymbolAddress((void**)&at_hi,  g_at_hi);  cudaGetSymbolAddress((void**)&at_lo,  g_at_lo);
    cudaGetSymbolAddress((void**)&qs_hi,  g_qs_hi);  cudaGetSymbolAddress((void**)&qs_lo,  g_qs_lo);
    cudaGetSymbolAddress((void**)&kvh,    g_kvh);    cudaGetSymbolAddress((void**)&kpeh,   g_kpeh);
    cudaGetSymbolAddress((void**)&wa_h,   g_wa_h);   cudaGetSymbolAddress((void**)&wqb_h,  g_wqb_h);
    cudaGetSymbolAddress((void**)&wkvb_h, g_wkvb_h); cudaGetSymbolAddress((void**)&wo_h,   g_wo_h);

    cudaFuncSetAttribute(mma_gemm, cudaFuncAttributeMaxDynamicSharedMemorySize, GSMEM);
    cudaFuncSetAttribute(flash_mma, cudaFuncAttributeMaxDynamicSharedMemorySize, FSMEM);

    // weight conversions (hi only) + hidden split
    cvt_hi<<<4096, 256>>>(w_a,    wa_h,   A_COLS_P * HID / 4, HID,    A_COLS);
    cvt_hi<<<4096, 256>>>(w_q_b,  wqb_h,  Q_COLS * Q_LORA / 4, Q_LORA, Q_COLS);
    cvt_hi<<<4096, 256>>>(w_kv_b, wkvb_h, KV_COLS * KV_LORA / 4, KV_LORA, KV_COLS);
    cvt_hi<<<4096, 256>>>(w_o,    wo_h,   HID * O_COLS / 4, O_COLS, HID);
    cvt_split<<<4096, 256>>>(hid, h_hi, h_lo, S * HID / 4, 1.f);

    // 1) fused-A GEMM (fp32 out)
    mma_gemm<<<dim3(A_COLS_P / 128, S / 128), 256, GSMEM>>>(
        h_hi, h_lo, wa_h, a, nullptr, A_COLS, A_COLS, HID, 0);

    // 2) RMSNorm + k_pe rope
    rmsnorm_rope_kernel<<<S, 256>>>(a, kpeh, cq_hi, cq_lo, ckv_hi, ckv_lo,
                                    wq_ln, wkv_ln, pos);

    // 3) q GEMM (fp32 out)
    mma_gemm<<<dim3(Q_COLS / 128, S / 128), 256, GSMEM>>>(
        cq_hi, cq_lo, wqb_h, q, nullptr, Q_COLS, Q_COLS, Q_LORA, 0);

    // 4) kv GEMM (fp16 hi out, direct flash operand)
    mma_gemm<<<dim3(KV_COLS / 128, S / 128), 256, GSMEM>>>(
        ckv_hi, ckv_lo, wkvb_h, nullptr, kvh, KV_COLS, KV_COLS, KV_LORA, 1);

    // 5) rope + scale + split on q
    rope_split_q<<<S, 256>>>(q, qs_hi, qs_lo, pos);

    // 6) HMMA flash attention (fp16 hi/lo out)
    flash_mma<<<dim3(S / 64, H), 128, FSMEM>>>(qs_hi, qs_lo, kvh, kpeh, at_hi, at_lo);

    // 7) output GEMM (fp32 out = final)
    mma_gemm<<<dim3(HID / 128, S / 128), 256, GSMEM>>>(
        at_hi, at_lo, wo_h, out, nullptr, HID, HID, O_COLS, 0);
}

// round 7
// speedup vs baseline: 8.3040x; 1.1321x over previous
#include <cuda_runtime.h>
#include <cuda_fp16.h>
#include <math.h>
#include <stdint.h>

// ---------------- problem constants ----------------
#define S        2048
#define HID      4096
#define H        32
#define Q_LORA   1536
#define KV_LORA  512
#define NOPE     128
#define ROPE     64
#define VDIM     128
#define A_COLS   (Q_LORA + KV_LORA + ROPE)   // 2112
#define A_COLS_P 2304                        // padded to 256-mult
#define QDIM     (NOPE + ROPE)               // 192
#define Q_COLS   (H * QDIM)                  // 6144
#define KV_COLS  (H * 2 * NOPE)              // 8192
#define O_COLS   (H * VDIM)                  // 4096
#define ATT_SCALE 0.07216878364870322992f    // 1/sqrt(192)

// ---------------- scratch ----------------
__device__ __align__(256) float g_a[S * A_COLS];
__device__ __align__(256) float g_q[S * Q_COLS];

// fp16 operands
__device__ __align__(256) __half g_h_hi[S * HID],     g_h_lo[S * HID];
__device__ __align__(256) __half g_cq_hi[S * Q_LORA], g_cq_lo[S * Q_LORA];
__device__ __align__(256) __half g_ckv_hi[S * KV_LORA], g_ckv_lo[S * KV_LORA];
__device__ __align__(256) __half g_at_hi[S * O_COLS], g_at_lo[S * O_COLS];
__device__ __align__(256) __half g_qs_hi[S * Q_COLS], g_qs_lo[S * Q_COLS];
__device__ __align__(256) __half g_kvh[S * KV_COLS];
__device__ __align__(256) __half g_kpeh[S * ROPE];
// weights: fp16 hi only (B-side operand), rows padded to 256-mult
__device__ __align__(256) __half g_wa_h[A_COLS_P * HID];
__device__ __align__(256) __half g_wqb_h[Q_COLS * Q_LORA];
__device__ __align__(256) __half g_wkvb_h[KV_COLS * KV_LORA];
__device__ __align__(256) __half g_wo_h[HID * O_COLS];

// ================= portable PTX helpers =================
__device__ __forceinline__ uint32_t smem_u32(const void* p) {
    uint32_t a;
    asm("{ .reg .u64 t; cvta.to.shared.u64 t, %1; cvt.u32.u64 %0, t; }"
        : "=r"(a) : "l"(p));
    return a;
}
__device__ __forceinline__ void cp16(uint32_t dst, const void* src) {
    asm volatile("cp.async.cg.shared.global [%0], [%1], 16;" :: "r"(dst), "l"(src));
}
#define CP_COMMIT()  asm volatile("cp.async.commit_group;" ::: "memory")
#define CP_WAIT(n)   asm volatile("cp.async.wait_group %0;" :: "n"(n) : "memory")

__device__ __forceinline__ void ldmx4(uint32_t* r, uint32_t addr) {
    asm volatile("ldmatrix.sync.aligned.m8n8.x4.shared.b16 {%0,%1,%2,%3}, [%4];"
                 : "=r"(r[0]), "=r"(r[1]), "=r"(r[2]), "=r"(r[3]) : "r"(addr));
}
__device__ __forceinline__ void ldmx2(uint32_t* r, uint32_t addr) {
    asm volatile("ldmatrix.sync.aligned.m8n8.x2.shared.b16 {%0,%1}, [%2];"
                 : "=r"(r[0]), "=r"(r[1]) : "r"(addr));
}
__device__ __forceinline__ void ldmx4t(uint32_t* r, uint32_t addr) {
    asm volatile("ldmatrix.sync.aligned.m8n8.x4.trans.shared.b16 {%0,%1,%2,%3}, [%4];"
                 : "=r"(r[0]), "=r"(r[1]), "=r"(r[2]), "=r"(r[3]) : "r"(addr));
}
__device__ __forceinline__ void mma16816(float* c, const uint32_t* a, const uint32_t* b) {
    asm volatile(
        "mma.sync.aligned.m16n8k16.row.col.f32.f16.f16.f32 "
        "{%0,%1,%2,%3},{%4,%5,%6,%7},{%8,%9},{%0,%1,%2,%3};"
        : "+f"(c[0]), "+f"(c[1]), "+f"(c[2]), "+f"(c[3])
        : "r"(a[0]), "r"(a[1]), "r"(a[2]), "r"(a[3]), "r"(b[0]), "r"(b[1]));
}
__device__ __forceinline__ uint32_t packh2(float x, float y) {
    __half2 h = __floats2half2_rn(x, y);
    return *(uint32_t*)&h;
}

// ================= fp32 -> fp16 hi/lo split (activations) =================
__global__ __launch_bounds__(256) void cvt_split(
    const float* __restrict__ src,
    __half* __restrict__ hi, __half* __restrict__ lo,
    int total4, float scale)
{
    for (int i = blockIdx.x * 256 + threadIdx.x; i < total4; i += gridDim.x * 256) {
        int e = i * 4;
        float4 f = *(const float4*)(src + (size_t)e);
        f.x *= scale; f.y *= scale; f.z *= scale; f.w *= scale;
        __half2 h01 = __floats2half2_rn(f.x, f.y);
        __half2 h23 = __floats2half2_rn(f.z, f.w);
        float2 b01 = __half22float2(h01), b23 = __half22float2(h23);
        *(__half2*)(hi + (size_t)e)     = h01;
        *(__half2*)(hi + (size_t)e + 2) = h23;
        *(__half2*)(lo + (size_t)e)     = __floats2half2_rn(f.x - b01.x, f.y - b01.y);
        *(__half2*)(lo + (size_t)e + 2) = __floats2half2_rn(f.z - b23.x, f.w - b23.y);
    }
}

// ================= fp32 -> fp16 hi only (weights, padded rows) ============
__global__ __launch_bounds__(256) void cvt_hi(
    const float* __restrict__ src, __half* __restrict__ hi,
    int total4, int cols, int rows)
{
    for (int i = blockIdx.x * 256 + threadIdx.x; i < total4; i += gridDim.x * 256) {
        int e = i * 4;
        int r = e / cols;
        float4 f = make_float4(0.f, 0.f, 0.f, 0.f);
        if (r < rows) f = *(const float4*)(src + (size_t)e);
        *(__half2*)(hi + (size_t)e)     = __floats2half2_rn(f.x, f.y);
        *(__half2*)(hi + (size_t)e + 2) = __floats2half2_rn(f.z, f.w);
    }
}

// ================= 2-term fp16 HMMA GEMM =================================
// CTA 128x256, warp tile 64x64 (8 warps, 2x4), BK=32, 4-stage cp.async ring.
// C[M,N] = (Ah+Al)[M,K] * Bh[N,K]^T, fp32 accum.
#define BKC   32
#define ROWB  80
#define ATILE (128 * ROWB)             // 10240
#define BTILE (256 * ROWB)             // 20480
#define STG   (2 * ATILE + BTILE)      // 40960
#define NS    4
#define GSMEM (NS * STG)               // 163840

__device__ __forceinline__ void issue_stage(
    const __half* __restrict__ Ah, const __half* __restrict__ Al,
    const __half* __restrict__ Bh,
    int row0, int col0, int K, int c, uint32_t sbase, int slot, int tid)
{
    uint32_t st = sbase + slot * STG;
    // A hi/lo: 128 rows x 4 float4 = 512 slots
    #pragma unroll
    for (int l = 0; l < 2; ++l) {
        int v = tid + l * 256;
        int r = v >> 2;
        int j = v & 3;
        size_t goffA = (size_t)(row0 + r) * K + c * BKC + j * 8;
        uint32_t so = r * ROWB + j * 16;
        cp16(st + so,         Ah + goffA);
        cp16(st + ATILE + so, Al + goffA);
    }
    // B: 256 rows x 4 float4 = 1024 slots
    #pragma unroll
    for (int l = 0; l < 4; ++l) {
        int v = tid + l * 256;
        int r = v >> 2;
        int j = v & 3;
        cp16(st + 2 * ATILE + r * ROWB + j * 16,
             Bh + (size_t)(col0 + r) * K + c * BKC + j * 8);
    }
}

__global__ __launch_bounds__(256, 1) void mma_gemm(
    const __half* __restrict__ Ah, const __half* __restrict__ Al,
    const __half* __restrict__ Bh,
    float* __restrict__ C, __half* __restrict__ Ch,
    int ldc, int N, int K, int half_out)
{
    extern __shared__ char sm[];
    uint32_t sbase = smem_u32(sm);
    const int tid    = threadIdx.x;
    const int lane   = tid & 31;
    const int warp   = tid >> 5;
    const int warp_m = warp >> 2;       // 0..1 -> 64 rows
    const int warp_n = warp & 3;        // 0..3 -> 64 cols
    const int row0 = blockIdx.y * 128;
    const int col0 = blockIdx.x * 256;

    float acc[4][8][4];
    #pragma unroll
    for (int mi = 0; mi < 4; ++mi)
        #pragma unroll
        for (int ni = 0; ni < 8; ++ni)
            #pragma unroll
            for (int e = 0; e < 4; ++e) acc[mi][ni][e] = 0.f;

    const int nch = K / BKC;

    #pragma unroll
    for (int p = 0; p < NS - 1; ++p) {
        if (p < nch) issue_stage(Ah, Al, Bh, row0, col0, K, p, sbase, p, tid);
        CP_COMMIT();
    }

    const uint32_t a_l = (uint32_t)((warp_m * 64 + (lane & 15)) * ROWB + (lane >> 4) * 16);
    const uint32_t b_l = (uint32_t)(2 * ATILE + (warp_n * 64 + (lane & 7)) * ROWB
                                    + ((lane >> 3) & 1) * 16);

    for (int c = 0; c < nch; ++c) {
        CP_WAIT(NS - 2);
        __syncthreads();
        int np = c + NS - 1;
        if (np < nch)
            issue_stage(Ah, Al, Bh, row0, col0, K, np, sbase, np & (NS - 1), tid);
        CP_COMMIT();

        uint32_t st = sbase + (c & (NS - 1)) * STG;

        #pragma unroll
        for (int ki = 0; ki < 2; ++ki) {
            uint32_t ah[4][4], al[4][4];
            #pragma unroll
            for (int mi = 0; mi < 4; ++mi) {
                uint32_t ad = st + a_l + mi * (16 * ROWB) + ki * 32;
                ldmx4(ah[mi], ad);
                ldmx4(al[mi], ad + ATILE);
            }
            #pragma unroll
            for (int ni = 0; ni < 8; ++ni) {
                uint32_t bh[2];
                ldmx2(bh, st + b_l + ni * (8 * ROWB) + ki * 32);
                #pragma unroll
                for (int mi = 0; mi < 4; ++mi) {
                    mma16816(acc[mi][ni], ah[mi], bh);
                    mma16816(acc[mi][ni], al[mi], bh);
                }
            }
        }
    }

    if (half_out) {
        #pragma unroll
        for (int mi = 0; mi < 4; ++mi) {
            int row = row0 + warp_m * 64 + mi * 16 + (lane >> 2);
            #pragma unroll
            for (int ni = 0; ni < 8; ++ni) {
                int col = col0 + warp_n * 64 + ni * 8 + (lane & 3) * 2;
                *(__half2*)&Ch[(size_t)row * ldc + col] =
                    __floats2half2_rn(acc[mi][ni][0], acc[mi][ni][1]);
                *(__half2*)&Ch[(size_t)(row + 8) * ldc + col] =
                    __floats2half2_rn(acc[mi][ni][2], acc[mi][ni][3]);
            }
        }
    } else {
        #pragma unroll
        for (int mi = 0; mi < 4; ++mi) {
            int row = row0 + warp_m * 64 + mi * 16 + (lane >> 2);
            #pragma unroll
            for (int ni = 0; ni < 8; ++ni) {
                int col = col0 + warp_n * 64 + ni * 8 + (lane & 3) * 2;
                if (col < N) {
                    *(float2*)&C[(size_t)row * ldc + col] =
                        make_float2(acc[mi][ni][0], acc[mi][ni][1]);
                    *(float2*)&C[(size_t)(row + 8) * ldc + col] =
                        make_float2(acc[mi][ni][2], acc[mi][ni][3]);
                }
            }
        }
    }
}

// ================= RMSNorm (fp16 hi/lo out) + k_pe RoPE (fp16) ============
__global__ __launch_bounds__(256) void rmsnorm_rope_kernel(
    const float* __restrict__ a,
    __half* __restrict__ kpeh,
    __half* __restrict__ cqh, __half* __restrict__ cql,
    __half* __restrict__ ckvh, __half* __restrict__ ckvl,
    const float* __restrict__ wq,
    const float* __restrict__ wkv,
    const int* __restrict__ pos_ids)
{
    const int s   = blockIdx.x;
    const int tid = threadIdx.x;
    const float* row = a + (size_t)s * A_COLS;
    __shared__ float red[8];

    float ss = 0.f;
    for (int i = tid; i < Q_LORA; i += 256) { float v = row[i]; ss += v * v; }
    #pragma unroll
    for (int o = 16; o; o >>= 1) ss += __shfl_xor_sync(0xffffffffu, ss, o);
    if ((tid & 31) == 0) red[tid >> 5] = ss;
    __syncthreads();
    float tot = 0.f;
    #pragma unroll
    for (int w = 0; w < 8; w++) tot += red[w];
    float inv = rsqrtf(tot / (float)Q_LORA + 1e-6f);
    for (int i = tid; i < Q_LORA; i += 256) {
        float v = row[i] * inv * wq[i];
        __half h = __float2half_rn(v);
        cqh[(size_t)s * Q_LORA + i] = h;
        cql[(size_t)s * Q_LORA + i] = __float2half_rn(v - __half2float(h));
    }
    __syncthreads();

    const float* row2 = row + Q_LORA;
    ss = 0.f;
    for (int i = tid; i < KV_LORA; i += 256) { float v = row2[i]; ss += v * v; }
    #pragma unroll
    for (int o = 16; o; o >>= 1) ss += __shfl_xor_sync(0xffffffffu, ss, o);
    if ((tid & 31) == 0) red[tid >> 5] = ss;
    __syncthreads();
    tot = 0.f;
    #pragma unroll
    for (int w = 0; w < 8; w++) tot += red[w];
    inv = rsqrtf(tot / (float)KV_LORA + 1e-6f);
    for (int i = tid; i < KV_LORA; i += 256) {
        float v = row2[i] * inv * wkv[i];
        __half h = __float2half_rn(v);
        ckvh[(size_t)s * KV_LORA + i] = h;
        ckvl[(size_t)s * KV_LORA + i] = __float2half_rn(v - __half2float(h));
    }

    if (tid < 32) {
        int p = pos_ids[s];
        float inv_freq = exp2f(-(float)tid * (13.287712379549449f / 32.0f));
        float ang = (float)p * inv_freq;
        float c, sn;
        __sincosf(ang, &sn, &c);
        float x1 = row[Q_LORA + KV_LORA + tid];
        float x2 = row[Q_LORA + KV_LORA + 32 + tid];
        kpeh[(size_t)s * ROPE + tid]      = __float2half_rn(x1 * c - x2 * sn);
        kpeh[(size_t)s * ROPE + 32 + tid] = __float2half_rn(x2 * c + x1 * sn);
    }
}

// ================= q: rope + scale + fp16 hi/lo split (one pass) ==========
__global__ __launch_bounds__(256) void rope_split_q(
    const float* __restrict__ q,
    __half* __restrict__ qh, __half* __restrict__ ql,
    const int* __restrict__ pos_ids)
{
    const int s = blockIdx.x;
    const int p = pos_ids[s];
    const float* row = q + (size_t)s * Q_COLS;
    #pragma unroll
    for (int l = 0; l < Q_COLS / 256; ++l) {
        int idx = threadIdx.x + l * 256;
        int d = idx % QDIM;
        float val;
        if (d < NOPE) {
            val = row[idx];
        } else if (d < NOPE + 32) {
            int i = d - NOPE;
            float inv_freq = exp2f(-(float)i * (13.287712379549449f / 32.0f));
            float c, sn; __sincosf((float)p * inv_freq, &sn, &c);
            val = row[idx] * c - row[idx + 32] * sn;
        } else {
            int i = d - NOPE - 32;
            float inv_freq = exp2f(-(float)i * (13.287712379549449f / 32.0f));
            float c, sn; __sincosf((float)p * inv_freq, &sn, &c);
            val = row[idx] * c + row[idx - 32] * sn;
        }
        val *= ATT_SCALE;
        __half h = __float2half_rn(val);
        qh[(size_t)s * Q_COLS + idx] = h;
        ql[(size_t)s * Q_COLS + idx] = __float2half_rn(val - __half2float(h));
    }
}

// ================= HMMA flash attention (2-term fp16) =====================
#define QSTR   400
#define VSTR   272
#define SM_QH  0
#define SM_QL  25600
#define SM_ST0 51200
#define VHOFF  25600
#define STGSZ  43008
#define FSMEM  (SM_ST0 + 2 * STGSZ)     // 137216

__device__ __forceinline__ void issue_kv(
    const __half* __restrict__ KVh, const __half* __restrict__ KPh,
    int n0, int h, uint32_t stg, int tid)
{
    #pragma unroll
    for (int l = 0; l < 12; ++l) {
        int i = tid + l * 128;
        int r = i / 24, j = i % 24;
        uint32_t dst = stg + r * QSTR + j * 16;
        if (j < 16)
            cp16(dst, KVh + (size_t)(n0 + r) * KV_COLS + h * 2 * NOPE + j * 8);
        else
            cp16(dst, KPh + (size_t)(n0 + r) * ROPE + (j - 16) * 8);
    }
    #pragma unroll
    for (int l = 0; l < 8; ++l) {
        int i = tid + l * 128;
        int r = i / 16, j = i % 16;
        cp16(stg + VHOFF + r * VSTR + j * 16,
             KVh + (size_t)(n0 + r) * KV_COLS + h * 2 * NOPE + NOPE + j * 8);
    }
}

__global__ __launch_bounds__(128, 1) void flash_mma(
    const __half* __restrict__ Qh, const __half* __restrict__ Ql,
    const __half* __restrict__ KVh, const __half* __restrict__ KPh,
    __half* __restrict__ Oh, __half* __restrict__ Ol)
{
    extern __shared__ char sm[];
    uint32_t sb = smem_u32(sm);
    const int qt = (int)gridDim.x - 1 - (int)blockIdx.x;
    const int h = blockIdx.y;
    const int qm0 = qt * 64;
    const int tid = threadIdx.x, lane = tid & 31, warp = tid >> 5;

    #pragma unroll
    for (int l = 0; l < 12; ++l) {
        int i = tid + l * 128;
        int r = i / 24, j = i % 24;
        size_t off = (size_t)(qm0 + r) * Q_COLS + h * QDIM + j * 8;
        cp16(sb + SM_QH + r * QSTR + j * 16, Qh + off);
        cp16(sb + SM_QL + r * QSTR + j * 16, Ql + off);
    }
    issue_kv(KVh, KPh, 0, h, sb + SM_ST0, tid);
    CP_COMMIT();

    float acc[16][4];
    #pragma unroll
    for (int vt = 0; vt < 16; ++vt)
        #pragma unroll
        for (int e = 0; e < 4; ++e) acc[vt][e] = 0.f;
    float miA = -1e30f, miB = -1e30f, liA = 0.f, liB = 0.f;

    const int T = qt + 1;
    const int rA = qm0 + warp * 16 + (lane >> 2);

    for (int t = 0; t < T; ++t) {
        if (t + 1 < T) {
            issue_kv(KVh, KPh, (t + 1) * 64, h, sb + SM_ST0 + ((t + 1) & 1) * STGSZ, tid);
            CP_COMMIT();
            CP_WAIT(1);
        } else {
            CP_WAIT(0);
        }
        __syncthreads();
        uint32_t stg = sb + SM_ST0 + (t & 1) * STGSZ;

        float sc[8][4];
        #pragma unroll
        for (int nt = 0; nt < 8; ++nt)
            #pragma unroll
            for (int e = 0; e < 4; ++e) sc[nt][e] = 0.f;

        const uint32_t qa = sb + (warp * 16 + (lane & 15)) * QSTR + (lane >> 4) * 16;
        #pragma unroll
        for (int kk = 0; kk < 12; ++kk) {
            uint32_t aH[4], aL[4];
            ldmx4(aH, qa + SM_QH + kk * 32);
            ldmx4(aL, qa + SM_QL + kk * 32);
            #pragma unroll
            for (int np = 0; np < 4; ++np) {
                uint32_t bH[4];
                uint32_t ba = stg + ((np * 2 + (lane >> 4)) * 8 + (lane & 7)) * QSTR
                              + ((lane >> 3) & 1) * 16 + kk * 32;
                ldmx4(bH, ba);
                mma16816(sc[np * 2],     aH, bH);
                mma16816(sc[np * 2],     aL, bH);
                mma16816(sc[np * 2 + 1], aH, bH + 2);
                mma16816(sc[np * 2 + 1], aL, bH + 2);
            }
        }

        if (t == qt) {
            #pragma unroll
            for (int nt = 0; nt < 8; ++nt) {
                int c0 = qm0 + nt * 8 + (lane & 3) * 2;
                if (c0     > rA)     sc[nt][0] = -1e30f;
                if (c0 + 1 > rA)     sc[nt][1] = -1e30f;
                if (c0     > rA + 8) sc[nt][2] = -1e30f;
                if (c0 + 1 > rA + 8) sc[nt][3] = -1e30f;
            }
        }

        float mA = -1e30f, mB = -1e30f;
        #pragma unroll
        for (int nt = 0; nt < 8; ++nt) {
            mA = fmaxf(mA, fmaxf(sc[nt][0], sc[nt][1]));
            mB = fmaxf(mB, fmaxf(sc[nt][2], sc[nt][3]));
        }
        mA = fmaxf(mA, __shfl_xor_sync(0xffffffffu, mA, 1));
        mA = fmaxf(mA, __shfl_xor_sync(0xffffffffu, mA, 2));
        mB = fmaxf(mB, __shfl_xor_sync(0xffffffffu, mB, 1));
        mB = fmaxf(mB, __shfl_xor_sync(0xffffffffu, mB, 2));
        float nmA = fmaxf(miA, mA), nmB = fmaxf(miB, mB);
        float cA = __expf(miA - nmA), cB = __expf(miB - nmB);
        miA = nmA; miB = nmB;

        float sA = 0.f, sB = 0.f;
        #pragma unroll
        for (int nt = 0; nt < 8; ++nt) {
            sc[nt][0] = __expf(sc[nt][0] - nmA); sA += sc[nt][0];
            sc[nt][1] = __expf(sc[nt][1] - nmA); sA += sc[nt][1];
            sc[nt][2] = __expf(sc[nt][2] - nmB); sB += sc[nt][2];
            sc[nt][3] = __expf(sc[nt][3] - nmB); sB += sc[nt][3];
        }
        sA += __shfl_xor_sync(0xffffffffu, sA, 1);
        sA += __shfl_xor_sync(0xffffffffu, sA, 2);
        sB += __shfl_xor_sync(0xffffffffu, sB, 1);
        sB += __shfl_xor_sync(0xffffffffu, sB, 2);
        liA = liA * cA + sA;
        liB = liB * cB + sB;
        #pragma unroll
        for (int vt = 0; vt < 16; ++vt) {
            acc[vt][0] *= cA; acc[vt][1] *= cA;
            acc[vt][2] *= cB; acc[vt][3] *= cB;
        }

        #pragma unroll
        for (int kp = 0; kp < 4; ++kp) {
            uint32_t aH[4], aL[4];
            #pragma unroll
            for (int q2 = 0; q2 < 2; ++q2) {
                const float* s0 = sc[2 * kp + q2];
                uint32_t h0 = packh2(s0[0], s0[1]);
                uint32_t h1 = packh2(s0[2], s0[3]);
                float2 f0 = __half22float2(*(__half2*)&h0);
                float2 f1 = __half22float2(*(__half2*)&h1);
                aH[q2 * 2 + 0] = h0;
                aH[q2 * 2 + 1] = h1;
                aL[q2 * 2 + 0] = packh2(s0[0] - f0.x, s0[1] - f0.y);
                aL[q2 * 2 + 1] = packh2(s0[2] - f1.x, s0[3] - f1.y);
            }
            #pragma unroll
            for (int vp = 0; vp < 8; ++vp) {
                uint32_t bH[4];
                uint32_t va = stg + VHOFF + (kp * 16 + (lane & 15)) * VSTR
                              + (vp * 2 + (lane >> 4)) * 16;
                ldmx4t(bH, va);
                mma16816(acc[vp * 2],     aH, bH);
                mma16816(acc[vp * 2],     aL, bH);
                mma16816(acc[vp * 2 + 1], aH, bH + 2);
                mma16816(acc[vp * 2 + 1], aL, bH + 2);
            }
        }
        __syncthreads();
    }

    float rlA = 1.f / liA, rlB = 1.f / liB;
    #pragma unroll
    for (int vt = 0; vt < 16; ++vt) {
        int col = h * VDIM + vt * 8 + (lane & 3) * 2;
        float a0 = acc[vt][0] * rlA, a1 = acc[vt][1] * rlA;
        float a2 = acc[vt][2] * rlB, a3 = acc[vt][3] * rlB;
        __half2 h0 = __floats2half2_rn(a0, a1);
        __half2 h1 = __floats2half2_rn(a2, a3);
        float2 f0 = __half22float2(h0), f1 = __half22float2(h1);
        *(__half2*)&Oh[(size_t)rA * O_COLS + col]       = h0;
        *(__half2*)&Oh[(size_t)(rA + 8) * O_COLS + col] = h1;
        *(__half2*)&Ol[(size_t)rA * O_COLS + col]       = __floats2half2_rn(a0 - f0.x, a1 - f0.y);
        *(__half2*)&Ol[(size_t)(rA + 8) * O_COLS + col] = __floats2half2_rn(a2 - f1.x, a3 - f1.y);
    }
}

// ================= launch =================
extern "C" void kernel_launch(void* const* d_in, const int* in_sizes, int n_in,
                              void* d_out, int out_size)
{
    const int*   pos   = (const int*)  d_in[0];
    const float* hid   = (const float*)d_in[1];
    const float* w_a   = (const float*)d_in[2];
    const float* wq_ln = (const float*)d_in[3];
    const float* wkv_ln= (const float*)d_in[4];
    const float* w_q_b = (const float*)d_in[5];
    const float* w_kv_b= (const float*)d_in[6];
    const float* w_o   = (const float*)d_in[7];
    float* out = (float*)d_out;

    float *a, *q;
    cudaGetSymbolAddress((void**)&a, g_a);
    cudaGetSymbolAddress((void**)&q, g_q);

    __half *h_hi, *h_lo, *cq_hi, *cq_lo, *ckv_hi, *ckv_lo, *at_hi, *at_lo;
    __half *qs_hi, *qs_lo, *kvh, *kpeh, *wa_h, *wqb_h, *wkvb_h, *wo_h;
    cudaGetSymbolAddress((void**)&h_hi,   g_h_hi);   cudaGetSymbolAddress((void**)&h_lo,   g_h_lo);
    cudaGetSymbolAddress((void**)&cq_hi,  g_cq_hi);  cudaGetSymbolAddress((void**)&cq_lo,  g_cq_lo);
    cudaGetSymbolAddress((void**)&ckv_hi, g_ckv_hi); cudaGetSymbolAddress((void**)&ckv_lo, g_ckv_lo);
    cudaGetSymbolAddress((void**)&at_hi,  g_at_hi);  cudaGetSymbolAddress((void**)&at_lo,  g_at_lo);
    cudaGetSymbolAddress((void**)&qs_hi,  g_qs_hi);  cudaGetSymbolAddress((void**)&qs_lo,  g_qs_lo);
    cudaGetSymbolAddress((void**)&kvh,    g_kvh);    cudaGetSymbolAddress((void**)&kpeh,   g_kpeh);
    cudaGetSymbolAddress((void**)&wa_h,   g_wa_h);   cudaGetSymbolAddress((void**)&wqb_h,  g_wqb_h);
    cudaGetSymbolAddress((void**)&wkvb_h, g_wkvb_h); cudaGetSymbolAddress((void**)&wo_h,   g_wo_h);

    cudaFuncSetAttribute(mma_gemm, cudaFuncAttributeMaxDynamicSharedMemorySize, GSMEM);
    cudaFuncSetAttribute(flash_mma, cudaFuncAttributeMaxDynamicSharedMemorySize, FSMEM);

    // weight conversions (hi only) + hidden split
    cvt_hi<<<4096, 256>>>(w_a,    wa_h,   A_COLS_P * HID / 4, HID,    A_COLS);
    cvt_hi<<<4096, 256>>>(w_q_b,  wqb_h,  Q_COLS * Q_LORA / 4, Q_LORA, Q_COLS);
    cvt_hi<<<4096, 256>>>(w_kv_b, wkvb_h, KV_COLS * KV_LORA / 4, KV_LORA, KV_COLS);
    cvt_hi<<<4096, 256>>>(w_o,    wo_h,   HID * O_COLS / 4, O_COLS, HID);
    cvt_split<<<4096, 256>>>(hid, h_hi, h_lo, S * HID / 4, 1.f);

    // 1) fused-A GEMM (fp32 out)
    mma_gemm<<<dim3(A_COLS_P / 256, S / 128), 256, GSMEM>>>(
        h_hi, h_lo, wa_h, a, nullptr, A_COLS, A_COLS, HID, 0);

    // 2) RMSNorm + k_pe rope
    rmsnorm_rope_kernel<<<S, 256>>>(a, kpeh, cq_hi, cq_lo, ckv_hi, ckv_lo,
                                    wq_ln, wkv_ln, pos);

    // 3) q GEMM (fp32 out)
    mma_gemm<<<dim3(Q_COLS / 256, S / 128), 256, GSMEM>>>(
        cq_hi, cq_lo, wqb_h, q, nullptr, Q_COLS, Q_COLS, Q_LORA, 0);

    // 4) kv GEMM (fp16 hi out, direct flash operand)
    mma_gemm<<<dim3(KV_COLS / 256, S / 128), 256, GSMEM>>>(
        ckv_hi, ckv_lo, wkvb_h, nullptr, kvh, KV_COLS, KV_COLS, KV_LORA, 1);

    // 5) rope + scale + split on q
    rope_split_q<<<S, 256>>>(q, qs_hi, qs_lo, pos);

    // 6) HMMA flash attention (fp16 hi/lo out)
    flash_mma<<<dim3(S / 64, H), 128, FSMEM>>>(qs_hi, qs_lo, kvh, kpeh, at_hi, at_lo);

    // 7) output GEMM (fp32 out = final)
    mma_gemm<<<dim3(HID / 256, S / 128), 256, GSMEM>>>(
        at_hi, at_lo, wo_h, out, nullptr, HID, HID, O_COLS, 0);
}

// round 8
// speedup vs baseline: 8.3421x; 1.0046x over previous
#include <cuda_runtime.h>
#include <cuda_fp16.h>
#include <math.h>
#include <stdint.h>

// ---------------- problem constants ----------------
#define S        2048
#define HID      4096
#define H        32
#define Q_LORA   1536
#define KV_LORA  512
#define NOPE     128
#define ROPE     64
#define VDIM     128
#define A_COLS   (Q_LORA + KV_LORA + ROPE)   // 2112
#define A_COLS_P 2304                        // padded to 256-mult
#define QDIM     (NOPE + ROPE)               // 192
#define Q_COLS   (H * QDIM)                  // 6144
#define KV_COLS  (H * 2 * NOPE)              // 8192
#define O_COLS   (H * VDIM)                  // 4096
#define ATT_SCALE 0.07216878364870322992f    // 1/sqrt(192)

// ---------------- scratch ----------------
__device__ __align__(256) float g_a[S * A_COLS];
__device__ __align__(256) float g_q[S * Q_COLS];

// fp16 operands
__device__ __align__(256) __half g_h_hi[S * HID],     g_h_lo[S * HID];
__device__ __align__(256) __half g_cq_hi[S * Q_LORA], g_cq_lo[S * Q_LORA];
__device__ __align__(256) __half g_ckv_hi[S * KV_LORA], g_ckv_lo[S * KV_LORA];
__device__ __align__(256) __half g_at_hi[S * O_COLS], g_at_lo[S * O_COLS];
__device__ __align__(256) __half g_qs_hi[S * Q_COLS], g_qs_lo[S * Q_COLS];
__device__ __align__(256) __half g_kvh[S * KV_COLS];
__device__ __align__(256) __half g_kpeh[S * ROPE];
// weights: fp16 hi only (B-side operand), rows padded to 256-mult
__device__ __align__(256) __half g_wa_h[A_COLS_P * HID];
__device__ __align__(256) __half g_wqb_h[Q_COLS * Q_LORA];
__device__ __align__(256) __half g_wkvb_h[KV_COLS * KV_LORA];
__device__ __align__(256) __half g_wo_h[HID * O_COLS];

// ================= portable PTX helpers =================
__device__ __forceinline__ uint32_t smem_u32(const void* p) {
    uint32_t a;
    asm("{ .reg .u64 t; cvta.to.shared.u64 t, %1; cvt.u32.u64 %0, t; }"
        : "=r"(a) : "l"(p));
    return a;
}
__device__ __forceinline__ void cp16(uint32_t dst, const void* src) {
    asm volatile("cp.async.cg.shared.global [%0], [%1], 16;" :: "r"(dst), "l"(src));
}
#define CP_COMMIT()  asm volatile("cp.async.commit_group;" ::: "memory")
#define CP_WAIT(n)   asm volatile("cp.async.wait_group %0;" :: "n"(n) : "memory")

__device__ __forceinline__ void ldmx4(uint32_t* r, uint32_t addr) {
    asm volatile("ldmatrix.sync.aligned.m8n8.x4.shared.b16 {%0,%1,%2,%3}, [%4];"
                 : "=r"(r[0]), "=r"(r[1]), "=r"(r[2]), "=r"(r[3]) : "r"(addr));
}
__device__ __forceinline__ void ldmx2(uint32_t* r, uint32_t addr) {
    asm volatile("ldmatrix.sync.aligned.m8n8.x2.shared.b16 {%0,%1}, [%2];"
                 : "=r"(r[0]), "=r"(r[1]) : "r"(addr));
}
__device__ __forceinline__ void ldmx4t(uint32_t* r, uint32_t addr) {
    asm volatile("ldmatrix.sync.aligned.m8n8.x4.trans.shared.b16 {%0,%1,%2,%3}, [%4];"
                 : "=r"(r[0]), "=r"(r[1]), "=r"(r[2]), "=r"(r[3]) : "r"(addr));
}
__device__ __forceinline__ void mma16816(float* c, const uint32_t* a, const uint32_t* b) {
    asm volatile(
        "mma.sync.aligned.m16n8k16.row.col.f32.f16.f16.f32 "
        "{%0,%1,%2,%3},{%4,%5,%6,%7},{%8,%9},{%0,%1,%2,%3};"
        : "+f"(c[0]), "+f"(c[1]), "+f"(c[2]), "+f"(c[3])
        : "r"(a[0]), "r"(a[1]), "r"(a[2]), "r"(a[3]), "r"(b[0]), "r"(b[1]));
}
__device__ __forceinline__ uint32_t packh2(float x, float y) {
    __half2 h = __floats2half2_rn(x, y);
    return *(uint32_t*)&h;
}

// ================= fp32 -> fp16 hi/lo split (activations) =================
__global__ __launch_bounds__(256) void cvt_split(
    const float* __restrict__ src,
    __half* __restrict__ hi, __half* __restrict__ lo,
    int total4, float scale)
{
    for (int i = blockIdx.x * 256 + threadIdx.x; i < total4; i += gridDim.x * 256) {
        int e = i * 4;
        float4 f = *(const float4*)(src + (size_t)e);
        f.x *= scale; f.y *= scale; f.z *= scale; f.w *= scale;
        __half2 h01 = __floats2half2_rn(f.x, f.y);
        __half2 h23 = __floats2half2_rn(f.z, f.w);
        float2 b01 = __half22float2(h01), b23 = __half22float2(h23);
        *(__half2*)(hi + (size_t)e)     = h01;
        *(__half2*)(hi + (size_t)e + 2) = h23;
        *(__half2*)(lo + (size_t)e)     = __floats2half2_rn(f.x - b01.x, f.y - b01.y);
        *(__half2*)(lo + (size_t)e + 2) = __floats2half2_rn(f.z - b23.x, f.w - b23.y);
    }
}

// ================= fp32 -> fp16 hi only (weights, padded rows) ============
__global__ __launch_bounds__(256) void cvt_hi(
    const float* __restrict__ src, __half* __restrict__ hi,
    int total4, int cols, int rows)
{
    for (int i = blockIdx.x * 256 + threadIdx.x; i < total4; i += gridDim.x * 256) {
        int e = i * 4;
        int r = e / cols;
        float4 f = make_float4(0.f, 0.f, 0.f, 0.f);
        if (r < rows) f = *(const float4*)(src + (size_t)e);
        *(__half2*)(hi + (size_t)e)     = __floats2half2_rn(f.x, f.y);
        *(__half2*)(hi + (size_t)e + 2) = __floats2half2_rn(f.z, f.w);
    }
}

// ================= 2-term fp16 HMMA GEMM =================================
// CTA 128x256, warp tile 64x64 (8 warps, 2x4), BK=32, 4-stage cp.async ring.
#define BKC   32
#define ROWB  80
#define ATILE (128 * ROWB)             // 10240
#define BTILE (256 * ROWB)             // 20480
#define STG   (2 * ATILE + BTILE)      // 40960
#define NS    4
#define GSMEM (NS * STG)               // 163840

__device__ __forceinline__ void issue_stage(
    const __half* __restrict__ Ah, const __half* __restrict__ Al,
    const __half* __restrict__ Bh,
    int row0, int col0, int K, int c, uint32_t sbase, int slot, int tid)
{
    uint32_t st = sbase + slot * STG;
    #pragma unroll
    for (int l = 0; l < 2; ++l) {
        int v = tid + l * 256;
        int r = v >> 2;
        int j = v & 3;
        size_t goffA = (size_t)(row0 + r) * K + c * BKC + j * 8;
        uint32_t so = r * ROWB + j * 16;
        cp16(st + so,         Ah + goffA);
        cp16(st + ATILE + so, Al + goffA);
    }
    #pragma unroll
    for (int l = 0; l < 4; ++l) {
        int v = tid + l * 256;
        int r = v >> 2;
        int j = v & 3;
        cp16(st + 2 * ATILE + r * ROWB + j * 16,
             Bh + (size_t)(col0 + r) * K + c * BKC + j * 8);
    }
}

__global__ __launch_bounds__(256, 1) void mma_gemm(
    const __half* __restrict__ Ah, const __half* __restrict__ Al,
    const __half* __restrict__ Bh,
    float* __restrict__ C, __half* __restrict__ Ch,
    int ldc, int N, int K, int half_out)
{
    extern __shared__ char sm[];
    uint32_t sbase = smem_u32(sm);
    const int tid    = threadIdx.x;
    const int lane   = tid & 31;
    const int warp   = tid >> 5;
    const int warp_m = warp >> 2;
    const int warp_n = warp & 3;
    const int row0 = blockIdx.y * 128;
    const int col0 = blockIdx.x * 256;

    float acc[4][8][4];
    #pragma unroll
    for (int mi = 0; mi < 4; ++mi)
        #pragma unroll
        for (int ni = 0; ni < 8; ++ni)
            #pragma unroll
            for (int e = 0; e < 4; ++e) acc[mi][ni][e] = 0.f;

    const int nch = K / BKC;

    #pragma unroll
    for (int p = 0; p < NS - 1; ++p) {
        if (p < nch) issue_stage(Ah, Al, Bh, row0, col0, K, p, sbase, p, tid);
        CP_COMMIT();
    }

    const uint32_t a_l = (uint32_t)((warp_m * 64 + (lane & 15)) * ROWB + (lane >> 4) * 16);
    const uint32_t b_l = (uint32_t)(2 * ATILE + (warp_n * 64 + (lane & 7)) * ROWB
                                    + ((lane >> 3) & 1) * 16);

    for (int c = 0; c < nch; ++c) {
        CP_WAIT(NS - 2);
        __syncthreads();
        int np = c + NS - 1;
        if (np < nch)
            issue_stage(Ah, Al, Bh, row0, col0, K, np, sbase, np & (NS - 1), tid);
        CP_COMMIT();

        uint32_t st = sbase + (c & (NS - 1)) * STG;

        #pragma unroll
        for (int ki = 0; ki < 2; ++ki) {
            uint32_t ah[4][4], al[4][4];
            #pragma unroll
            for (int mi = 0; mi < 4; ++mi) {
                uint32_t ad = st + a_l + mi * (16 * ROWB) + ki * 32;
                ldmx4(ah[mi], ad);
                ldmx4(al[mi], ad + ATILE);
            }
            #pragma unroll
            for (int ni = 0; ni < 8; ++ni) {
                uint32_t bh[2];
                ldmx2(bh, st + b_l + ni * (8 * ROWB) + ki * 32);
                #pragma unroll
                for (int mi = 0; mi < 4; ++mi) {
                    mma16816(acc[mi][ni], ah[mi], bh);
                    mma16816(acc[mi][ni], al[mi], bh);
                }
            }
        }
    }

    if (half_out) {
        #pragma unroll
        for (int mi = 0; mi < 4; ++mi) {
            int row = row0 + warp_m * 64 + mi * 16 + (lane >> 2);
            #pragma unroll
            for (int ni = 0; ni < 8; ++ni) {
                int col = col0 + warp_n * 64 + ni * 8 + (lane & 3) * 2;
                *(__half2*)&Ch[(size_t)row * ldc + col] =
                    __floats2half2_rn(acc[mi][ni][0], acc[mi][ni][1]);
                *(__half2*)&Ch[(size_t)(row + 8) * ldc + col] =
                    __floats2half2_rn(acc[mi][ni][2], acc[mi][ni][3]);
            }
        }
    } else {
        #pragma unroll
        for (int mi = 0; mi < 4; ++mi) {
            int row = row0 + warp_m * 64 + mi * 16 + (lane >> 2);
            #pragma unroll
            for (int ni = 0; ni < 8; ++ni) {
                int col = col0 + warp_n * 64 + ni * 8 + (lane & 3) * 2;
                if (col < N) {
                    *(float2*)&C[(size_t)row * ldc + col] =
                        make_float2(acc[mi][ni][0], acc[mi][ni][1]);
                    *(float2*)&C[(size_t)(row + 8) * ldc + col] =
                        make_float2(acc[mi][ni][2], acc[mi][ni][3]);
                }
            }
        }
    }
}

// ================= RMSNorm (fp16 hi/lo out) + k_pe RoPE (fp16) ============
__global__ __launch_bounds__(256) void rmsnorm_rope_kernel(
    const float* __restrict__ a,
    __half* __restrict__ kpeh,
    __half* __restrict__ cqh, __half* __restrict__ cql,
    __half* __restrict__ ckvh, __half* __restrict__ ckvl,
    const float* __restrict__ wq,
    const float* __restrict__ wkv,
    const int* __restrict__ pos_ids)
{
    const int s   = blockIdx.x;
    const int tid = threadIdx.x;
    const float* row = a + (size_t)s * A_COLS;
    __shared__ float red[8];

    float ss = 0.f;
    for (int i = tid; i < Q_LORA; i += 256) { float v = row[i]; ss += v * v; }
    #pragma unroll
    for (int o = 16; o; o >>= 1) ss += __shfl_xor_sync(0xffffffffu, ss, o);
    if ((tid & 31) == 0) red[tid >> 5] = ss;
    __syncthreads();
    float tot = 0.f;
    #pragma unroll
    for (int w = 0; w < 8; w++) tot += red[w];
    float inv = rsqrtf(tot / (float)Q_LORA + 1e-6f);
    for (int i = tid; i < Q_LORA; i += 256) {
        float v = row[i] * inv * wq[i];
        __half h = __float2half_rn(v);
        cqh[(size_t)s * Q_LORA + i] = h;
        cql[(size_t)s * Q_LORA + i] = __float2half_rn(v - __half2float(h));
    }
    __syncthreads();

    const float* row2 = row + Q_LORA;
    ss = 0.f;
    for (int i = tid; i < KV_LORA; i += 256) { float v = row2[i]; ss += v * v; }
    #pragma unroll
    for (int o = 16; o; o >>= 1) ss += __shfl_xor_sync(0xffffffffu, ss, o);
    if ((tid & 31) == 0) red[tid >> 5] = ss;
    __syncthreads();
    tot = 0.f;
    #pragma unroll
    for (int w = 0; w < 8; w++) tot += red[w];
    inv = rsqrtf(tot / (float)KV_LORA + 1e-6f);
    for (int i = tid; i < KV_LORA; i += 256) {
        float v = row2[i] * inv * wkv[i];
        __half h = __float2half_rn(v);
        ckvh[(size_t)s * KV_LORA + i] = h;
        ckvl[(size_t)s * KV_LORA + i] = __float2half_rn(v - __half2float(h));
    }

    if (tid < 32) {
        int p = pos_ids[s];
        float inv_freq = exp2f(-(float)tid * (13.287712379549449f / 32.0f));
        float ang = (float)p * inv_freq;
        float c, sn;
        __sincosf(ang, &sn, &c);
        float x1 = row[Q_LORA + KV_LORA + tid];
        float x2 = row[Q_LORA + KV_LORA + 32 + tid];
        kpeh[(size_t)s * ROPE + tid]      = __float2half_rn(x1 * c - x2 * sn);
        kpeh[(size_t)s * ROPE + 32 + tid] = __float2half_rn(x2 * c + x1 * sn);
    }
}

// ================= q: rope + scale + fp16 hi/lo split (one pass) ==========
__global__ __launch_bounds__(256) void rope_split_q(
    const float* __restrict__ q,
    __half* __restrict__ qh, __half* __restrict__ ql,
    const int* __restrict__ pos_ids)
{
    const int s = blockIdx.x;
    const int p = pos_ids[s];
    const float* row = q + (size_t)s * Q_COLS;
    #pragma unroll
    for (int l = 0; l < Q_COLS / 256; ++l) {
        int idx = threadIdx.x + l * 256;
        int d = idx % QDIM;
        float val;
        if (d < NOPE) {
            val = row[idx];
        } else if (d < NOPE + 32) {
            int i = d - NOPE;
            float inv_freq = exp2f(-(float)i * (13.287712379549449f / 32.0f));
            float c, sn; __sincosf((float)p * inv_freq, &sn, &c);
            val = row[idx] * c - row[idx + 32] * sn;
        } else {
            int i = d - NOPE - 32;
            float inv_freq = exp2f(-(float)i * (13.287712379549449f / 32.0f));
            float c, sn; __sincosf((float)p * inv_freq, &sn, &c);
            val = row[idx] * c + row[idx - 32] * sn;
        }
        val *= ATT_SCALE;
        __half h = __float2half_rn(val);
        qh[(size_t)s * Q_COLS + idx] = h;
        ql[(size_t)s * Q_COLS + idx] = __float2half_rn(val - __half2float(h));
    }
}

// ================= HMMA flash attention (2-term fp16, 128-query tiles) ====
// CTA: 128 queries x 64-key tiles, 256 threads (8 warps x 16 rows).
#define QSTR   400
#define VSTR   272
#define SM_QH  0
#define SM_QL  51200
#define SM_ST0 102400
#define VHOFF  25600
#define STGSZ  43008
#define FSMEM  (SM_ST0 + 2 * STGSZ)     // 188416

__device__ __forceinline__ void issue_kv(
    const __half* __restrict__ KVh, const __half* __restrict__ KPh,
    int n0, int h, uint32_t stg, int tid)
{
    #pragma unroll
    for (int l = 0; l < 6; ++l) {                 // 64*24 / 256
        int i = tid + l * 256;
        int r = i / 24, j = i % 24;
        uint32_t dst = stg + r * QSTR + j * 16;
        if (j < 16)
            cp16(dst, KVh + (size_t)(n0 + r) * KV_COLS + h * 2 * NOPE + j * 8);
        else
            cp16(dst, KPh + (size_t)(n0 + r) * ROPE + (j - 16) * 8);
    }
    #pragma unroll
    for (int l = 0; l < 4; ++l) {                 // 64*16 / 256
        int i = tid + l * 256;
        int r = i / 16, j = i % 16;
        cp16(stg + VHOFF + r * VSTR + j * 16,
             KVh + (size_t)(n0 + r) * KV_COLS + h * 2 * NOPE + NOPE + j * 8);
    }
}

__global__ __launch_bounds__(256, 1) void flash_mma(
    const __half* __restrict__ Qh, const __half* __restrict__ Ql,
    const __half* __restrict__ KVh, const __half* __restrict__ KPh,
    __half* __restrict__ Oh, __half* __restrict__ Ol)
{
    extern __shared__ char sm[];
    uint32_t sb = smem_u32(sm);
    const int qt = (int)gridDim.x - 1 - (int)blockIdx.x;   // longest CTAs first
    const int h = blockIdx.y;
    const int qm0 = qt * 128;
    const int tid = threadIdx.x, lane = tid & 31, warp = tid >> 5;

    // Q tile (hi+lo): 128 rows x 24 chunks = 3072 slots / 256 threads
    #pragma unroll
    for (int l = 0; l < 12; ++l) {
        int i = tid + l * 256;
        int r = i / 24, j = i % 24;
        size_t off = (size_t)(qm0 + r) * Q_COLS + h * QDIM + j * 8;
        cp16(sb + SM_QH + r * QSTR + j * 16, Qh + off);
        cp16(sb + SM_QL + r * QSTR + j * 16, Ql + off);
    }
    issue_kv(KVh, KPh, 0, h, sb + SM_ST0, tid);
    CP_COMMIT();

    float acc[16][4];
    #pragma unroll
    for (int vt = 0; vt < 16; ++vt)
        #pragma unroll
        for (int e = 0; e < 4; ++e) acc[vt][e] = 0.f;
    float miA = -1e30f, miB = -1e30f, liA = 0.f, liB = 0.f;

    const int T = 2 * (qt + 1);
    const int rA = qm0 + warp * 16 + (lane >> 2);

    for (int t = 0; t < T; ++t) {
        if (t + 1 < T) {
            issue_kv(KVh, KPh, (t + 1) * 64, h, sb + SM_ST0 + ((t + 1) & 1) * STGSZ, tid);
            CP_COMMIT();
            CP_WAIT(1);
        } else {
            CP_WAIT(0);
        }
        __syncthreads();
        uint32_t stg = sb + SM_ST0 + (t & 1) * STGSZ;

        // ---- S = Q K^T (2-term) ----
        float sc[8][4];
        #pragma unroll
        for (int nt = 0; nt < 8; ++nt)
            #pragma unroll
            for (int e = 0; e < 4; ++e) sc[nt][e] = 0.f;

        const uint32_t qa = sb + (warp * 16 + (lane & 15)) * QSTR + (lane >> 4) * 16;
        #pragma unroll
        for (int kk = 0; kk < 12; ++kk) {
            uint32_t aH[4], aL[4];
            ldmx4(aH, qa + SM_QH + kk * 32);
            ldmx4(aL, qa + SM_QL + kk * 32);
            #pragma unroll
            for (int np = 0; np < 4; ++np) {
                uint32_t bH[4];
                uint32_t ba = stg + ((np * 2 + (lane >> 4)) * 8 + (lane & 7)) * QSTR
                              + ((lane >> 3) & 1) * 16 + kk * 32;
                ldmx4(bH, ba);
                mma16816(sc[np * 2],     aH, bH);
                mma16816(sc[np * 2],     aL, bH);
                mma16816(sc[np * 2 + 1], aH, bH + 2);
                mma16816(sc[np * 2 + 1], aL, bH + 2);
            }
        }

        // ---- causal mask on last two key tiles ----
        if (t >= T - 2) {
            #pragma unroll
            for (int nt = 0; nt < 8; ++nt) {
                int c0 = t * 64 + nt * 8 + (lane & 3) * 2;
                if (c0     > rA)     sc[nt][0] = -1e30f;
                if (c0 + 1 > rA)     sc[nt][1] = -1e30f;
                if (c0     > rA + 8) sc[nt][2] = -1e30f;
                if (c0 + 1 > rA + 8) sc[nt][3] = -1e30f;
            }
        }

        // ---- online softmax ----
        float mA = -1e30f, mB = -1e30f;
        #pragma unroll
        for (int nt = 0; nt < 8; ++nt) {
            mA = fmaxf(mA, fmaxf(sc[nt][0], sc[nt][1]));
            mB = fmaxf(mB, fmaxf(sc[nt][2], sc[nt][3]));
        }
        mA = fmaxf(mA, __shfl_xor_sync(0xffffffffu, mA, 1));
        mA = fmaxf(mA, __shfl_xor_sync(0xffffffffu, mA, 2));
        mB = fmaxf(mB, __shfl_xor_sync(0xffffffffu, mB, 1));
        mB = fmaxf(mB, __shfl_xor_sync(0xffffffffu, mB, 2));
        float nmA = fmaxf(miA, mA), nmB = fmaxf(miB, mB);
        float cA = __expf(miA - nmA), cB = __expf(miB - nmB);
        miA = nmA; miB = nmB;

        float sA = 0.f, sB = 0.f;
        #pragma unroll
        for (int nt = 0; nt < 8; ++nt) {
            sc[nt][0] = __expf(sc[nt][0] - nmA); sA += sc[nt][0];
            sc[nt][1] = __expf(sc[nt][1] - nmA); sA += sc[nt][1];
            sc[nt][2] = __expf(sc[nt][2] - nmB); sB += sc[nt][2];
            sc[nt][3] = __expf(sc[nt][3] - nmB); sB += sc[nt][3];
        }
        sA += __shfl_xor_sync(0xffffffffu, sA, 1);
        sA += __shfl_xor_sync(0xffffffffu, sA, 2);
        sB += __shfl_xor_sync(0xffffffffu, sB, 1);
        sB += __shfl_xor_sync(0xffffffffu, sB, 2);
        liA = liA * cA + sA;
        liB = liB * cB + sB;
        #pragma unroll
        for (int vt = 0; vt < 16; ++vt) {
            acc[vt][0] *= cA; acc[vt][1] *= cA;
            acc[vt][2] *= cB; acc[vt][3] *= cB;
        }

        // ---- attn += P V (2-term: Ph,Pl x Vh) ----
        #pragma unroll
        for (int kp = 0; kp < 4; ++kp) {
            uint32_t aH[4], aL[4];
            #pragma unroll
            for (int q2 = 0; q2 < 2; ++q2) {
                const float* s0 = sc[2 * kp + q2];
                uint32_t h0 = packh2(s0[0], s0[1]);
                uint32_t h1 = packh2(s0[2], s0[3]);
                float2 f0 = __half22float2(*(__half2*)&h0);
                float2 f1 = __half22float2(*(__half2*)&h1);
                aH[q2 * 2 + 0] = h0;
                aH[q2 * 2 + 1] = h1;
                aL[q2 * 2 + 0] = packh2(s0[0] - f0.x, s0[1] - f0.y);
                aL[q2 * 2 + 1] = packh2(s0[2] - f1.x, s0[3] - f1.y);
            }
            #pragma unroll
            for (int vp = 0; vp < 8; ++vp) {
                uint32_t bH[4];
                uint32_t va = stg + VHOFF + (kp * 16 + (lane & 15)) * VSTR
                              + (vp * 2 + (lane >> 4)) * 16;
                ldmx4t(bH, va);
                mma16816(acc[vp * 2],     aH, bH);
                mma16816(acc[vp * 2],     aL, bH);
                mma16816(acc[vp * 2 + 1], aH, bH + 2);
                mma16816(acc[vp * 2 + 1], aL, bH + 2);
            }
        }
        __syncthreads();
    }

    float rlA = 1.f / liA, rlB = 1.f / liB;
    #pragma unroll
    for (int vt = 0; vt < 16; ++vt) {
        int col = h * VDIM + vt * 8 + (lane & 3) * 2;
        float a0 = acc[vt][0] * rlA, a1 = acc[vt][1] * rlA;
        float a2 = acc[vt][2] * rlB, a3 = acc[vt][3] * rlB;
        __half2 h0 = __floats2half2_rn(a0, a1);
        __half2 h1 = __floats2half2_rn(a2, a3);
        float2 f0 = __half22float2(h0), f1 = __half22float2(h1);
        *(__half2*)&Oh[(size_t)rA * O_COLS + col]       = h0;
        *(__half2*)&Oh[(size_t)(rA + 8) * O_COLS + col] = h1;
        *(__half2*)&Ol[(size_t)rA * O_COLS + col]       = __floats2half2_rn(a0 - f0.x, a1 - f0.y);
        *(__half2*)&Ol[(size_t)(rA + 8) * O_COLS + col] = __floats2half2_rn(a2 - f1.x, a3 - f1.y);
    }
}

// ================= launch =================
extern "C" void kernel_launch(void* const* d_in, const int* in_sizes, int n_in,
                              void* d_out, int out_size)
{
    const int*   pos   = (const int*)  d_in[0];
    const float* hid   = (const float*)d_in[1];
    const float* w_a   = (const float*)d_in[2];
    const float* wq_ln = (const float*)d_in[3];
    const float* wkv_ln= (const float*)d_in[4];
    const float* w_q_b = (const float*)d_in[5];
    const float* w_kv_b= (const float*)d_in[6];
    const float* w_o   = (const float*)d_in[7];
    float* out = (float*)d_out;

    float *a, *q;
    cudaGetSymbolAddress((void**)&a, g_a);
    cudaGetSymbolAddress((void**)&q, g_q);

    __half *h_hi, *h_lo, *cq_hi, *cq_lo, *ckv_hi, *ckv_lo, *at_hi, *at_lo;
    __half *qs_hi, *qs_lo, *kvh, *kpeh, *wa_h, *wqb_h, *wkvb_h, *wo_h;
    cudaGetSymbolAddress((void**)&h_hi,   g_h_hi);   cudaGetSymbolAddress((void**)&h_lo,   g_h_lo);
    cudaGetSymbolAddress((void**)&cq_hi,  g_cq_hi);  cudaGetSymbolAddress((void**)&cq_lo,  g_cq_lo);
    cudaGetSymbolAddress((void**)&ckv_hi, g_ckv_hi); cudaGetSymbolAddress((void**)&ckv_lo, g_ckv_lo);
    cudaGetSymbolAddress((void**)&at_hi,  g_at_hi);  cudaGetSymbolAddress((void**)&at_lo,  g_at_lo);
    cudaGetSymbolAddress((void**)&qs_hi,  g_qs_hi);  cudaGetSymbolAddress((void**)&qs_lo,  g_qs_lo);
    cudaGetSymbolAddress((void**)&kvh,    g_kvh);    cudaGetSymbolAddress((void**)&kpeh,   g_kpeh);
    cudaGetSymbolAddress((void**)&wa_h,   g_wa_h);   cudaGetSymbolAddress((void**)&wqb_h,  g_wqb_h);
    cudaGetSymbolAddress((void**)&wkvb_h, g_wkvb_h); cudaGetSymbolAddress((void**)&wo_h,   g_wo_h);

    cudaFuncSetAttribute(mma_gemm, cudaFuncAttributeMaxDynamicSharedMemorySize, GSMEM);
    cudaFuncSetAttribute(flash_mma, cudaFuncAttributeMaxDynamicSharedMemorySize, FSMEM);

    // weight conversions (hi only) + hidden split
    cvt_hi<<<4096, 256>>>(w_a,    wa_h,   A_COLS_P * HID / 4, HID,    A_COLS);
    cvt_hi<<<4096, 256>>>(w_q_b,  wqb_h,  Q_COLS * Q_LORA / 4, Q_LORA, Q_COLS);
    cvt_hi<<<4096, 256>>>(w_kv_b, wkvb_h, KV_COLS * KV_LORA / 4, KV_LORA, KV_COLS);
    cvt_hi<<<4096, 256>>>(w_o,    wo_h,   HID * O_COLS / 4, O_COLS, HID);
    cvt_split<<<4096, 256>>>(hid, h_hi, h_lo, S * HID / 4, 1.f);

    // 1) fused-A GEMM (fp32 out)
    mma_gemm<<<dim3(A_COLS_P / 256, S / 128), 256, GSMEM>>>(
        h_hi, h_lo, wa_h, a, nullptr, A_COLS, A_COLS, HID, 0);

    // 2) RMSNorm + k_pe rope
    rmsnorm_rope_kernel<<<S, 256>>>(a, kpeh, cq_hi, cq_lo, ckv_hi, ckv_lo,
                                    wq_ln, wkv_ln, pos);

    // 3) q GEMM (fp32 out)
    mma_gemm<<<dim3(Q_COLS / 256, S / 128), 256, GSMEM>>>(
        cq_hi, cq_lo, wqb_h, q, nullptr, Q_COLS, Q_COLS, Q_LORA, 0);

    // 4) kv GEMM (fp16 hi out, direct flash operand)
    mma_gemm<<<dim3(KV_COLS / 256, S / 128), 256, GSMEM>>>(
        ckv_hi, ckv_lo, wkvb_h, nullptr, kvh, KV_COLS, KV_COLS, KV_LORA, 1);

    // 5) rope + scale + split on q
    rope_split_q<<<S, 256>>>(q, qs_hi, qs_lo, pos);

    // 6) HMMA flash attention (fp16 hi/lo out), 128-query tiles
    flash_mma<<<dim3(S / 128, H), 256, FSMEM>>>(qs_hi, qs_lo, kvh, kpeh, at_hi, at_lo);

    // 7) output GEMM (fp32 out = final)
    mma_gemm<<<dim3(HID / 256, S / 128), 256, GSMEM>>>(
        at_hi, at_lo, wo_h, out, nullptr, HID, HID, O_COLS, 0);
}

// round 9
// speedup vs baseline: 8.4495x; 1.0129x over previous
#include <cuda_runtime.h>
#include <cuda_fp16.h>
#include <math.h>
#include <stdint.h>

// ---------------- problem constants ----------------
#define S        2048
#define HID      4096
#define H        32
#define Q_LORA   1536
#define KV_LORA  512
#define NOPE     128
#define ROPE     64
#define VDIM     128
#define A_COLS   (Q_LORA + KV_LORA + ROPE)   // 2112
#define A_COLS_P 2304                        // padded to 256-mult
#define QDIM     (NOPE + ROPE)               // 192
#define Q_COLS   (H * QDIM)                  // 6144
#define KV_COLS  (H * 2 * NOPE)              // 8192
#define O_COLS   (H * VDIM)                  // 4096
#define ATT_SCALE 0.07216878364870322992f    // 1/sqrt(192)
#define ROPE_L2  13.287712379549449f         // log2(10000)

// ---------------- scratch ----------------
__device__ __align__(256) float g_a[S * A_COLS];

// fp16 operands
__device__ __align__(256) __half g_h_hi[S * HID],     g_h_lo[S * HID];
__device__ __align__(256) __half g_cq_hi[S * Q_LORA], g_cq_lo[S * Q_LORA];
__device__ __align__(256) __half g_ckv_hi[S * KV_LORA], g_ckv_lo[S * KV_LORA];
__device__ __align__(256) __half g_at_hi[S * O_COLS], g_at_lo[S * O_COLS];
__device__ __align__(256) __half g_qs_hi[S * Q_COLS], g_qs_lo[S * Q_COLS];
__device__ __align__(256) __half g_kvh[S * KV_COLS];
__device__ __align__(256) __half g_kpeh[S * ROPE];
// weights: fp16 hi only (B-side operand), rows padded to 256-mult
__device__ __align__(256) __half g_wa_h[A_COLS_P * HID];
__device__ __align__(256) __half g_wqb_h[Q_COLS * Q_LORA];
__device__ __align__(256) __half g_wkvb_h[KV_COLS * KV_LORA];
__device__ __align__(256) __half g_wo_h[HID * O_COLS];

// ================= portable PTX helpers =================
__device__ __forceinline__ uint32_t smem_u32(const void* p) {
    uint32_t a;
    asm("{ .reg .u64 t; cvta.to.shared.u64 t, %1; cvt.u32.u64 %0, t; }"
        : "=r"(a) : "l"(p));
    return a;
}
__device__ __forceinline__ void cp16(uint32_t dst, const void* src) {
    asm volatile("cp.async.cg.shared.global [%0], [%1], 16;" :: "r"(dst), "l"(src));
}
#define CP_COMMIT()  asm volatile("cp.async.commit_group;" ::: "memory")
#define CP_WAIT(n)   asm volatile("cp.async.wait_group %0;" :: "n"(n) : "memory")

__device__ __forceinline__ void ldmx4(uint32_t* r, uint32_t addr) {
    asm volatile("ldmatrix.sync.aligned.m8n8.x4.shared.b16 {%0,%1,%2,%3}, [%4];"
                 : "=r"(r[0]), "=r"(r[1]), "=r"(r[2]), "=r"(r[3]) : "r"(addr));
}
__device__ __forceinline__ void ldmx2(uint32_t* r, uint32_t addr) {
    asm volatile("ldmatrix.sync.aligned.m8n8.x2.shared.b16 {%0,%1}, [%2];"
                 : "=r"(r[0]), "=r"(r[1]) : "r"(addr));
}
__device__ __forceinline__ void ldmx4t(uint32_t* r, uint32_t addr) {
    asm volatile("ldmatrix.sync.aligned.m8n8.x4.trans.shared.b16 {%0,%1,%2,%3}, [%4];"
                 : "=r"(r[0]), "=r"(r[1]), "=r"(r[2]), "=r"(r[3]) : "r"(addr));
}
__device__ __forceinline__ void mma16816(float* c, const uint32_t* a, const uint32_t* b) {
    asm volatile(
        "mma.sync.aligned.m16n8k16.row.col.f32.f16.f16.f32 "
        "{%0,%1,%2,%3},{%4,%5,%6,%7},{%8,%9},{%0,%1,%2,%3};"
        : "+f"(c[0]), "+f"(c[1]), "+f"(c[2]), "+f"(c[3])
        : "r"(a[0]), "r"(a[1]), "r"(a[2]), "r"(a[3]), "r"(b[0]), "r"(b[1]));
}
__device__ __forceinline__ uint32_t packh2(float x, float y) {
    __half2 h = __floats2half2_rn(x, y);
    return *(uint32_t*)&h;
}

// ================= fp32 -> fp16 hi/lo split (activations) =================
__global__ __launch_bounds__(256) void cvt_split(
    const float* __restrict__ src,
    __half* __restrict__ hi, __half* __restrict__ lo,
    int total4, float scale)
{
    for (int i = blockIdx.x * 256 + threadIdx.x; i < total4; i += gridDim.x * 256) {
        int e = i * 4;
        float4 f = *(const float4*)(src + (size_t)e);
        f.x *= scale; f.y *= scale; f.z *= scale; f.w *= scale;
        __half2 h01 = __floats2half2_rn(f.x, f.y);
        __half2 h23 = __floats2half2_rn(f.z, f.w);
        float2 b01 = __half22float2(h01), b23 = __half22float2(h23);
        *(__half2*)(hi + (size_t)e)     = h01;
        *(__half2*)(hi + (size_t)e + 2) = h23;
        *(__half2*)(lo + (size_t)e)     = __floats2half2_rn(f.x - b01.x, f.y - b01.y);
        *(__half2*)(lo + (size_t)e + 2) = __floats2half2_rn(f.z - b23.x, f.w - b23.y);
    }
}

// ================= fp32 -> fp16 hi only (weights, padded rows) ============
__global__ __launch_bounds__(256) void cvt_hi(
    const float* __restrict__ src, __half* __restrict__ hi,
    int total4, int cols, int rows)
{
    for (int i = blockIdx.x * 256 + threadIdx.x; i < total4; i += gridDim.x * 256) {
        int e = i * 4;
        int r = e / cols;
        float4 f = make_float4(0.f, 0.f, 0.f, 0.f);
        if (r < rows) f = *(const float4*)(src + (size_t)e);
        *(__half2*)(hi + (size_t)e)     = __floats2half2_rn(f.x, f.y);
        *(__half2*)(hi + (size_t)e + 2) = __floats2half2_rn(f.z, f.w);
    }
}

// ================= 2-term fp16 HMMA GEMM =================================
// CTA 128x256, warp tile 64x64 (8 warps, 2x4), BK=32, 4-stage cp.async ring.
// mode 0: fp32 C.  mode 1: fp16 hi -> Ch.  mode 2: rope+scale+split -> Ch,Cl.
#define BKC   32
#define ROWB  80
#define ATILE (128 * ROWB)             // 10240
#define BTILE (256 * ROWB)             // 20480
#define STG   (2 * ATILE + BTILE)      // 40960
#define NS    4
#define GSMEM (NS * STG)               // 163840

__device__ __forceinline__ void issue_stage(
    const __half* __restrict__ Ah, const __half* __restrict__ Al,
    const __half* __restrict__ Bh,
    int row0, int col0, int K, int c, uint32_t sbase, int slot, int tid)
{
    uint32_t st = sbase + slot * STG;
    #pragma unroll
    for (int l = 0; l < 2; ++l) {
        int v = tid + l * 256;
        int r = v >> 2;
        int j = v & 3;
        size_t goffA = (size_t)(row0 + r) * K + c * BKC + j * 8;
        uint32_t so = r * ROWB + j * 16;
        cp16(st + so,         Ah + goffA);
        cp16(st + ATILE + so, Al + goffA);
    }
    #pragma unroll
    for (int l = 0; l < 4; ++l) {
        int v = tid + l * 256;
        int r = v >> 2;
        int j = v & 3;
        cp16(st + 2 * ATILE + r * ROWB + j * 16,
             Bh + (size_t)(col0 + r) * K + c * BKC + j * 8);
    }
}

__global__ __launch_bounds__(256, 1) void mma_gemm(
    const __half* __restrict__ Ah, const __half* __restrict__ Al,
    const __half* __restrict__ Bh,
    float* __restrict__ C, __half* __restrict__ Ch, __half* __restrict__ Cl,
    const int* __restrict__ pos,
    int ldc, int N, int K, int mode)
{
    extern __shared__ char sm[];
    uint32_t sbase = smem_u32(sm);
    const int tid    = threadIdx.x;
    const int lane   = tid & 31;
    const int warp   = tid >> 5;
    const int warp_m = warp >> 2;
    const int warp_n = warp & 3;
    const int row0 = blockIdx.y * 128;
    const int col0 = blockIdx.x * 256;

    float acc[4][8][4];
    #pragma unroll
    for (int mi = 0; mi < 4; ++mi)
        #pragma unroll
        for (int ni = 0; ni < 8; ++ni)
            #pragma unroll
            for (int e = 0; e < 4; ++e) acc[mi][ni][e] = 0.f;

    const int nch = K / BKC;

    #pragma unroll
    for (int p = 0; p < NS - 1; ++p) {
        if (p < nch) issue_stage(Ah, Al, Bh, row0, col0, K, p, sbase, p, tid);
        CP_COMMIT();
    }

    const uint32_t a_l = (uint32_t)((warp_m * 64 + (lane & 15)) * ROWB + (lane >> 4) * 16);
    const uint32_t b_l = (uint32_t)(2 * ATILE + (warp_n * 64 + (lane & 7)) * ROWB
                                    + ((lane >> 3) & 1) * 16);

    for (int c = 0; c < nch; ++c) {
        CP_WAIT(NS - 2);
        __syncthreads();
        int np = c + NS - 1;
        if (np < nch)
            issue_stage(Ah, Al, Bh, row0, col0, K, np, sbase, np & (NS - 1), tid);
        CP_COMMIT();

        uint32_t st = sbase + (c & (NS - 1)) * STG;

        #pragma unroll
        for (int ki = 0; ki < 2; ++ki) {
            uint32_t ah[4][4], al[4][4];
            #pragma unroll
            for (int mi = 0; mi < 4; ++mi) {
                uint32_t ad = st + a_l + mi * (16 * ROWB) + ki * 32;
                ldmx4(ah[mi], ad);
                ldmx4(al[mi], ad + ATILE);
            }
            #pragma unroll
            for (int ni = 0; ni < 8; ++ni) {
                uint32_t bh[2];
                ldmx2(bh, st + b_l + ni * (8 * ROWB) + ki * 32);
                #pragma unroll
                for (int mi = 0; mi < 4; ++mi) {
                    mma16816(acc[mi][ni], ah[mi], bh);
                    mma16816(acc[mi][ni], al[mi], bh);
                }
            }
        }
    }

    if (mode == 2) {
        // q epilogue: rope on pe tiles, then scale + fp16 hi/lo split.
        // pe tile iff (col_base/64) % 3 == 2 (head pe span is 64-aligned).
        int ttype = ((col0 >> 6) + warp_n) % 3;
        if (ttype == 2) {
            #pragma unroll
            for (int mi = 0; mi < 4; ++mi) {
                int r0 = row0 + warp_m * 64 + mi * 16 + (lane >> 2);
                float p0 = (float)pos[r0];
                float p1 = (float)pos[r0 + 8];
                #pragma unroll
                for (int ni = 0; ni < 4; ++ni) {
                    #pragma unroll
                    for (int e = 0; e < 2; ++e) {
                        int i = ni * 8 + (lane & 3) * 2 + e;
                        float f = exp2f(-(float)i * (ROPE_L2 / 32.0f));
                        float c0, s0, c1, s1;
                        __sincosf(p0 * f, &s0, &c0);
                        __sincosf(p1 * f, &s1, &c1);
                        float x1 = acc[mi][ni][e],     x2 = acc[mi][ni + 4][e];
                        acc[mi][ni][e]       = x1 * c0 - x2 * s0;
                        acc[mi][ni + 4][e]   = x2 * c0 + x1 * s0;
                        float y1 = acc[mi][ni][e + 2], y2 = acc[mi][ni + 4][e + 2];
                        acc[mi][ni][e + 2]     = y1 * c1 - y2 * s1;
                        acc[mi][ni + 4][e + 2] = y2 * c1 + y1 * s1;
                    }
                }
            }
        }
        #pragma unroll
        for (int mi = 0; mi < 4; ++mi) {
            int row = row0 + warp_m * 64 + mi * 16 + (lane >> 2);
            #pragma unroll
            for (int ni = 0; ni < 8; ++ni) {
                int col = col0 + warp_n * 64 + ni * 8 + (lane & 3) * 2;
                float a0 = acc[mi][ni][0] * ATT_SCALE;
                float a1 = acc[mi][ni][1] * ATT_SCALE;
                float a2 = acc[mi][ni][2] * ATT_SCALE;
                float a3 = acc[mi][ni][3] * ATT_SCALE;
                __half2 h0 = __floats2half2_rn(a0, a1);
                __half2 h1 = __floats2half2_rn(a2, a3);
                float2 f0 = __half22float2(h0), f1 = __half22float2(h1);
                *(__half2*)&Ch[(size_t)row * ldc + col]       = h0;
                *(__half2*)&Ch[(size_t)(row + 8) * ldc + col] = h1;
                *(__half2*)&Cl[(size_t)row * ldc + col] =
                    __floats2half2_rn(a0 - f0.x, a1 - f0.y);
                *(__half2*)&Cl[(size_t)(row + 8) * ldc + col] =
                    __floats2half2_rn(a2 - f1.x, a3 - f1.y);
            }
        }
    } else if (mode == 1) {
        #pragma unroll
        for (int mi = 0; mi < 4; ++mi) {
            int row = row0 + warp_m * 64 + mi * 16 + (lane >> 2);
            #pragma unroll
            for (int ni = 0; ni < 8; ++ni) {
                int col = col0 + warp_n * 64 + ni * 8 + (lane & 3) * 2;
                *(__half2*)&Ch[(size_t)row * ldc + col] =
                    __floats2half2_rn(acc[mi][ni][0], acc[mi][ni][1]);
                *(__half2*)&Ch[(size_t)(row + 8) * ldc + col] =
                    __floats2half2_rn(acc[mi][ni][2], acc[mi][ni][3]);
            }
        }
    } else {
        #pragma unroll
        for (int mi = 0; mi < 4; ++mi) {
            int row = row0 + warp_m * 64 + mi * 16 + (lane >> 2);
            #pragma unroll
            for (int ni = 0; ni < 8; ++ni) {
                int col = col0 + warp_n * 64 + ni * 8 + (lane & 3) * 2;
                if (col < N) {
                    *(float2*)&C[(size_t)row * ldc + col] =
                        make_float2(acc[mi][ni][0], acc[mi][ni][1]);
                    *(float2*)&C[(size_t)(row + 8) * ldc + col] =
                        make_float2(acc[mi][ni][2], acc[mi][ni][3]);
                }
            }
        }
    }
}

// ================= RMSNorm (fp16 hi/lo out) + k_pe RoPE (fp16) ============
__global__ __launch_bounds__(256) void rmsnorm_rope_kernel(
    const float* __restrict__ a,
    __half* __restrict__ kpeh,
    __half* __restrict__ cqh, __half* __restrict__ cql,
    __half* __restrict__ ckvh, __half* __restrict__ ckvl,
    const float* __restrict__ wq,
    const float* __restrict__ wkv,
    const int* __restrict__ pos_ids)
{
    const int s   = blockIdx.x;
    const int tid = threadIdx.x;
    const float* row = a + (size_t)s * A_COLS;
    __shared__ float red[8];

    float ss = 0.f;
    for (int i = tid; i < Q_LORA; i += 256) { float v = row[i]; ss += v * v; }
    #pragma unroll
    for (int o = 16; o; o >>= 1) ss += __shfl_xor_sync(0xffffffffu, ss, o);
    if ((tid & 31) == 0) red[tid >> 5] = ss;
    __syncthreads();
    float tot = 0.f;
    #pragma unroll
    for (int w = 0; w < 8; w++) tot += red[w];
    float inv = rsqrtf(tot / (float)Q_LORA + 1e-6f);
    for (int i = tid; i < Q_LORA; i += 256) {
        float v = row[i] * inv * wq[i];
        __half h = __float2half_rn(v);
        cqh[(size_t)s * Q_LORA + i] = h;
        cql[(size_t)s * Q_LORA + i] = __float2half_rn(v - __half2float(h));
    }
    __syncthreads();

    const float* row2 = row + Q_LORA;
    ss = 0.f;
    for (int i = tid; i < KV_LORA; i += 256) { float v = row2[i]; ss += v * v; }
    #pragma unroll
    for (int o = 16; o; o >>= 1) ss += __shfl_xor_sync(0xffffffffu, ss, o);
    if ((tid & 31) == 0) red[tid >> 5] = ss;
    __syncthreads();
    tot = 0.f;
    #pragma unroll
    for (int w = 0; w < 8; w++) tot += red[w];
    inv = rsqrtf(tot / (float)KV_LORA + 1e-6f);
    for (int i = tid; i < KV_LORA; i += 256) {
        float v = row2[i] * inv * wkv[i];
        __half h = __float2half_rn(v);
        ckvh[(size_t)s * KV_LORA + i] = h;
        ckvl[(size_t)s * KV_LORA + i] = __float2half_rn(v - __half2float(h));
    }

    if (tid < 32) {
        int p = pos_ids[s];
        float inv_freq = exp2f(-(float)tid * (ROPE_L2 / 32.0f));
        float ang = (float)p * inv_freq;
        float c, sn;
        __sincosf(ang, &sn, &c);
        float x1 = row[Q_LORA + KV_LORA + tid];
        float x2 = row[Q_LORA + KV_LORA + 32 + tid];
        kpeh[(size_t)s * ROPE + tid]      = __float2half_rn(x1 * c - x2 * sn);
        kpeh[(size_t)s * ROPE + 32 + tid] = __float2half_rn(x2 * c + x1 * sn);
    }
}

// ================= HMMA flash attention (2-term fp16, 128-query tiles) ====
#define QSTR   400
#define VSTR   272
#define SM_QH  0
#define SM_QL  51200
#define SM_ST0 102400
#define VHOFF  25600
#define STGSZ  43008
#define FSMEM  (SM_ST0 + 2 * STGSZ)     // 188416

__device__ __forceinline__ void issue_kv(
    const __half* __restrict__ KVh, const __half* __restrict__ KPh,
    int n0, int h, uint32_t stg, int tid)
{
    #pragma unroll
    for (int l = 0; l < 6; ++l) {
        int i = tid + l * 256;
        int r = i / 24, j = i % 24;
        uint32_t dst = stg + r * QSTR + j * 16;
        if (j < 16)
            cp16(dst, KVh + (size_t)(n0 + r) * KV_COLS + h * 2 * NOPE + j * 8);
        else
            cp16(dst, KPh + (size_t)(n0 + r) * ROPE + (j - 16) * 8);
    }
    #pragma unroll
    for (int l = 0; l < 4; ++l) {
        int i = tid + l * 256;
        int r = i / 16, j = i % 16;
        cp16(stg + VHOFF + r * VSTR + j * 16,
             KVh + (size_t)(n0 + r) * KV_COLS + h * 2 * NOPE + NOPE + j * 8);
    }
}

__global__ __launch_bounds__(256, 1) void flash_mma(
    const __half* __restrict__ Qh, const __half* __restrict__ Ql,
    const __half* __restrict__ KVh, const __half* __restrict__ KPh,
    __half* __restrict__ Oh, __half* __restrict__ Ol)
{
    extern __shared__ char sm[];
    uint32_t sb = smem_u32(sm);
    const int qt = (int)gridDim.x - 1 - (int)blockIdx.x;
    const int h = blockIdx.y;
    const int qm0 = qt * 128;
    const int tid = threadIdx.x, lane = tid & 31, warp = tid >> 5;

    #pragma unroll
    for (int l = 0; l < 12; ++l) {
        int i = tid + l * 256;
        int r = i / 24, j = i % 24;
        size_t off = (size_t)(qm0 + r) * Q_COLS + h * QDIM + j * 8;
        cp16(sb + SM_QH + r * QSTR + j * 16, Qh + off);
        cp16(sb + SM_QL + r * QSTR + j * 16, Ql + off);
    }
    issue_kv(KVh, KPh, 0, h, sb + SM_ST0, tid);
    CP_COMMIT();

    float acc[16][4];
    #pragma unroll
    for (int vt = 0; vt < 16; ++vt)
        #pragma unroll
        for (int e = 0; e < 4; ++e) acc[vt][e] = 0.f;
    float miA = -1e30f, miB = -1e30f, liA = 0.f, liB = 0.f;

    const int T = 2 * (qt + 1);
    const int rA = qm0 + warp * 16 + (lane >> 2);

    for (int t = 0; t < T; ++t) {
        if (t + 1 < T) {
            issue_kv(KVh, KPh, (t + 1) * 64, h, sb + SM_ST0 + ((t + 1) & 1) * STGSZ, tid);
            CP_COMMIT();
            CP_WAIT(1);
        } else {
            CP_WAIT(0);
        }
        __syncthreads();
        uint32_t stg = sb + SM_ST0 + (t & 1) * STGSZ;

        float sc[8][4];
        #pragma unroll
        for (int nt = 0; nt < 8; ++nt)
            #pragma unroll
            for (int e = 0; e < 4; ++e) sc[nt][e] = 0.f;

        const uint32_t qa = sb + (warp * 16 + (lane & 15)) * QSTR + (lane >> 4) * 16;
        #pragma unroll
        for (int kk = 0; kk < 12; ++kk) {
            uint32_t aH[4], aL[4];
            ldmx4(aH, qa + SM_QH + kk * 32);
            ldmx4(aL, qa + SM_QL + kk * 32);
            #pragma unroll
            for (int np = 0; np < 4; ++np) {
                uint32_t bH[4];
                uint32_t ba = stg + ((np * 2 + (lane >> 4)) * 8 + (lane & 7)) * QSTR
                              + ((lane >> 3) & 1) * 16 + kk * 32;
                ldmx4(bH, ba);
                mma16816(sc[np * 2],     aH, bH);
                mma16816(sc[np * 2],     aL, bH);
                mma16816(sc[np * 2 + 1], aH, bH + 2);
                mma16816(sc[np * 2 + 1], aL, bH + 2);
            }
        }

        if (t >= T - 2) {
            #pragma unroll
            for (int nt = 0; nt < 8; ++nt) {
                int c0 = t * 64 + nt * 8 + (lane & 3) * 2;
                if (c0     > rA)     sc[nt][0] = -1e30f;
                if (c0 + 1 > rA)     sc[nt][1] = -1e30f;
                if (c0     > rA + 8) sc[nt][2] = -1e30f;
                if (c0 + 1 > rA + 8) sc[nt][3] = -1e30f;
            }
        }

        float mA = -1e30f, mB = -1e30f;
        #pragma unroll
        for (int nt = 0; nt < 8; ++nt) {
            mA = fmaxf(mA, fmaxf(sc[nt][0], sc[nt][1]));
            mB = fmaxf(mB, fmaxf(sc[nt][2], sc[nt][3]));
        }
        mA = fmaxf(mA, __shfl_xor_sync(0xffffffffu, mA, 1));
        mA = fmaxf(mA, __shfl_xor_sync(0xffffffffu, mA, 2));
        mB = fmaxf(mB, __shfl_xor_sync(0xffffffffu, mB, 1));
        mB = fmaxf(mB, __shfl_xor_sync(0xffffffffu, mB, 2));
        float nmA = fmaxf(miA, mA), nmB = fmaxf(miB, mB);
        float cA = __expf(miA - nmA), cB = __expf(miB - nmB);
        miA = nmA; miB = nmB;

        float sA = 0.f, sB = 0.f;
        #pragma unroll
        for (int nt = 0; nt < 8; ++nt) {
            sc[nt][0] = __expf(sc[nt][0] - nmA); sA += sc[nt][0];
            sc[nt][1] = __expf(sc[nt][1] - nmA); sA += sc[nt][1];
            sc[nt][2] = __expf(sc[nt][2] - nmB); sB += sc[nt][2];
            sc[nt][3] = __expf(sc[nt][3] - nmB); sB += sc[nt][3];
        }
        sA += __shfl_xor_sync(0xffffffffu, sA, 1);
        sA += __shfl_xor_sync(0xffffffffu, sA, 2);
        sB += __shfl_xor_sync(0xffffffffu, sB, 1);
        sB += __shfl_xor_sync(0xffffffffu, sB, 2);
        liA = liA * cA + sA;
        liB = liB * cB + sB;
        #pragma unroll
        for (int vt = 0; vt < 16; ++vt) {
            acc[vt][0] *= cA; acc[vt][1] *= cA;
            acc[vt][2] *= cB; acc[vt][3] *= cB;
        }

        #pragma unroll
        for (int kp = 0; kp < 4; ++kp) {
            uint32_t aH[4], aL[4];
            #pragma unroll
            for (int q2 = 0; q2 < 2; ++q2) {
                const float* s0 = sc[2 * kp + q2];
                uint32_t h0 = packh2(s0[0], s0[1]);
                uint32_t h1 = packh2(s0[2], s0[3]);
                float2 f0 = __half22float2(*(__half2*)&h0);
                float2 f1 = __half22float2(*(__half2*)&h1);
                aH[q2 * 2 + 0] = h0;
                aH[q2 * 2 + 1] = h1;
                aL[q2 * 2 + 0] = packh2(s0[0] - f0.x, s0[1] - f0.y);
                aL[q2 * 2 + 1] = packh2(s0[2] - f1.x, s0[3] - f1.y);
            }
            #pragma unroll
            for (int vp = 0; vp < 8; ++vp) {
                uint32_t bH[4];
                uint32_t va = stg + VHOFF + (kp * 16 + (lane & 15)) * VSTR
                              + (vp * 2 + (lane >> 4)) * 16;
                ldmx4t(bH, va);
                mma16816(acc[vp * 2],     aH, bH);
                mma16816(acc[vp * 2],     aL, bH);
                mma16816(acc[vp * 2 + 1], aH, bH + 2);
                mma16816(acc[vp * 2 + 1], aL, bH + 2);
            }
        }
        __syncthreads();
    }

    float rlA = 1.f / liA, rlB = 1.f / liB;
    #pragma unroll
    for (int vt = 0; vt < 16; ++vt) {
        int col = h * VDIM + vt * 8 + (lane & 3) * 2;
        float a0 = acc[vt][0] * rlA, a1 = acc[vt][1] * rlA;
        float a2 = acc[vt][2] * rlB, a3 = acc[vt][3] * rlB;
        __half2 h0 = __floats2half2_rn(a0, a1);
        __half2 h1 = __floats2half2_rn(a2, a3);
        float2 f0 = __half22float2(h0), f1 = __half22float2(h1);
        *(__half2*)&Oh[(size_t)rA * O_COLS + col]       = h0;
        *(__half2*)&Oh[(size_t)(rA + 8) * O_COLS + col] = h1;
        *(__half2*)&Ol[(size_t)rA * O_COLS + col]       = __floats2half2_rn(a0 - f0.x, a1 - f0.y);
        *(__half2*)&Ol[(size_t)(rA + 8) * O_COLS + col] = __floats2half2_rn(a2 - f1.x, a3 - f1.y);
    }
}

// ================= launch =================
extern "C" void kernel_launch(void* const* d_in, const int* in_sizes, int n_in,
                              void* d_out, int out_size)
{
    const int*   pos   = (const int*)  d_in[0];
    const float* hid   = (const float*)d_in[1];
    const float* w_a   = (const float*)d_in[2];
    const float* wq_ln = (const float*)d_in[3];
    const float* wkv_ln= (const float*)d_in[4];
    const float* w_q_b = (const float*)d_in[5];
    const float* w_kv_b= (const float*)d_in[6];
    const float* w_o   = (const float*)d_in[7];
    float* out = (float*)d_out;

    float* a;
    cudaGetSymbolAddress((void**)&a, g_a);

    __half *h_hi, *h_lo, *cq_hi, *cq_lo, *ckv_hi, *ckv_lo, *at_hi, *at_lo;
    __half *qs_hi, *qs_lo, *kvh, *kpeh, *wa_h, *wqb_h, *wkvb_h, *wo_h;
    cudaGetSymbolAddress((void**)&h_hi,   g_h_hi);   cudaGetSymbolAddress((void**)&h_lo,   g_h_lo);
    cudaGetSymbolAddress((void**)&cq_hi,  g_cq_hi);  cudaGetSymbolAddress((void**)&cq_lo,  g_cq_lo);
    cudaGetSymbolAddress((void**)&ckv_hi, g_ckv_hi); cudaGetSymbolAddress((void**)&ckv_lo, g_ckv_lo);
    cudaGetSymbolAddress((void**)&at_hi,  g_at_hi);  cudaGetSymbolAddress((void**)&at_lo,  g_at_lo);
    cudaGetSymbolAddress((void**)&qs_hi,  g_qs_hi);  cudaGetSymbolAddress((void**)&qs_lo,  g_qs_lo);
    cudaGetSymbolAddress((void**)&kvh,    g_kvh);    cudaGetSymbolAddress((void**)&kpeh,   g_kpeh);
    cudaGetSymbolAddress((void**)&wa_h,   g_wa_h);   cudaGetSymbolAddress((void**)&wqb_h,  g_wqb_h);
    cudaGetSymbolAddress((void**)&wkvb_h, g_wkvb_h); cudaGetSymbolAddress((void**)&wo_h,   g_wo_h);

    cudaFuncSetAttribute(mma_gemm, cudaFuncAttributeMaxDynamicSharedMemorySize, GSMEM);
    cudaFuncSetAttribute(flash_mma, cudaFuncAttributeMaxDynamicSharedMemorySize, FSMEM);

    // ---- side stream: weight conversions not needed until GEMM 3 ----
    cudaStream_t s2;
    cudaStreamCreateWithFlags(&s2, cudaStreamNonBlocking);
    cudaEvent_t evFork, evJoin;
    cudaEventCreateWithFlags(&evFork, cudaEventDisableTiming);
    cudaEventCreateWithFlags(&evJoin, cudaEventDisableTiming);

    cudaEventRecord(evFork, 0);
    cudaStreamWaitEvent(s2, evFork, 0);
    cvt_hi<<<2048, 256, 0, s2>>>(w_q_b,  wqb_h,  Q_COLS * Q_LORA / 4, Q_LORA, Q_COLS);
    cvt_hi<<<2048, 256, 0, s2>>>(w_kv_b, wkvb_h, KV_COLS * KV_LORA / 4, KV_LORA, KV_COLS);
    cvt_hi<<<2048, 256, 0, s2>>>(w_o,    wo_h,   HID * O_COLS / 4, O_COLS, HID);
    cudaEventRecord(evJoin, s2);

    // ---- main stream ----
    cvt_hi<<<4096, 256>>>(w_a, wa_h, A_COLS_P * HID / 4, HID, A_COLS);
    cvt_split<<<4096, 256>>>(hid, h_hi, h_lo, S * HID / 4, 1.f);

    // 1) fused-A GEMM (fp32 out)
    mma_gemm<<<dim3(A_COLS_P / 256, S / 128), 256, GSMEM>>>(
        h_hi, h_lo, wa_h, a, nullptr, nullptr, pos, A_COLS, A_COLS, HID, 0);

    // 2) RMSNorm + k_pe rope
    rmsnorm_rope_kernel<<<S, 256>>>(a, kpeh, cq_hi, cq_lo, ckv_hi, ckv_lo,
                                    wq_ln, wkv_ln, pos);

    cudaStreamWaitEvent(0, evJoin, 0);

    // 3) q GEMM (rope + scale + fp16 hi/lo split fused in epilogue)
    mma_gemm<<<dim3(Q_COLS / 256, S / 128), 256, GSMEM>>>(
        cq_hi, cq_lo, wqb_h, nullptr, qs_hi, qs_lo, pos, Q_COLS, Q_COLS, Q_LORA, 2);

    // 4) kv GEMM (fp16 hi out, direct flash operand)
    mma_gemm<<<dim3(KV_COLS / 256, S / 128), 256, GSMEM>>>(
        ckv_hi, ckv_lo, wkvb_h, nullptr, kvh, nullptr, pos, KV_COLS, KV_COLS, KV_LORA, 1);

    // 5) HMMA flash attention (fp16 hi/lo out), 128-query tiles
    flash_mma<<<dim3(S / 128, H), 256, FSMEM>>>(qs_hi, qs_lo, kvh, kpeh, at_hi, at_lo);

    // 6) output GEMM (fp32 out = final)
    mma_gemm<<<dim3(HID / 256, S / 128), 256, GSMEM>>>(
        at_hi, at_lo, wo_h, out, nullptr, nullptr, pos, HID, HID, O_COLS, 0);

    cudaEventDestroy(evFork);
    cudaEventDestroy(evJoin);
    cudaStreamDestroy(s2);
}

// round 10
// speedup vs baseline: 9.1243x; 1.0799x over previous
#include <cuda_runtime.h>
#include <cuda_fp16.h>
#include <math.h>
#include <stdint.h>

// ---------------- problem constants ----------------
#define S        2048
#define HID      4096
#define H        32
#define Q_LORA   1536
#define KV_LORA  512
#define NOPE     128
#define ROPE     64
#define VDIM     128
#define A_COLS   (Q_LORA + KV_LORA + ROPE)   // 2112
#define A_COLS_P 2304                        // padded to 256-mult
#define QDIM     (NOPE + ROPE)               // 192
#define Q_COLS   (H * QDIM)                  // 6144
#define KV_COLS  (H * 2 * NOPE)              // 8192
#define O_COLS   (H * VDIM)                  // 4096
#define ATT_SCALE 0.07216878364870322992f    // 1/sqrt(192)
#define ROPE_L2  13.287712379549449f         // log2(10000)

// ---------------- scratch ----------------
__device__ __align__(256) float g_a[S * A_COLS];

// fp16 operands
__device__ __align__(256) __half g_h_hi[S * HID],     g_h_lo[S * HID];
__device__ __align__(256) __half g_cq_hi[S * Q_LORA], g_cq_lo[S * Q_LORA];
__device__ __align__(256) __half g_ckv_hi[S * KV_LORA], g_ckv_lo[S * KV_LORA];
__device__ __align__(256) __half g_at_hi[S * O_COLS], g_at_lo[S * O_COLS];
__device__ __align__(256) __half g_qs_hi[S * Q_COLS], g_qs_lo[S * Q_COLS];
__device__ __align__(256) __half g_kvh[S * KV_COLS];
__device__ __align__(256) __half g_kpeh[S * ROPE];
// weights: fp16 hi only (B-side operand), rows padded to 256-mult
__device__ __align__(256) __half g_wa_h[A_COLS_P * HID];
__device__ __align__(256) __half g_wqb_h[Q_COLS * Q_LORA];
__device__ __align__(256) __half g_wkvb_h[KV_COLS * KV_LORA];
__device__ __align__(256) __half g_wo_h[HID * O_COLS];

// ================= portable PTX helpers =================
__device__ __forceinline__ uint32_t smem_u32(const void* p) {
    uint32_t a;
    asm("{ .reg .u64 t; cvta.to.shared.u64 t, %1; cvt.u32.u64 %0, t; }"
        : "=r"(a) : "l"(p));
    return a;
}
__device__ __forceinline__ void cp16(uint32_t dst, const void* src) {
    asm volatile("cp.async.cg.shared.global [%0], [%1], 16;" :: "r"(dst), "l"(src));
}
#define CP_COMMIT()  asm volatile("cp.async.commit_group;" ::: "memory")
#define CP_WAIT(n)   asm volatile("cp.async.wait_group %0;" :: "n"(n) : "memory")

__device__ __forceinline__ void ldmx4(uint32_t* r, uint32_t addr) {
    asm volatile("ldmatrix.sync.aligned.m8n8.x4.shared.b16 {%0,%1,%2,%3}, [%4];"
                 : "=r"(r[0]), "=r"(r[1]), "=r"(r[2]), "=r"(r[3]) : "r"(addr));
}
__device__ __forceinline__ void ldmx2(uint32_t* r, uint32_t addr) {
    asm volatile("ldmatrix.sync.aligned.m8n8.x2.shared.b16 {%0,%1}, [%2];"
                 : "=r"(r[0]), "=r"(r[1]) : "r"(addr));
}
__device__ __forceinline__ void ldmx4t(uint32_t* r, uint32_t addr) {
    asm volatile("ldmatrix.sync.aligned.m8n8.x4.trans.shared.b16 {%0,%1,%2,%3}, [%4];"
                 : "=r"(r[0]), "=r"(r[1]), "=r"(r[2]), "=r"(r[3]) : "r"(addr));
}
__device__ __forceinline__ void mma16816(float* c, const uint32_t* a, const uint32_t* b) {
    asm volatile(
        "mma.sync.aligned.m16n8k16.row.col.f32.f16.f16.f32 "
        "{%0,%1,%2,%3},{%4,%5,%6,%7},{%8,%9},{%0,%1,%2,%3};"
        : "+f"(c[0]), "+f"(c[1]), "+f"(c[2]), "+f"(c[3])
        : "r"(a[0]), "r"(a[1]), "r"(a[2]), "r"(a[3]), "r"(b[0]), "r"(b[1]));
}
__device__ __forceinline__ uint32_t packh2(float x, float y) {
    __half2 h = __floats2half2_rn(x, y);
    return *(uint32_t*)&h;
}

// ================= fp32 -> fp16 hi/lo split (activations) =================
__global__ __launch_bounds__(256) void cvt_split(
    const float* __restrict__ src,
    __half* __restrict__ hi, __half* __restrict__ lo,
    int total4, float scale)
{
    for (int i = blockIdx.x * 256 + threadIdx.x; i < total4; i += gridDim.x * 256) {
        int e = i * 4;
        float4 f = *(const float4*)(src + (size_t)e);
        f.x *= scale; f.y *= scale; f.z *= scale; f.w *= scale;
        __half2 h01 = __floats2half2_rn(f.x, f.y);
        __half2 h23 = __floats2half2_rn(f.z, f.w);
        float2 b01 = __half22float2(h01), b23 = __half22float2(h23);
        *(__half2*)(hi + (size_t)e)     = h01;
        *(__half2*)(hi + (size_t)e + 2) = h23;
        *(__half2*)(lo + (size_t)e)     = __floats2half2_rn(f.x - b01.x, f.y - b01.y);
        *(__half2*)(lo + (size_t)e + 2) = __floats2half2_rn(f.z - b23.x, f.w - b23.y);
    }
}

// ================= fp32 -> fp16 hi only (weights, padded rows) ============
__global__ __launch_bounds__(256) void cvt_hi(
    const float* __restrict__ src, __half* __restrict__ hi,
    int total4, int cols, int rows)
{
    for (int i = blockIdx.x * 256 + threadIdx.x; i < total4; i += gridDim.x * 256) {
        int e = i * 4;
        int r = e / cols;
        float4 f = make_float4(0.f, 0.f, 0.f, 0.f);
        if (r < rows) f = *(const float4*)(src + (size_t)e);
        *(__half2*)(hi + (size_t)e)     = __floats2half2_rn(f.x, f.y);
        *(__half2*)(hi + (size_t)e + 2) = __floats2half2_rn(f.z, f.w);
    }
}

// ================= 2-term fp16 HMMA GEMM =================================
// CTA 128x256, warp tile 64x64 (8 warps, 2x4), BK=32, 4-stage cp.async ring.
// mode 0: fp32 C.  mode 1: fp16 hi -> Ch.  mode 2: rope+scale+split -> Ch,Cl.
#define BKC   32
#define ROWB  80
#define ATILE (128 * ROWB)             // 10240
#define BTILE (256 * ROWB)             // 20480
#define STG   (2 * ATILE + BTILE)      // 40960
#define NS    4
#define GSMEM (NS * STG)               // 163840

__device__ __forceinline__ void issue_stage(
    const __half* __restrict__ Ah, const __half* __restrict__ Al,
    const __half* __restrict__ Bh,
    int row0, int col0, int K, int c, uint32_t sbase, int slot, int tid)
{
    uint32_t st = sbase + slot * STG;
    #pragma unroll
    for (int l = 0; l < 2; ++l) {
        int v = tid + l * 256;
        int r = v >> 2;
        int j = v & 3;
        size_t goffA = (size_t)(row0 + r) * K + c * BKC + j * 8;
        uint32_t so = r * ROWB + j * 16;
        cp16(st + so,         Ah + goffA);
        cp16(st + ATILE + so, Al + goffA);
    }
    #pragma unroll
    for (int l = 0; l < 4; ++l) {
        int v = tid + l * 256;
        int r = v >> 2;
        int j = v & 3;
        cp16(st + 2 * ATILE + r * ROWB + j * 16,
             Bh + (size_t)(col0 + r) * K + c * BKC + j * 8);
    }
}

__global__ __launch_bounds__(256, 1) void mma_gemm(
    const __half* __restrict__ Ah, const __half* __restrict__ Al,
    const __half* __restrict__ Bh,
    float* __restrict__ C, __half* __restrict__ Ch, __half* __restrict__ Cl,
    const int* __restrict__ pos,
    int ldc, int N, int K, int mode)
{
    extern __shared__ char sm[];
    uint32_t sbase = smem_u32(sm);
    const int tid    = threadIdx.x;
    const int lane   = tid & 31;
    const int warp   = tid >> 5;
    const int warp_m = warp >> 2;
    const int warp_n = warp & 3;
    const int row0 = blockIdx.y * 128;
    const int col0 = blockIdx.x * 256;

    float acc[4][8][4];
    #pragma unroll
    for (int mi = 0; mi < 4; ++mi)
        #pragma unroll
        for (int ni = 0; ni < 8; ++ni)
            #pragma unroll
            for (int e = 0; e < 4; ++e) acc[mi][ni][e] = 0.f;

    const int nch = K / BKC;

    #pragma unroll
    for (int p = 0; p < NS - 1; ++p) {
        if (p < nch) issue_stage(Ah, Al, Bh, row0, col0, K, p, sbase, p, tid);
        CP_COMMIT();
    }

    const uint32_t a_l = (uint32_t)((warp_m * 64 + (lane & 15)) * ROWB + (lane >> 4) * 16);
    const uint32_t b_l = (uint32_t)(2 * ATILE + (warp_n * 64 + (lane & 7)) * ROWB
                                    + ((lane >> 3) & 1) * 16);

    for (int c = 0; c < nch; ++c) {
        CP_WAIT(NS - 2);
        __syncthreads();
        int np = c + NS - 1;
        if (np < nch)
            issue_stage(Ah, Al, Bh, row0, col0, K, np, sbase, np & (NS - 1), tid);
        CP_COMMIT();

        uint32_t st = sbase + (c & (NS - 1)) * STG;

        #pragma unroll
        for (int ki = 0; ki < 2; ++ki) {
            uint32_t ah[4][4], al[4][4];
            #pragma unroll
            for (int mi = 0; mi < 4; ++mi) {
                uint32_t ad = st + a_l + mi * (16 * ROWB) + ki * 32;
                ldmx4(ah[mi], ad);
                ldmx4(al[mi], ad + ATILE);
            }
            #pragma unroll
            for (int ni = 0; ni < 8; ++ni) {
                uint32_t bh[2];
                ldmx2(bh, st + b_l + ni * (8 * ROWB) + ki * 32);
                #pragma unroll
                for (int mi = 0; mi < 4; ++mi) {
                    mma16816(acc[mi][ni], ah[mi], bh);
                    mma16816(acc[mi][ni], al[mi], bh);
                }
            }
        }
    }

    if (mode == 2) {
        // q epilogue: rope on pe tiles, then scale + fp16 hi/lo split.
        int ttype = ((col0 >> 6) + warp_n) % 3;
        if (ttype == 2) {
            #pragma unroll
            for (int mi = 0; mi < 4; ++mi) {
                int r0 = row0 + warp_m * 64 + mi * 16 + (lane >> 2);
                float p0 = (float)pos[r0];
                float p1 = (float)pos[r0 + 8];
                #pragma unroll
                for (int ni = 0; ni < 4; ++ni) {
                    #pragma unroll
                    for (int e = 0; e < 2; ++e) {
                        int i = ni * 8 + (lane & 3) * 2 + e;
                        float f = exp2f(-(float)i * (ROPE_L2 / 32.0f));
                        float c0, s0, c1, s1;
                        __sincosf(p0 * f, &s0, &c0);
                        __sincosf(p1 * f, &s1, &c1);
                        float x1 = acc[mi][ni][e],     x2 = acc[mi][ni + 4][e];
                        acc[mi][ni][e]       = x1 * c0 - x2 * s0;
                        acc[mi][ni + 4][e]   = x2 * c0 + x1 * s0;
                        float y1 = acc[mi][ni][e + 2], y2 = acc[mi][ni + 4][e + 2];
                        acc[mi][ni][e + 2]     = y1 * c1 - y2 * s1;
                        acc[mi][ni + 4][e + 2] = y2 * c1 + y1 * s1;
                    }
                }
            }
        }
        #pragma unroll
        for (int mi = 0; mi < 4; ++mi) {
            int row = row0 + warp_m * 64 + mi * 16 + (lane >> 2);
            #pragma unroll
            for (int ni = 0; ni < 8; ++ni) {
                int col = col0 + warp_n * 64 + ni * 8 + (lane & 3) * 2;
                float a0 = acc[mi][ni][0] * ATT_SCALE;
                float a1 = acc[mi][ni][1] * ATT_SCALE;
                float a2 = acc[mi][ni][2] * ATT_SCALE;
                float a3 = acc[mi][ni][3] * ATT_SCALE;
                __half2 h0 = __floats2half2_rn(a0, a1);
                __half2 h1 = __floats2half2_rn(a2, a3);
                float2 f0 = __half22float2(h0), f1 = __half22float2(h1);
                *(__half2*)&Ch[(size_t)row * ldc + col]       = h0;
                *(__half2*)&Ch[(size_t)(row + 8) * ldc + col] = h1;
                *(__half2*)&Cl[(size_t)row * ldc + col] =
                    __floats2half2_rn(a0 - f0.x, a1 - f0.y);
                *(__half2*)&Cl[(size_t)(row + 8) * ldc + col] =
                    __floats2half2_rn(a2 - f1.x, a3 - f1.y);
            }
        }
    } else if (mode == 1) {
        #pragma unroll
        for (int mi = 0; mi < 4; ++mi) {
            int row = row0 + warp_m * 64 + mi * 16 + (lane >> 2);
            #pragma unroll
            for (int ni = 0; ni < 8; ++ni) {
                int col = col0 + warp_n * 64 + ni * 8 + (lane & 3) * 2;
                *(__half2*)&Ch[(size_t)row * ldc + col] =
                    __floats2half2_rn(acc[mi][ni][0], acc[mi][ni][1]);
                *(__half2*)&Ch[(size_t)(row + 8) * ldc + col] =
                    __floats2half2_rn(acc[mi][ni][2], acc[mi][ni][3]);
            }
        }
    } else {
        #pragma unroll
        for (int mi = 0; mi < 4; ++mi) {
            int row = row0 + warp_m * 64 + mi * 16 + (lane >> 2);
            #pragma unroll
            for (int ni = 0; ni < 8; ++ni) {
                int col = col0 + warp_n * 64 + ni * 8 + (lane & 3) * 2;
                if (col < N) {
                    *(float2*)&C[(size_t)row * ldc + col] =
                        make_float2(acc[mi][ni][0], acc[mi][ni][1]);
                    *(float2*)&C[(size_t)(row + 8) * ldc + col] =
                        make_float2(acc[mi][ni][2], acc[mi][ni][3]);
                }
            }
        }
    }
}

// ================= RMSNorm (fp16 hi/lo out) + k_pe RoPE (fp16) ============
__global__ __launch_bounds__(256) void rmsnorm_rope_kernel(
    const float* __restrict__ a,
    __half* __restrict__ kpeh,
    __half* __restrict__ cqh, __half* __restrict__ cql,
    __half* __restrict__ ckvh, __half* __restrict__ ckvl,
    const float* __restrict__ wq,
    const float* __restrict__ wkv,
    const int* __restrict__ pos_ids)
{
    const int s   = blockIdx.x;
    const int tid = threadIdx.x;
    const float* row = a + (size_t)s * A_COLS;
    __shared__ float red[8];

    float ss = 0.f;
    for (int i = tid; i < Q_LORA; i += 256) { float v = row[i]; ss += v * v; }
    #pragma unroll
    for (int o = 16; o; o >>= 1) ss += __shfl_xor_sync(0xffffffffu, ss, o);
    if ((tid & 31) == 0) red[tid >> 5] = ss;
    __syncthreads();
    float tot = 0.f;
    #pragma unroll
    for (int w = 0; w < 8; w++) tot += red[w];
    float inv = rsqrtf(tot / (float)Q_LORA + 1e-6f);
    for (int i = tid; i < Q_LORA; i += 256) {
        float v = row[i] * inv * wq[i];
        __half h = __float2half_rn(v);
        cqh[(size_t)s * Q_LORA + i] = h;
        cql[(size_t)s * Q_LORA + i] = __float2half_rn(v - __half2float(h));
    }
    __syncthreads();

    const float* row2 = row + Q_LORA;
    ss = 0.f;
    for (int i = tid; i < KV_LORA; i += 256) { float v = row2[i]; ss += v * v; }
    #pragma unroll
    for (int o = 16; o; o >>= 1) ss += __shfl_xor_sync(0xffffffffu, ss, o);
    if ((tid & 31) == 0) red[tid >> 5] = ss;
    __syncthreads();
    tot = 0.f;
    #pragma unroll
    for (int w = 0; w < 8; w++) tot += red[w];
    inv = rsqrtf(tot / (float)KV_LORA + 1e-6f);
    for (int i = tid; i < KV_LORA; i += 256) {
        float v = row2[i] * inv * wkv[i];
        __half h = __float2half_rn(v);
        ckvh[(size_t)s * KV_LORA + i] = h;
        ckvl[(size_t)s * KV_LORA + i] = __float2half_rn(v - __half2float(h));
    }

    if (tid < 32) {
        int p = pos_ids[s];
        float inv_freq = exp2f(-(float)tid * (ROPE_L2 / 32.0f));
        float ang = (float)p * inv_freq;
        float c, sn;
        __sincosf(ang, &sn, &c);
        float x1 = row[Q_LORA + KV_LORA + tid];
        float x2 = row[Q_LORA + KV_LORA + 32 + tid];
        kpeh[(size_t)s * ROPE + tid]      = __float2half_rn(x1 * c - x2 * sn);
        kpeh[(size_t)s * ROPE + 32 + tid] = __float2half_rn(x2 * c + x1 * sn);
    }
}

// ================= HMMA flash attention =====================
// 2-term QK^T, 1-term PV. 128-query tiles, 256 threads.
#define QSTR   400
#define VSTR   272
#define SM_QH  0
#define SM_QL  51200
#define SM_ST0 102400
#define VHOFF  25600
#define STGSZ  43008
#define FSMEM  (SM_ST0 + 2 * STGSZ)     // 188416

__device__ __forceinline__ void issue_kv(
    const __half* __restrict__ KVh, const __half* __restrict__ KPh,
    int n0, int h, uint32_t stg, int tid)
{
    #pragma unroll
    for (int l = 0; l < 6; ++l) {
        int i = tid + l * 256;
        int r = i / 24, j = i % 24;
        uint32_t dst = stg + r * QSTR + j * 16;
        if (j < 16)
            cp16(dst, KVh + (size_t)(n0 + r) * KV_COLS + h * 2 * NOPE + j * 8);
        else
            cp16(dst, KPh + (size_t)(n0 + r) * ROPE + (j - 16) * 8);
    }
    #pragma unroll
    for (int l = 0; l < 4; ++l) {
        int i = tid + l * 256;
        int r = i / 16, j = i % 16;
        cp16(stg + VHOFF + r * VSTR + j * 16,
             KVh + (size_t)(n0 + r) * KV_COLS + h * 2 * NOPE + NOPE + j * 8);
    }
}

__global__ __launch_bounds__(256, 1) void flash_mma(
    const __half* __restrict__ Qh, const __half* __restrict__ Ql,
    const __half* __restrict__ KVh, const __half* __restrict__ KPh,
    __half* __restrict__ Oh, __half* __restrict__ Ol)
{
    extern __shared__ char sm[];
    uint32_t sb = smem_u32(sm);
    const int qt = (int)gridDim.x - 1 - (int)blockIdx.x;
    const int h = blockIdx.y;
    const int qm0 = qt * 128;
    const int tid = threadIdx.x, lane = tid & 31, warp = tid >> 5;

    #pragma unroll
    for (int l = 0; l < 12; ++l) {
        int i = tid + l * 256;
        int r = i / 24, j = i % 24;
        size_t off = (size_t)(qm0 + r) * Q_COLS + h * QDIM + j * 8;
        cp16(sb + SM_QH + r * QSTR + j * 16, Qh + off);
        cp16(sb + SM_QL + r * QSTR + j * 16, Ql + off);
    }
    issue_kv(KVh, KPh, 0, h, sb + SM_ST0, tid);
    CP_COMMIT();

    float acc[16][4];
    #pragma unroll
    for (int vt = 0; vt < 16; ++vt)
        #pragma unroll
        for (int e = 0; e < 4; ++e) acc[vt][e] = 0.f;
    float miA = -1e30f, miB = -1e30f, liA = 0.f, liB = 0.f;

    const int T = 2 * (qt + 1);
    const int rA = qm0 + warp * 16 + (lane >> 2);

    for (int t = 0; t < T; ++t) {
        if (t + 1 < T) {
            issue_kv(KVh, KPh, (t + 1) * 64, h, sb + SM_ST0 + ((t + 1) & 1) * STGSZ, tid);
            CP_COMMIT();
            CP_WAIT(1);
        } else {
            CP_WAIT(0);
        }
        __syncthreads();
        uint32_t stg = sb + SM_ST0 + (t & 1) * STGSZ;

        float sc[8][4];
        #pragma unroll
        for (int nt = 0; nt < 8; ++nt)
            #pragma unroll
            for (int e = 0; e < 4; ++e) sc[nt][e] = 0.f;

        const uint32_t qa = sb + (warp * 16 + (lane & 15)) * QSTR + (lane >> 4) * 16;
        #pragma unroll
        for (int kk = 0; kk < 12; ++kk) {
            uint32_t aH[4], aL[4];
            ldmx4(aH, qa + SM_QH + kk * 32);
            ldmx4(aL, qa + SM_QL + kk * 32);
            #pragma unroll
            for (int np = 0; np < 4; ++np) {
                uint32_t bH[4];
                uint32_t ba = stg + ((np * 2 + (lane >> 4)) * 8 + (lane & 7)) * QSTR
                              + ((lane >> 3) & 1) * 16 + kk * 32;
                ldmx4(bH, ba);
                mma16816(sc[np * 2],     aH, bH);
                mma16816(sc[np * 2],     aL, bH);
                mma16816(sc[np * 2 + 1], aH, bH + 2);
                mma16816(sc[np * 2 + 1], aL, bH + 2);
            }
        }

        if (t >= T - 2) {
            #pragma unroll
            for (int nt = 0; nt < 8; ++nt) {
                int c0 = t * 64 + nt * 8 + (lane & 3) * 2;
                if (c0     > rA)     sc[nt][0] = -1e30f;
                if (c0 + 1 > rA)     sc[nt][1] = -1e30f;
                if (c0     > rA + 8) sc[nt][2] = -1e30f;
                if (c0 + 1 > rA + 8) sc[nt][3] = -1e30f;
            }
        }

        float mA = -1e30f, mB = -1e30f;
        #pragma unroll
        for (int nt = 0; nt < 8; ++nt) {
            mA = fmaxf(mA, fmaxf(sc[nt][0], sc[nt][1]));
            mB = fmaxf(mB, fmaxf(sc[nt][2], sc[nt][3]));
        }
        mA = fmaxf(mA, __shfl_xor_sync(0xffffffffu, mA, 1));
        mA = fmaxf(mA, __shfl_xor_sync(0xffffffffu, mA, 2));
        mB = fmaxf(mB, __shfl_xor_sync(0xffffffffu, mB, 1));
        mB = fmaxf(mB, __shfl_xor_sync(0xffffffffu, mB, 2));
        float nmA = fmaxf(miA, mA), nmB = fmaxf(miB, mB);
        float cA = __expf(miA - nmA), cB = __expf(miB - nmB);
        miA = nmA; miB = nmB;

        float sA = 0.f, sB = 0.f;
        #pragma unroll
        for (int nt = 0; nt < 8; ++nt) {
            sc[nt][0] = __expf(sc[nt][0] - nmA); sA += sc[nt][0];
            sc[nt][1] = __expf(sc[nt][1] - nmA); sA += sc[nt][1];
            sc[nt][2] = __expf(sc[nt][2] - nmB); sB += sc[nt][2];
            sc[nt][3] = __expf(sc[nt][3] - nmB); sB += sc[nt][3];
        }
        sA += __shfl_xor_sync(0xffffffffu, sA, 1);
        sA += __shfl_xor_sync(0xffffffffu, sA, 2);
        sB += __shfl_xor_sync(0xffffffffu, sB, 1);
        sB += __shfl_xor_sync(0xffffffffu, sB, 2);
        liA = liA * cA + sA;
        liB = liB * cB + sB;
        #pragma unroll
        for (int vt = 0; vt < 16; ++vt) {
            acc[vt][0] *= cA; acc[vt][1] *= cA;
            acc[vt][2] *= cB; acc[vt][3] *= cB;
        }

        // ---- attn += P V (1-term: P rounded to fp16) ----
        #pragma unroll
        for (int kp = 0; kp < 4; ++kp) {
            uint32_t aH[4];
            #pragma unroll
            for (int q2 = 0; q2 < 2; ++q2) {
                const float* s0 = sc[2 * kp + q2];
                aH[q2 * 2 + 0] = packh2(s0[0], s0[1]);
                aH[q2 * 2 + 1] = packh2(s0[2], s0[3]);
            }
            #pragma unroll
            for (int vp = 0; vp < 8; ++vp) {
                uint32_t bH[4];
                uint32_t va = stg + VHOFF + (kp * 16 + (lane & 15)) * VSTR
                              + (vp * 2 + (lane >> 4)) * 16;
                ldmx4t(bH, va);
                mma16816(acc[vp * 2],     aH, bH);
                mma16816(acc[vp * 2 + 1], aH, bH + 2);
            }
        }
        __syncthreads();
    }

    float rlA = 1.f / liA, rlB = 1.f / liB;
    #pragma unroll
    for (int vt = 0; vt < 16; ++vt) {
        int col = h * VDIM + vt * 8 + (lane & 3) * 2;
        float a0 = acc[vt][0] * rlA, a1 = acc[vt][1] * rlA;
        float a2 = acc[vt][2] * rlB, a3 = acc[vt][3] * rlB;
        __half2 h0 = __floats2half2_rn(a0, a1);
        __half2 h1 = __floats2half2_rn(a2, a3);
        float2 f0 = __half22float2(h0), f1 = __half22float2(h1);
        *(__half2*)&Oh[(size_t)rA * O_COLS + col]       = h0;
        *(__half2*)&Oh[(size_t)(rA + 8) * O_COLS + col] = h1;
        *(__half2*)&Ol[(size_t)rA * O_COLS + col]       = __floats2half2_rn(a0 - f0.x, a1 - f0.y);
        *(__half2*)&Ol[(size_t)(rA + 8) * O_COLS + col] = __floats2half2_rn(a2 - f1.x, a3 - f1.y);
    }
}

// ================= launch =================
extern "C" void kernel_launch(void* const* d_in, const int* in_sizes, int n_in,
                              void* d_out, int out_size)
{
    const int*   pos   = (const int*)  d_in[0];
    const float* hid   = (const float*)d_in[1];
    const float* w_a   = (const float*)d_in[2];
    const float* wq_ln = (const float*)d_in[3];
    const float* wkv_ln= (const float*)d_in[4];
    const float* w_q_b = (const float*)d_in[5];
    const float* w_kv_b= (const float*)d_in[6];
    const float* w_o   = (const float*)d_in[7];
    float* out = (float*)d_out;

    float* a;
    cudaGetSymbolAddress((void**)&a, g_a);

    __half *h_hi, *h_lo, *cq_hi, *cq_lo, *ckv_hi, *ckv_lo, *at_hi, *at_lo;
    __half *qs_hi, *qs_lo, *kvh, *kpeh, *wa_h, *wqb_h, *wkvb_h, *wo_h;
    cudaGetSymbolAddress((void**)&h_hi,   g_h_hi);   cudaGetSymbolAddress((void**)&h_lo,   g_h_lo);
    cudaGetSymbolAddress((void**)&cq_hi,  g_cq_hi);  cudaGetSymbolAddress((void**)&cq_lo,  g_cq_lo);
    cudaGetSymbolAddress((void**)&ckv_hi, g_ckv_hi); cudaGetSymbolAddress((void**)&ckv_lo, g_ckv_lo);
    cudaGetSymbolAddress((void**)&at_hi,  g_at_hi);  cudaGetSymbolAddress((void**)&at_lo,  g_at_lo);
    cudaGetSymbolAddress((void**)&qs_hi,  g_qs_hi);  cudaGetSymbolAddress((void**)&qs_lo,  g_qs_lo);
    cudaGetSymbolAddress((void**)&kvh,    g_kvh);    cudaGetSymbolAddress((void**)&kpeh,   g_kpeh);
    cudaGetSymbolAddress((void**)&wa_h,   g_wa_h);   cudaGetSymbolAddress((void**)&wqb_h,  g_wqb_h);
    cudaGetSymbolAddress((void**)&wkvb_h, g_wkvb_h); cudaGetSymbolAddress((void**)&wo_h,   g_wo_h);

    cudaFuncSetAttribute(mma_gemm, cudaFuncAttributeMaxDynamicSharedMemorySize, GSMEM);
    cudaFuncSetAttribute(flash_mma, cudaFuncAttributeMaxDynamicSharedMemorySize, FSMEM);

    // ---- side stream s2 ----
    cudaStream_t s2;
    cudaStreamCreateWithFlags(&s2, cudaStreamNonBlocking);
    cudaEvent_t evFork, evW, evNorm, evKV;
    cudaEventCreateWithFlags(&evFork, cudaEventDisableTiming);
    cudaEventCreateWithFlags(&evW,    cudaEventDisableTiming);
    cudaEventCreateWithFlags(&evNorm, cudaEventDisableTiming);
    cudaEventCreateWithFlags(&evKV,   cudaEventDisableTiming);

    cudaEventRecord(evFork, 0);
    cudaStreamWaitEvent(s2, evFork, 0);
    // s2: weight conversions needed for GEMMs 3/4/6
    cvt_hi<<<2048, 256, 0, s2>>>(w_q_b,  wqb_h,  Q_COLS * Q_LORA / 4, Q_LORA, Q_COLS);
    cvt_hi<<<2048, 256, 0, s2>>>(w_kv_b, wkvb_h, KV_COLS * KV_LORA / 4, KV_LORA, KV_COLS);
    cvt_hi<<<2048, 256, 0, s2>>>(w_o,    wo_h,   HID * O_COLS / 4, O_COLS, HID);
    cudaEventRecord(evW, s2);

    // ---- main stream ----
    cvt_hi<<<4096, 256>>>(w_a, wa_h, A_COLS_P * HID / 4, HID, A_COLS);
    cvt_split<<<4096, 256>>>(hid, h_hi, h_lo, S * HID / 4, 1.f);

    // 1) fused-A GEMM (fp32 out)
    mma_gemm<<<dim3(A_COLS_P / 256, S / 128), 256, GSMEM>>>(
        h_hi, h_lo, wa_h, a, nullptr, nullptr, pos, A_COLS, A_COLS, HID, 0);

    // 2) RMSNorm + k_pe rope
    rmsnorm_rope_kernel<<<S, 256>>>(a, kpeh, cq_hi, cq_lo, ckv_hi, ckv_lo,
                                    wq_ln, wkv_ln, pos);
    cudaEventRecord(evNorm, 0);

    // s2: kv GEMM runs concurrently with q GEMM (independent)
    cudaStreamWaitEvent(s2, evNorm, 0);
    mma_gemm<<<dim3(KV_COLS / 256, S / 128), 256, GSMEM, s2>>>(
        ckv_hi, ckv_lo, wkvb_h, nullptr, kvh, nullptr, pos, KV_COLS, KV_COLS, KV_LORA, 1);
    cudaEventRecord(evKV, s2);

    // main: q GEMM (rope + scale + split fused)
    cudaStreamWaitEvent(0, evW, 0);
    mma_gemm<<<dim3(Q_COLS / 256, S / 128), 256, GSMEM>>>(
        cq_hi, cq_lo, wqb_h, nullptr, qs_hi, qs_lo, pos, Q_COLS, Q_COLS, Q_LORA, 2);

    // flash needs both q and kv
    cudaStreamWaitEvent(0, evKV, 0);
    flash_mma<<<dim3(S / 128, H), 256, FSMEM>>>(qs_hi, qs_lo, kvh, kpeh, at_hi, at_lo);

    // output GEMM (fp32 out = final)
    mma_gemm<<<dim3(HID / 256, S / 128), 256, GSMEM>>>(
        at_hi, at_lo, wo_h, out, nullptr, nullptr, pos, HID, HID, O_COLS, 0);

    cudaEventDestroy(evFork);
    cudaEventDestroy(evW);
    cudaEventDestroy(evNorm);
    cudaEventDestroy(evKV);
    cudaStreamDestroy(s2);
}

// round 11
// speedup vs baseline: 9.4798x; 1.0390x over previous
#include <cuda_runtime.h>
#include <cuda_fp16.h>
#include <math.h>
#include <stdint.h>

// ---------------- problem constants ----------------
#define S        2048
#define HID      4096
#define H        32
#define Q_LORA   1536
#define KV_LORA  512
#define NOPE     128
#define ROPE     64
#define VDIM     128
#define A_COLS   (Q_LORA + KV_LORA + ROPE)   // 2112
#define A_COLS_P 2304                        // padded to 256-mult
#define QDIM     (NOPE + ROPE)               // 192
#define Q_COLS   (H * QDIM)                  // 6144
#define KV_COLS  (H * 2 * NOPE)              // 8192
#define O_COLS   (H * VDIM)                  // 4096
#define ATT_SCALE 0.07216878364870322992f    // 1/sqrt(192)
#define ROPE_L2  13.287712379549449f         // log2(10000)

// ---------------- scratch ----------------
__device__ __align__(256) float g_a[S * A_COLS];

// fp16 operands
__device__ __align__(256) __half g_h_hi[S * HID],     g_h_lo[S * HID];
__device__ __align__(256) __half g_cq_hi[S * Q_LORA], g_cq_lo[S * Q_LORA];
__device__ __align__(256) __half g_ckv_hi[S * KV_LORA], g_ckv_lo[S * KV_LORA];
__device__ __align__(256) __half g_at_hi[S * O_COLS];
__device__ __align__(256) __half g_qs_hi[S * Q_COLS], g_qs_lo[S * Q_COLS];
__device__ __align__(256) __half g_kvh[S * KV_COLS];
__device__ __align__(256) __half g_kpeh[S * ROPE];
// weights: fp16 hi only (B-side operand), rows padded to 256-mult
__device__ __align__(256) __half g_wa_h[A_COLS_P * HID];
__device__ __align__(256) __half g_wqb_h[Q_COLS * Q_LORA];
__device__ __align__(256) __half g_wkvb_h[KV_COLS * KV_LORA];
__device__ __align__(256) __half g_wo_h[HID * O_COLS];

// ================= portable PTX helpers =================
__device__ __forceinline__ uint32_t smem_u32(const void* p) {
    uint32_t a;
    asm("{ .reg .u64 t; cvta.to.shared.u64 t, %1; cvt.u32.u64 %0, t; }"
        : "=r"(a) : "l"(p));
    return a;
}
__device__ __forceinline__ void cp16(uint32_t dst, const void* src) {
    asm volatile("cp.async.cg.shared.global [%0], [%1], 16;" :: "r"(dst), "l"(src));
}
#define CP_COMMIT()  asm volatile("cp.async.commit_group;" ::: "memory")
#define CP_WAIT(n)   asm volatile("cp.async.wait_group %0;" :: "n"(n) : "memory")

__device__ __forceinline__ void ldmx4(uint32_t* r, uint32_t addr) {
    asm volatile("ldmatrix.sync.aligned.m8n8.x4.shared.b16 {%0,%1,%2,%3}, [%4];"
                 : "=r"(r[0]), "=r"(r[1]), "=r"(r[2]), "=r"(r[3]) : "r"(addr));
}
__device__ __forceinline__ void ldmx2(uint32_t* r, uint32_t addr) {
    asm volatile("ldmatrix.sync.aligned.m8n8.x2.shared.b16 {%0,%1}, [%2];"
                 : "=r"(r[0]), "=r"(r[1]) : "r"(addr));
}
__device__ __forceinline__ void ldmx4t(uint32_t* r, uint32_t addr) {
    asm volatile("ldmatrix.sync.aligned.m8n8.x4.trans.shared.b16 {%0,%1,%2,%3}, [%4];"
                 : "=r"(r[0]), "=r"(r[1]), "=r"(r[2]), "=r"(r[3]) : "r"(addr));
}
__device__ __forceinline__ void mma16816(float* c, const uint32_t* a, const uint32_t* b) {
    asm volatile(
        "mma.sync.aligned.m16n8k16.row.col.f32.f16.f16.f32 "
        "{%0,%1,%2,%3},{%4,%5,%6,%7},{%8,%9},{%0,%1,%2,%3};"
        : "+f"(c[0]), "+f"(c[1]), "+f"(c[2]), "+f"(c[3])
        : "r"(a[0]), "r"(a[1]), "r"(a[2]), "r"(a[3]), "r"(b[0]), "r"(b[1]));
}
__device__ __forceinline__ uint32_t packh2(float x, float y) {
    __half2 h = __floats2half2_rn(x, y);
    return *(uint32_t*)&h;
}

// ================= fp32 -> fp16 hi/lo split (activations) =================
__global__ __launch_bounds__(256) void cvt_split(
    const float* __restrict__ src,
    __half* __restrict__ hi, __half* __restrict__ lo,
    int total4, float scale)
{
    for (int i = blockIdx.x * 256 + threadIdx.x; i < total4; i += gridDim.x * 256) {
        int e = i * 4;
        float4 f = *(const float4*)(src + (size_t)e);
        f.x *= scale; f.y *= scale; f.z *= scale; f.w *= scale;
        __half2 h01 = __floats2half2_rn(f.x, f.y);
        __half2 h23 = __floats2half2_rn(f.z, f.w);
        float2 b01 = __half22float2(h01), b23 = __half22float2(h23);
        *(__half2*)(hi + (size_t)e)     = h01;
        *(__half2*)(hi + (size_t)e + 2) = h23;
        *(__half2*)(lo + (size_t)e)     = __floats2half2_rn(f.x - b01.x, f.y - b01.y);
        *(__half2*)(lo + (size_t)e + 2) = __floats2half2_rn(f.z - b23.x, f.w - b23.y);
    }
}

// ================= fp32 -> fp16 hi only (weights, padded rows) ============
__global__ __launch_bounds__(256) void cvt_hi(
    const float* __restrict__ src, __half* __restrict__ hi,
    int total4, int cols, int rows)
{
    for (int i = blockIdx.x * 256 + threadIdx.x; i < total4; i += gridDim.x * 256) {
        int e = i * 4;
        int r = e / cols;
        float4 f = make_float4(0.f, 0.f, 0.f, 0.f);
        if (r < rows) f = *(const float4*)(src + (size_t)e);
        *(__half2*)(hi + (size_t)e)     = __floats2half2_rn(f.x, f.y);
        *(__half2*)(hi + (size_t)e + 2) = __floats2half2_rn(f.z, f.w);
    }
}

// ================= fp16 HMMA GEMM (1 or 2 A-terms) =======================
// CTA 128x256, warp tile 64x64 (8 warps, 2x4), BK=32, 4-stage cp.async ring.
// Al == nullptr -> single-term (A rounded to fp16 hi only).
// mode 0: fp32 C.  mode 1: fp16 hi -> Ch.  mode 2: rope+scale+split -> Ch,Cl.
#define BKC   32
#define ROWB  80
#define ATILE (128 * ROWB)             // 10240
#define BTILE (256 * ROWB)             // 20480
#define STG   (2 * ATILE + BTILE)      // 40960
#define NS    4
#define GSMEM (NS * STG)               // 163840

__device__ __forceinline__ void issue_stage(
    const __half* __restrict__ Ah, const __half* __restrict__ Al,
    const __half* __restrict__ Bh,
    int row0, int col0, int K, int c, uint32_t sbase, int slot, int tid)
{
    uint32_t st = sbase + slot * STG;
    #pragma unroll
    for (int l = 0; l < 2; ++l) {
        int v = tid + l * 256;
        int r = v >> 2;
        int j = v & 3;
        size_t goffA = (size_t)(row0 + r) * K + c * BKC + j * 8;
        uint32_t so = r * ROWB + j * 16;
        cp16(st + so, Ah + goffA);
        if (Al) cp16(st + ATILE + so, Al + goffA);
    }
    #pragma unroll
    for (int l = 0; l < 4; ++l) {
        int v = tid + l * 256;
        int r = v >> 2;
        int j = v & 3;
        cp16(st + 2 * ATILE + r * ROWB + j * 16,
             Bh + (size_t)(col0 + r) * K + c * BKC + j * 8);
    }
}

__global__ __launch_bounds__(256, 1) void mma_gemm(
    const __half* __restrict__ Ah, const __half* __restrict__ Al,
    const __half* __restrict__ Bh,
    float* __restrict__ C, __half* __restrict__ Ch, __half* __restrict__ Cl,
    const int* __restrict__ pos,
    int ldc, int N, int K, int mode)
{
    extern __shared__ char sm[];
    uint32_t sbase = smem_u32(sm);
    const int tid    = threadIdx.x;
    const int lane   = tid & 31;
    const int warp   = tid >> 5;
    const int warp_m = warp >> 2;
    const int warp_n = warp & 3;
    const int row0 = blockIdx.y * 128;
    const int col0 = blockIdx.x * 256;

    float acc[4][8][4];
    #pragma unroll
    for (int mi = 0; mi < 4; ++mi)
        #pragma unroll
        for (int ni = 0; ni < 8; ++ni)
            #pragma unroll
            for (int e = 0; e < 4; ++e) acc[mi][ni][e] = 0.f;

    const int nch = K / BKC;

    #pragma unroll
    for (int p = 0; p < NS - 1; ++p) {
        if (p < nch) issue_stage(Ah, Al, Bh, row0, col0, K, p, sbase, p, tid);
        CP_COMMIT();
    }

    const uint32_t a_l = (uint32_t)((warp_m * 64 + (lane & 15)) * ROWB + (lane >> 4) * 16);
    const uint32_t b_l = (uint32_t)(2 * ATILE + (warp_n * 64 + (lane & 7)) * ROWB
                                    + ((lane >> 3) & 1) * 16);

    for (int c = 0; c < nch; ++c) {
        CP_WAIT(NS - 2);
        __syncthreads();
        int np = c + NS - 1;
        if (np < nch)
            issue_stage(Ah, Al, Bh, row0, col0, K, np, sbase, np & (NS - 1), tid);
        CP_COMMIT();

        uint32_t st = sbase + (c & (NS - 1)) * STG;

        #pragma unroll
        for (int ki = 0; ki < 2; ++ki) {
            uint32_t ah[4][4], al[4][4];
            #pragma unroll
            for (int mi = 0; mi < 4; ++mi) {
                uint32_t ad = st + a_l + mi * (16 * ROWB) + ki * 32;
                ldmx4(ah[mi], ad);
                if (Al) ldmx4(al[mi], ad + ATILE);
            }
            #pragma unroll
            for (int ni = 0; ni < 8; ++ni) {
                uint32_t bh[2];
                ldmx2(bh, st + b_l + ni * (8 * ROWB) + ki * 32);
                #pragma unroll
                for (int mi = 0; mi < 4; ++mi) {
                    mma16816(acc[mi][ni], ah[mi], bh);
                    if (Al) mma16816(acc[mi][ni], al[mi], bh);
                }
            }
        }
    }

    if (mode == 2) {
        // q epilogue: rope on pe tiles, then scale + fp16 hi/lo split.
        int ttype = ((col0 >> 6) + warp_n) % 3;
        if (ttype == 2) {
            #pragma unroll
            for (int mi = 0; mi < 4; ++mi) {
                int r0 = row0 + warp_m * 64 + mi * 16 + (lane >> 2);
                float p0 = (float)pos[r0];
                float p1 = (float)pos[r0 + 8];
                #pragma unroll
                for (int ni = 0; ni < 4; ++ni) {
                    #pragma unroll
                    for (int e = 0; e < 2; ++e) {
                        int i = ni * 8 + (lane & 3) * 2 + e;
                        float f = exp2f(-(float)i * (ROPE_L2 / 32.0f));
                        float c0, s0, c1, s1;
                        __sincosf(p0 * f, &s0, &c0);
                        __sincosf(p1 * f, &s1, &c1);
                        float x1 = acc[mi][ni][e],     x2 = acc[mi][ni + 4][e];
                        acc[mi][ni][e]       = x1 * c0 - x2 * s0;
                        acc[mi][ni + 4][e]   = x2 * c0 + x1 * s0;
                        float y1 = acc[mi][ni][e + 2], y2 = acc[mi][ni + 4][e + 2];
                        acc[mi][ni][e + 2]     = y1 * c1 - y2 * s1;
                        acc[mi][ni + 4][e + 2] = y2 * c1 + y1 * s1;
                    }
                }
            }
        }
        #pragma unroll
        for (int mi = 0; mi < 4; ++mi) {
            int row = row0 + warp_m * 64 + mi * 16 + (lane >> 2);
            #pragma unroll
            for (int ni = 0; ni < 8; ++ni) {
                int col = col0 + warp_n * 64 + ni * 8 + (lane & 3) * 2;
                float a0 = acc[mi][ni][0] * ATT_SCALE;
                float a1 = acc[mi][ni][1] * ATT_SCALE;
                float a2 = acc[mi][ni][2] * ATT_SCALE;
                float a3 = acc[mi][ni][3] * ATT_SCALE;
                __half2 h0 = __floats2half2_rn(a0, a1);
                __half2 h1 = __floats2half2_rn(a2, a3);
                float2 f0 = __half22float2(h0), f1 = __half22float2(h1);
                *(__half2*)&Ch[(size_t)row * ldc + col]       = h0;
                *(__half2*)&Ch[(size_t)(row + 8) * ldc + col] = h1;
                *(__half2*)&Cl[(size_t)row * ldc + col] =
                    __floats2half2_rn(a0 - f0.x, a1 - f0.y);
                *(__half2*)&Cl[(size_t)(row + 8) * ldc + col] =
                    __floats2half2_rn(a2 - f1.x, a3 - f1.y);
            }
        }
    } else if (mode == 1) {
        #pragma unroll
        for (int mi = 0; mi < 4; ++mi) {
            int row = row0 + warp_m * 64 + mi * 16 + (lane >> 2);
            #pragma unroll
            for (int ni = 0; ni < 8; ++ni) {
                int col = col0 + warp_n * 64 + ni * 8 + (lane & 3) * 2;
                *(__half2*)&Ch[(size_t)row * ldc + col] =
                    __floats2half2_rn(acc[mi][ni][0], acc[mi][ni][1]);
                *(__half2*)&Ch[(size_t)(row + 8) * ldc + col] =
                    __floats2half2_rn(acc[mi][ni][2], acc[mi][ni][3]);
            }
        }
    } else {
        #pragma unroll
        for (int mi = 0; mi < 4; ++mi) {
            int row = row0 + warp_m * 64 + mi * 16 + (lane >> 2);
            #pragma unroll
            for (int ni = 0; ni < 8; ++ni) {
                int col = col0 + warp_n * 64 + ni * 8 + (lane & 3) * 2;
                if (col < N) {
                    *(float2*)&C[(size_t)row * ldc + col] =
                        make_float2(acc[mi][ni][0], acc[mi][ni][1]);
                    *(float2*)&C[(size_t)(row + 8) * ldc + col] =
                        make_float2(acc[mi][ni][2], acc[mi][ni][3]);
                }
            }
        }
    }
}

// ================= RMSNorm (fp16 hi/lo out) + k_pe RoPE (fp16) ============
__global__ __launch_bounds__(256) void rmsnorm_rope_kernel(
    const float* __restrict__ a,
    __half* __restrict__ kpeh,
    __half* __restrict__ cqh, __half* __restrict__ cql,
    __half* __restrict__ ckvh, __half* __restrict__ ckvl,
    const float* __restrict__ wq,
    const float* __restrict__ wkv,
    const int* __restrict__ pos_ids)
{
    const int s   = blockIdx.x;
    const int tid = threadIdx.x;
    const float* row = a + (size_t)s * A_COLS;
    __shared__ float red[8];

    float ss = 0.f;
    for (int i = tid; i < Q_LORA; i += 256) { float v = row[i]; ss += v * v; }
    #pragma unroll
    for (int o = 16; o; o >>= 1) ss += __shfl_xor_sync(0xffffffffu, ss, o);
    if ((tid & 31) == 0) red[tid >> 5] = ss;
    __syncthreads();
    float tot = 0.f;
    #pragma unroll
    for (int w = 0; w < 8; w++) tot += red[w];
    float inv = rsqrtf(tot / (float)Q_LORA + 1e-6f);
    for (int i = tid; i < Q_LORA; i += 256) {
        float v = row[i] * inv * wq[i];
        __half h = __float2half_rn(v);
        cqh[(size_t)s * Q_LORA + i] = h;
        cql[(size_t)s * Q_LORA + i] = __float2half_rn(v - __half2float(h));
    }
    __syncthreads();

    const float* row2 = row + Q_LORA;
    ss = 0.f;
    for (int i = tid; i < KV_LORA; i += 256) { float v = row2[i]; ss += v * v; }
    #pragma unroll
    for (int o = 16; o; o >>= 1) ss += __shfl_xor_sync(0xffffffffu, ss, o);
    if ((tid & 31) == 0) red[tid >> 5] = ss;
    __syncthreads();
    tot = 0.f;
    #pragma unroll
    for (int w = 0; w < 8; w++) tot += red[w];
    inv = rsqrtf(tot / (float)KV_LORA + 1e-6f);
    for (int i = tid; i < KV_LORA; i += 256) {
        float v = row2[i] * inv * wkv[i];
        __half h = __float2half_rn(v);
        ckvh[(size_t)s * KV_LORA + i] = h;
        ckvl[(size_t)s * KV_LORA + i] = __float2half_rn(v - __half2float(h));
    }

    if (tid < 32) {
        int p = pos_ids[s];
        float inv_freq = exp2f(-(float)tid * (ROPE_L2 / 32.0f));
        float ang = (float)p * inv_freq;
        float c, sn;
        __sincosf(ang, &sn, &c);
        float x1 = row[Q_LORA + KV_LORA + tid];
        float x2 = row[Q_LORA + KV_LORA + 32 + tid];
        kpeh[(size_t)s * ROPE + tid]      = __float2half_rn(x1 * c - x2 * sn);
        kpeh[(size_t)s * ROPE + 32 + tid] = __float2half_rn(x2 * c + x1 * sn);
    }
}

// ================= HMMA flash attention =====================
// 2-term QK^T, 1-term PV, fp16-hi output. 128-query tiles, 256 threads.
#define QSTR   400
#define VSTR   272
#define SM_QH  0
#define SM_QL  51200
#define SM_ST0 102400
#define VHOFF  25600
#define STGSZ  43008
#define FSMEM  (SM_ST0 + 2 * STGSZ)     // 188416

__device__ __forceinline__ void issue_kv(
    const __half* __restrict__ KVh, const __half* __restrict__ KPh,
    int n0, int h, uint32_t stg, int tid)
{
    #pragma unroll
    for (int l = 0; l < 6; ++l) {
        int i = tid + l * 256;
        int r = i / 24, j = i % 24;
        uint32_t dst = stg + r * QSTR + j * 16;
        if (j < 16)
            cp16(dst, KVh + (size_t)(n0 + r) * KV_COLS + h * 2 * NOPE + j * 8);
        else
            cp16(dst, KPh + (size_t)(n0 + r) * ROPE + (j - 16) * 8);
    }
    #pragma unroll
    for (int l = 0; l < 4; ++l) {
        int i = tid + l * 256;
        int r = i / 16, j = i % 16;
        cp16(stg + VHOFF + r * VSTR + j * 16,
             KVh + (size_t)(n0 + r) * KV_COLS + h * 2 * NOPE + NOPE + j * 8);
    }
}

__global__ __launch_bounds__(256, 1) void flash_mma(
    const __half* __restrict__ Qh, const __half* __restrict__ Ql,
    const __half* __restrict__ KVh, const __half* __restrict__ KPh,
    __half* __restrict__ Oh)
{
    extern __shared__ char sm[];
    uint32_t sb = smem_u32(sm);
    const int qt = (int)gridDim.x - 1 - (int)blockIdx.x;
    const int h = blockIdx.y;
    const int qm0 = qt * 128;
    const int tid = threadIdx.x, lane = tid & 31, warp = tid >> 5;

    #pragma unroll
    for (int l = 0; l < 12; ++l) {
        int i = tid + l * 256;
        int r = i / 24, j = i % 24;
        size_t off = (size_t)(qm0 + r) * Q_COLS + h * QDIM + j * 8;
        cp16(sb + SM_QH + r * QSTR + j * 16, Qh + off);
        cp16(sb + SM_QL + r * QSTR + j * 16, Ql + off);
    }
    issue_kv(KVh, KPh, 0, h, sb + SM_ST0, tid);
    CP_COMMIT();

    float acc[16][4];
    #pragma unroll
    for (int vt = 0; vt < 16; ++vt)
        #pragma unroll
        for (int e = 0; e < 4; ++e) acc[vt][e] = 0.f;
    float miA = -1e30f, miB = -1e30f, liA = 0.f, liB = 0.f;

    const int T = 2 * (qt + 1);
    const int rA = qm0 + warp * 16 + (lane >> 2);

    for (int t = 0; t < T; ++t) {
        if (t + 1 < T) {
            issue_kv(KVh, KPh, (t + 1) * 64, h, sb + SM_ST0 + ((t + 1) & 1) * STGSZ, tid);
            CP_COMMIT();
            CP_WAIT(1);
        } else {
            CP_WAIT(0);
        }
        __syncthreads();
        uint32_t stg = sb + SM_ST0 + (t & 1) * STGSZ;

        float sc[8][4];
        #pragma unroll
        for (int nt = 0; nt < 8; ++nt)
            #pragma unroll
            for (int e = 0; e < 4; ++e) sc[nt][e] = 0.f;

        const uint32_t qa = sb + (warp * 16 + (lane & 15)) * QSTR + (lane >> 4) * 16;
        #pragma unroll
        for (int kk = 0; kk < 12; ++kk) {
            uint32_t aH[4], aL[4];
            ldmx4(aH, qa + SM_QH + kk * 32);
            ldmx4(aL, qa + SM_QL + kk * 32);
            #pragma unroll
            for (int np = 0; np < 4; ++np) {
                uint32_t bH[4];
                uint32_t ba = stg + ((np * 2 + (lane >> 4)) * 8 + (lane & 7)) * QSTR
                              + ((lane >> 3) & 1) * 16 + kk * 32;
                ldmx4(bH, ba);
                mma16816(sc[np * 2],     aH, bH);
                mma16816(sc[np * 2],     aL, bH);
                mma16816(sc[np * 2 + 1], aH, bH + 2);
                mma16816(sc[np * 2 + 1], aL, bH + 2);
            }
        }

        if (t >= T - 2) {
            #pragma unroll
            for (int nt = 0; nt < 8; ++nt) {
                int c0 = t * 64 + nt * 8 + (lane & 3) * 2;
                if (c0     > rA)     sc[nt][0] = -1e30f;
                if (c0 + 1 > rA)     sc[nt][1] = -1e30f;
                if (c0     > rA + 8) sc[nt][2] = -1e30f;
                if (c0 + 1 > rA + 8) sc[nt][3] = -1e30f;
            }
        }

        float mA = -1e30f, mB = -1e30f;
        #pragma unroll
        for (int nt = 0; nt < 8; ++nt) {
            mA = fmaxf(mA, fmaxf(sc[nt][0], sc[nt][1]));
            mB = fmaxf(mB, fmaxf(sc[nt][2], sc[nt][3]));
        }
        mA = fmaxf(mA, __shfl_xor_sync(0xffffffffu, mA, 1));
        mA = fmaxf(mA, __shfl_xor_sync(0xffffffffu, mA, 2));
        mB = fmaxf(mB, __shfl_xor_sync(0xffffffffu, mB, 1));
        mB = fmaxf(mB, __shfl_xor_sync(0xffffffffu, mB, 2));
        float nmA = fmaxf(miA, mA), nmB = fmaxf(miB, mB);
        float cA = __expf(miA - nmA), cB = __expf(miB - nmB);
        miA = nmA; miB = nmB;

        float sA = 0.f, sB = 0.f;
        #pragma unroll
        for (int nt = 0; nt < 8; ++nt) {
            sc[nt][0] = __expf(sc[nt][0] - nmA); sA += sc[nt][0];
            sc[nt][1] = __expf(sc[nt][1] - nmA); sA += sc[nt][1];
            sc[nt][2] = __expf(sc[nt][2] - nmB); sB += sc[nt][2];
            sc[nt][3] = __expf(sc[nt][3] - nmB); sB += sc[nt][3];
        }
        sA += __shfl_xor_sync(0xffffffffu, sA, 1);
        sA += __shfl_xor_sync(0xffffffffu, sA, 2);
        sB += __shfl_xor_sync(0xffffffffu, sB, 1);
        sB += __shfl_xor_sync(0xffffffffu, sB, 2);
        liA = liA * cA + sA;
        liB = liB * cB + sB;
        #pragma unroll
        for (int vt = 0; vt < 16; ++vt) {
            acc[vt][0] *= cA; acc[vt][1] *= cA;
            acc[vt][2] *= cB; acc[vt][3] *= cB;
        }

        // ---- attn += P V (1-term: P rounded to fp16) ----
        #pragma unroll
        for (int kp = 0; kp < 4; ++kp) {
            uint32_t aH[4];
            #pragma unroll
            for (int q2 = 0; q2 < 2; ++q2) {
                const float* s0 = sc[2 * kp + q2];
                aH[q2 * 2 + 0] = packh2(s0[0], s0[1]);
                aH[q2 * 2 + 1] = packh2(s0[2], s0[3]);
            }
            #pragma unroll
            for (int vp = 0; vp < 8; ++vp) {
                uint32_t bH[4];
                uint32_t va = stg + VHOFF + (kp * 16 + (lane & 15)) * VSTR
                              + (vp * 2 + (lane >> 4)) * 16;
                ldmx4t(bH, va);
                mma16816(acc[vp * 2],     aH, bH);
                mma16816(acc[vp * 2 + 1], aH, bH + 2);
            }
        }
        __syncthreads();
    }

    float rlA = 1.f / liA, rlB = 1.f / liB;
    #pragma unroll
    for (int vt = 0; vt < 16; ++vt) {
        int col = h * VDIM + vt * 8 + (lane & 3) * 2;
        *(__half2*)&Oh[(size_t)rA * O_COLS + col] =
            __floats2half2_rn(acc[vt][0] * rlA, acc[vt][1] * rlA);
        *(__half2*)&Oh[(size_t)(rA + 8) * O_COLS + col] =
            __floats2half2_rn(acc[vt][2] * rlB, acc[vt][3] * rlB);
    }
}

// ================= launch =================
extern "C" void kernel_launch(void* const* d_in, const int* in_sizes, int n_in,
                              void* d_out, int out_size)
{
    const int*   pos   = (const int*)  d_in[0];
    const float* hid   = (const float*)d_in[1];
    const float* w_a   = (const float*)d_in[2];
    const float* wq_ln = (const float*)d_in[3];
    const float* wkv_ln= (const float*)d_in[4];
    const float* w_q_b = (const float*)d_in[5];
    const float* w_kv_b= (const float*)d_in[6];
    const float* w_o   = (const float*)d_in[7];
    float* out = (float*)d_out;

    float* a;
    cudaGetSymbolAddress((void**)&a, g_a);

    __half *h_hi, *h_lo, *cq_hi, *cq_lo, *ckv_hi, *ckv_lo, *at_hi;
    __half *qs_hi, *qs_lo, *kvh, *kpeh, *wa_h, *wqb_h, *wkvb_h, *wo_h;
    cudaGetSymbolAddress((void**)&h_hi,   g_h_hi);   cudaGetSymbolAddress((void**)&h_lo,   g_h_lo);
    cudaGetSymbolAddress((void**)&cq_hi,  g_cq_hi);  cudaGetSymbolAddress((void**)&cq_lo,  g_cq_lo);
    cudaGetSymbolAddress((void**)&ckv_hi, g_ckv_hi); cudaGetSymbolAddress((void**)&ckv_lo, g_ckv_lo);
    cudaGetSymbolAddress((void**)&at_hi,  g_at_hi);
    cudaGetSymbolAddress((void**)&qs_hi,  g_qs_hi);  cudaGetSymbolAddress((void**)&qs_lo,  g_qs_lo);
    cudaGetSymbolAddress((void**)&kvh,    g_kvh);    cudaGetSymbolAddress((void**)&kpeh,   g_kpeh);
    cudaGetSymbolAddress((void**)&wa_h,   g_wa_h);   cudaGetSymbolAddress((void**)&wqb_h,  g_wqb_h);
    cudaGetSymbolAddress((void**)&wkvb_h, g_wkvb_h); cudaGetSymbolAddress((void**)&wo_h,   g_wo_h);

    cudaFuncSetAttribute(mma_gemm, cudaFuncAttributeMaxDynamicSharedMemorySize, GSMEM);
    cudaFuncSetAttribute(flash_mma, cudaFuncAttributeMaxDynamicSharedMemorySize, FSMEM);

    // ---- side stream s2 ----
    cudaStream_t s2;
    cudaStreamCreateWithFlags(&s2, cudaStreamNonBlocking);
    cudaEvent_t evFork, evW, evNorm, evKV;
    cudaEventCreateWithFlags(&evFork, cudaEventDisableTiming);
    cudaEventCreateWithFlags(&evW,    cudaEventDisableTiming);
    cudaEventCreateWithFlags(&evNorm, cudaEventDisableTiming);
    cudaEventCreateWithFlags(&evKV,   cudaEventDisableTiming);

    cudaEventRecord(evFork, 0);
    cudaStreamWaitEvent(s2, evFork, 0);
    // s2: weight conversions needed for GEMMs 3/4/6
    cvt_hi<<<2048, 256, 0, s2>>>(w_q_b,  wqb_h,  Q_COLS * Q_LORA / 4, Q_LORA, Q_COLS);
    cvt_hi<<<2048, 256, 0, s2>>>(w_kv_b, wkvb_h, KV_COLS * KV_LORA / 4, KV_LORA, KV_COLS);
    cvt_hi<<<2048, 256, 0, s2>>>(w_o,    wo_h,   HID * O_COLS / 4, O_COLS, HID);
    cudaEventRecord(evW, s2);

    // ---- main stream ----
    cvt_hi<<<4096, 256>>>(w_a, wa_h, A_COLS_P * HID / 4, HID, A_COLS);
    cvt_split<<<4096, 256>>>(hid, h_hi, h_lo, S * HID / 4, 1.f);

    // 1) fused-A GEMM (fp32 out, 2-term)
    mma_gemm<<<dim3(A_COLS_P / 256, S / 128), 256, GSMEM>>>(
        h_hi, h_lo, wa_h, a, nullptr, nullptr, pos, A_COLS, A_COLS, HID, 0);

    // 2) RMSNorm + k_pe rope
    rmsnorm_rope_kernel<<<S, 256>>>(a, kpeh, cq_hi, cq_lo, ckv_hi, ckv_lo,
                                    wq_ln, wkv_ln, pos);
    cudaEventRecord(evNorm, 0);

    // s2: kv GEMM runs concurrently with q GEMM (independent)
    cudaStreamWaitEvent(s2, evNorm, 0);
    mma_gemm<<<dim3(KV_COLS / 256, S / 128), 256, GSMEM, s2>>>(
        ckv_hi, ckv_lo, wkvb_h, nullptr, kvh, nullptr, pos, KV_COLS, KV_COLS, KV_LORA, 1);
    cudaEventRecord(evKV, s2);

    // main: q GEMM (rope + scale + split fused, 2-term)
    cudaStreamWaitEvent(0, evW, 0);
    mma_gemm<<<dim3(Q_COLS / 256, S / 128), 256, GSMEM>>>(
        cq_hi, cq_lo, wqb_h, nullptr, qs_hi, qs_lo, pos, Q_COLS, Q_COLS, Q_LORA, 2);

    // flash needs both q and kv
    cudaStreamWaitEvent(0, evKV, 0);
    flash_mma<<<dim3(S / 128, H), 256, FSMEM>>>(qs_hi, qs_lo, kvh, kpeh, at_hi);

    // output GEMM: 1-term (attn rounded to fp16), fp32 out = final
    mma_gemm<<<dim3(HID / 256, S / 128), 256, GSMEM>>>(
        at_hi, nullptr, wo_h, out, nullptr, nullptr, pos, HID, HID, O_COLS, 0);

    cudaEventDestroy(evFork);
    cudaEventDestroy(evW);
    cudaEventDestroy(evNorm);
    cudaEventDestroy(evKV);
    cudaStreamDestroy(s2);
}

// round 12
// speedup vs baseline: 9.9481x; 1.0494x over previous
#include <cuda_runtime.h>
#include <cuda_fp16.h>
#include <math.h>
#include <stdint.h>

// ---------------- problem constants ----------------
#define S        2048
#define HID      4096
#define H        32
#define Q_LORA   1536
#define KV_LORA  512
#define NOPE     128
#define ROPE     64
#define VDIM     128
#define A_COLS   (Q_LORA + KV_LORA + ROPE)   // 2112
#define A_COLS_P 2304                        // padded to 256-mult
#define QDIM     (NOPE + ROPE)               // 192
#define Q_COLS   (H * QDIM)                  // 6144
#define KV_COLS  (H * 2 * NOPE)              // 8192
#define O_COLS   (H * VDIM)                  // 4096
#define ATT_SCALE 0.07216878364870322992f    // 1/sqrt(192)
#define ROPE_L2  13.287712379549449f         // log2(10000)

// ---------------- scratch ----------------
__device__ __align__(256) float g_a[S * A_COLS];

// fp16 operands
__device__ __align__(256) __half g_h_hi[S * HID],     g_h_lo[S * HID];
__device__ __align__(256) __half g_cq_hi[S * Q_LORA], g_cq_lo[S * Q_LORA];
__device__ __align__(256) __half g_ckv_hi[S * KV_LORA], g_ckv_lo[S * KV_LORA];
__device__ __align__(256) __half g_at_hi[S * O_COLS];
__device__ __align__(256) __half g_qs_hi[S * Q_COLS];
__device__ __align__(256) __half g_kvh[S * KV_COLS];
__device__ __align__(256) __half g_kpeh[S * ROPE];
// weights: fp16 hi only (B-side operand), rows padded to 256-mult
__device__ __align__(256) __half g_wa_h[A_COLS_P * HID];
__device__ __align__(256) __half g_wqb_h[Q_COLS * Q_LORA];
__device__ __align__(256) __half g_wkvb_h[KV_COLS * KV_LORA];
__device__ __align__(256) __half g_wo_h[HID * O_COLS];

// ================= portable PTX helpers =================
__device__ __forceinline__ uint32_t smem_u32(const void* p) {
    uint32_t a;
    asm("{ .reg .u64 t; cvta.to.shared.u64 t, %1; cvt.u32.u64 %0, t; }"
        : "=r"(a) : "l"(p));
    return a;
}
__device__ __forceinline__ void cp16(uint32_t dst, const void* src) {
    asm volatile("cp.async.cg.shared.global [%0], [%1], 16;" :: "r"(dst), "l"(src));
}
#define CP_COMMIT()  asm volatile("cp.async.commit_group;" ::: "memory")
#define CP_WAIT(n)   asm volatile("cp.async.wait_group %0;" :: "n"(n) : "memory")

__device__ __forceinline__ void ldmx4(uint32_t* r, uint32_t addr) {
    asm volatile("ldmatrix.sync.aligned.m8n8.x4.shared.b16 {%0,%1,%2,%3}, [%4];"
                 : "=r"(r[0]), "=r"(r[1]), "=r"(r[2]), "=r"(r[3]) : "r"(addr));
}
__device__ __forceinline__ void ldmx2(uint32_t* r, uint32_t addr) {
    asm volatile("ldmatrix.sync.aligned.m8n8.x2.shared.b16 {%0,%1}, [%2];"
                 : "=r"(r[0]), "=r"(r[1]) : "r"(addr));
}
__device__ __forceinline__ void ldmx4t(uint32_t* r, uint32_t addr) {
    asm volatile("ldmatrix.sync.aligned.m8n8.x4.trans.shared.b16 {%0,%1,%2,%3}, [%4];"
                 : "=r"(r[0]), "=r"(r[1]), "=r"(r[2]), "=r"(r[3]) : "r"(addr));
}
__device__ __forceinline__ void mma16816(float* c, const uint32_t* a, const uint32_t* b) {
    asm volatile(
        "mma.sync.aligned.m16n8k16.row.col.f32.f16.f16.f32 "
        "{%0,%1,%2,%3},{%4,%5,%6,%7},{%8,%9},{%0,%1,%2,%3};"
        : "+f"(c[0]), "+f"(c[1]), "+f"(c[2]), "+f"(c[3])
        : "r"(a[0]), "r"(a[1]), "r"(a[2]), "r"(a[3]), "r"(b[0]), "r"(b[1]));
}
__device__ __forceinline__ uint32_t packh2(float x, float y) {
    __half2 h = __floats2half2_rn(x, y);
    return *(uint32_t*)&h;
}

// ================= fp32 -> fp16 hi/lo split (activations) =================
__global__ __launch_bounds__(256) void cvt_split(
    const float* __restrict__ src,
    __half* __restrict__ hi, __half* __restrict__ lo,
    int total4, float scale)
{
    for (int i = blockIdx.x * 256 + threadIdx.x; i < total4; i += gridDim.x * 256) {
        int e = i * 4;
        float4 f = *(const float4*)(src + (size_t)e);
        f.x *= scale; f.y *= scale; f.z *= scale; f.w *= scale;
        __half2 h01 = __floats2half2_rn(f.x, f.y);
        __half2 h23 = __floats2half2_rn(f.z, f.w);
        float2 b01 = __half22float2(h01), b23 = __half22float2(h23);
        *(__half2*)(hi + (size_t)e)     = h01;
        *(__half2*)(hi + (size_t)e + 2) = h23;
        *(__half2*)(lo + (size_t)e)     = __floats2half2_rn(f.x - b01.x, f.y - b01.y);
        *(__half2*)(lo + (size_t)e + 2) = __floats2half2_rn(f.z - b23.x, f.w - b23.y);
    }
}

// ================= fp32 -> fp16 hi only (weights, padded rows) ============
__global__ __launch_bounds__(256) void cvt_hi(
    const float* __restrict__ src, __half* __restrict__ hi,
    int total4, int cols, int rows)
{
    for (int i = blockIdx.x * 256 + threadIdx.x; i < total4; i += gridDim.x * 256) {
        int e = i * 4;
        int r = e / cols;
        float4 f = make_float4(0.f, 0.f, 0.f, 0.f);
        if (r < rows) f = *(const float4*)(src + (size_t)e);
        *(__half2*)(hi + (size_t)e)     = __floats2half2_rn(f.x, f.y);
        *(__half2*)(hi + (size_t)e + 2) = __floats2half2_rn(f.z, f.w);
    }
}

// ================= fp16 HMMA GEMM (1 or 2 A-terms) =======================
// CTA 128x256, warp tile 64x64 (8 warps, 2x4), BK=32, 4-stage cp.async ring.
// Al == nullptr -> single-term.
// mode 0: fp32 C.  mode 1: fp16 hi -> Ch.  mode 2: rope+scale -> Ch (fp16).
#define BKC   32
#define ROWB  80
#define ATILE (128 * ROWB)             // 10240
#define BTILE (256 * ROWB)             // 20480
#define STG   (2 * ATILE + BTILE)      // 40960
#define NS    4
#define GSMEM (NS * STG)               // 163840

__device__ __forceinline__ void issue_stage(
    const __half* __restrict__ Ah, const __half* __restrict__ Al,
    const __half* __restrict__ Bh,
    int row0, int col0, int K, int c, uint32_t sbase, int slot, int tid)
{
    uint32_t st = sbase + slot * STG;
    #pragma unroll
    for (int l = 0; l < 2; ++l) {
        int v = tid + l * 256;
        int r = v >> 2;
        int j = v & 3;
        size_t goffA = (size_t)(row0 + r) * K + c * BKC + j * 8;
        uint32_t so = r * ROWB + j * 16;
        cp16(st + so, Ah + goffA);
        if (Al) cp16(st + ATILE + so, Al + goffA);
    }
    #pragma unroll
    for (int l = 0; l < 4; ++l) {
        int v = tid + l * 256;
        int r = v >> 2;
        int j = v & 3;
        cp16(st + 2 * ATILE + r * ROWB + j * 16,
             Bh + (size_t)(col0 + r) * K + c * BKC + j * 8);
    }
}

__global__ __launch_bounds__(256, 1) void mma_gemm(
    const __half* __restrict__ Ah, const __half* __restrict__ Al,
    const __half* __restrict__ Bh,
    float* __restrict__ C, __half* __restrict__ Ch,
    const int* __restrict__ pos,
    int ldc, int N, int K, int mode)
{
    extern __shared__ char sm[];
    uint32_t sbase = smem_u32(sm);
    const int tid    = threadIdx.x;
    const int lane   = tid & 31;
    const int warp   = tid >> 5;
    const int warp_m = warp >> 2;
    const int warp_n = warp & 3;
    const int row0 = blockIdx.y * 128;
    const int col0 = blockIdx.x * 256;

    float acc[4][8][4];
    #pragma unroll
    for (int mi = 0; mi < 4; ++mi)
        #pragma unroll
        for (int ni = 0; ni < 8; ++ni)
            #pragma unroll
            for (int e = 0; e < 4; ++e) acc[mi][ni][e] = 0.f;

    const int nch = K / BKC;

    #pragma unroll
    for (int p = 0; p < NS - 1; ++p) {
        if (p < nch) issue_stage(Ah, Al, Bh, row0, col0, K, p, sbase, p, tid);
        CP_COMMIT();
    }

    const uint32_t a_l = (uint32_t)((warp_m * 64 + (lane & 15)) * ROWB + (lane >> 4) * 16);
    const uint32_t b_l = (uint32_t)(2 * ATILE + (warp_n * 64 + (lane & 7)) * ROWB
                                    + ((lane >> 3) & 1) * 16);

    for (int c = 0; c < nch; ++c) {
        CP_WAIT(NS - 2);
        __syncthreads();
        int np = c + NS - 1;
        if (np < nch)
            issue_stage(Ah, Al, Bh, row0, col0, K, np, sbase, np & (NS - 1), tid);
        CP_COMMIT();

        uint32_t st = sbase + (c & (NS - 1)) * STG;

        #pragma unroll
        for (int ki = 0; ki < 2; ++ki) {
            uint32_t ah[4][4], al[4][4];
            #pragma unroll
            for (int mi = 0; mi < 4; ++mi) {
                uint32_t ad = st + a_l + mi * (16 * ROWB) + ki * 32;
                ldmx4(ah[mi], ad);
                if (Al) ldmx4(al[mi], ad + ATILE);
            }
            #pragma unroll
            for (int ni = 0; ni < 8; ++ni) {
                uint32_t bh[2];
                ldmx2(bh, st + b_l + ni * (8 * ROWB) + ki * 32);
                #pragma unroll
                for (int mi = 0; mi < 4; ++mi) {
                    mma16816(acc[mi][ni], ah[mi], bh);
                    if (Al) mma16816(acc[mi][ni], al[mi], bh);
                }
            }
        }
    }

    if (mode == 2) {
        // q epilogue: rope on pe tiles, then scale + fp16 round.
        int ttype = ((col0 >> 6) + warp_n) % 3;
        if (ttype == 2) {
            #pragma unroll
            for (int mi = 0; mi < 4; ++mi) {
                int r0 = row0 + warp_m * 64 + mi * 16 + (lane >> 2);
                float p0 = (float)pos[r0];
                float p1 = (float)pos[r0 + 8];
                #pragma unroll
                for (int ni = 0; ni < 4; ++ni) {
                    #pragma unroll
                    for (int e = 0; e < 2; ++e) {
                        int i = ni * 8 + (lane & 3) * 2 + e;
                        float f = exp2f(-(float)i * (ROPE_L2 / 32.0f));
                        float c0, s0, c1, s1;
                        __sincosf(p0 * f, &s0, &c0);
                        __sincosf(p1 * f, &s1, &c1);
                        float x1 = acc[mi][ni][e],     x2 = acc[mi][ni + 4][e];
                        acc[mi][ni][e]       = x1 * c0 - x2 * s0;
                        acc[mi][ni + 4][e]   = x2 * c0 + x1 * s0;
                        float y1 = acc[mi][ni][e + 2], y2 = acc[mi][ni + 4][e + 2];
                        acc[mi][ni][e + 2]     = y1 * c1 - y2 * s1;
                        acc[mi][ni + 4][e + 2] = y2 * c1 + y1 * s1;
                    }
                }
            }
        }
        #pragma unroll
        for (int mi = 0; mi < 4; ++mi) {
            int row = row0 + warp_m * 64 + mi * 16 + (lane >> 2);
            #pragma unroll
            for (int ni = 0; ni < 8; ++ni) {
                int col = col0 + warp_n * 64 + ni * 8 + (lane & 3) * 2;
                *(__half2*)&Ch[(size_t)row * ldc + col] =
                    __floats2half2_rn(acc[mi][ni][0] * ATT_SCALE,
                                      acc[mi][ni][1] * ATT_SCALE);
                *(__half2*)&Ch[(size_t)(row + 8) * ldc + col] =
                    __floats2half2_rn(acc[mi][ni][2] * ATT_SCALE,
                                      acc[mi][ni][3] * ATT_SCALE);
            }
        }
    } else if (mode == 1) {
        #pragma unroll
        for (int mi = 0; mi < 4; ++mi) {
            int row = row0 + warp_m * 64 + mi * 16 + (lane >> 2);
            #pragma unroll
            for (int ni = 0; ni < 8; ++ni) {
                int col = col0 + warp_n * 64 + ni * 8 + (lane & 3) * 2;
                *(__half2*)&Ch[(size_t)row * ldc + col] =
                    __floats2half2_rn(acc[mi][ni][0], acc[mi][ni][1]);
                *(__half2*)&Ch[(size_t)(row + 8) * ldc + col] =
                    __floats2half2_rn(acc[mi][ni][2], acc[mi][ni][3]);
            }
        }
    } else {
        #pragma unroll
        for (int mi = 0; mi < 4; ++mi) {
            int row = row0 + warp_m * 64 + mi * 16 + (lane >> 2);
            #pragma unroll
            for (int ni = 0; ni < 8; ++ni) {
                int col = col0 + warp_n * 64 + ni * 8 + (lane & 3) * 2;
                if (col < N) {
                    *(float2*)&C[(size_t)row * ldc + col] =
                        make_float2(acc[mi][ni][0], acc[mi][ni][1]);
                    *(float2*)&C[(size_t)(row + 8) * ldc + col] =
                        make_float2(acc[mi][ni][2], acc[mi][ni][3]);
                }
            }
        }
    }
}

// ================= RMSNorm (fp16 hi/lo out) + k_pe RoPE (fp16) ============
__global__ __launch_bounds__(256) void rmsnorm_rope_kernel(
    const float* __restrict__ a,
    __half* __restrict__ kpeh,
    __half* __restrict__ cqh, __half* __restrict__ cql,
    __half* __restrict__ ckvh, __half* __restrict__ ckvl,
    const float* __restrict__ wq,
    const float* __restrict__ wkv,
    const int* __restrict__ pos_ids)
{
    const int s   = blockIdx.x;
    const int tid = threadIdx.x;
    const float* row = a + (size_t)s * A_COLS;
    __shared__ float red[8];

    float ss = 0.f;
    for (int i = tid; i < Q_LORA; i += 256) { float v = row[i]; ss += v * v; }
    #pragma unroll
    for (int o = 16; o; o >>= 1) ss += __shfl_xor_sync(0xffffffffu, ss, o);
    if ((tid & 31) == 0) red[tid >> 5] = ss;
    __syncthreads();
    float tot = 0.f;
    #pragma unroll
    for (int w = 0; w < 8; w++) tot += red[w];
    float inv = rsqrtf(tot / (float)Q_LORA + 1e-6f);
    for (int i = tid; i < Q_LORA; i += 256) {
        float v = row[i] * inv * wq[i];
        __half h = __float2half_rn(v);
        cqh[(size_t)s * Q_LORA + i] = h;
        cql[(size_t)s * Q_LORA + i] = __float2half_rn(v - __half2float(h));
    }
    __syncthreads();

    const float* row2 = row + Q_LORA;
    ss = 0.f;
    for (int i = tid; i < KV_LORA; i += 256) { float v = row2[i]; ss += v * v; }
    #pragma unroll
    for (int o = 16; o; o >>= 1) ss += __shfl_xor_sync(0xffffffffu, ss, o);
    if ((tid & 31) == 0) red[tid >> 5] = ss;
    __syncthreads();
    tot = 0.f;
    #pragma unroll
    for (int w = 0; w < 8; w++) tot += red[w];
    inv = rsqrtf(tot / (float)KV_LORA + 1e-6f);
    for (int i = tid; i < KV_LORA; i += 256) {
        float v = row2[i] * inv * wkv[i];
        __half h = __float2half_rn(v);
        ckvh[(size_t)s * KV_LORA + i] = h;
        ckvl[(size_t)s * KV_LORA + i] = __float2half_rn(v - __half2float(h));
    }

    if (tid < 32) {
        int p = pos_ids[s];
        float inv_freq = exp2f(-(float)tid * (ROPE_L2 / 32.0f));
        float ang = (float)p * inv_freq;
        float c, sn;
        __sincosf(ang, &sn, &c);
        float x1 = row[Q_LORA + KV_LORA + tid];
        float x2 = row[Q_LORA + KV_LORA + 32 + tid];
        kpeh[(size_t)s * ROPE + tid]      = __float2half_rn(x1 * c - x2 * sn);
        kpeh[(size_t)s * ROPE + 32 + tid] = __float2half_rn(x2 * c + x1 * sn);
    }
}

// ================= HMMA flash attention =====================
// 1-term QK^T (Q fp16), 1-term PV, fp16-hi output. 128-query tiles.
#define QSTR   400
#define VSTR   272
#define SM_QH  0
#define SM_ST0 51200
#define VHOFF  25600
#define STGSZ  43008
#define FSMEM  (SM_ST0 + 2 * STGSZ)     // 137216

__device__ __forceinline__ void issue_kv(
    const __half* __restrict__ KVh, const __half* __restrict__ KPh,
    int n0, int h, uint32_t stg, int tid)
{
    #pragma unroll
    for (int l = 0; l < 6; ++l) {
        int i = tid + l * 256;
        int r = i / 24, j = i % 24;
        uint32_t dst = stg + r * QSTR + j * 16;
        if (j < 16)
            cp16(dst, KVh + (size_t)(n0 + r) * KV_COLS + h * 2 * NOPE + j * 8);
        else
            cp16(dst, KPh + (size_t)(n0 + r) * ROPE + (j - 16) * 8);
    }
    #pragma unroll
    for (int l = 0; l < 4; ++l) {
        int i = tid + l * 256;
        int r = i / 16, j = i % 16;
        cp16(stg + VHOFF + r * VSTR + j * 16,
             KVh + (size_t)(n0 + r) * KV_COLS + h * 2 * NOPE + NOPE + j * 8);
    }
}

__global__ __launch_bounds__(256, 1) void flash_mma(
    const __half* __restrict__ Qh,
    const __half* __restrict__ KVh, const __half* __restrict__ KPh,
    __half* __restrict__ Oh)
{
    extern __shared__ char sm[];
    uint32_t sb = smem_u32(sm);
    const int qt = (int)gridDim.x - 1 - (int)blockIdx.x;
    const int h = blockIdx.y;
    const int qm0 = qt * 128;
    const int tid = threadIdx.x, lane = tid & 31, warp = tid >> 5;

    // Q tile (hi only): 128 rows x 24 chunks = 3072 slots
    #pragma unroll
    for (int l = 0; l < 12; ++l) {
        int i = tid + l * 256;
        int r = i / 24, j = i % 24;
        cp16(sb + SM_QH + r * QSTR + j * 16,
             Qh + (size_t)(qm0 + r) * Q_COLS + h * QDIM + j * 8);
    }
    issue_kv(KVh, KPh, 0, h, sb + SM_ST0, tid);
    CP_COMMIT();

    float acc[16][4];
    #pragma unroll
    for (int vt = 0; vt < 16; ++vt)
        #pragma unroll
        for (int e = 0; e < 4; ++e) acc[vt][e] = 0.f;
    float miA = -1e30f, miB = -1e30f, liA = 0.f, liB = 0.f;

    const int T = 2 * (qt + 1);
    const int rA = qm0 + warp * 16 + (lane >> 2);

    for (int t = 0; t < T; ++t) {
        if (t + 1 < T) {
            issue_kv(KVh, KPh, (t + 1) * 64, h, sb + SM_ST0 + ((t + 1) & 1) * STGSZ, tid);
            CP_COMMIT();
            CP_WAIT(1);
        } else {
            CP_WAIT(0);
        }
        __syncthreads();
        uint32_t stg = sb + SM_ST0 + (t & 1) * STGSZ;

        float sc[8][4];
        #pragma unroll
        for (int nt = 0; nt < 8; ++nt)
            #pragma unroll
            for (int e = 0; e < 4; ++e) sc[nt][e] = 0.f;

        const uint32_t qa = sb + (warp * 16 + (lane & 15)) * QSTR + (lane >> 4) * 16;
        #pragma unroll
        for (int kk = 0; kk < 12; ++kk) {
            uint32_t aH[4];
            ldmx4(aH, qa + SM_QH + kk * 32);
            #pragma unroll
            for (int np = 0; np < 4; ++np) {
                uint32_t bH[4];
                uint32_t ba = stg + ((np * 2 + (lane >> 4)) * 8 + (lane & 7)) * QSTR
                              + ((lane >> 3) & 1) * 16 + kk * 32;
                ldmx4(bH, ba);
                mma16816(sc[np * 2],     aH, bH);
                mma16816(sc[np * 2 + 1], aH, bH + 2);
            }
        }

        if (t >= T - 2) {
            #pragma unroll
            for (int nt = 0; nt < 8; ++nt) {
                int c0 = t * 64 + nt * 8 + (lane & 3) * 2;
                if (c0     > rA)     sc[nt][0] = -1e30f;
                if (c0 + 1 > rA)     sc[nt][1] = -1e30f;
                if (c0     > rA + 8) sc[nt][2] = -1e30f;
                if (c0 + 1 > rA + 8) sc[nt][3] = -1e30f;
            }
        }

        float mA = -1e30f, mB = -1e30f;
        #pragma unroll
        for (int nt = 0; nt < 8; ++nt) {
            mA = fmaxf(mA, fmaxf(sc[nt][0], sc[nt][1]));
            mB = fmaxf(mB, fmaxf(sc[nt][2], sc[nt][3]));
        }
        mA = fmaxf(mA, __shfl_xor_sync(0xffffffffu, mA, 1));
        mA = fmaxf(mA, __shfl_xor_sync(0xffffffffu, mA, 2));
        mB = fmaxf(mB, __shfl_xor_sync(0xffffffffu, mB, 1));
        mB = fmaxf(mB, __shfl_xor_sync(0xffffffffu, mB, 2));
        float nmA = fmaxf(miA, mA), nmB = fmaxf(miB, mB);
        float cA = __expf(miA - nmA), cB = __expf(miB - nmB);
        miA = nmA; miB = nmB;

        float sA = 0.f, sB = 0.f;
        #pragma unroll
        for (int nt = 0; nt < 8; ++nt) {
            sc[nt][0] = __expf(sc[nt][0] - nmA); sA += sc[nt][0];
            sc[nt][1] = __expf(sc[nt][1] - nmA); sA += sc[nt][1];
            sc[nt][2] = __expf(sc[nt][2] - nmB); sB += sc[nt][2];
            sc[nt][3] = __expf(sc[nt][3] - nmB); sB += sc[nt][3];
        }
        sA += __shfl_xor_sync(0xffffffffu, sA, 1);
        sA += __shfl_xor_sync(0xffffffffu, sA, 2);
        sB += __shfl_xor_sync(0xffffffffu, sB, 1);
        sB += __shfl_xor_sync(0xffffffffu, sB, 2);
        liA = liA * cA + sA;
        liB = liB * cB + sB;
        #pragma unroll
        for (int vt = 0; vt < 16; ++vt) {
            acc[vt][0] *= cA; acc[vt][1] *= cA;
            acc[vt][2] *= cB; acc[vt][3] *= cB;
        }

        // ---- attn += P V (1-term) ----
        #pragma unroll
        for (int kp = 0; kp < 4; ++kp) {
            uint32_t aH[4];
            #pragma unroll
            for (int q2 = 0; q2 < 2; ++q2) {
                const float* s0 = sc[2 * kp + q2];
                aH[q2 * 2 + 0] = packh2(s0[0], s0[1]);
                aH[q2 * 2 + 1] = packh2(s0[2], s0[3]);
            }
            #pragma unroll
            for (int vp = 0; vp < 8; ++vp) {
                uint32_t bH[4];
                uint32_t va = stg + VHOFF + (kp * 16 + (lane & 15)) * VSTR
                              + (vp * 2 + (lane >> 4)) * 16;
                ldmx4t(bH, va);
                mma16816(acc[vp * 2],     aH, bH);
                mma16816(acc[vp * 2 + 1], aH, bH + 2);
            }
        }
        __syncthreads();
    }

    float rlA = 1.f / liA, rlB = 1.f / liB;
    #pragma unroll
    for (int vt = 0; vt < 16; ++vt) {
        int col = h * VDIM + vt * 8 + (lane & 3) * 2;
        *(__half2*)&Oh[(size_t)rA * O_COLS + col] =
            __floats2half2_rn(acc[vt][0] * rlA, acc[vt][1] * rlA);
        *(__half2*)&Oh[(size_t)(rA + 8) * O_COLS + col] =
            __floats2half2_rn(acc[vt][2] * rlB, acc[vt][3] * rlB);
    }
}

// ================= launch =================
extern "C" void kernel_launch(void* const* d_in, const int* in_sizes, int n_in,
                              void* d_out, int out_size)
{
    const int*   pos   = (const int*)  d_in[0];
    const float* hid   = (const float*)d_in[1];
    const float* w_a   = (const float*)d_in[2];
    const float* wq_ln = (const float*)d_in[3];
    const float* wkv_ln= (const float*)d_in[4];
    const float* w_q_b = (const float*)d_in[5];
    const float* w_kv_b= (const float*)d_in[6];
    const float* w_o   = (const float*)d_in[7];
    float* out = (float*)d_out;

    float* a;
    cudaGetSymbolAddress((void**)&a, g_a);

    __half *h_hi, *h_lo, *cq_hi, *cq_lo, *ckv_hi, *ckv_lo, *at_hi;
    __half *qs_hi, *kvh, *kpeh, *wa_h, *wqb_h, *wkvb_h, *wo_h;
    cudaGetSymbolAddress((void**)&h_hi,   g_h_hi);   cudaGetSymbolAddress((void**)&h_lo,   g_h_lo);
    cudaGetSymbolAddress((void**)&cq_hi,  g_cq_hi);  cudaGetSymbolAddress((void**)&cq_lo,  g_cq_lo);
    cudaGetSymbolAddress((void**)&ckv_hi, g_ckv_hi); cudaGetSymbolAddress((void**)&ckv_lo, g_ckv_lo);
    cudaGetSymbolAddress((void**)&at_hi,  g_at_hi);
    cudaGetSymbolAddress((void**)&qs_hi,  g_qs_hi);
    cudaGetSymbolAddress((void**)&kvh,    g_kvh);    cudaGetSymbolAddress((void**)&kpeh,   g_kpeh);
    cudaGetSymbolAddress((void**)&wa_h,   g_wa_h);   cudaGetSymbolAddress((void**)&wqb_h,  g_wqb_h);
    cudaGetSymbolAddress((void**)&wkvb_h, g_wkvb_h); cudaGetSymbolAddress((void**)&wo_h,   g_wo_h);

    cudaFuncSetAttribute(mma_gemm, cudaFuncAttributeMaxDynamicSharedMemorySize, GSMEM);
    cudaFuncSetAttribute(flash_mma, cudaFuncAttributeMaxDynamicSharedMemorySize, FSMEM);

    // ---- side stream s2 ----
    cudaStream_t s2;
    cudaStreamCreateWithFlags(&s2, cudaStreamNonBlocking);
    cudaEvent_t evFork, evW, evNorm, evKV;
    cudaEventCreateWithFlags(&evFork, cudaEventDisableTiming);
    cudaEventCreateWithFlags(&evW,    cudaEventDisableTiming);
    cudaEventCreateWithFlags(&evNorm, cudaEventDisableTiming);
    cudaEventCreateWithFlags(&evKV,   cudaEventDisableTiming);

    cudaEventRecord(evFork, 0);
    cudaStreamWaitEvent(s2, evFork, 0);
    // s2: weight conversions needed for GEMMs 3/4/6
    cvt_hi<<<2048, 256, 0, s2>>>(w_q_b,  wqb_h,  Q_COLS * Q_LORA / 4, Q_LORA, Q_COLS);
    cvt_hi<<<2048, 256, 0, s2>>>(w_kv_b, wkvb_h, KV_COLS * KV_LORA / 4, KV_LORA, KV_COLS);
    cvt_hi<<<2048, 256, 0, s2>>>(w_o,    wo_h,   HID * O_COLS / 4, O_COLS, HID);
    cudaEventRecord(evW, s2);

    // ---- main stream ----
    cvt_hi<<<4096, 256>>>(w_a, wa_h, A_COLS_P * HID / 4, HID, A_COLS);
    cvt_split<<<4096, 256>>>(hid, h_hi, h_lo, S * HID / 4, 1.f);

    // 1) fused-A GEMM (fp32 out, 2-term)
    mma_gemm<<<dim3(A_COLS_P / 256, S / 128), 256, GSMEM>>>(
        h_hi, h_lo, wa_h, a, nullptr, pos, A_COLS, A_COLS, HID, 0);

    // 2) RMSNorm + k_pe rope
    rmsnorm_rope_kernel<<<S, 256>>>(a, kpeh, cq_hi, cq_lo, ckv_hi, ckv_lo,
                                    wq_ln, wkv_ln, pos);
    cudaEventRecord(evNorm, 0);

    // s2: kv GEMM runs concurrently with q GEMM (independent)
    cudaStreamWaitEvent(s2, evNorm, 0);
    mma_gemm<<<dim3(KV_COLS / 256, S / 128), 256, GSMEM, s2>>>(
        ckv_hi, ckv_lo, wkvb_h, nullptr, kvh, pos, KV_COLS, KV_COLS, KV_LORA, 1);
    cudaEventRecord(evKV, s2);

    // main: q GEMM (rope + scale fused, fp16 out, 2-term)
    cudaStreamWaitEvent(0, evW, 0);
    mma_gemm<<<dim3(Q_COLS / 256, S / 128), 256, GSMEM>>>(
        cq_hi, cq_lo, wqb_h, nullptr, qs_hi, pos, Q_COLS, Q_COLS, Q_LORA, 2);

    // flash needs both q and kv
    cudaStreamWaitEvent(0, evKV, 0);
    flash_mma<<<dim3(S / 128, H), 256, FSMEM>>>(qs_hi, kvh, kpeh, at_hi);

    // output GEMM: 1-term (attn rounded to fp16), fp32 out = final
    mma_gemm<<<dim3(HID / 256, S / 128), 256, GSMEM>>>(
        at_hi, nullptr, wo_h, out, nullptr, pos, HID, HID, O_COLS, 0);

    cudaEventDestroy(evFork);
    cudaEventDestroy(evW);
    cudaEventDestroy(evNorm);
    cudaEventDestroy(evKV);
    cudaStreamDestroy(s2);
}

// round 13
// speedup vs baseline: 13.8183x; 1.3890x over previous
#include <cuda_runtime.h>
#include <cuda_fp16.h>
#include <math.h>
#include <stdint.h>

// ---------------- problem constants ----------------
#define S        2048
#define HID      4096
#define H        32
#define Q_LORA   1536
#define KV_LORA  512
#define NOPE     128
#define ROPE     64
#define VDIM     128
#define A_COLS   (Q_LORA + KV_LORA + ROPE)   // 2112
#define A_COLS_P 2304                        // padded to 256-mult
#define QDIM     (NOPE + ROPE)               // 192
#define Q_COLS   (H * QDIM)                  // 6144
#define KV_COLS  (H * 2 * NOPE)              // 8192
#define O_COLS   (H * VDIM)                  // 4096
#define ATT_SCALE 0.07216878364870322992f    // 1/sqrt(192)
#define ROPE_L2  13.287712379549449f         // log2(10000)

// ---------------- scratch ----------------
__device__ __align__(256) float g_a[S * A_COLS];

// fp16 operands (all hi-only now)
__device__ __align__(256) __half g_h_hi[S * HID];
__device__ __align__(256) __half g_cq_hi[S * Q_LORA];
__device__ __align__(256) __half g_ckv_hi[S * KV_LORA];
__device__ __align__(256) __half g_at_hi[S * O_COLS];
__device__ __align__(256) __half g_qs_hi[S * Q_COLS];
__device__ __align__(256) __half g_kvh[S * KV_COLS];
__device__ __align__(256) __half g_kpeh[S * ROPE];
// weights (fp16 hi, rows padded to 256-mult)
__device__ __align__(256) __half g_wa_h[A_COLS_P * HID];
__device__ __align__(256) __half g_wqb_h[Q_COLS * Q_LORA];
__device__ __align__(256) __half g_wkvb_h[KV_COLS * KV_LORA];
__device__ __align__(256) __half g_wo_h[HID * O_COLS];

// ================= portable PTX helpers =================
__device__ __forceinline__ uint32_t smem_u32(const void* p) {
    uint32_t a;
    asm("{ .reg .u64 t; cvta.to.shared.u64 t, %1; cvt.u32.u64 %0, t; }"
        : "=r"(a) : "l"(p));
    return a;
}
__device__ __forceinline__ void cp16(uint32_t dst, const void* src) {
    asm volatile("cp.async.cg.shared.global [%0], [%1], 16;" :: "r"(dst), "l"(src));
}
#define CP_COMMIT()  asm volatile("cp.async.commit_group;" ::: "memory")
#define CP_WAIT(n)   asm volatile("cp.async.wait_group %0;" :: "n"(n) : "memory")

__device__ __forceinline__ void ldmx4(uint32_t* r, uint32_t addr) {
    asm volatile("ldmatrix.sync.aligned.m8n8.x4.shared.b16 {%0,%1,%2,%3}, [%4];"
                 : "=r"(r[0]), "=r"(r[1]), "=r"(r[2]), "=r"(r[3]) : "r"(addr));
}
__device__ __forceinline__ void ldmx2(uint32_t* r, uint32_t addr) {
    asm volatile("ldmatrix.sync.aligned.m8n8.x2.shared.b16 {%0,%1}, [%2];"
                 : "=r"(r[0]), "=r"(r[1]) : "r"(addr));
}
__device__ __forceinline__ void ldmx4t(uint32_t* r, uint32_t addr) {
    asm volatile("ldmatrix.sync.aligned.m8n8.x4.trans.shared.b16 {%0,%1,%2,%3}, [%4];"
                 : "=r"(r[0]), "=r"(r[1]), "=r"(r[2]), "=r"(r[3]) : "r"(addr));
}
__device__ __forceinline__ void mma16816(float* c, const uint32_t* a, const uint32_t* b) {
    asm volatile(
        "mma.sync.aligned.m16n8k16.row.col.f32.f16.f16.f32 "
        "{%0,%1,%2,%3},{%4,%5,%6,%7},{%8,%9},{%0,%1,%2,%3};"
        : "+f"(c[0]), "+f"(c[1]), "+f"(c[2]), "+f"(c[3])
        : "r"(a[0]), "r"(a[1]), "r"(a[2]), "r"(a[3]), "r"(b[0]), "r"(b[1]));
}
__device__ __forceinline__ uint32_t packh2(float x, float y) {
    __half2 h = __floats2half2_rn(x, y);
    return *(uint32_t*)&h;
}

// ================= fp32 -> fp16 (rows guarded/padded) =====================
__global__ __launch_bounds__(256) void cvt_hi(
    const float* __restrict__ src, __half* __restrict__ hi,
    int total4, int cols, int rows)
{
    for (int i = blockIdx.x * 256 + threadIdx.x; i < total4; i += gridDim.x * 256) {
        int e = i * 4;
        int r = e / cols;
        float4 f = make_float4(0.f, 0.f, 0.f, 0.f);
        if (r < rows) f = *(const float4*)(src + (size_t)e);
        *(__half2*)(hi + (size_t)e)     = __floats2half2_rn(f.x, f.y);
        *(__half2*)(hi + (size_t)e + 2) = __floats2half2_rn(f.z, f.w);
    }
}

// ================= fp16 HMMA GEMM (1-term) ===============================
// CTA 128x256, warp tile 64x64 (8 warps, 2x4), BK=32, 4-stage cp.async ring.
// mode 0: fp32 C.  mode 1: fp16 -> Ch.  mode 2: rope+scale -> Ch (fp16).
#define BKC   32
#define ROWB  80
#define ATILE (128 * ROWB)             // 10240
#define BTILE (256 * ROWB)             // 20480
#define STG   (ATILE + BTILE)          // 30720
#define NS    4
#define GSMEM (NS * STG)               // 122880

__device__ __forceinline__ void issue_stage(
    const __half* __restrict__ Ah, const __half* __restrict__ Bh,
    int row0, int col0, int K, int c, uint32_t sbase, int slot, int tid)
{
    uint32_t st = sbase + slot * STG;
    #pragma unroll
    for (int l = 0; l < 2; ++l) {
        int v = tid + l * 256;
        int r = v >> 2;
        int j = v & 3;
        cp16(st + r * ROWB + j * 16,
             Ah + (size_t)(row0 + r) * K + c * BKC + j * 8);
    }
    #pragma unroll
    for (int l = 0; l < 4; ++l) {
        int v = tid + l * 256;
        int r = v >> 2;
        int j = v & 3;
        cp16(st + ATILE + r * ROWB + j * 16,
             Bh + (size_t)(col0 + r) * K + c * BKC + j * 8);
    }
}

__global__ __launch_bounds__(256, 1) void mma_gemm(
    const __half* __restrict__ Ah, const __half* __restrict__ Bh,
    float* __restrict__ C, __half* __restrict__ Ch,
    const int* __restrict__ pos,
    int ldc, int N, int K, int mode)
{
    extern __shared__ char sm[];
    uint32_t sbase = smem_u32(sm);
    const int tid    = threadIdx.x;
    const int lane   = tid & 31;
    const int warp   = tid >> 5;
    const int warp_m = warp >> 2;
    const int warp_n = warp & 3;
    const int row0 = blockIdx.y * 128;
    const int col0 = blockIdx.x * 256;

    float acc[4][8][4];
    #pragma unroll
    for (int mi = 0; mi < 4; ++mi)
        #pragma unroll
        for (int ni = 0; ni < 8; ++ni)
            #pragma unroll
            for (int e = 0; e < 4; ++e) acc[mi][ni][e] = 0.f;

    const int nch = K / BKC;

    #pragma unroll
    for (int p = 0; p < NS - 1; ++p) {
        if (p < nch) issue_stage(Ah, Bh, row0, col0, K, p, sbase, p, tid);
        CP_COMMIT();
    }

    const uint32_t a_l = (uint32_t)((warp_m * 64 + (lane & 15)) * ROWB + (lane >> 4) * 16);
    const uint32_t b_l = (uint32_t)(ATILE + (warp_n * 64 + (lane & 7)) * ROWB
                                    + ((lane >> 3) & 1) * 16);

    for (int c = 0; c < nch; ++c) {
        CP_WAIT(NS - 2);
        __syncthreads();
        int np = c + NS - 1;
        if (np < nch)
            issue_stage(Ah, Bh, row0, col0, K, np, sbase, np & (NS - 1), tid);
        CP_COMMIT();

        uint32_t st = sbase + (c & (NS - 1)) * STG;

        #pragma unroll
        for (int ki = 0; ki < 2; ++ki) {
            uint32_t ah[4][4];
            #pragma unroll
            for (int mi = 0; mi < 4; ++mi)
                ldmx4(ah[mi], st + a_l + mi * (16 * ROWB) + ki * 32);
            #pragma unroll
            for (int ni = 0; ni < 8; ++ni) {
                uint32_t bh[2];
                ldmx2(bh, st + b_l + ni * (8 * ROWB) + ki * 32);
                #pragma unroll
                for (int mi = 0; mi < 4; ++mi)
                    mma16816(acc[mi][ni], ah[mi], bh);
            }
        }
    }

    if (mode == 2) {
        // q epilogue: rope on pe tiles, then scale + fp16 round.
        int ttype = ((col0 >> 6) + warp_n) % 3;
        if (ttype == 2) {
            #pragma unroll
            for (int mi = 0; mi < 4; ++mi) {
                int r0 = row0 + warp_m * 64 + mi * 16 + (lane >> 2);
                float p0 = (float)pos[r0];
                float p1 = (float)pos[r0 + 8];
                #pragma unroll
                for (int ni = 0; ni < 4; ++ni) {
                    #pragma unroll
                    for (int e = 0; e < 2; ++e) {
                        int i = ni * 8 + (lane & 3) * 2 + e;
                        float f = exp2f(-(float)i * (ROPE_L2 / 32.0f));
                        float c0, s0, c1, s1;
                        __sincosf(p0 * f, &s0, &c0);
                        __sincosf(p1 * f, &s1, &c1);
                        float x1 = acc[mi][ni][e],     x2 = acc[mi][ni + 4][e];
                        acc[mi][ni][e]       = x1 * c0 - x2 * s0;
                        acc[mi][ni + 4][e]   = x2 * c0 + x1 * s0;
                        float y1 = acc[mi][ni][e + 2], y2 = acc[mi][ni + 4][e + 2];
                        acc[mi][ni][e + 2]     = y1 * c1 - y2 * s1;
                        acc[mi][ni + 4][e + 2] = y2 * c1 + y1 * s1;
                    }
                }
            }
        }
        #pragma unroll
        for (int mi = 0; mi < 4; ++mi) {
            int row = row0 + warp_m * 64 + mi * 16 + (lane >> 2);
            #pragma unroll
            for (int ni = 0; ni < 8; ++ni) {
                int col = col0 + warp_n * 64 + ni * 8 + (lane & 3) * 2;
                *(__half2*)&Ch[(size_t)row * ldc + col] =
                    __floats2half2_rn(acc[mi][ni][0] * ATT_SCALE,
                                      acc[mi][ni][1] * ATT_SCALE);
                *(__half2*)&Ch[(size_t)(row + 8) * ldc + col] =
                    __floats2half2_rn(acc[mi][ni][2] * ATT_SCALE,
                                      acc[mi][ni][3] * ATT_SCALE);
            }
        }
    } else if (mode == 1) {
        #pragma unroll
        for (int mi = 0; mi < 4; ++mi) {
            int row = row0 + warp_m * 64 + mi * 16 + (lane >> 2);
            #pragma unroll
            for (int ni = 0; ni < 8; ++ni) {
                int col = col0 + warp_n * 64 + ni * 8 + (lane & 3) * 2;
                *(__half2*)&Ch[(size_t)row * ldc + col] =
                    __floats2half2_rn(acc[mi][ni][0], acc[mi][ni][1]);
                *(__half2*)&Ch[(size_t)(row + 8) * ldc + col] =
                    __floats2half2_rn(acc[mi][ni][2], acc[mi][ni][3]);
            }
        }
    } else {
        #pragma unroll
        for (int mi = 0; mi < 4; ++mi) {
            int row = row0 + warp_m * 64 + mi * 16 + (lane >> 2);
            #pragma unroll
            for (int ni = 0; ni < 8; ++ni) {
                int col = col0 + warp_n * 64 + ni * 8 + (lane & 3) * 2;
                if (col < N) {
                    *(float2*)&C[(size_t)row * ldc + col] =
                        make_float2(acc[mi][ni][0], acc[mi][ni][1]);
                    *(float2*)&C[(size_t)(row + 8) * ldc + col] =
                        make_float2(acc[mi][ni][2], acc[mi][ni][3]);
                }
            }
        }
    }
}

// ================= RMSNorm (fp16 out) + k_pe RoPE (fp16) ==================
__global__ __launch_bounds__(256) void rmsnorm_rope_kernel(
    const float* __restrict__ a,
    __half* __restrict__ kpeh,
    __half* __restrict__ cqh,
    __half* __restrict__ ckvh,
    const float* __restrict__ wq,
    const float* __restrict__ wkv,
    const int* __restrict__ pos_ids)
{
    const int s   = blockIdx.x;
    const int tid = threadIdx.x;
    const float* row = a + (size_t)s * A_COLS;
    __shared__ float red[8];

    float ss = 0.f;
    for (int i = tid; i < Q_LORA; i += 256) { float v = row[i]; ss += v * v; }
    #pragma unroll
    for (int o = 16; o; o >>= 1) ss += __shfl_xor_sync(0xffffffffu, ss, o);
    if ((tid & 31) == 0) red[tid >> 5] = ss;
    __syncthreads();
    float tot = 0.f;
    #pragma unroll
    for (int w = 0; w < 8; w++) tot += red[w];
    float inv = rsqrtf(tot / (float)Q_LORA + 1e-6f);
    for (int i = tid; i < Q_LORA; i += 256)
        cqh[(size_t)s * Q_LORA + i] = __float2half_rn(row[i] * inv * wq[i]);
    __syncthreads();

    const float* row2 = row + Q_LORA;
    ss = 0.f;
    for (int i = tid; i < KV_LORA; i += 256) { float v = row2[i]; ss += v * v; }
    #pragma unroll
    for (int o = 16; o; o >>= 1) ss += __shfl_xor_sync(0xffffffffu, ss, o);
    if ((tid & 31) == 0) red[tid >> 5] = ss;
    __syncthreads();
    tot = 0.f;
    #pragma unroll
    for (int w = 0; w < 8; w++) tot += red[w];
    inv = rsqrtf(tot / (float)KV_LORA + 1e-6f);
    for (int i = tid; i < KV_LORA; i += 256)
        ckvh[(size_t)s * KV_LORA + i] = __float2half_rn(row2[i] * inv * wkv[i]);

    if (tid < 32) {
        int p = pos_ids[s];
        float inv_freq = exp2f(-(float)tid * (ROPE_L2 / 32.0f));
        float ang = (float)p * inv_freq;
        float c, sn;
        __sincosf(ang, &sn, &c);
        float x1 = row[Q_LORA + KV_LORA + tid];
        float x2 = row[Q_LORA + KV_LORA + 32 + tid];
        kpeh[(size_t)s * ROPE + tid]      = __float2half_rn(x1 * c - x2 * sn);
        kpeh[(size_t)s * ROPE + 32 + tid] = __float2half_rn(x2 * c + x1 * sn);
    }
}

// ================= HMMA flash attention =====================
// 1-term QK^T, 1-term PV, fp16-hi output. 128-query tiles.
#define QSTR   400
#define VSTR   272
#define SM_QH  0
#define SM_ST0 51200
#define VHOFF  25600
#define STGSZ  43008
#define FSMEM  (SM_ST0 + 2 * STGSZ)     // 137216

__device__ __forceinline__ void issue_kv(
    const __half* __restrict__ KVh, const __half* __restrict__ KPh,
    int n0, int h, uint32_t stg, int tid)
{
    #pragma unroll
    for (int l = 0; l < 6; ++l) {
        int i = tid + l * 256;
        int r = i / 24, j = i % 24;
        uint32_t dst = stg + r * QSTR + j * 16;
        if (j < 16)
            cp16(dst, KVh + (size_t)(n0 + r) * KV_COLS + h * 2 * NOPE + j * 8);
        else
            cp16(dst, KPh + (size_t)(n0 + r) * ROPE + (j - 16) * 8);
    }
    #pragma unroll
    for (int l = 0; l < 4; ++l) {
        int i = tid + l * 256;
        int r = i / 16, j = i % 16;
        cp16(stg + VHOFF + r * VSTR + j * 16,
             KVh + (size_t)(n0 + r) * KV_COLS + h * 2 * NOPE + NOPE + j * 8);
    }
}

__global__ __launch_bounds__(256, 1) void flash_mma(
    const __half* __restrict__ Qh,
    const __half* __restrict__ KVh, const __half* __restrict__ KPh,
    __half* __restrict__ Oh)
{
    extern __shared__ char sm[];
    uint32_t sb = smem_u32(sm);
    const int qt = (int)gridDim.x - 1 - (int)blockIdx.x;
    const int h = blockIdx.y;
    const int qm0 = qt * 128;
    const int tid = threadIdx.x, lane = tid & 31, warp = tid >> 5;

    #pragma unroll
    for (int l = 0; l < 12; ++l) {
        int i = tid + l * 256;
        int r = i / 24, j = i % 24;
        cp16(sb + SM_QH + r * QSTR + j * 16,
             Qh + (size_t)(qm0 + r) * Q_COLS + h * QDIM + j * 8);
    }
    issue_kv(KVh, KPh, 0, h, sb + SM_ST0, tid);
    CP_COMMIT();

    float acc[16][4];
    #pragma unroll
    for (int vt = 0; vt < 16; ++vt)
        #pragma unroll
        for (int e = 0; e < 4; ++e) acc[vt][e] = 0.f;
    float miA = -1e30f, miB = -1e30f, liA = 0.f, liB = 0.f;

    const int T = 2 * (qt + 1);
    const int rA = qm0 + warp * 16 + (lane >> 2);

    for (int t = 0; t < T; ++t) {
        if (t + 1 < T) {
            issue_kv(KVh, KPh, (t + 1) * 64, h, sb + SM_ST0 + ((t + 1) & 1) * STGSZ, tid);
            CP_COMMIT();
            CP_WAIT(1);
        } else {
            CP_WAIT(0);
        }
        __syncthreads();
        uint32_t stg = sb + SM_ST0 + (t & 1) * STGSZ;

        float sc[8][4];
        #pragma unroll
        for (int nt = 0; nt < 8; ++nt)
            #pragma unroll
            for (int e = 0; e < 4; ++e) sc[nt][e] = 0.f;

        const uint32_t qa = sb + (warp * 16 + (lane & 15)) * QSTR + (lane >> 4) * 16;
        #pragma unroll
        for (int kk = 0; kk < 12; ++kk) {
            uint32_t aH[4];
            ldmx4(aH, qa + SM_QH + kk * 32);
            #pragma unroll
            for (int np = 0; np < 4; ++np) {
                uint32_t bH[4];
                uint32_t ba = stg + ((np * 2 + (lane >> 4)) * 8 + (lane & 7)) * QSTR
                              + ((lane >> 3) & 1) * 16 + kk * 32;
                ldmx4(bH, ba);
                mma16816(sc[np * 2],     aH, bH);
                mma16816(sc[np * 2 + 1], aH, bH + 2);
            }
        }

        if (t >= T - 2) {
            #pragma unroll
            for (int nt = 0; nt < 8; ++nt) {
                int c0 = t * 64 + nt * 8 + (lane & 3) * 2;
                if (c0     > rA)     sc[nt][0] = -1e30f;
                if (c0 + 1 > rA)     sc[nt][1] = -1e30f;
                if (c0     > rA + 8) sc[nt][2] = -1e30f;
                if (c0 + 1 > rA + 8) sc[nt][3] = -1e30f;
            }
        }

        float mA = -1e30f, mB = -1e30f;
        #pragma unroll
        for (int nt = 0; nt < 8; ++nt) {
            mA = fmaxf(mA, fmaxf(sc[nt][0], sc[nt][1]));
            mB = fmaxf(mB, fmaxf(sc[nt][2], sc[nt][3]));
        }
        mA = fmaxf(mA, __shfl_xor_sync(0xffffffffu, mA, 1));
        mA = fmaxf(mA, __shfl_xor_sync(0xffffffffu, mA, 2));
        mB = fmaxf(mB, __shfl_xor_sync(0xffffffffu, mB, 1));
        mB = fmaxf(mB, __shfl_xor_sync(0xffffffffu, mB, 2));
        float nmA = fmaxf(miA, mA), nmB = fmaxf(miB, mB);
        float cA = __expf(miA - nmA), cB = __expf(miB - nmB);
        miA = nmA; miB = nmB;

        float sA = 0.f, sB = 0.f;
        #pragma unroll
        for (int nt = 0; nt < 8; ++nt) {
            sc[nt][0] = __expf(sc[nt][0] - nmA); sA += sc[nt][0];
            sc[nt][1] = __expf(sc[nt][1] - nmA); sA += sc[nt][1];
            sc[nt][2] = __expf(sc[nt][2] - nmB); sB += sc[nt][2];
            sc[nt][3] = __expf(sc[nt][3] - nmB); sB += sc[nt][3];
        }
        sA += __shfl_xor_sync(0xffffffffu, sA, 1);
        sA += __shfl_xor_sync(0xffffffffu, sA, 2);
        sB += __shfl_xor_sync(0xffffffffu, sB, 1);
        sB += __shfl_xor_sync(0xffffffffu, sB, 2);
        liA = liA * cA + sA;
        liB = liB * cB + sB;
        #pragma unroll
        for (int vt = 0; vt < 16; ++vt) {
            acc[vt][0] *= cA; acc[vt][1] *= cA;
            acc[vt][2] *= cB; acc[vt][3] *= cB;
        }

        #pragma unroll
        for (int kp = 0; kp < 4; ++kp) {
            uint32_t aH[4];
            #pragma unroll
            for (int q2 = 0; q2 < 2; ++q2) {
                const float* s0 = sc[2 * kp + q2];
                aH[q2 * 2 + 0] = packh2(s0[0], s0[1]);
                aH[q2 * 2 + 1] = packh2(s0[2], s0[3]);
            }
            #pragma unroll
            for (int vp = 0; vp < 8; ++vp) {
                uint32_t bH[4];
                uint32_t va = stg + VHOFF + (kp * 16 + (lane & 15)) * VSTR
                              + (vp * 2 + (lane >> 4)) * 16;
                ldmx4t(bH, va);
                mma16816(acc[vp * 2],     aH, bH);
                mma16816(acc[vp * 2 + 1], aH, bH + 2);
            }
        }
        __syncthreads();
    }

    float rlA = 1.f / liA, rlB = 1.f / liB;
    #pragma unroll
    for (int vt = 0; vt < 16; ++vt) {
        int col = h * VDIM + vt * 8 + (lane & 3) * 2;
        *(__half2*)&Oh[(size_t)rA * O_COLS + col] =
            __floats2half2_rn(acc[vt][0] * rlA, acc[vt][1] * rlA);
        *(__half2*)&Oh[(size_t)(rA + 8) * O_COLS + col] =
            __floats2half2_rn(acc[vt][2] * rlB, acc[vt][3] * rlB);
    }
}

// ================= launch =================
extern "C" void kernel_launch(void* const* d_in, const int* in_sizes, int n_in,
                              void* d_out, int out_size)
{
    const int*   pos   = (const int*)  d_in[0];
    const float* hid   = (const float*)d_in[1];
    const float* w_a   = (const float*)d_in[2];
    const float* wq_ln = (const float*)d_in[3];
    const float* wkv_ln= (const float*)d_in[4];
    const float* w_q_b = (const float*)d_in[5];
    const float* w_kv_b= (const float*)d_in[6];
    const float* w_o   = (const float*)d_in[7];
    float* out = (float*)d_out;

    float* a;
    cudaGetSymbolAddress((void**)&a, g_a);

    __half *h_hi, *cq_hi, *ckv_hi, *at_hi;
    __half *qs_hi, *kvh, *kpeh, *wa_h, *wqb_h, *wkvb_h, *wo_h;
    cudaGetSymbolAddress((void**)&h_hi,   g_h_hi);
    cudaGetSymbolAddress((void**)&cq_hi,  g_cq_hi);
    cudaGetSymbolAddress((void**)&ckv_hi, g_ckv_hi);
    cudaGetSymbolAddress((void**)&at_hi,  g_at_hi);
    cudaGetSymbolAddress((void**)&qs_hi,  g_qs_hi);
    cudaGetSymbolAddress((void**)&kvh,    g_kvh);    cudaGetSymbolAddress((void**)&kpeh,   g_kpeh);
    cudaGetSymbolAddress((void**)&wa_h,   g_wa_h);   cudaGetSymbolAddress((void**)&wqb_h,  g_wqb_h);
    cudaGetSymbolAddress((void**)&wkvb_h, g_wkvb_h); cudaGetSymbolAddress((void**)&wo_h,   g_wo_h);

    cudaFuncSetAttribute(mma_gemm, cudaFuncAttributeMaxDynamicSharedMemorySize, GSMEM);
    cudaFuncSetAttribute(flash_mma, cudaFuncAttributeMaxDynamicSharedMemorySize, FSMEM);

    // ---- side stream s2 ----
    cudaStream_t s2;
    cudaStreamCreateWithFlags(&s2, cudaStreamNonBlocking);
    cudaEvent_t evFork, evW, evNorm, evKV;
    cudaEventCreateWithFlags(&evFork, cudaEventDisableTiming);
    cudaEventCreateWithFlags(&evW,    cudaEventDisableTiming);
    cudaEventCreateWithFlags(&evNorm, cudaEventDisableTiming);
    cudaEventCreateWithFlags(&evKV,   cudaEventDisableTiming);

    cudaEventRecord(evFork, 0);
    cudaStreamWaitEvent(s2, evFork, 0);
    // s2: weight conversions needed for GEMMs 3/4/6
    cvt_hi<<<2048, 256, 0, s2>>>(w_q_b,  wqb_h,  Q_COLS * Q_LORA / 4, Q_LORA, Q_COLS);
    cvt_hi<<<2048, 256, 0, s2>>>(w_kv_b, wkvb_h, KV_COLS * KV_LORA / 4, KV_LORA, KV_COLS);
    cvt_hi<<<2048, 256, 0, s2>>>(w_o,    wo_h,   HID * O_COLS / 4, O_COLS, HID);
    cudaEventRecord(evW, s2);

    // ---- main stream ----
    cvt_hi<<<4096, 256>>>(w_a, wa_h, A_COLS_P * HID / 4, HID, A_COLS);
    cvt_hi<<<4096, 256>>>(hid, h_hi, S * HID / 4, HID, S);

    // 1) fused-A GEMM (fp32 out)
    mma_gemm<<<dim3(A_COLS_P / 256, S / 128), 256, GSMEM>>>(
        h_hi, wa_h, a, nullptr, pos, A_COLS, A_COLS, HID, 0);

    // 2) RMSNorm + k_pe rope
    rmsnorm_rope_kernel<<<S, 256>>>(a, kpeh, cq_hi, ckv_hi, wq_ln, wkv_ln, pos);
    cudaEventRecord(evNorm, 0);

    // s2: kv GEMM runs concurrently with q GEMM (independent)
    cudaStreamWaitEvent(s2, evNorm, 0);
    mma_gemm<<<dim3(KV_COLS / 256, S / 128), 256, GSMEM, s2>>>(
        ckv_hi, wkvb_h, nullptr, kvh, pos, KV_COLS, KV_COLS, KV_LORA, 1);
    cudaEventRecord(evKV, s2);

    // main: q GEMM (rope + scale fused, fp16 out)
    cudaStreamWaitEvent(0, evW, 0);
    mma_gemm<<<dim3(Q_COLS / 256, S / 128), 256, GSMEM>>>(
        cq_hi, wqb_h, nullptr, qs_hi, pos, Q_COLS, Q_COLS, Q_LORA, 2);

    // flash needs both q and kv
    cudaStreamWaitEvent(0, evKV, 0);
    flash_mma<<<dim3(S / 128, H), 256, FSMEM>>>(qs_hi, kvh, kpeh, at_hi);

    // output GEMM (fp32 out = final)
    mma_gemm<<<dim3(HID / 256, S / 128), 256, GSMEM>>>(
        at_hi, wo_h, out, nullptr, pos, HID, HID, O_COLS, 0);

    cudaEventDestroy(evFork);
    cudaEventDestroy(evW);
    cudaEventDestroy(evNorm);
    cudaEventDestroy(evKV);
    cudaStreamDestroy(s2);
}

// round 14
// speedup vs baseline: 14.0313x; 1.0154x over previous
#include <cuda_runtime.h>
#include <cuda_fp16.h>
#include <math.h>
#include <stdint.h>

// ---------------- problem constants ----------------
#define S        2048
#define HID      4096
#define H        32
#define Q_LORA   1536
#define KV_LORA  512
#define NOPE     128
#define ROPE     64
#define VDIM     128
#define A_COLS   (Q_LORA + KV_LORA + ROPE)   // 2112
#define A_COLS_P 2304                        // padded to 256-mult
#define QDIM     (NOPE + ROPE)               // 192
#define Q_COLS   (H * QDIM)                  // 6144
#define KV_COLS  (H * 2 * NOPE)              // 8192
#define O_COLS   (H * VDIM)                  // 4096
#define ATT_SCALE 0.07216878364870322992f    // 1/sqrt(192)
#define ROPE_L2  13.287712379549449f         // log2(10000)

// ---------------- scratch ----------------
__device__ __align__(256) float g_a[S * A_COLS];

// fp16 operands
__device__ __align__(256) __half g_h_hi[S * HID];
__device__ __align__(256) __half g_cq_hi[S * Q_LORA];
__device__ __align__(256) __half g_ckv_hi[S * KV_LORA];
__device__ __align__(256) __half g_at_hi[S * O_COLS];
__device__ __align__(256) __half g_qs_hi[S * Q_COLS];
__device__ __align__(256) __half g_kvh[S * KV_COLS];
__device__ __align__(256) __half g_kpeh[S * ROPE];
// weights (fp16, rows padded to 256-mult)
__device__ __align__(256) __half g_wa_h[A_COLS_P * HID];
__device__ __align__(256) __half g_wqb_h[Q_COLS * Q_LORA];
__device__ __align__(256) __half g_wkvb_h[KV_COLS * KV_LORA];
__device__ __align__(256) __half g_wo_h[HID * O_COLS];

// ================= portable PTX helpers =================
__device__ __forceinline__ uint32_t smem_u32(const void* p) {
    uint32_t a;
    asm("{ .reg .u64 t; cvta.to.shared.u64 t, %1; cvt.u32.u64 %0, t; }"
        : "=r"(a) : "l"(p));
    return a;
}
__device__ __forceinline__ void cp16(uint32_t dst, const void* src) {
    asm volatile("cp.async.cg.shared.global [%0], [%1], 16;" :: "r"(dst), "l"(src));
}
#define CP_COMMIT()  asm volatile("cp.async.commit_group;" ::: "memory")
#define CP_WAIT(n)   asm volatile("cp.async.wait_group %0;" :: "n"(n) : "memory")

__device__ __forceinline__ void ldmx4(uint32_t* r, uint32_t addr) {
    asm volatile("ldmatrix.sync.aligned.m8n8.x4.shared.b16 {%0,%1,%2,%3}, [%4];"
                 : "=r"(r[0]), "=r"(r[1]), "=r"(r[2]), "=r"(r[3]) : "r"(addr));
}
__device__ __forceinline__ void ldmx2(uint32_t* r, uint32_t addr) {
    asm volatile("ldmatrix.sync.aligned.m8n8.x2.shared.b16 {%0,%1}, [%2];"
                 : "=r"(r[0]), "=r"(r[1]) : "r"(addr));
}
__device__ __forceinline__ void ldmx4t(uint32_t* r, uint32_t addr) {
    asm volatile("ldmatrix.sync.aligned.m8n8.x4.trans.shared.b16 {%0,%1,%2,%3}, [%4];"
                 : "=r"(r[0]), "=r"(r[1]), "=r"(r[2]), "=r"(r[3]) : "r"(addr));
}
__device__ __forceinline__ void mma16816(float* c, const uint32_t* a, const uint32_t* b) {
    asm volatile(
        "mma.sync.aligned.m16n8k16.row.col.f32.f16.f16.f32 "
        "{%0,%1,%2,%3},{%4,%5,%6,%7},{%8,%9},{%0,%1,%2,%3};"
        : "+f"(c[0]), "+f"(c[1]), "+f"(c[2]), "+f"(c[3])
        : "r"(a[0]), "r"(a[1]), "r"(a[2]), "r"(a[3]), "r"(b[0]), "r"(b[1]));
}
__device__ __forceinline__ uint32_t packh2(float x, float y) {
    __half2 h = __floats2half2_rn(x, y);
    return *(uint32_t*)&h;
}

// ================= fp32 -> fp16 (rows guarded/padded) =====================
__global__ __launch_bounds__(256) void cvt_hi(
    const float* __restrict__ src, __half* __restrict__ hi,
    int total4, int cols, int rows)
{
    for (int i = blockIdx.x * 256 + threadIdx.x; i < total4; i += gridDim.x * 256) {
        int e = i * 4;
        int r = e / cols;
        float4 f = make_float4(0.f, 0.f, 0.f, 0.f);
        if (r < rows) f = *(const float4*)(src + (size_t)e);
        *(__half2*)(hi + (size_t)e)     = __floats2half2_rn(f.x, f.y);
        *(__half2*)(hi + (size_t)e + 2) = __floats2half2_rn(f.z, f.w);
    }
}

// ================= fp16 HMMA GEMM (1-term) ===============================
// CTA 128x256, warp tile 64x64 (8 warps, 2x4), BK=32, 4-stage cp.async ring.
// mode 0: fp32 C.  mode 1: fp16 -> Ch.  mode 2: rope+scale -> Ch (fp16).
#define BKC   32
#define ROWB  80
#define ATILE (128 * ROWB)             // 10240
#define BTILE (256 * ROWB)             // 20480
#define STG   (ATILE + BTILE)          // 30720
#define NS    4
#define GSMEM (NS * STG)               // 122880

__device__ __forceinline__ void issue_stage(
    const __half* __restrict__ Ah, const __half* __restrict__ Bh,
    int row0, int col0, int K, int c, uint32_t sbase, int slot, int tid)
{
    uint32_t st = sbase + slot * STG;
    #pragma unroll
    for (int l = 0; l < 2; ++l) {
        int v = tid + l * 256;
        int r = v >> 2;
        int j = v & 3;
        cp16(st + r * ROWB + j * 16,
             Ah + (size_t)(row0 + r) * K + c * BKC + j * 8);
    }
    #pragma unroll
    for (int l = 0; l < 4; ++l) {
        int v = tid + l * 256;
        int r = v >> 2;
        int j = v & 3;
        cp16(st + ATILE + r * ROWB + j * 16,
             Bh + (size_t)(col0 + r) * K + c * BKC + j * 8);
    }
}

__global__ __launch_bounds__(256, 1) void mma_gemm(
    const __half* __restrict__ Ah, const __half* __restrict__ Bh,
    float* __restrict__ C, __half* __restrict__ Ch,
    const int* __restrict__ pos,
    int ldc, int N, int K, int mode)
{
    extern __shared__ char sm[];
    uint32_t sbase = smem_u32(sm);
    const int tid    = threadIdx.x;
    const int lane   = tid & 31;
    const int warp   = tid >> 5;
    const int warp_m = warp >> 2;
    const int warp_n = warp & 3;
    const int row0 = blockIdx.y * 128;
    const int col0 = blockIdx.x * 256;

    float acc[4][8][4];
    #pragma unroll
    for (int mi = 0; mi < 4; ++mi)
        #pragma unroll
        for (int ni = 0; ni < 8; ++ni)
            #pragma unroll
            for (int e = 0; e < 4; ++e) acc[mi][ni][e] = 0.f;

    const int nch = K / BKC;

    #pragma unroll
    for (int p = 0; p < NS - 1; ++p) {
        if (p < nch) issue_stage(Ah, Bh, row0, col0, K, p, sbase, p, tid);
        CP_COMMIT();
    }

    const uint32_t a_l = (uint32_t)((warp_m * 64 + (lane & 15)) * ROWB + (lane >> 4) * 16);
    const uint32_t b_l = (uint32_t)(ATILE + (warp_n * 64 + (lane & 7)) * ROWB
                                    + ((lane >> 3) & 1) * 16);

    for (int c = 0; c < nch; ++c) {
        CP_WAIT(NS - 2);
        __syncthreads();
        int np = c + NS - 1;
        if (np < nch)
            issue_stage(Ah, Bh, row0, col0, K, np, sbase, np & (NS - 1), tid);
        CP_COMMIT();

        uint32_t st = sbase + (c & (NS - 1)) * STG;

        #pragma unroll
        for (int ki = 0; ki < 2; ++ki) {
            uint32_t ah[4][4];
            #pragma unroll
            for (int mi = 0; mi < 4; ++mi)
                ldmx4(ah[mi], st + a_l + mi * (16 * ROWB) + ki * 32);
            #pragma unroll
            for (int ni = 0; ni < 8; ++ni) {
                uint32_t bh[2];
                ldmx2(bh, st + b_l + ni * (8 * ROWB) + ki * 32);
                #pragma unroll
                for (int mi = 0; mi < 4; ++mi)
                    mma16816(acc[mi][ni], ah[mi], bh);
            }
        }
    }

    if (mode == 2) {
        int ttype = ((col0 >> 6) + warp_n) % 3;
        if (ttype == 2) {
            #pragma unroll
            for (int mi = 0; mi < 4; ++mi) {
                int r0 = row0 + warp_m * 64 + mi * 16 + (lane >> 2);
                float p0 = (float)pos[r0];
                float p1 = (float)pos[r0 + 8];
                #pragma unroll
                for (int ni = 0; ni < 4; ++ni) {
                    #pragma unroll
                    for (int e = 0; e < 2; ++e) {
                        int i = ni * 8 + (lane & 3) * 2 + e;
                        float f = exp2f(-(float)i * (ROPE_L2 / 32.0f));
                        float c0, s0, c1, s1;
                        __sincosf(p0 * f, &s0, &c0);
                        __sincosf(p1 * f, &s1, &c1);
                        float x1 = acc[mi][ni][e],     x2 = acc[mi][ni + 4][e];
                        acc[mi][ni][e]       = x1 * c0 - x2 * s0;
                        acc[mi][ni + 4][e]   = x2 * c0 + x1 * s0;
                        float y1 = acc[mi][ni][e + 2], y2 = acc[mi][ni + 4][e + 2];
                        acc[mi][ni][e + 2]     = y1 * c1 - y2 * s1;
                        acc[mi][ni + 4][e + 2] = y2 * c1 + y1 * s1;
                    }
                }
            }
        }
        #pragma unroll
        for (int mi = 0; mi < 4; ++mi) {
            int row = row0 + warp_m * 64 + mi * 16 + (lane >> 2);
            #pragma unroll
            for (int ni = 0; ni < 8; ++ni) {
                int col = col0 + warp_n * 64 + ni * 8 + (lane & 3) * 2;
                *(__half2*)&Ch[(size_t)row * ldc + col] =
                    __floats2half2_rn(acc[mi][ni][0] * ATT_SCALE,
                                      acc[mi][ni][1] * ATT_SCALE);
                *(__half2*)&Ch[(size_t)(row + 8) * ldc + col] =
                    __floats2half2_rn(acc[mi][ni][2] * ATT_SCALE,
                                      acc[mi][ni][3] * ATT_SCALE);
            }
        }
    } else if (mode == 1) {
        #pragma unroll
        for (int mi = 0; mi < 4; ++mi) {
            int row = row0 + warp_m * 64 + mi * 16 + (lane >> 2);
            #pragma unroll
            for (int ni = 0; ni < 8; ++ni) {
                int col = col0 + warp_n * 64 + ni * 8 + (lane & 3) * 2;
                *(__half2*)&Ch[(size_t)row * ldc + col] =
                    __floats2half2_rn(acc[mi][ni][0], acc[mi][ni][1]);
                *(__half2*)&Ch[(size_t)(row + 8) * ldc + col] =
                    __floats2half2_rn(acc[mi][ni][2], acc[mi][ni][3]);
            }
        }
    } else {
        #pragma unroll
        for (int mi = 0; mi < 4; ++mi) {
            int row = row0 + warp_m * 64 + mi * 16 + (lane >> 2);
            #pragma unroll
            for (int ni = 0; ni < 8; ++ni) {
                int col = col0 + warp_n * 64 + ni * 8 + (lane & 3) * 2;
                if (col < N) {
                    *(float2*)&C[(size_t)row * ldc + col] =
                        make_float2(acc[mi][ni][0], acc[mi][ni][1]);
                    *(float2*)&C[(size_t)(row + 8) * ldc + col] =
                        make_float2(acc[mi][ni][2], acc[mi][ni][3]);
                }
            }
        }
    }
}

// ================= RMSNorm (fp16 out) + k_pe RoPE (fp16) ==================
__global__ __launch_bounds__(256) void rmsnorm_rope_kernel(
    const float* __restrict__ a,
    __half* __restrict__ kpeh,
    __half* __restrict__ cqh,
    __half* __restrict__ ckvh,
    const float* __restrict__ wq,
    const float* __restrict__ wkv,
    const int* __restrict__ pos_ids)
{
    const int s   = blockIdx.x;
    const int tid = threadIdx.x;
    const float* row = a + (size_t)s * A_COLS;
    __shared__ float red[8];

    float ss = 0.f;
    for (int i = tid; i < Q_LORA; i += 256) { float v = row[i]; ss += v * v; }
    #pragma unroll
    for (int o = 16; o; o >>= 1) ss += __shfl_xor_sync(0xffffffffu, ss, o);
    if ((tid & 31) == 0) red[tid >> 5] = ss;
    __syncthreads();
    float tot = 0.f;
    #pragma unroll
    for (int w = 0; w < 8; w++) tot += red[w];
    float inv = rsqrtf(tot / (float)Q_LORA + 1e-6f);
    for (int i = tid; i < Q_LORA; i += 256)
        cqh[(size_t)s * Q_LORA + i] = __float2half_rn(row[i] * inv * wq[i]);
    __syncthreads();

    const float* row2 = row + Q_LORA;
    ss = 0.f;
    for (int i = tid; i < KV_LORA; i += 256) { float v = row2[i]; ss += v * v; }
    #pragma unroll
    for (int o = 16; o; o >>= 1) ss += __shfl_xor_sync(0xffffffffu, ss, o);
    if ((tid & 31) == 0) red[tid >> 5] = ss;
    __syncthreads();
    tot = 0.f;
    #pragma unroll
    for (int w = 0; w < 8; w++) tot += red[w];
    inv = rsqrtf(tot / (float)KV_LORA + 1e-6f);
    for (int i = tid; i < KV_LORA; i += 256)
        ckvh[(size_t)s * KV_LORA + i] = __float2half_rn(row2[i] * inv * wkv[i]);

    if (tid < 32) {
        int p = pos_ids[s];
        float inv_freq = exp2f(-(float)tid * (ROPE_L2 / 32.0f));
        float ang = (float)p * inv_freq;
        float c, sn;
        __sincosf(ang, &sn, &c);
        float x1 = row[Q_LORA + KV_LORA + tid];
        float x2 = row[Q_LORA + KV_LORA + 32 + tid];
        kpeh[(size_t)s * ROPE + tid]      = __float2half_rn(x1 * c - x2 * sn);
        kpeh[(size_t)s * ROPE + 32 + tid] = __float2half_rn(x2 * c + x1 * sn);
    }
}

// ================= HMMA flash attention =====================
// 1-term QK^T, 1-term PV, fp16 out. 64-query tiles, 128 threads,
// 2 CTAs/SM (smem 111616 x2 = 223232 < 228KB) to interleave softmax
// bubbles of one CTA with MMA bursts of the other.
#define QSTR   400
#define VSTR   272
#define SM_QH  0
#define SM_ST0 25600
#define VHOFF  25600
#define STGSZ  43008
#define FSMEM  (SM_ST0 + 2 * STGSZ)     // 111616

__device__ __forceinline__ void issue_kv(
    const __half* __restrict__ KVh, const __half* __restrict__ KPh,
    int n0, int h, uint32_t stg, int tid)
{
    #pragma unroll
    for (int l = 0; l < 12; ++l) {                // 64*24 / 128
        int i = tid + l * 128;
        int r = i / 24, j = i % 24;
        uint32_t dst = stg + r * QSTR + j * 16;
        if (j < 16)
            cp16(dst, KVh + (size_t)(n0 + r) * KV_COLS + h * 2 * NOPE + j * 8);
        else
            cp16(dst, KPh + (size_t)(n0 + r) * ROPE + (j - 16) * 8);
    }
    #pragma unroll
    for (int l = 0; l < 8; ++l) {                 // 64*16 / 128
        int i = tid + l * 128;
        int r = i / 16, j = i % 16;
        cp16(stg + VHOFF + r * VSTR + j * 16,
             KVh + (size_t)(n0 + r) * KV_COLS + h * 2 * NOPE + NOPE + j * 8);
    }
}

__global__ __launch_bounds__(128, 2) void flash_mma(
    const __half* __restrict__ Qh,
    const __half* __restrict__ KVh, const __half* __restrict__ KPh,
    __half* __restrict__ Oh)
{
    extern __shared__ char sm[];
    uint32_t sb = smem_u32(sm);
    const int qt = (int)gridDim.x - 1 - (int)blockIdx.x;   // longest-first
    const int h = blockIdx.y;
    const int qm0 = qt * 64;
    const int tid = threadIdx.x, lane = tid & 31, warp = tid >> 5;

    // Q tile: 64 rows x 24 chunks = 1536 slots / 128 threads
    #pragma unroll
    for (int l = 0; l < 12; ++l) {
        int i = tid + l * 128;
        int r = i / 24, j = i % 24;
        cp16(sb + SM_QH + r * QSTR + j * 16,
             Qh + (size_t)(qm0 + r) * Q_COLS + h * QDIM + j * 8);
    }
    issue_kv(KVh, KPh, 0, h, sb + SM_ST0, tid);
    CP_COMMIT();

    float acc[16][4];
    #pragma unroll
    for (int vt = 0; vt < 16; ++vt)
        #pragma unroll
        for (int e = 0; e < 4; ++e) acc[vt][e] = 0.f;
    float miA = -1e30f, miB = -1e30f, liA = 0.f, liB = 0.f;

    const int T = qt + 1;
    const int rA = qm0 + warp * 16 + (lane >> 2);

    for (int t = 0; t < T; ++t) {
        if (t + 1 < T) {
            issue_kv(KVh, KPh, (t + 1) * 64, h, sb + SM_ST0 + ((t + 1) & 1) * STGSZ, tid);
            CP_COMMIT();
            CP_WAIT(1);
        } else {
            CP_WAIT(0);
        }
        __syncthreads();
        uint32_t stg = sb + SM_ST0 + (t & 1) * STGSZ;

        float sc[8][4];
        #pragma unroll
        for (int nt = 0; nt < 8; ++nt)
            #pragma unroll
            for (int e = 0; e < 4; ++e) sc[nt][e] = 0.f;

        const uint32_t qa = sb + (warp * 16 + (lane & 15)) * QSTR + (lane >> 4) * 16;
        #pragma unroll
        for (int kk = 0; kk < 12; ++kk) {
            uint32_t aH[4];
            ldmx4(aH, qa + SM_QH + kk * 32);
            #pragma unroll
            for (int np = 0; np < 4; ++np) {
                uint32_t bH[4];
                uint32_t ba = stg + ((np * 2 + (lane >> 4)) * 8 + (lane & 7)) * QSTR
                              + ((lane >> 3) & 1) * 16 + kk * 32;
                ldmx4(bH, ba);
                mma16816(sc[np * 2],     aH, bH);
                mma16816(sc[np * 2 + 1], aH, bH + 2);
            }
        }

        if (t == T - 1) {
            #pragma unroll
            for (int nt = 0; nt < 8; ++nt) {
                int c0 = qm0 + nt * 8 + (lane & 3) * 2;
                if (c0     > rA)     sc[nt][0] = -1e30f;
                if (c0 + 1 > rA)     sc[nt][1] = -1e30f;
                if (c0     > rA + 8) sc[nt][2] = -1e30f;
                if (c0 + 1 > rA + 8) sc[nt][3] = -1e30f;
            }
        }

        float mA = -1e30f, mB = -1e30f;
        #pragma unroll
        for (int nt = 0; nt < 8; ++nt) {
            mA = fmaxf(mA, fmaxf(sc[nt][0], sc[nt][1]));
            mB = fmaxf(mB, fmaxf(sc[nt][2], sc[nt][3]));
        }
        mA = fmaxf(mA, __shfl_xor_sync(0xffffffffu, mA, 1));
        mA = fmaxf(mA, __shfl_xor_sync(0xffffffffu, mA, 2));
        mB = fmaxf(mB, __shfl_xor_sync(0xffffffffu, mB, 1));
        mB = fmaxf(mB, __shfl_xor_sync(0xffffffffu, mB, 2));
        float nmA = fmaxf(miA, mA), nmB = fmaxf(miB, mB);
        float cA = __expf(miA - nmA), cB = __expf(miB - nmB);
        miA = nmA; miB = nmB;

        float sA = 0.f, sB = 0.f;
        #pragma unroll
        for (int nt = 0; nt < 8; ++nt) {
            sc[nt][0] = __expf(sc[nt][0] - nmA); sA += sc[nt][0];
            sc[nt][1] = __expf(sc[nt][1] - nmA); sA += sc[nt][1];
            sc[nt][2] = __expf(sc[nt][2] - nmB); sB += sc[nt][2];
            sc[nt][3] = __expf(sc[nt][3] - nmB); sB += sc[nt][3];
        }
        sA += __shfl_xor_sync(0xffffffffu, sA, 1);
        sA += __shfl_xor_sync(0xffffffffu, sA, 2);
        sB += __shfl_xor_sync(0xffffffffu, sB, 1);
        sB += __shfl_xor_sync(0xffffffffu, sB, 2);
        liA = liA * cA + sA;
        liB = liB * cB + sB;
        #pragma unroll
        for (int vt = 0; vt < 16; ++vt) {
            acc[vt][0] *= cA; acc[vt][1] *= cA;
            acc[vt][2] *= cB; acc[vt][3] *= cB;
        }

        #pragma unroll
        for (int kp = 0; kp < 4; ++kp) {
            uint32_t aH[4];
            #pragma unroll
            for (int q2 = 0; q2 < 2; ++q2) {
                const float* s0 = sc[2 * kp + q2];
                aH[q2 * 2 + 0] = packh2(s0[0], s0[1]);
                aH[q2 * 2 + 1] = packh2(s0[2], s0[3]);
            }
            #pragma unroll
            for (int vp = 0; vp < 8; ++vp) {
                uint32_t bH[4];
                uint32_t va = stg + VHOFF + (kp * 16 + (lane & 15)) * VSTR
                              + (vp * 2 + (lane >> 4)) * 16;
                ldmx4t(bH, va);
                mma16816(acc[vp * 2],     aH, bH);
                mma16816(acc[vp * 2 + 1], aH, bH + 2);
            }
        }
        __syncthreads();
    }

    float rlA = 1.f / liA, rlB = 1.f / liB;
    #pragma unroll
    for (int vt = 0; vt < 16; ++vt) {
        int col = h * VDIM + vt * 8 + (lane & 3) * 2;
        *(__half2*)&Oh[(size_t)rA * O_COLS + col] =
            __floats2half2_rn(acc[vt][0] * rlA, acc[vt][1] * rlA);
        *(__half2*)&Oh[(size_t)(rA + 8) * O_COLS + col] =
            __floats2half2_rn(acc[vt][2] * rlB, acc[vt][3] * rlB);
    }
}

// ================= launch =================
extern "C" void kernel_launch(void* const* d_in, const int* in_sizes, int n_in,
                              void* d_out, int out_size)
{
    const int*   pos   = (const int*)  d_in[0];
    const float* hid   = (const float*)d_in[1];
    const float* w_a   = (const float*)d_in[2];
    const float* wq_ln = (const float*)d_in[3];
    const float* wkv_ln= (const float*)d_in[4];
    const float* w_q_b = (const float*)d_in[5];
    const float* w_kv_b= (const float*)d_in[6];
    const float* w_o   = (const float*)d_in[7];
    float* out = (float*)d_out;

    float* a;
    cudaGetSymbolAddress((void**)&a, g_a);

    __half *h_hi, *cq_hi, *ckv_hi, *at_hi;
    __half *qs_hi, *kvh, *kpeh, *wa_h, *wqb_h, *wkvb_h, *wo_h;
    cudaGetSymbolAddress((void**)&h_hi,   g_h_hi);
    cudaGetSymbolAddress((void**)&cq_hi,  g_cq_hi);
    cudaGetSymbolAddress((void**)&ckv_hi, g_ckv_hi);
    cudaGetSymbolAddress((void**)&at_hi,  g_at_hi);
    cudaGetSymbolAddress((void**)&qs_hi,  g_qs_hi);
    cudaGetSymbolAddress((void**)&kvh,    g_kvh);    cudaGetSymbolAddress((void**)&kpeh,   g_kpeh);
    cudaGetSymbolAddress((void**)&wa_h,   g_wa_h);   cudaGetSymbolAddress((void**)&wqb_h,  g_wqb_h);
    cudaGetSymbolAddress((void**)&wkvb_h, g_wkvb_h); cudaGetSymbolAddress((void**)&wo_h,   g_wo_h);

    cudaFuncSetAttribute(mma_gemm, cudaFuncAttributeMaxDynamicSharedMemorySize, GSMEM);
    cudaFuncSetAttribute(flash_mma, cudaFuncAttributeMaxDynamicSharedMemorySize, FSMEM);

    // ---- side stream s2 ----
    cudaStream_t s2;
    cudaStreamCreateWithFlags(&s2, cudaStreamNonBlocking);
    cudaEvent_t evFork, evW, evNorm, evKV;
    cudaEventCreateWithFlags(&evFork, cudaEventDisableTiming);
    cudaEventCreateWithFlags(&evW,    cudaEventDisableTiming);
    cudaEventCreateWithFlags(&evNorm, cudaEventDisableTiming);
    cudaEventCreateWithFlags(&evKV,   cudaEventDisableTiming);

    cudaEventRecord(evFork, 0);
    cudaStreamWaitEvent(s2, evFork, 0);
    // s2: weight conversions needed for GEMMs 3/4/6
    cvt_hi<<<2048, 256, 0, s2>>>(w_q_b,  wqb_h,  Q_COLS * Q_LORA / 4, Q_LORA, Q_COLS);
    cvt_hi<<<2048, 256, 0, s2>>>(w_kv_b, wkvb_h, KV_COLS * KV_LORA / 4, KV_LORA, KV_COLS);
    cvt_hi<<<2048, 256, 0, s2>>>(w_o,    wo_h,   HID * O_COLS / 4, O_COLS, HID);
    cudaEventRecord(evW, s2);

    // ---- main stream ----
    cvt_hi<<<4096, 256>>>(w_a, wa_h, A_COLS_P * HID / 4, HID, A_COLS);
    cvt_hi<<<4096, 256>>>(hid, h_hi, S * HID / 4, HID, S);

    // 1) fused-A GEMM (fp32 out)
    mma_gemm<<<dim3(A_COLS_P / 256, S / 128), 256, GSMEM>>>(
        h_hi, wa_h, a, nullptr, pos, A_COLS, A_COLS, HID, 0);

    // 2) RMSNorm + k_pe rope
    rmsnorm_rope_kernel<<<S, 256>>>(a, kpeh, cq_hi, ckv_hi, wq_ln, wkv_ln, pos);
    cudaEventRecord(evNorm, 0);

    // s2: kv GEMM concurrent with q GEMM
    cudaStreamWaitEvent(s2, evNorm, 0);
    mma_gemm<<<dim3(KV_COLS / 256, S / 128), 256, GSMEM, s2>>>(
        ckv_hi, wkvb_h, nullptr, kvh, pos, KV_COLS, KV_COLS, KV_LORA, 1);
    cudaEventRecord(evKV, s2);

    // main: q GEMM (rope + scale fused, fp16 out)
    cudaStreamWaitEvent(0, evW, 0);
    mma_gemm<<<dim3(Q_COLS / 256, S / 128), 256, GSMEM>>>(
        cq_hi, wqb_h, nullptr, qs_hi, pos, Q_COLS, Q_COLS, Q_LORA, 2);

    // flash needs both q and kv
    cudaStreamWaitEvent(0, evKV, 0);
    flash_mma<<<dim3(S / 64, H), 128, FSMEM>>>(qs_hi, kvh, kpeh, at_hi);

    // output GEMM (fp32 out = final)
    mma_gemm<<<dim3(HID / 256, S / 128), 256, GSMEM>>>(
        at_hi, wo_h, out, nullptr, pos, HID, HID, O_COLS, 0);

    cudaEventDestroy(evFork);
    cudaEventDestroy(evW);
    cudaEventDestroy(evNorm);
    cudaEventDestroy(evKV);
    cudaStreamDestroy(s2);
}

// round 15
// speedup vs baseline: 14.2277x; 1.0140x over previous
#include <cuda_runtime.h>
#include <cuda_fp16.h>
#include <math.h>
#include <stdint.h>

// ---------------- problem constants ----------------
#define S        2048
#define HID      4096
#define H        32
#define Q_LORA   1536
#define KV_LORA  512
#define NOPE     128
#define ROPE     64
#define VDIM     128
#define A_COLS   (Q_LORA + KV_LORA + ROPE)   // 2112
#define A_COLS_P 2304                        // padded to 256-mult
#define QDIM     (NOPE + ROPE)               // 192
#define Q_COLS   (H * QDIM)                  // 6144
#define KV_COLS  (H * 2 * NOPE)              // 8192
#define O_COLS   (H * VDIM)                  // 4096
#define ATT_SCALE 0.07216878364870322992f    // 1/sqrt(192)
#define ROPE_L2  13.287712379549449f         // log2(10000)

// ---------------- scratch ----------------
__device__ __align__(256) float g_a[S * A_COLS];

// fp16 operands
__device__ __align__(256) __half g_h_hi[S * HID];
__device__ __align__(256) __half g_cq_hi[S * Q_LORA];
__device__ __align__(256) __half g_ckv_hi[S * KV_LORA];
__device__ __align__(256) __half g_at_hi[S * O_COLS];
__device__ __align__(256) __half g_qs_hi[S * Q_COLS];
__device__ __align__(256) __half g_kvh[S * KV_COLS];
__device__ __align__(256) __half g_kpeh[S * ROPE];
// weights (fp16, rows padded to 256-mult)
__device__ __align__(256) __half g_wa_h[A_COLS_P * HID];
__device__ __align__(256) __half g_wqb_h[Q_COLS * Q_LORA];
__device__ __align__(256) __half g_wkvb_h[KV_COLS * KV_LORA];
__device__ __align__(256) __half g_wo_h[HID * O_COLS];

// ================= portable PTX helpers =================
__device__ __forceinline__ uint32_t smem_u32(const void* p) {
    uint32_t a;
    asm("{ .reg .u64 t; cvta.to.shared.u64 t, %1; cvt.u32.u64 %0, t; }"
        : "=r"(a) : "l"(p));
    return a;
}
__device__ __forceinline__ void cp16(uint32_t dst, const void* src) {
    asm volatile("cp.async.cg.shared.global [%0], [%1], 16;" :: "r"(dst), "l"(src));
}
#define CP_COMMIT()  asm volatile("cp.async.commit_group;" ::: "memory")
#define CP_WAIT(n)   asm volatile("cp.async.wait_group %0;" :: "n"(n) : "memory")

__device__ __forceinline__ void ldmx4(uint32_t* r, uint32_t addr) {
    asm volatile("ldmatrix.sync.aligned.m8n8.x4.shared.b16 {%0,%1,%2,%3}, [%4];"
                 : "=r"(r[0]), "=r"(r[1]), "=r"(r[2]), "=r"(r[3]) : "r"(addr));
}
__device__ __forceinline__ void ldmx2(uint32_t* r, uint32_t addr) {
    asm volatile("ldmatrix.sync.aligned.m8n8.x2.shared.b16 {%0,%1}, [%2];"
                 : "=r"(r[0]), "=r"(r[1]) : "r"(addr));
}
__device__ __forceinline__ void ldmx4t(uint32_t* r, uint32_t addr) {
    asm volatile("ldmatrix.sync.aligned.m8n8.x4.trans.shared.b16 {%0,%1,%2,%3}, [%4];"
                 : "=r"(r[0]), "=r"(r[1]), "=r"(r[2]), "=r"(r[3]) : "r"(addr));
}
__device__ __forceinline__ void mma16816(float* c, const uint32_t* a, const uint32_t* b) {
    asm volatile(
        "mma.sync.aligned.m16n8k16.row.col.f32.f16.f16.f32 "
        "{%0,%1,%2,%3},{%4,%5,%6,%7},{%8,%9},{%0,%1,%2,%3};"
        : "+f"(c[0]), "+f"(c[1]), "+f"(c[2]), "+f"(c[3])
        : "r"(a[0]), "r"(a[1]), "r"(a[2]), "r"(a[3]), "r"(b[0]), "r"(b[1]));
}
__device__ __forceinline__ uint32_t packh2(float x, float y) {
    __half2 h = __floats2half2_rn(x, y);
    return *(uint32_t*)&h;
}

// ================= fp32 -> fp16 (rows guarded/padded) =====================
__global__ __launch_bounds__(256) void cvt_hi(
    const float* __restrict__ src, __half* __restrict__ hi,
    int total4, int cols, int rows)
{
    for (int i = blockIdx.x * 256 + threadIdx.x; i < total4; i += gridDim.x * 256) {
        int e = i * 4;
        int r = e / cols;
        float4 f = make_float4(0.f, 0.f, 0.f, 0.f);
        if (r < rows) f = *(const float4*)(src + (size_t)e);
        *(__half2*)(hi + (size_t)e)     = __floats2half2_rn(f.x, f.y);
        *(__half2*)(hi + (size_t)e + 2) = __floats2half2_rn(f.z, f.w);
    }
}

// ================= fp16 HMMA GEMM (1-term) ===============================
// CTA 128x256, warp tile 64x64 (8 warps, 2x4), BK=32, 4-stage cp.async ring.
// mode 0: fp32 C.  mode 1: fp16 -> Ch.  mode 2: rope+scale -> Ch (fp16).
#define BKC   32
#define ROWB  80
#define ATILE (128 * ROWB)             // 10240
#define BTILE (256 * ROWB)             // 20480
#define STG   (ATILE + BTILE)          // 30720
#define NS    4
#define GSMEM (NS * STG)               // 122880

__device__ __forceinline__ void issue_stage(
    const __half* __restrict__ Ah, const __half* __restrict__ Bh,
    int row0, int col0, int K, int c, uint32_t sbase, int slot, int tid)
{
    uint32_t st = sbase + slot * STG;
    #pragma unroll
    for (int l = 0; l < 2; ++l) {
        int v = tid + l * 256;
        int r = v >> 2;
        int j = v & 3;
        cp16(st + r * ROWB + j * 16,
             Ah + (size_t)(row0 + r) * K + c * BKC + j * 8);
    }
    #pragma unroll
    for (int l = 0; l < 4; ++l) {
        int v = tid + l * 256;
        int r = v >> 2;
        int j = v & 3;
        cp16(st + ATILE + r * ROWB + j * 16,
             Bh + (size_t)(col0 + r) * K + c * BKC + j * 8);
    }
}

__global__ __launch_bounds__(256, 1) void mma_gemm(
    const __half* __restrict__ Ah, const __half* __restrict__ Bh,
    float* __restrict__ C, __half* __restrict__ Ch,
    const int* __restrict__ pos,
    int ldc, int N, int K, int mode)
{
    extern __shared__ char sm[];
    uint32_t sbase = smem_u32(sm);
    const int tid    = threadIdx.x;
    const int lane   = tid & 31;
    const int warp   = tid >> 5;
    const int warp_m = warp >> 2;
    const int warp_n = warp & 3;
    const int row0 = blockIdx.y * 128;
    const int col0 = blockIdx.x * 256;

    float acc[4][8][4];
    #pragma unroll
    for (int mi = 0; mi < 4; ++mi)
        #pragma unroll
        for (int ni = 0; ni < 8; ++ni)
            #pragma unroll
            for (int e = 0; e < 4; ++e) acc[mi][ni][e] = 0.f;

    const int nch = K / BKC;

    #pragma unroll
    for (int p = 0; p < NS - 1; ++p) {
        if (p < nch) issue_stage(Ah, Bh, row0, col0, K, p, sbase, p, tid);
        CP_COMMIT();
    }

    const uint32_t a_l = (uint32_t)((warp_m * 64 + (lane & 15)) * ROWB + (lane >> 4) * 16);
    const uint32_t b_l = (uint32_t)(ATILE + (warp_n * 64 + (lane & 7)) * ROWB
                                    + ((lane >> 3) & 1) * 16);

    for (int c = 0; c < nch; ++c) {
        CP_WAIT(NS - 2);
        __syncthreads();
        int np = c + NS - 1;
        if (np < nch)
            issue_stage(Ah, Bh, row0, col0, K, np, sbase, np & (NS - 1), tid);
        CP_COMMIT();

        uint32_t st = sbase + (c & (NS - 1)) * STG;

        #pragma unroll
        for (int ki = 0; ki < 2; ++ki) {
            uint32_t ah[4][4];
            #pragma unroll
            for (int mi = 0; mi < 4; ++mi)
                ldmx4(ah[mi], st + a_l + mi * (16 * ROWB) + ki * 32);
            #pragma unroll
            for (int ni = 0; ni < 8; ++ni) {
                uint32_t bh[2];
                ldmx2(bh, st + b_l + ni * (8 * ROWB) + ki * 32);
                #pragma unroll
                for (int mi = 0; mi < 4; ++mi)
                    mma16816(acc[mi][ni], ah[mi], bh);
            }
        }
    }

    if (mode == 2) {
        int ttype = ((col0 >> 6) + warp_n) % 3;
        if (ttype == 2) {
            #pragma unroll
            for (int mi = 0; mi < 4; ++mi) {
                int r0 = row0 + warp_m * 64 + mi * 16 + (lane >> 2);
                float p0 = (float)pos[r0];
                float p1 = (float)pos[r0 + 8];
                #pragma unroll
                for (int ni = 0; ni < 4; ++ni) {
                    #pragma unroll
                    for (int e = 0; e < 2; ++e) {
                        int i = ni * 8 + (lane & 3) * 2 + e;
                        float f = exp2f(-(float)i * (ROPE_L2 / 32.0f));
                        float c0, s0, c1, s1;
                        __sincosf(p0 * f, &s0, &c0);
                        __sincosf(p1 * f, &s1, &c1);
                        float x1 = acc[mi][ni][e],     x2 = acc[mi][ni + 4][e];
                        acc[mi][ni][e]       = x1 * c0 - x2 * s0;
                        acc[mi][ni + 4][e]   = x2 * c0 + x1 * s0;
                        float y1 = acc[mi][ni][e + 2], y2 = acc[mi][ni + 4][e + 2];
                        acc[mi][ni][e + 2]     = y1 * c1 - y2 * s1;
                        acc[mi][ni + 4][e + 2] = y2 * c1 + y1 * s1;
                    }
                }
            }
        }
        #pragma unroll
        for (int mi = 0; mi < 4; ++mi) {
            int row = row0 + warp_m * 64 + mi * 16 + (lane >> 2);
            #pragma unroll
            for (int ni = 0; ni < 8; ++ni) {
                int col = col0 + warp_n * 64 + ni * 8 + (lane & 3) * 2;
                *(__half2*)&Ch[(size_t)row * ldc + col] =
                    __floats2half2_rn(acc[mi][ni][0] * ATT_SCALE,
                                      acc[mi][ni][1] * ATT_SCALE);
                *(__half2*)&Ch[(size_t)(row + 8) * ldc + col] =
                    __floats2half2_rn(acc[mi][ni][2] * ATT_SCALE,
                                      acc[mi][ni][3] * ATT_SCALE);
            }
        }
    } else if (mode == 1) {
        #pragma unroll
        for (int mi = 0; mi < 4; ++mi) {
            int row = row0 + warp_m * 64 + mi * 16 + (lane >> 2);
            #pragma unroll
            for (int ni = 0; ni < 8; ++ni) {
                int col = col0 + warp_n * 64 + ni * 8 + (lane & 3) * 2;
                *(__half2*)&Ch[(size_t)row * ldc + col] =
                    __floats2half2_rn(acc[mi][ni][0], acc[mi][ni][1]);
                *(__half2*)&Ch[(size_t)(row + 8) * ldc + col] =
                    __floats2half2_rn(acc[mi][ni][2], acc[mi][ni][3]);
            }
        }
    } else {
        #pragma unroll
        for (int mi = 0; mi < 4; ++mi) {
            int row = row0 + warp_m * 64 + mi * 16 + (lane >> 2);
            #pragma unroll
            for (int ni = 0; ni < 8; ++ni) {
                int col = col0 + warp_n * 64 + ni * 8 + (lane & 3) * 2;
                if (col < N) {
                    *(float2*)&C[(size_t)row * ldc + col] =
                        make_float2(acc[mi][ni][0], acc[mi][ni][1]);
                    *(float2*)&C[(size_t)(row + 8) * ldc + col] =
                        make_float2(acc[mi][ni][2], acc[mi][ni][3]);
                }
            }
        }
    }
}

// ================= RMSNorm (fp16 out) + k_pe RoPE (fp16) ==================
__global__ __launch_bounds__(256) void rmsnorm_rope_kernel(
    const float* __restrict__ a,
    __half* __restrict__ kpeh,
    __half* __restrict__ cqh,
    __half* __restrict__ ckvh,
    const float* __restrict__ wq,
    const float* __restrict__ wkv,
    const int* __restrict__ pos_ids)
{
    const int s   = blockIdx.x;
    const int tid = threadIdx.x;
    const float* row = a + (size_t)s * A_COLS;
    __shared__ float red[8];

    float ss = 0.f;
    for (int i = tid; i < Q_LORA; i += 256) { float v = row[i]; ss += v * v; }
    #pragma unroll
    for (int o = 16; o; o >>= 1) ss += __shfl_xor_sync(0xffffffffu, ss, o);
    if ((tid & 31) == 0) red[tid >> 5] = ss;
    __syncthreads();
    float tot = 0.f;
    #pragma unroll
    for (int w = 0; w < 8; w++) tot += red[w];
    float inv = rsqrtf(tot / (float)Q_LORA + 1e-6f);
    for (int i = tid; i < Q_LORA; i += 256)
        cqh[(size_t)s * Q_LORA + i] = __float2half_rn(row[i] * inv * wq[i]);
    __syncthreads();

    const float* row2 = row + Q_LORA;
    ss = 0.f;
    for (int i = tid; i < KV_LORA; i += 256) { float v = row2[i]; ss += v * v; }
    #pragma unroll
    for (int o = 16; o; o >>= 1) ss += __shfl_xor_sync(0xffffffffu, ss, o);
    if ((tid & 31) == 0) red[tid >> 5] = ss;
    __syncthreads();
    tot = 0.f;
    #pragma unroll
    for (int w = 0; w < 8; w++) tot += red[w];
    inv = rsqrtf(tot / (float)KV_LORA + 1e-6f);
    for (int i = tid; i < KV_LORA; i += 256)
        ckvh[(size_t)s * KV_LORA + i] = __float2half_rn(row2[i] * inv * wkv[i]);

    if (tid < 32) {
        int p = pos_ids[s];
        float inv_freq = exp2f(-(float)tid * (ROPE_L2 / 32.0f));
        float ang = (float)p * inv_freq;
        float c, sn;
        __sincosf(ang, &sn, &c);
        float x1 = row[Q_LORA + KV_LORA + tid];
        float x2 = row[Q_LORA + KV_LORA + 32 + tid];
        kpeh[(size_t)s * ROPE + tid]      = __float2half_rn(x1 * c - x2 * sn);
        kpeh[(size_t)s * ROPE + 32 + tid] = __float2half_rn(x2 * c + x1 * sn);
    }
}

// ================= HMMA flash attention =====================
// 1-term QK^T, 1-term PV, fp16 out. 64-query tiles, 128 threads, 2 CTAs/SM.
// qt = qt_hi - blockIdx.x (longest-first within each partition).
#define QSTR   400
#define VSTR   272
#define SM_QH  0
#define SM_ST0 25600
#define VHOFF  25600
#define STGSZ  43008
#define FSMEM  (SM_ST0 + 2 * STGSZ)     // 111616

__device__ __forceinline__ void issue_kv(
    const __half* __restrict__ KVh, const __half* __restrict__ KPh,
    int n0, int h, uint32_t stg, int tid)
{
    #pragma unroll
    for (int l = 0; l < 12; ++l) {
        int i = tid + l * 128;
        int r = i / 24, j = i % 24;
        uint32_t dst = stg + r * QSTR + j * 16;
        if (j < 16)
            cp16(dst, KVh + (size_t)(n0 + r) * KV_COLS + h * 2 * NOPE + j * 8);
        else
            cp16(dst, KPh + (size_t)(n0 + r) * ROPE + (j - 16) * 8);
    }
    #pragma unroll
    for (int l = 0; l < 8; ++l) {
        int i = tid + l * 128;
        int r = i / 16, j = i % 16;
        cp16(stg + VHOFF + r * VSTR + j * 16,
             KVh + (size_t)(n0 + r) * KV_COLS + h * 2 * NOPE + NOPE + j * 8);
    }
}

__global__ __launch_bounds__(128, 2) void flash_mma(
    const __half* __restrict__ Qh,
    const __half* __restrict__ KVh, const __half* __restrict__ KPh,
    __half* __restrict__ Oh, int qt_hi)
{
    extern __shared__ char sm[];
    uint32_t sb = smem_u32(sm);
    const int qt = qt_hi - (int)blockIdx.x;
    const int h = blockIdx.y;
    const int qm0 = qt * 64;
    const int tid = threadIdx.x, lane = tid & 31, warp = tid >> 5;

    #pragma unroll
    for (int l = 0; l < 12; ++l) {
        int i = tid + l * 128;
        int r = i / 24, j = i % 24;
        cp16(sb + SM_QH + r * QSTR + j * 16,
             Qh + (size_t)(qm0 + r) * Q_COLS + h * QDIM + j * 8);
    }
    issue_kv(KVh, KPh, 0, h, sb + SM_ST0, tid);
    CP_COMMIT();

    float acc[16][4];
    #pragma unroll
    for (int vt = 0; vt < 16; ++vt)
        #pragma unroll
        for (int e = 0; e < 4; ++e) acc[vt][e] = 0.f;
    float miA = -1e30f, miB = -1e30f, liA = 0.f, liB = 0.f;

    const int T = qt + 1;
    const int rA = qm0 + warp * 16 + (lane >> 2);
    uint32_t qf[12][4];   // Q fragments, loaded once at t==0

    for (int t = 0; t < T; ++t) {
        if (t + 1 < T) {
            issue_kv(KVh, KPh, (t + 1) * 64, h, sb + SM_ST0 + ((t + 1) & 1) * STGSZ, tid);
            CP_COMMIT();
            CP_WAIT(1);
        } else {
            CP_WAIT(0);
        }
        __syncthreads();
        uint32_t stg = sb + SM_ST0 + (t & 1) * STGSZ;

        if (t == 0) {
            const uint32_t qa = sb + (warp * 16 + (lane & 15)) * QSTR + (lane >> 4) * 16;
            #pragma unroll
            for (int kk = 0; kk < 12; ++kk)
                ldmx4(qf[kk], qa + kk * 32);
        }

        float sc[8][4];
        #pragma unroll
        for (int nt = 0; nt < 8; ++nt)
            #pragma unroll
            for (int e = 0; e < 4; ++e) sc[nt][e] = 0.f;

        #pragma unroll
        for (int kk = 0; kk < 12; ++kk) {
            #pragma unroll
            for (int np = 0; np < 4; ++np) {
                uint32_t bH[4];
                uint32_t ba = stg + ((np * 2 + (lane >> 4)) * 8 + (lane & 7)) * QSTR
                              + ((lane >> 3) & 1) * 16 + kk * 32;
                ldmx4(bH, ba);
                mma16816(sc[np * 2],     qf[kk], bH);
                mma16816(sc[np * 2 + 1], qf[kk], bH + 2);
            }
        }

        if (t == T - 1) {
            #pragma unroll
            for (int nt = 0; nt < 8; ++nt) {
                int c0 = qm0 + nt * 8 + (lane & 3) * 2;
                if (c0     > rA)     sc[nt][0] = -1e30f;
                if (c0 + 1 > rA)     sc[nt][1] = -1e30f;
                if (c0     > rA + 8) sc[nt][2] = -1e30f;
                if (c0 + 1 > rA + 8) sc[nt][3] = -1e30f;
            }
        }

        float mA = -1e30f, mB = -1e30f;
        #pragma unroll
        for (int nt = 0; nt < 8; ++nt) {
            mA = fmaxf(mA, fmaxf(sc[nt][0], sc[nt][1]));
            mB = fmaxf(mB, fmaxf(sc[nt][2], sc[nt][3]));
        }
        mA = fmaxf(mA, __shfl_xor_sync(0xffffffffu, mA, 1));
        mA = fmaxf(mA, __shfl_xor_sync(0xffffffffu, mA, 2));
        mB = fmaxf(mB, __shfl_xor_sync(0xffffffffu, mB, 1));
        mB = fmaxf(mB, __shfl_xor_sync(0xffffffffu, mB, 2));
        float nmA = fmaxf(miA, mA), nmB = fmaxf(miB, mB);
        float cA = __expf(miA - nmA), cB = __expf(miB - nmB);
        miA = nmA; miB = nmB;

        float sA = 0.f, sB = 0.f;
        #pragma unroll
        for (int nt = 0; nt < 8; ++nt) {
            sc[nt][0] = __expf(sc[nt][0] - nmA); sA += sc[nt][0];
            sc[nt][1] = __expf(sc[nt][1] - nmA); sA += sc[nt][1];
            sc[nt][2] = __expf(sc[nt][2] - nmB); sB += sc[nt][2];
            sc[nt][3] = __expf(sc[nt][3] - nmB); sB += sc[nt][3];
        }
        sA += __shfl_xor_sync(0xffffffffu, sA, 1);
        sA += __shfl_xor_sync(0xffffffffu, sA, 2);
        sB += __shfl_xor_sync(0xffffffffu, sB, 1);
        sB += __shfl_xor_sync(0xffffffffu, sB, 2);
        liA = liA * cA + sA;
        liB = liB * cB + sB;
        #pragma unroll
        for (int vt = 0; vt < 16; ++vt) {
            acc[vt][0] *= cA; acc[vt][1] *= cA;
            acc[vt][2] *= cB; acc[vt][3] *= cB;
        }

        #pragma unroll
        for (int kp = 0; kp < 4; ++kp) {
            uint32_t aH[4];
            #pragma unroll
            for (int q2 = 0; q2 < 2; ++q2) {
                const float* s0 = sc[2 * kp + q2];
                aH[q2 * 2 + 0] = packh2(s0[0], s0[1]);
                aH[q2 * 2 + 1] = packh2(s0[2], s0[3]);
            }
            #pragma unroll
            for (int vp = 0; vp < 8; ++vp) {
                uint32_t bH[4];
                uint32_t va = stg + VHOFF + (kp * 16 + (lane & 15)) * VSTR
                              + (vp * 2 + (lane >> 4)) * 16;
                ldmx4t(bH, va);
                mma16816(acc[vp * 2],     aH, bH);
                mma16816(acc[vp * 2 + 1], aH, bH + 2);
            }
        }
        __syncthreads();
    }

    float rlA = 1.f / liA, rlB = 1.f / liB;
    #pragma unroll
    for (int vt = 0; vt < 16; ++vt) {
        int col = h * VDIM + vt * 8 + (lane & 3) * 2;
        *(__half2*)&Oh[(size_t)rA * O_COLS + col] =
            __floats2half2_rn(acc[vt][0] * rlA, acc[vt][1] * rlA);
        *(__half2*)&Oh[(size_t)(rA + 8) * O_COLS + col] =
            __floats2half2_rn(acc[vt][2] * rlB, acc[vt][3] * rlB);
    }
}

// ================= launch =================
extern "C" void kernel_launch(void* const* d_in, const int* in_sizes, int n_in,
                              void* d_out, int out_size)
{
    const int*   pos   = (const int*)  d_in[0];
    const float* hid   = (const float*)d_in[1];
    const float* w_a   = (const float*)d_in[2];
    const float* wq_ln = (const float*)d_in[3];
    const float* wkv_ln= (const float*)d_in[4];
    const float* w_q_b = (const float*)d_in[5];
    const float* w_kv_b= (const float*)d_in[6];
    const float* w_o   = (const float*)d_in[7];
    float* out = (float*)d_out;

    float* a;
    cudaGetSymbolAddress((void**)&a, g_a);

    __half *h_hi, *cq_hi, *ckv_hi, *at_hi;
    __half *qs_hi, *kvh, *kpeh, *wa_h, *wqb_h, *wkvb_h, *wo_h;
    cudaGetSymbolAddress((void**)&h_hi,   g_h_hi);
    cudaGetSymbolAddress((void**)&cq_hi,  g_cq_hi);
    cudaGetSymbolAddress((void**)&ckv_hi, g_ckv_hi);
    cudaGetSymbolAddress((void**)&at_hi,  g_at_hi);
    cudaGetSymbolAddress((void**)&qs_hi,  g_qs_hi);
    cudaGetSymbolAddress((void**)&kvh,    g_kvh);    cudaGetSymbolAddress((void**)&kpeh,   g_kpeh);
    cudaGetSymbolAddress((void**)&wa_h,   g_wa_h);   cudaGetSymbolAddress((void**)&wqb_h,  g_wqb_h);
    cudaGetSymbolAddress((void**)&wkvb_h, g_wkvb_h); cudaGetSymbolAddress((void**)&wo_h,   g_wo_h);

    cudaFuncSetAttribute(mma_gemm, cudaFuncAttributeMaxDynamicSharedMemorySize, GSMEM);
    cudaFuncSetAttribute(flash_mma, cudaFuncAttributeMaxDynamicSharedMemorySize, FSMEM);

    // ---- side stream s2 ----
    cudaStream_t s2;
    cudaStreamCreateWithFlags(&s2, cudaStreamNonBlocking);
    cudaEvent_t evFork, evW, evNorm, evKV, evQ, evG6B;
    cudaEventCreateWithFlags(&evFork, cudaEventDisableTiming);
    cudaEventCreateWithFlags(&evW,    cudaEventDisableTiming);
    cudaEventCreateWithFlags(&evNorm, cudaEventDisableTiming);
    cudaEventCreateWithFlags(&evKV,   cudaEventDisableTiming);
    cudaEventCreateWithFlags(&evQ,    cudaEventDisableTiming);
    cudaEventCreateWithFlags(&evG6B,  cudaEventDisableTiming);

    cudaEventRecord(evFork, 0);
    cudaStreamWaitEvent(s2, evFork, 0);
    // s2: weight conversions needed for GEMMs 3/4/6
    cvt_hi<<<2048, 256, 0, s2>>>(w_q_b,  wqb_h,  Q_COLS * Q_LORA / 4, Q_LORA, Q_COLS);
    cvt_hi<<<2048, 256, 0, s2>>>(w_kv_b, wkvb_h, KV_COLS * KV_LORA / 4, KV_LORA, KV_COLS);
    cvt_hi<<<2048, 256, 0, s2>>>(w_o,    wo_h,   HID * O_COLS / 4, O_COLS, HID);
    cudaEventRecord(evW, s2);

    // ---- main stream ----
    cvt_hi<<<4096, 256>>>(w_a, wa_h, A_COLS_P * HID / 4, HID, A_COLS);
    cvt_hi<<<4096, 256>>>(hid, h_hi, S * HID / 4, HID, S);

    // 1) fused-A GEMM (fp32 out)
    mma_gemm<<<dim3(A_COLS_P / 256, S / 128), 256, GSMEM>>>(
        h_hi, wa_h, a, nullptr, pos, A_COLS, A_COLS, HID, 0);

    // 2) RMSNorm + k_pe rope
    rmsnorm_rope_kernel<<<S, 256>>>(a, kpeh, cq_hi, ckv_hi, wq_ln, wkv_ln, pos);
    cudaEventRecord(evNorm, 0);

    // s2: kv GEMM concurrent with q GEMM
    cudaStreamWaitEvent(s2, evNorm, 0);
    mma_gemm<<<dim3(KV_COLS / 256, S / 128), 256, GSMEM, s2>>>(
        ckv_hi, wkvb_h, nullptr, kvh, pos, KV_COLS, KV_COLS, KV_LORA, 1);
    cudaEventRecord(evKV, s2);

    // main: q GEMM (rope + scale fused, fp16 out)
    cudaStreamWaitEvent(0, evW, 0);
    mma_gemm<<<dim3(Q_COLS / 256, S / 128), 256, GSMEM>>>(
        cq_hi, wqb_h, nullptr, qs_hi, pos, Q_COLS, Q_COLS, Q_LORA, 2);
    cudaEventRecord(evQ, 0);

    // main: flashA (heavy: qt 16..31, rows 1024..2047)
    cudaStreamWaitEvent(0, evKV, 0);
    flash_mma<<<dim3(16, H), 128, FSMEM>>>(qs_hi, kvh, kpeh, at_hi, 31);

    // s2: flashB (light: qt 0..15, rows 0..1023) then G6-low overlapping flashA
    cudaStreamWaitEvent(s2, evQ, 0);   // s2 already ordered after its own kv GEMM
    flash_mma<<<dim3(16, H), 128, FSMEM, s2>>>(qs_hi, kvh, kpeh, at_hi, 15);
    mma_gemm<<<dim3(HID / 256, 8), 256, GSMEM, s2>>>(
        at_hi, wo_h, out, nullptr, pos, HID, HID, O_COLS, 0);
    cudaEventRecord(evG6B, s2);

    // main: G6-high (rows 1024..2047) after flashA
    mma_gemm<<<dim3(HID / 256, 8), 256, GSMEM>>>(
        at_hi + (size_t)1024 * O_COLS, wo_h, out + (size_t)1024 * HID, nullptr,
        pos, HID, HID, O_COLS, 0);

    // join s2 back into main before capture end
    cudaStreamWaitEvent(0, evG6B, 0);

    cudaEventDestroy(evFork);
    cudaEventDestroy(evW);
    cudaEventDestroy(evNorm);
    cudaEventDestroy(evKV);
    cudaEventDestroy(evQ);
    cudaEventDestroy(evG6B);
    cudaStreamDestroy(s2);
}

// round 16
// speedup vs baseline: 14.2782x; 1.0036x over previous
#include <cuda_runtime.h>
#include <cuda_fp16.h>
#include <math.h>
#include <stdint.h>

// ---------------- problem constants ----------------
#define S        2048
#define HID      4096
#define H        32
#define Q_LORA   1536
#define KV_LORA  512
#define NOPE     128
#define ROPE     64
#define VDIM     128
#define A_COLS   (Q_LORA + KV_LORA + ROPE)   // 2112
#define A_COLS_P 2304                        // padded to 256-mult
#define QDIM     (NOPE + ROPE)               // 192
#define Q_COLS   (H * QDIM)                  // 6144
#define KV_COLS  (H * 2 * NOPE)              // 8192
#define O_COLS   (H * VDIM)                  // 4096
#define ATT_SCALE 0.07216878364870322992f    // 1/sqrt(192)
#define ROPE_L2  13.287712379549449f         // log2(10000)

// ---------------- scratch ----------------
__device__ __align__(256) __half g_ah[S * A_COLS];   // fused-A out (fp16)

__device__ __align__(256) __half g_h_hi[S * HID];
__device__ __align__(256) __half g_cq_hi[S * Q_LORA];
__device__ __align__(256) __half g_ckv_hi[S * KV_LORA];
__device__ __align__(256) __half g_at_hi[S * O_COLS];
__device__ __align__(256) __half g_qs_hi[S * Q_COLS];
__device__ __align__(256) __half g_kvh[S * KV_COLS];
__device__ __align__(256) __half g_kpeh[S * ROPE];
// weights (fp16, rows padded to 256-mult)
__device__ __align__(256) __half g_wa_h[A_COLS_P * HID];
__device__ __align__(256) __half g_wqb_h[Q_COLS * Q_LORA];
__device__ __align__(256) __half g_wkvb_h[KV_COLS * KV_LORA];
__device__ __align__(256) __half g_wo_h[HID * O_COLS];

// ================= portable PTX helpers =================
__device__ __forceinline__ uint32_t smem_u32(const void* p) {
    uint32_t a;
    asm("{ .reg .u64 t; cvta.to.shared.u64 t, %1; cvt.u32.u64 %0, t; }"
        : "=r"(a) : "l"(p));
    return a;
}
__device__ __forceinline__ void cp16(uint32_t dst, const void* src) {
    asm volatile("cp.async.cg.shared.global [%0], [%1], 16;" :: "r"(dst), "l"(src));
}
#define CP_COMMIT()  asm volatile("cp.async.commit_group;" ::: "memory")
#define CP_WAIT(n)   asm volatile("cp.async.wait_group %0;" :: "n"(n) : "memory")

__device__ __forceinline__ void ldmx4(uint32_t* r, uint32_t addr) {
    asm volatile("ldmatrix.sync.aligned.m8n8.x4.shared.b16 {%0,%1,%2,%3}, [%4];"
                 : "=r"(r[0]), "=r"(r[1]), "=r"(r[2]), "=r"(r[3]) : "r"(addr));
}
__device__ __forceinline__ void ldmx4t(uint32_t* r, uint32_t addr) {
    asm volatile("ldmatrix.sync.aligned.m8n8.x4.trans.shared.b16 {%0,%1,%2,%3}, [%4];"
                 : "=r"(r[0]), "=r"(r[1]), "=r"(r[2]), "=r"(r[3]) : "r"(addr));
}
__device__ __forceinline__ void mma16816(float* c, const uint32_t* a, const uint32_t* b) {
    asm volatile(
        "mma.sync.aligned.m16n8k16.row.col.f32.f16.f16.f32 "
        "{%0,%1,%2,%3},{%4,%5,%6,%7},{%8,%9},{%0,%1,%2,%3};"
        : "+f"(c[0]), "+f"(c[1]), "+f"(c[2]), "+f"(c[3])
        : "r"(a[0]), "r"(a[1]), "r"(a[2]), "r"(a[3]), "r"(b[0]), "r"(b[1]));
}
__device__ __forceinline__ uint32_t packh2(float x, float y) {
    __half2 h = __floats2half2_rn(x, y);
    return *(uint32_t*)&h;
}

// ================= fp32 -> fp16 (rows guarded/padded) =====================
__global__ __launch_bounds__(256) void cvt_hi(
    const float* __restrict__ src, __half* __restrict__ hi,
    int total4, int cols, int rows)
{
    for (int i = blockIdx.x * 256 + threadIdx.x; i < total4; i += gridDim.x * 256) {
        int e = i * 4;
        int r = e / cols;
        float4 f = make_float4(0.f, 0.f, 0.f, 0.f);
        if (r < rows) f = *(const float4*)(src + (size_t)e);
        *(__half2*)(hi + (size_t)e)     = __floats2half2_rn(f.x, f.y);
        *(__half2*)(hi + (size_t)e + 2) = __floats2half2_rn(f.z, f.w);
    }
}

// ================= fp16 HMMA GEMM (1-term) ===============================
// CTA 128x256, warp tile 64x64 (8 warps, 2x4), BK=32, 4-stage cp.async ring.
// B fragments loaded in ldmx4 pairs.
// mode 0: fp32 C.  mode 1: fp16 -> Ch (col<N guard).  mode 2: rope+scale -> Ch.
#define BKC   32
#define ROWB  80
#define ATILE (128 * ROWB)             // 10240
#define BTILE (256 * ROWB)             // 20480
#define STG   (ATILE + BTILE)          // 30720
#define NS    4
#define GSMEM (NS * STG)               // 122880

__device__ __forceinline__ void issue_stage(
    const __half* __restrict__ Ah, const __half* __restrict__ Bh,
    int row0, int col0, int K, int c, uint32_t sbase, int slot, int tid)
{
    uint32_t st = sbase + slot * STG;
    #pragma unroll
    for (int l = 0; l < 2; ++l) {
        int v = tid + l * 256;
        int r = v >> 2;
        int j = v & 3;
        cp16(st + r * ROWB + j * 16,
             Ah + (size_t)(row0 + r) * K + c * BKC + j * 8);
    }
    #pragma unroll
    for (int l = 0; l < 4; ++l) {
        int v = tid + l * 256;
        int r = v >> 2;
        int j = v & 3;
        cp16(st + ATILE + r * ROWB + j * 16,
             Bh + (size_t)(col0 + r) * K + c * BKC + j * 8);
    }
}

__global__ __launch_bounds__(256, 1) void mma_gemm(
    const __half* __restrict__ Ah, const __half* __restrict__ Bh,
    float* __restrict__ C, __half* __restrict__ Ch,
    const int* __restrict__ pos,
    int ldc, int N, int K, int mode)
{
    extern __shared__ char sm[];
    uint32_t sbase = smem_u32(sm);
    const int tid    = threadIdx.x;
    const int lane   = tid & 31;
    const int warp   = tid >> 5;
    const int warp_m = warp >> 2;
    const int warp_n = warp & 3;
    const int row0 = blockIdx.y * 128;
    const int col0 = blockIdx.x * 256;

    float acc[4][8][4];
    #pragma unroll
    for (int mi = 0; mi < 4; ++mi)
        #pragma unroll
        for (int ni = 0; ni < 8; ++ni)
            #pragma unroll
            for (int e = 0; e < 4; ++e) acc[mi][ni][e] = 0.f;

    const int nch = K / BKC;

    #pragma unroll
    for (int p = 0; p < NS - 1; ++p) {
        if (p < nch) issue_stage(Ah, Bh, row0, col0, K, p, sbase, p, tid);
        CP_COMMIT();
    }

    const uint32_t a_l = (uint32_t)((warp_m * 64 + (lane & 15)) * ROWB + (lane >> 4) * 16);
    // paired-B ldmx4: groups (lane>>3): 0,1 -> ni row-block k0/k16; 2,3 -> ni+1
    const uint32_t b4_l = (uint32_t)(ATILE
        + (warp_n * 64 + ((lane >> 4) ? 8 : 0) + (lane & 7)) * ROWB
        + ((lane >> 3) & 1) * 16);

    for (int c = 0; c < nch; ++c) {
        CP_WAIT(NS - 2);
        __syncthreads();
        int np = c + NS - 1;
        if (np < nch)
            issue_stage(Ah, Bh, row0, col0, K, np, sbase, np & (NS - 1), tid);
        CP_COMMIT();

        uint32_t st = sbase + (c & (NS - 1)) * STG;

        #pragma unroll
        for (int ki = 0; ki < 2; ++ki) {
            uint32_t ah[4][4];
            #pragma unroll
            for (int mi = 0; mi < 4; ++mi)
                ldmx4(ah[mi], st + a_l + mi * (16 * ROWB) + ki * 32);
            #pragma unroll
            for (int n2 = 0; n2 < 4; ++n2) {
                uint32_t bq[4];
                ldmx4(bq, st + b4_l + n2 * (16 * ROWB) + ki * 32);
                #pragma unroll
                for (int mi = 0; mi < 4; ++mi) {
                    mma16816(acc[mi][2 * n2],     ah[mi], bq);
                    mma16816(acc[mi][2 * n2 + 1], ah[mi], bq + 2);
                }
            }
        }
    }

    if (mode == 2) {
        int ttype = ((col0 >> 6) + warp_n) % 3;
        if (ttype == 2) {
            #pragma unroll
            for (int mi = 0; mi < 4; ++mi) {
                int r0 = row0 + warp_m * 64 + mi * 16 + (lane >> 2);
                float p0 = (float)pos[r0];
                float p1 = (float)pos[r0 + 8];
                #pragma unroll
                for (int ni = 0; ni < 4; ++ni) {
                    #pragma unroll
                    for (int e = 0; e < 2; ++e) {
                        int i = ni * 8 + (lane & 3) * 2 + e;
                        float f = exp2f(-(float)i * (ROPE_L2 / 32.0f));
                        float c0, s0, c1, s1;
                        __sincosf(p0 * f, &s0, &c0);
                        __sincosf(p1 * f, &s1, &c1);
                        float x1 = acc[mi][ni][e],     x2 = acc[mi][ni + 4][e];
                        acc[mi][ni][e]       = x1 * c0 - x2 * s0;
                        acc[mi][ni + 4][e]   = x2 * c0 + x1 * s0;
                        float y1 = acc[mi][ni][e + 2], y2 = acc[mi][ni + 4][e + 2];
                        acc[mi][ni][e + 2]     = y1 * c1 - y2 * s1;
                        acc[mi][ni + 4][e + 2] = y2 * c1 + y1 * s1;
                    }
                }
            }
        }
        #pragma unroll
        for (int mi = 0; mi < 4; ++mi) {
            int row = row0 + warp_m * 64 + mi * 16 + (lane >> 2);
            #pragma unroll
            for (int ni = 0; ni < 8; ++ni) {
                int col = col0 + warp_n * 64 + ni * 8 + (lane & 3) * 2;
                *(__half2*)&Ch[(size_t)row * ldc + col] =
                    __floats2half2_rn(acc[mi][ni][0] * ATT_SCALE,
                                      acc[mi][ni][1] * ATT_SCALE);
                *(__half2*)&Ch[(size_t)(row + 8) * ldc + col] =
                    __floats2half2_rn(acc[mi][ni][2] * ATT_SCALE,
                                      acc[mi][ni][3] * ATT_SCALE);
            }
        }
    } else if (mode == 1) {
        #pragma unroll
        for (int mi = 0; mi < 4; ++mi) {
            int row = row0 + warp_m * 64 + mi * 16 + (lane >> 2);
            #pragma unroll
            for (int ni = 0; ni < 8; ++ni) {
                int col = col0 + warp_n * 64 + ni * 8 + (lane & 3) * 2;
                if (col < N) {
                    *(__half2*)&Ch[(size_t)row * ldc + col] =
                        __floats2half2_rn(acc[mi][ni][0], acc[mi][ni][1]);
                    *(__half2*)&Ch[(size_t)(row + 8) * ldc + col] =
                        __floats2half2_rn(acc[mi][ni][2], acc[mi][ni][3]);
                }
            }
        }
    } else {
        #pragma unroll
        for (int mi = 0; mi < 4; ++mi) {
            int row = row0 + warp_m * 64 + mi * 16 + (lane >> 2);
            #pragma unroll
            for (int ni = 0; ni < 8; ++ni) {
                int col = col0 + warp_n * 64 + ni * 8 + (lane & 3) * 2;
                if (col < N) {
                    *(float2*)&C[(size_t)row * ldc + col] =
                        make_float2(acc[mi][ni][0], acc[mi][ni][1]);
                    *(float2*)&C[(size_t)(row + 8) * ldc + col] =
                        make_float2(acc[mi][ni][2], acc[mi][ni][3]);
                }
            }
        }
    }
}

// ================= RMSNorm (fp16 in/out) + k_pe RoPE ======================
__global__ __launch_bounds__(256) void rmsnorm_rope_kernel(
    const __half* __restrict__ a,
    __half* __restrict__ kpeh,
    __half* __restrict__ cqh,
    __half* __restrict__ ckvh,
    const float* __restrict__ wq,
    const float* __restrict__ wkv,
    const int* __restrict__ pos_ids)
{
    const int s   = blockIdx.x;
    const int tid = threadIdx.x;
    const __half* row = a + (size_t)s * A_COLS;
    __shared__ float red[8];

    float ss = 0.f;
    for (int i = tid; i < Q_LORA; i += 256) {
        float v = __half2float(row[i]); ss += v * v;
    }
    #pragma unroll
    for (int o = 16; o; o >>= 1) ss += __shfl_xor_sync(0xffffffffu, ss, o);
    if ((tid & 31) == 0) red[tid >> 5] = ss;
    __syncthreads();
    float tot = 0.f;
    #pragma unroll
    for (int w = 0; w < 8; w++) tot += red[w];
    float inv = rsqrtf(tot / (float)Q_LORA + 1e-6f);
    for (int i = tid; i < Q_LORA; i += 256)
        cqh[(size_t)s * Q_LORA + i] =
            __float2half_rn(__half2float(row[i]) * inv * wq[i]);
    __syncthreads();

    const __half* row2 = row + Q_LORA;
    ss = 0.f;
    for (int i = tid; i < KV_LORA; i += 256) {
        float v = __half2float(row2[i]); ss += v * v;
    }
    #pragma unroll
    for (int o = 16; o; o >>= 1) ss += __shfl_xor_sync(0xffffffffu, ss, o);
    if ((tid & 31) == 0) red[tid >> 5] = ss;
    __syncthreads();
    tot = 0.f;
    #pragma unroll
    for (int w = 0; w < 8; w++) tot += red[w];
    inv = rsqrtf(tot / (float)KV_LORA + 1e-6f);
    for (int i = tid; i < KV_LORA; i += 256)
        ckvh[(size_t)s * KV_LORA + i] =
            __float2half_rn(__half2float(row2[i]) * inv * wkv[i]);

    if (tid < 32) {
        int p = pos_ids[s];
        float inv_freq = exp2f(-(float)tid * (ROPE_L2 / 32.0f));
        float ang = (float)p * inv_freq;
        float c, sn;
        __sincosf(ang, &sn, &c);
        float x1 = __half2float(row[Q_LORA + KV_LORA + tid]);
        float x2 = __half2float(row[Q_LORA + KV_LORA + 32 + tid]);
        kpeh[(size_t)s * ROPE + tid]      = __float2half_rn(x1 * c - x2 * sn);
        kpeh[(size_t)s * ROPE + 32 + tid] = __float2half_rn(x2 * c + x1 * sn);
    }
}

// ================= HMMA flash attention =====================
#define QSTR   400
#define VSTR   272
#define SM_QH  0
#define SM_ST0 25600
#define VHOFF  25600
#define STGSZ  43008
#define FSMEM  (SM_ST0 + 2 * STGSZ)     // 111616

__device__ __forceinline__ void issue_kv(
    const __half* __restrict__ KVh, const __half* __restrict__ KPh,
    int n0, int h, uint32_t stg, int tid)
{
    #pragma unroll
    for (int l = 0; l < 12; ++l) {
        int i = tid + l * 128;
        int r = i / 24, j = i % 24;
        uint32_t dst = stg + r * QSTR + j * 16;
        if (j < 16)
            cp16(dst, KVh + (size_t)(n0 + r) * KV_COLS + h * 2 * NOPE + j * 8);
        else
            cp16(dst, KPh + (size_t)(n0 + r) * ROPE + (j - 16) * 8);
    }
    #pragma unroll
    for (int l = 0; l < 8; ++l) {
        int i = tid + l * 128;
        int r = i / 16, j = i % 16;
        cp16(stg + VHOFF + r * VSTR + j * 16,
             KVh + (size_t)(n0 + r) * KV_COLS + h * 2 * NOPE + NOPE + j * 8);
    }
}

__global__ __launch_bounds__(128, 2) void flash_mma(
    const __half* __restrict__ Qh,
    const __half* __restrict__ KVh, const __half* __restrict__ KPh,
    __half* __restrict__ Oh, int qt_hi)
{
    extern __shared__ char sm[];
    uint32_t sb = smem_u32(sm);
    const int qt = qt_hi - (int)blockIdx.x;
    const int h = blockIdx.y;
    const int qm0 = qt * 64;
    const int tid = threadIdx.x, lane = tid & 31, warp = tid >> 5;

    #pragma unroll
    for (int l = 0; l < 12; ++l) {
        int i = tid + l * 128;
        int r = i / 24, j = i % 24;
        cp16(sb + SM_QH + r * QSTR + j * 16,
             Qh + (size_t)(qm0 + r) * Q_COLS + h * QDIM + j * 8);
    }
    issue_kv(KVh, KPh, 0, h, sb + SM_ST0, tid);
    CP_COMMIT();

    float acc[16][4];
    #pragma unroll
    for (int vt = 0; vt < 16; ++vt)
        #pragma unroll
        for (int e = 0; e < 4; ++e) acc[vt][e] = 0.f;
    float miA = -1e30f, miB = -1e30f, liA = 0.f, liB = 0.f;

    const int T = qt + 1;
    const int rA = qm0 + warp * 16 + (lane >> 2);
    uint32_t qf[12][4];

    for (int t = 0; t < T; ++t) {
        if (t + 1 < T) {
            issue_kv(KVh, KPh, (t + 1) * 64, h, sb + SM_ST0 + ((t + 1) & 1) * STGSZ, tid);
            CP_COMMIT();
            CP_WAIT(1);
        } else {
            CP_WAIT(0);
        }
        __syncthreads();
        uint32_t stg = sb + SM_ST0 + (t & 1) * STGSZ;

        if (t == 0) {
            const uint32_t qa = sb + (warp * 16 + (lane & 15)) * QSTR + (lane >> 4) * 16;
            #pragma unroll
            for (int kk = 0; kk < 12; ++kk)
                ldmx4(qf[kk], qa + kk * 32);
        }

        float sc[8][4];
        #pragma unroll
        for (int nt = 0; nt < 8; ++nt)
            #pragma unroll
            for (int e = 0; e < 4; ++e) sc[nt][e] = 0.f;

        #pragma unroll
        for (int kk = 0; kk < 12; ++kk) {
            #pragma unroll
            for (int np = 0; np < 4; ++np) {
                uint32_t bH[4];
                uint32_t ba = stg + ((np * 2 + (lane >> 4)) * 8 + (lane & 7)) * QSTR
                              + ((lane >> 3) & 1) * 16 + kk * 32;
                ldmx4(bH, ba);
                mma16816(sc[np * 2],     qf[kk], bH);
                mma16816(sc[np * 2 + 1], qf[kk], bH + 2);
            }
        }

        if (t == T - 1) {
            #pragma unroll
            for (int nt = 0; nt < 8; ++nt) {
                int c0 = qm0 + nt * 8 + (lane & 3) * 2;
                if (c0     > rA)     sc[nt][0] = -1e30f;
                if (c0 + 1 > rA)     sc[nt][1] = -1e30f;
                if (c0     > rA + 8) sc[nt][2] = -1e30f;
                if (c0 + 1 > rA + 8) sc[nt][3] = -1e30f;
            }
        }

        float mA = -1e30f, mB = -1e30f;
        #pragma unroll
        for (int nt = 0; nt < 8; ++nt) {
            mA = fmaxf(mA, fmaxf(sc[nt][0], sc[nt][1]));
            mB = fmaxf(mB, fmaxf(sc[nt][2], sc[nt][3]));
        }
        mA = fmaxf(mA, __shfl_xor_sync(0xffffffffu, mA, 1));
        mA = fmaxf(mA, __shfl_xor_sync(0xffffffffu, mA, 2));
        mB = fmaxf(mB, __shfl_xor_sync(0xffffffffu, mB, 1));
        mB = fmaxf(mB, __shfl_xor_sync(0xffffffffu, mB, 2));
        float nmA = fmaxf(miA, mA), nmB = fmaxf(miB, mB);
        float cA = __expf(miA - nmA), cB = __expf(miB - nmB);
        miA = nmA; miB = nmB;

        float sA = 0.f, sB = 0.f;
        #pragma unroll
        for (int nt = 0; nt < 8; ++nt) {
            sc[nt][0] = __expf(sc[nt][0] - nmA); sA += sc[nt][0];
            sc[nt][1] = __expf(sc[nt][1] - nmA); sA += sc[nt][1];
            sc[nt][2] = __expf(sc[nt][2] - nmB); sB += sc[nt][2];
            sc[nt][3] = __expf(sc[nt][3] - nmB); sB += sc[nt][3];
        }
        sA += __shfl_xor_sync(0xffffffffu, sA, 1);
        sA += __shfl_xor_sync(0xffffffffu, sA, 2);
        sB += __shfl_xor_sync(0xffffffffu, sB, 1);
        sB += __shfl_xor_sync(0xffffffffu, sB, 2);
        liA = liA * cA + sA;
        liB = liB * cB + sB;
        #pragma unroll
        for (int vt = 0; vt < 16; ++vt) {
            acc[vt][0] *= cA; acc[vt][1] *= cA;
            acc[vt][2] *= cB; acc[vt][3] *= cB;
        }

        #pragma unroll
        for (int kp = 0; kp < 4; ++kp) {
            uint32_t aH[4];
            #pragma unroll
            for (int q2 = 0; q2 < 2; ++q2) {
                const float* s0 = sc[2 * kp + q2];
                aH[q2 * 2 + 0] = packh2(s0[0], s0[1]);
                aH[q2 * 2 + 1] = packh2(s0[2], s0[3]);
            }
            #pragma unroll
            for (int vp = 0; vp < 8; ++vp) {
                uint32_t bH[4];
                uint32_t va = stg + VHOFF + (kp * 16 + (lane & 15)) * VSTR
                              + (vp * 2 + (lane >> 4)) * 16;
                ldmx4t(bH, va);
                mma16816(acc[vp * 2],     aH, bH);
                mma16816(acc[vp * 2 + 1], aH, bH + 2);
            }
        }
        __syncthreads();
    }

    float rlA = 1.f / liA, rlB = 1.f / liB;
    #pragma unroll
    for (int vt = 0; vt < 16; ++vt) {
        int col = h * VDIM + vt * 8 + (lane & 3) * 2;
        *(__half2*)&Oh[(size_t)rA * O_COLS + col] =
            __floats2half2_rn(acc[vt][0] * rlA, acc[vt][1] * rlA);
        *(__half2*)&Oh[(size_t)(rA + 8) * O_COLS + col] =
            __floats2half2_rn(acc[vt][2] * rlB, acc[vt][3] * rlB);
    }
}

// ================= launch =================
extern "C" void kernel_launch(void* const* d_in, const int* in_sizes, int n_in,
                              void* d_out, int out_size)
{
    const int*   pos   = (const int*)  d_in[0];
    const float* hid   = (const float*)d_in[1];
    const float* w_a   = (const float*)d_in[2];
    const float* wq_ln = (const float*)d_in[3];
    const float* wkv_ln= (const float*)d_in[4];
    const float* w_q_b = (const float*)d_in[5];
    const float* w_kv_b= (const float*)d_in[6];
    const float* w_o   = (const float*)d_in[7];
    float* out = (float*)d_out;

    __half *ah, *h_hi, *cq_hi, *ckv_hi, *at_hi;
    __half *qs_hi, *kvh, *kpeh, *wa_h, *wqb_h, *wkvb_h, *wo_h;
    cudaGetSymbolAddress((void**)&ah,     g_ah);
    cudaGetSymbolAddress((void**)&h_hi,   g_h_hi);
    cudaGetSymbolAddress((void**)&cq_hi,  g_cq_hi);
    cudaGetSymbolAddress((void**)&ckv_hi, g_ckv_hi);
    cudaGetSymbolAddress((void**)&at_hi,  g_at_hi);
    cudaGetSymbolAddress((void**)&qs_hi,  g_qs_hi);
    cudaGetSymbolAddress((void**)&kvh,    g_kvh);    cudaGetSymbolAddress((void**)&kpeh,   g_kpeh);
    cudaGetSymbolAddress((void**)&wa_h,   g_wa_h);   cudaGetSymbolAddress((void**)&wqb_h,  g_wqb_h);
    cudaGetSymbolAddress((void**)&wkvb_h, g_wkvb_h); cudaGetSymbolAddress((void**)&wo_h,   g_wo_h);

    cudaFuncSetAttribute(mma_gemm, cudaFuncAttributeMaxDynamicSharedMemorySize, GSMEM);
    cudaFuncSetAttribute(flash_mma, cudaFuncAttributeMaxDynamicSharedMemorySize, FSMEM);

    // ---- side stream s2 ----
    cudaStream_t s2;
    cudaStreamCreateWithFlags(&s2, cudaStreamNonBlocking);
    cudaEvent_t evFork, evW, evNorm, evKV, evQ, evG6B;
    cudaEventCreateWithFlags(&evFork, cudaEventDisableTiming);
    cudaEventCreateWithFlags(&evW,    cudaEventDisableTiming);
    cudaEventCreateWithFlags(&evNorm, cudaEventDisableTiming);
    cudaEventCreateWithFlags(&evKV,   cudaEventDisableTiming);
    cudaEventCreateWithFlags(&evQ,    cudaEventDisableTiming);
    cudaEventCreateWithFlags(&evG6B,  cudaEventDisableTiming);

    cudaEventRecord(evFork, 0);
    cudaStreamWaitEvent(s2, evFork, 0);
    cvt_hi<<<2048, 256, 0, s2>>>(w_q_b,  wqb_h,  Q_COLS * Q_LORA / 4, Q_LORA, Q_COLS);
    cvt_hi<<<2048, 256, 0, s2>>>(w_kv_b, wkvb_h, KV_COLS * KV_LORA / 4, KV_LORA, KV_COLS);
    cvt_hi<<<2048, 256, 0, s2>>>(w_o,    wo_h,   HID * O_COLS / 4, O_COLS, HID);
    cudaEventRecord(evW, s2);

    // ---- main stream ----
    cvt_hi<<<4096, 256>>>(w_a, wa_h, A_COLS_P * HID / 4, HID, A_COLS);
    cvt_hi<<<4096, 256>>>(hid, h_hi, S * HID / 4, HID, S);

    // 1) fused-A GEMM (fp16 out, guarded)
    mma_gemm<<<dim3(A_COLS_P / 256, S / 128), 256, GSMEM>>>(
        h_hi, wa_h, nullptr, ah, pos, A_COLS, A_COLS, HID, 1);

    // 2) RMSNorm + k_pe rope (fp16 input)
    rmsnorm_rope_kernel<<<S, 256>>>(ah, kpeh, cq_hi, ckv_hi, wq_ln, wkv_ln, pos);
    cudaEventRecord(evNorm, 0);

    // s2: kv GEMM concurrent with q GEMM
    cudaStreamWaitEvent(s2, evNorm, 0);
    mma_gemm<<<dim3(KV_COLS / 256, S / 128), 256, GSMEM, s2>>>(
        ckv_hi, wkvb_h, nullptr, kvh, pos, KV_COLS, KV_COLS, KV_LORA, 1);
    cudaEventRecord(evKV, s2);

    // main: q GEMM (rope + scale fused, fp16 out)
    cudaStreamWaitEvent(0, evW, 0);
    mma_gemm<<<dim3(Q_COLS / 256, S / 128), 256, GSMEM>>>(
        cq_hi, wqb_h, nullptr, qs_hi, pos, Q_COLS, Q_COLS, Q_LORA, 2);
    cudaEventRecord(evQ, 0);

    // main: flashA (heavy: qt 16..31)
    cudaStreamWaitEvent(0, evKV, 0);
    flash_mma<<<dim3(16, H), 128, FSMEM>>>(qs_hi, kvh, kpeh, at_hi, 31);

    // s2: flashB (light: qt 0..15) then G6-low
    cudaStreamWaitEvent(s2, evQ, 0);
    flash_mma<<<dim3(16, H), 128, FSMEM, s2>>>(qs_hi, kvh, kpeh, at_hi, 15);
    mma_gemm<<<dim3(HID / 256, 8), 256, GSMEM, s2>>>(
        at_hi, wo_h, out, nullptr, pos, HID, HID, O_COLS, 0);
    cudaEventRecord(evG6B, s2);

    // main: G6-high after flashA
    mma_gemm<<<dim3(HID / 256, 8), 256, GSMEM>>>(
        at_hi + (size_t)1024 * O_COLS, wo_h, out + (size_t)1024 * HID, nullptr,
        pos, HID, HID, O_COLS, 0);

    cudaStreamWaitEvent(0, evG6B, 0);

    cudaEventDestroy(evFork);
    cudaEventDestroy(evW);
    cudaEventDestroy(evNorm);
    cudaEventDestroy(evKV);
    cudaEventDestroy(evQ);
    cudaEventDestroy(evG6B);
    cudaStreamDestroy(s2);
}

// round 17
// speedup vs baseline: 14.4799x; 1.0141x over previous
#include <cuda_runtime.h>
#include <cuda_fp16.h>
#include <math.h>
#include <stdint.h>

// ---------------- problem constants ----------------
#define S        2048
#define HID      4096
#define H        32
#define Q_LORA   1536
#define KV_LORA  512
#define NOPE     128
#define ROPE     64
#define VDIM     128
#define A_COLS   (Q_LORA + KV_LORA + ROPE)   // 2112
#define A_COLS_P 2304                        // padded to 256-mult
#define QDIM     (NOPE + ROPE)               // 192
#define Q_COLS   (H * QDIM)                  // 6144
#define KV_COLS  (H * 2 * NOPE)              // 8192
#define O_COLS   (H * VDIM)                  // 4096
#define ATT_SCALE 0.07216878364870322992f    // 1/sqrt(192)
#define ROPE_L2  13.287712379549449f         // log2(10000)

// ---------------- scratch ----------------
__device__ __align__(256) __half g_ah[S * A_COLS];   // fused-A out (fp16)
__device__ __align__(256) float  g_invq[S];
__device__ __align__(256) float  g_invkv[S];

__device__ __align__(256) __half g_h_hi[S * HID];
__device__ __align__(256) __half g_at_hi[S * O_COLS];
__device__ __align__(256) __half g_qs_hi[S * Q_COLS];
__device__ __align__(256) __half g_kvh[S * KV_COLS];
__device__ __align__(256) __half g_kpeh[S * ROPE];
// weights (fp16, rows padded to 256-mult; wqb/wkvb have ln-weight folded in)
__device__ __align__(256) __half g_wa_h[A_COLS_P * HID];
__device__ __align__(256) __half g_wqb_h[Q_COLS * Q_LORA];
__device__ __align__(256) __half g_wkvb_h[KV_COLS * KV_LORA];
__device__ __align__(256) __half g_wo_h[HID * O_COLS];

// ================= portable PTX helpers =================
__device__ __forceinline__ uint32_t smem_u32(const void* p) {
    uint32_t a;
    asm("{ .reg .u64 t; cvta.to.shared.u64 t, %1; cvt.u32.u64 %0, t; }"
        : "=r"(a) : "l"(p));
    return a;
}
__device__ __forceinline__ void cp16(uint32_t dst, const void* src) {
    asm volatile("cp.async.cg.shared.global [%0], [%1], 16;" :: "r"(dst), "l"(src));
}
#define CP_COMMIT()  asm volatile("cp.async.commit_group;" ::: "memory")
#define CP_WAIT(n)   asm volatile("cp.async.wait_group %0;" :: "n"(n) : "memory")

__device__ __forceinline__ void ldmx4(uint32_t* r, uint32_t addr) {
    asm volatile("ldmatrix.sync.aligned.m8n8.x4.shared.b16 {%0,%1,%2,%3}, [%4];"
                 : "=r"(r[0]), "=r"(r[1]), "=r"(r[2]), "=r"(r[3]) : "r"(addr));
}
__device__ __forceinline__ void ldmx4t(uint32_t* r, uint32_t addr) {
    asm volatile("ldmatrix.sync.aligned.m8n8.x4.trans.shared.b16 {%0,%1,%2,%3}, [%4];"
                 : "=r"(r[0]), "=r"(r[1]), "=r"(r[2]), "=r"(r[3]) : "r"(addr));
}
__device__ __forceinline__ void mma16816(float* c, const uint32_t* a, const uint32_t* b) {
    asm volatile(
        "mma.sync.aligned.m16n8k16.row.col.f32.f16.f16.f32 "
        "{%0,%1,%2,%3},{%4,%5,%6,%7},{%8,%9},{%0,%1,%2,%3};"
        : "+f"(c[0]), "+f"(c[1]), "+f"(c[2]), "+f"(c[3])
        : "r"(a[0]), "r"(a[1]), "r"(a[2]), "r"(a[3]), "r"(b[0]), "r"(b[1]));
}
__device__ __forceinline__ uint32_t packh2(float x, float y) {
    __half2 h = __floats2half2_rn(x, y);
    return *(uint32_t*)&h;
}

// ====== fp32 -> fp16 (rows guarded/padded, optional per-col ln weight) ====
__global__ __launch_bounds__(256) void cvt_hi(
    const float* __restrict__ src, __half* __restrict__ hi,
    int total4, int cols, int rows, const float* __restrict__ lnw)
{
    for (int i = blockIdx.x * 256 + threadIdx.x; i < total4; i += gridDim.x * 256) {
        int e = i * 4;
        int r = e / cols;
        float4 f = make_float4(0.f, 0.f, 0.f, 0.f);
        if (r < rows) f = *(const float4*)(src + (size_t)e);
        if (lnw) {
            int c0 = e - r * cols;
            f.x *= lnw[c0]; f.y *= lnw[c0 + 1];
            f.z *= lnw[c0 + 2]; f.w *= lnw[c0 + 3];
        }
        *(__half2*)(hi + (size_t)e)     = __floats2half2_rn(f.x, f.y);
        *(__half2*)(hi + (size_t)e + 2) = __floats2half2_rn(f.z, f.w);
    }
}

// ================= fp16 HMMA GEMM (1-term, strided A) ====================
// CTA 128x256, warp tile 64x64 (8 warps, 2x4), BK=32, 4-stage cp.async ring.
// mode 0: fp32 C.  mode 1: fp16 -> Ch (col<N guard).  mode 2: rope+scale -> Ch.
// rowscale (optional): per-row multiplier applied before conversion.
#define BKC   32
#define ROWB  80
#define ATILE (128 * ROWB)             // 10240
#define BTILE (256 * ROWB)             // 20480
#define STG   (ATILE + BTILE)          // 30720
#define NS    4
#define GSMEM (NS * STG)               // 122880

__device__ __forceinline__ void issue_stage(
    const __half* __restrict__ Ah, int lda, const __half* __restrict__ Bh,
    int row0, int col0, int K, int c, uint32_t sbase, int slot, int tid)
{
    uint32_t st = sbase + slot * STG;
    #pragma unroll
    for (int l = 0; l < 2; ++l) {
        int v = tid + l * 256;
        int r = v >> 2;
        int j = v & 3;
        cp16(st + r * ROWB + j * 16,
             Ah + (size_t)(row0 + r) * lda + c * BKC + j * 8);
    }
    #pragma unroll
    for (int l = 0; l < 4; ++l) {
        int v = tid + l * 256;
        int r = v >> 2;
        int j = v & 3;
        cp16(st + ATILE + r * ROWB + j * 16,
             Bh + (size_t)(col0 + r) * K + c * BKC + j * 8);
    }
}

__global__ __launch_bounds__(256, 1) void mma_gemm(
    const __half* __restrict__ Ah, int lda, const __half* __restrict__ Bh,
    float* __restrict__ C, __half* __restrict__ Ch,
    const int* __restrict__ pos, const float* __restrict__ rowscale,
    int ldc, int N, int K, int mode)
{
    extern __shared__ char sm[];
    uint32_t sbase = smem_u32(sm);
    const int tid    = threadIdx.x;
    const int lane   = tid & 31;
    const int warp   = tid >> 5;
    const int warp_m = warp >> 2;
    const int warp_n = warp & 3;
    const int row0 = blockIdx.y * 128;
    const int col0 = blockIdx.x * 256;

    float acc[4][8][4];
    #pragma unroll
    for (int mi = 0; mi < 4; ++mi)
        #pragma unroll
        for (int ni = 0; ni < 8; ++ni)
            #pragma unroll
            for (int e = 0; e < 4; ++e) acc[mi][ni][e] = 0.f;

    const int nch = K / BKC;

    #pragma unroll
    for (int p = 0; p < NS - 1; ++p) {
        if (p < nch) issue_stage(Ah, lda, Bh, row0, col0, K, p, sbase, p, tid);
        CP_COMMIT();
    }

    const uint32_t a_l = (uint32_t)((warp_m * 64 + (lane & 15)) * ROWB + (lane >> 4) * 16);
    const uint32_t b4_l = (uint32_t)(ATILE
        + (warp_n * 64 + ((lane >> 4) ? 8 : 0) + (lane & 7)) * ROWB
        + ((lane >> 3) & 1) * 16);

    for (int c = 0; c < nch; ++c) {
        CP_WAIT(NS - 2);
        __syncthreads();
        int np = c + NS - 1;
        if (np < nch)
            issue_stage(Ah, lda, Bh, row0, col0, K, np, sbase, np & (NS - 1), tid);
        CP_COMMIT();

        uint32_t st = sbase + (c & (NS - 1)) * STG;

        #pragma unroll
        for (int ki = 0; ki < 2; ++ki) {
            uint32_t ah[4][4];
            #pragma unroll
            for (int mi = 0; mi < 4; ++mi)
                ldmx4(ah[mi], st + a_l + mi * (16 * ROWB) + ki * 32);
            #pragma unroll
            for (int n2 = 0; n2 < 4; ++n2) {
                uint32_t bq[4];
                ldmx4(bq, st + b4_l + n2 * (16 * ROWB) + ki * 32);
                #pragma unroll
                for (int mi = 0; mi < 4; ++mi) {
                    mma16816(acc[mi][2 * n2],     ah[mi], bq);
                    mma16816(acc[mi][2 * n2 + 1], ah[mi], bq + 2);
                }
            }
        }
    }

    if (mode == 2) {
        int ttype = ((col0 >> 6) + warp_n) % 3;
        if (ttype == 2) {
            #pragma unroll
            for (int mi = 0; mi < 4; ++mi) {
                int r0 = row0 + warp_m * 64 + mi * 16 + (lane >> 2);
                float p0 = (float)pos[r0];
                float p1 = (float)pos[r0 + 8];
                #pragma unroll
                for (int ni = 0; ni < 4; ++ni) {
                    #pragma unroll
                    for (int e = 0; e < 2; ++e) {
                        int i = ni * 8 + (lane & 3) * 2 + e;
                        float f = exp2f(-(float)i * (ROPE_L2 / 32.0f));
                        float c0, s0, c1, s1;
                        __sincosf(p0 * f, &s0, &c0);
                        __sincosf(p1 * f, &s1, &c1);
                        float x1 = acc[mi][ni][e],     x2 = acc[mi][ni + 4][e];
                        acc[mi][ni][e]       = x1 * c0 - x2 * s0;
                        acc[mi][ni + 4][e]   = x2 * c0 + x1 * s0;
                        float y1 = acc[mi][ni][e + 2], y2 = acc[mi][ni + 4][e + 2];
                        acc[mi][ni][e + 2]     = y1 * c1 - y2 * s1;
                        acc[mi][ni + 4][e + 2] = y2 * c1 + y1 * s1;
                    }
                }
            }
        }
        #pragma unroll
        for (int mi = 0; mi < 4; ++mi) {
            int row = row0 + warp_m * 64 + mi * 16 + (lane >> 2);
            float s0 = rowscale[row]     * ATT_SCALE;
            float s1 = rowscale[row + 8] * ATT_SCALE;
            #pragma unroll
            for (int ni = 0; ni < 8; ++ni) {
                int col = col0 + warp_n * 64 + ni * 8 + (lane & 3) * 2;
                *(__half2*)&Ch[(size_t)row * ldc + col] =
                    __floats2half2_rn(acc[mi][ni][0] * s0, acc[mi][ni][1] * s0);
                *(__half2*)&Ch[(size_t)(row + 8) * ldc + col] =
                    __floats2half2_rn(acc[mi][ni][2] * s1, acc[mi][ni][3] * s1);
            }
        }
    } else if (mode == 1) {
        #pragma unroll
        for (int mi = 0; mi < 4; ++mi) {
            int row = row0 + warp_m * 64 + mi * 16 + (lane >> 2);
            float s0 = rowscale ? rowscale[row]     : 1.f;
            float s1 = rowscale ? rowscale[row + 8] : 1.f;
            #pragma unroll
            for (int ni = 0; ni < 8; ++ni) {
                int col = col0 + warp_n * 64 + ni * 8 + (lane & 3) * 2;
                if (col < N) {
                    *(__half2*)&Ch[(size_t)row * ldc + col] =
                        __floats2half2_rn(acc[mi][ni][0] * s0, acc[mi][ni][1] * s0);
                    *(__half2*)&Ch[(size_t)(row + 8) * ldc + col] =
                        __floats2half2_rn(acc[mi][ni][2] * s1, acc[mi][ni][3] * s1);
                }
            }
        }
    } else {
        #pragma unroll
        for (int mi = 0; mi < 4; ++mi) {
            int row = row0 + warp_m * 64 + mi * 16 + (lane >> 2);
            #pragma unroll
            for (int ni = 0; ni < 8; ++ni) {
                int col = col0 + warp_n * 64 + ni * 8 + (lane & 3) * 2;
                if (col < N) {
                    *(float2*)&C[(size_t)row * ldc + col] =
                        make_float2(acc[mi][ni][0], acc[mi][ni][1]);
                    *(float2*)&C[(size_t)(row + 8) * ldc + col] =
                        make_float2(acc[mi][ni][2], acc[mi][ni][3]);
                }
            }
        }
    }
}

// ====== per-row rms inverse scales + k_pe RoPE (reads fp16 a) =============
__global__ __launch_bounds__(256) void rms_inv_kernel(
    const __half* __restrict__ a,
    float* __restrict__ invq, float* __restrict__ invkv,
    __half* __restrict__ kpeh,
    const int* __restrict__ pos_ids)
{
    const int s   = blockIdx.x;
    const int tid = threadIdx.x;
    const __half* row = a + (size_t)s * A_COLS;
    __shared__ float red[8];

    float ss = 0.f;
    for (int i = tid; i < Q_LORA; i += 256) {
        float v = __half2float(row[i]); ss += v * v;
    }
    #pragma unroll
    for (int o = 16; o; o >>= 1) ss += __shfl_xor_sync(0xffffffffu, ss, o);
    if ((tid & 31) == 0) red[tid >> 5] = ss;
    __syncthreads();
    if (tid == 0) {
        float tot = 0.f;
        #pragma unroll
        for (int w = 0; w < 8; w++) tot += red[w];
        invq[s] = rsqrtf(tot / (float)Q_LORA + 1e-6f);
    }
    __syncthreads();

    const __half* row2 = row + Q_LORA;
    ss = 0.f;
    for (int i = tid; i < KV_LORA; i += 256) {
        float v = __half2float(row2[i]); ss += v * v;
    }
    #pragma unroll
    for (int o = 16; o; o >>= 1) ss += __shfl_xor_sync(0xffffffffu, ss, o);
    if ((tid & 31) == 0) red[tid >> 5] = ss;
    __syncthreads();
    if (tid == 0) {
        float tot = 0.f;
        #pragma unroll
        for (int w = 0; w < 8; w++) tot += red[w];
        invkv[s] = rsqrtf(tot / (float)KV_LORA + 1e-6f);
    }

    if (tid < 32) {
        int p = pos_ids[s];
        float inv_freq = exp2f(-(float)tid * (ROPE_L2 / 32.0f));
        float ang = (float)p * inv_freq;
        float c, sn;
        __sincosf(ang, &sn, &c);
        float x1 = __half2float(row[Q_LORA + KV_LORA + tid]);
        float x2 = __half2float(row[Q_LORA + KV_LORA + 32 + tid]);
        kpeh[(size_t)s * ROPE + tid]      = __float2half_rn(x1 * c - x2 * sn);
        kpeh[(size_t)s * ROPE + 32 + tid] = __float2half_rn(x2 * c + x1 * sn);
    }
}

// ================= HMMA flash attention =====================
#define QSTR   400
#define VSTR   272
#define SM_QH  0
#define SM_ST0 25600
#define VHOFF  25600
#define STGSZ  43008
#define FSMEM  (SM_ST0 + 2 * STGSZ)     // 111616

__device__ __forceinline__ void issue_kv(
    const __half* __restrict__ KVh, const __half* __restrict__ KPh,
    int n0, int h, uint32_t stg, int tid)
{
    #pragma unroll
    for (int l = 0; l < 12; ++l) {
        int i = tid + l * 128;
        int r = i / 24, j = i % 24;
        uint32_t dst = stg + r * QSTR + j * 16;
        if (j < 16)
            cp16(dst, KVh + (size_t)(n0 + r) * KV_COLS + h * 2 * NOPE + j * 8);
        else
            cp16(dst, KPh + (size_t)(n0 + r) * ROPE + (j - 16) * 8);
    }
    #pragma unroll
    for (int l = 0; l < 8; ++l) {
        int i = tid + l * 128;
        int r = i / 16, j = i % 16;
        cp16(stg + VHOFF + r * VSTR + j * 16,
             KVh + (size_t)(n0 + r) * KV_COLS + h * 2 * NOPE + NOPE + j * 8);
    }
}

__global__ __launch_bounds__(128, 2) void flash_mma(
    const __half* __restrict__ Qh,
    const __half* __restrict__ KVh, const __half* __restrict__ KPh,
    __half* __restrict__ Oh, int qt_hi)
{
    extern __shared__ char sm[];
    uint32_t sb = smem_u32(sm);
    const int qt = qt_hi - (int)blockIdx.x;
    const int h = blockIdx.y;
    const int qm0 = qt * 64;
    const int tid = threadIdx.x, lane = tid & 31, warp = tid >> 5;

    #pragma unroll
    for (int l = 0; l < 12; ++l) {
        int i = tid + l * 128;
        int r = i / 24, j = i % 24;
        cp16(sb + SM_QH + r * QSTR + j * 16,
             Qh + (size_t)(qm0 + r) * Q_COLS + h * QDIM + j * 8);
    }
    issue_kv(KVh, KPh, 0, h, sb + SM_ST0, tid);
    CP_COMMIT();

    float acc[16][4];
    #pragma unroll
    for (int vt = 0; vt < 16; ++vt)
        #pragma unroll
        for (int e = 0; e < 4; ++e) acc[vt][e] = 0.f;
    float miA = -1e30f, miB = -1e30f, liA = 0.f, liB = 0.f;

    const int T = qt + 1;
    const int rA = qm0 + warp * 16 + (lane >> 2);
    uint32_t qf[12][4];

    for (int t = 0; t < T; ++t) {
        if (t + 1 < T) {
            issue_kv(KVh, KPh, (t + 1) * 64, h, sb + SM_ST0 + ((t + 1) & 1) * STGSZ, tid);
            CP_COMMIT();
            CP_WAIT(1);
        } else {
            CP_WAIT(0);
        }
        __syncthreads();
        uint32_t stg = sb + SM_ST0 + (t & 1) * STGSZ;

        if (t == 0) {
            const uint32_t qa = sb + (warp * 16 + (lane & 15)) * QSTR + (lane >> 4) * 16;
            #pragma unroll
            for (int kk = 0; kk < 12; ++kk)
                ldmx4(qf[kk], qa + kk * 32);
        }

        float sc[8][4];
        #pragma unroll
        for (int nt = 0; nt < 8; ++nt)
            #pragma unroll
            for (int e = 0; e < 4; ++e) sc[nt][e] = 0.f;

        #pragma unroll
        for (int kk = 0; kk < 12; ++kk) {
            #pragma unroll
            for (int np = 0; np < 4; ++np) {
                uint32_t bH[4];
                uint32_t ba = stg + ((np * 2 + (lane >> 4)) * 8 + (lane & 7)) * QSTR
                              + ((lane >> 3) & 1) * 16 + kk * 32;
                ldmx4(bH, ba);
                mma16816(sc[np * 2],     qf[kk], bH);
                mma16816(sc[np * 2 + 1], qf[kk], bH + 2);
            }
        }

        if (t == T - 1) {
            #pragma unroll
            for (int nt = 0; nt < 8; ++nt) {
                int c0 = qm0 + nt * 8 + (lane & 3) * 2;
                if (c0     > rA)     sc[nt][0] = -1e30f;
                if (c0 + 1 > rA)     sc[nt][1] = -1e30f;
                if (c0     > rA + 8) sc[nt][2] = -1e30f;
                if (c0 + 1 > rA + 8) sc[nt][3] = -1e30f;
            }
        }

        float mA = -1e30f, mB = -1e30f;
        #pragma unroll
        for (int nt = 0; nt < 8; ++nt) {
            mA = fmaxf(mA, fmaxf(sc[nt][0], sc[nt][1]));
            mB = fmaxf(mB, fmaxf(sc[nt][2], sc[nt][3]));
        }
        mA = fmaxf(mA, __shfl_xor_sync(0xffffffffu, mA, 1));
        mA = fmaxf(mA, __shfl_xor_sync(0xffffffffu, mA, 2));
        mB = fmaxf(mB, __shfl_xor_sync(0xffffffffu, mB, 1));
        mB = fmaxf(mB, __shfl_xor_sync(0xffffffffu, mB, 2));
        float nmA = fmaxf(miA, mA), nmB = fmaxf(miB, mB);
        float cA = __expf(miA - nmA), cB = __expf(miB - nmB);
        miA = nmA; miB = nmB;

        float sA = 0.f, sB = 0.f;
        #pragma unroll
        for (int nt = 0; nt < 8; ++nt) {
            sc[nt][0] = __expf(sc[nt][0] - nmA); sA += sc[nt][0];
            sc[nt][1] = __expf(sc[nt][1] - nmA); sA += sc[nt][1];
            sc[nt][2] = __expf(sc[nt][2] - nmB); sB += sc[nt][2];
            sc[nt][3] = __expf(sc[nt][3] - nmB); sB += sc[nt][3];
        }
        sA += __shfl_xor_sync(0xffffffffu, sA, 1);
        sA += __shfl_xor_sync(0xffffffffu, sA, 2);
        sB += __shfl_xor_sync(0xffffffffu, sB, 1);
        sB += __shfl_xor_sync(0xffffffffu, sB, 2);
        liA = liA * cA + sA;
        liB = liB * cB + sB;
        #pragma unroll
        for (int vt = 0; vt < 16; ++vt) {
            acc[vt][0] *= cA; acc[vt][1] *= cA;
            acc[vt][2] *= cB; acc[vt][3] *= cB;
        }

        #pragma unroll
        for (int kp = 0; kp < 4; ++kp) {
            uint32_t aH[4];
            #pragma unroll
            for (int q2 = 0; q2 < 2; ++q2) {
                const float* s0 = sc[2 * kp + q2];
                aH[q2 * 2 + 0] = packh2(s0[0], s0[1]);
                aH[q2 * 2 + 1] = packh2(s0[2], s0[3]);
            }
            #pragma unroll
            for (int vp = 0; vp < 8; ++vp) {
                uint32_t bH[4];
                uint32_t va = stg + VHOFF + (kp * 16 + (lane & 15)) * VSTR
                              + (vp * 2 + (lane >> 4)) * 16;
                ldmx4t(bH, va);
                mma16816(acc[vp * 2],     aH, bH);
                mma16816(acc[vp * 2 + 1], aH, bH + 2);
            }
        }
        __syncthreads();
    }

    float rlA = 1.f / liA, rlB = 1.f / liB;
    #pragma unroll
    for (int vt = 0; vt < 16; ++vt) {
        int col = h * VDIM + vt * 8 + (lane & 3) * 2;
        *(__half2*)&Oh[(size_t)rA * O_COLS + col] =
            __floats2half2_rn(acc[vt][0] * rlA, acc[vt][1] * rlA);
        *(__half2*)&Oh[(size_t)(rA + 8) * O_COLS + col] =
            __floats2half2_rn(acc[vt][2] * rlB, acc[vt][3] * rlB);
    }
}

// ================= launch =================
extern "C" void kernel_launch(void* const* d_in, const int* in_sizes, int n_in,
                              void* d_out, int out_size)
{
    const int*   pos   = (const int*)  d_in[0];
    const float* hid   = (const float*)d_in[1];
    const float* w_a   = (const float*)d_in[2];
    const float* wq_ln = (const float*)d_in[3];
    const float* wkv_ln= (const float*)d_in[4];
    const float* w_q_b = (const float*)d_in[5];
    const float* w_kv_b= (const float*)d_in[6];
    const float* w_o   = (const float*)d_in[7];
    float* out = (float*)d_out;

    __half *ah, *h_hi, *at_hi;
    __half *qs_hi, *kvh, *kpeh, *wa_h, *wqb_h, *wkvb_h, *wo_h;
    float *invq, *invkv;
    cudaGetSymbolAddress((void**)&ah,     g_ah);
    cudaGetSymbolAddress((void**)&invq,   g_invq);
    cudaGetSymbolAddress((void**)&invkv,  g_invkv);
    cudaGetSymbolAddress((void**)&h_hi,   g_h_hi);
    cudaGetSymbolAddress((void**)&at_hi,  g_at_hi);
    cudaGetSymbolAddress((void**)&qs_hi,  g_qs_hi);
    cudaGetSymbolAddress((void**)&kvh,    g_kvh);    cudaGetSymbolAddress((void**)&kpeh,   g_kpeh);
    cudaGetSymbolAddress((void**)&wa_h,   g_wa_h);   cudaGetSymbolAddress((void**)&wqb_h,  g_wqb_h);
    cudaGetSymbolAddress((void**)&wkvb_h, g_wkvb_h); cudaGetSymbolAddress((void**)&wo_h,   g_wo_h);

    cudaFuncSetAttribute(mma_gemm, cudaFuncAttributeMaxDynamicSharedMemorySize, GSMEM);
    cudaFuncSetAttribute(flash_mma, cudaFuncAttributeMaxDynamicSharedMemorySize, FSMEM);

    // ---- side stream s2 ----
    cudaStream_t s2;
    cudaStreamCreateWithFlags(&s2, cudaStreamNonBlocking);
    cudaEvent_t evFork, evW, evNorm, evKV, evQ, evG6B;
    cudaEventCreateWithFlags(&evFork, cudaEventDisableTiming);
    cudaEventCreateWithFlags(&evW,    cudaEventDisableTiming);
    cudaEventCreateWithFlags(&evNorm, cudaEventDisableTiming);
    cudaEventCreateWithFlags(&evKV,   cudaEventDisableTiming);
    cudaEventCreateWithFlags(&evQ,    cudaEventDisableTiming);
    cudaEventCreateWithFlags(&evG6B,  cudaEventDisableTiming);

    cudaEventRecord(evFork, 0);
    cudaStreamWaitEvent(s2, evFork, 0);
    // s2: weight conversions (ln weights folded into wqb/wkvb)
    cvt_hi<<<2048, 256, 0, s2>>>(w_q_b,  wqb_h,  Q_COLS * Q_LORA / 4, Q_LORA, Q_COLS, wq_ln);
    cvt_hi<<<2048, 256, 0, s2>>>(w_kv_b, wkvb_h, KV_COLS * KV_LORA / 4, KV_LORA, KV_COLS, wkv_ln);
    cvt_hi<<<2048, 256, 0, s2>>>(w_o,    wo_h,   HID * O_COLS / 4, O_COLS, HID, nullptr);
    cudaEventRecord(evW, s2);

    // ---- main stream ----
    cvt_hi<<<4096, 256>>>(w_a, wa_h, A_COLS_P * HID / 4, HID, A_COLS, nullptr);
    cvt_hi<<<4096, 256>>>(hid, h_hi, S * HID / 4, HID, S, nullptr);

    // 1) fused-A GEMM (fp16 out, guarded)
    mma_gemm<<<dim3(A_COLS_P / 256, S / 128), 256, GSMEM>>>(
        h_hi, HID, wa_h, nullptr, ah, pos, nullptr, A_COLS, A_COLS, HID, 1);

    // 2) per-row rms inverse scales + k_pe rope
    rms_inv_kernel<<<S, 256>>>(ah, invq, invkv, kpeh, pos);
    cudaEventRecord(evNorm, 0);

    // s2: kv GEMM (A = raw a rows, rms folded via rowscale) concurrent with q GEMM
    cudaStreamWaitEvent(s2, evNorm, 0);
    mma_gemm<<<dim3(KV_COLS / 256, S / 128), 256, GSMEM, s2>>>(
        ah + Q_LORA, A_COLS, wkvb_h, nullptr, kvh, pos, invkv,
        KV_COLS, KV_COLS, KV_LORA, 1);
    cudaEventRecord(evKV, s2);

    // main: q GEMM (rms + rope + scale fused, fp16 out)
    cudaStreamWaitEvent(0, evW, 0);
    mma_gemm<<<dim3(Q_COLS / 256, S / 128), 256, GSMEM>>>(
        ah, A_COLS, wqb_h, nullptr, qs_hi, pos, invq,
        Q_COLS, Q_COLS, Q_LORA, 2);
    cudaEventRecord(evQ, 0);

    // main: flashA (heavy: qt 16..31)
    cudaStreamWaitEvent(0, evKV, 0);
    flash_mma<<<dim3(16, H), 128, FSMEM>>>(qs_hi, kvh, kpeh, at_hi, 31);

    // s2: flashB (light: qt 0..15) then G6-low
    cudaStreamWaitEvent(s2, evQ, 0);
    flash_mma<<<dim3(16, H), 128, FSMEM, s2>>>(qs_hi, kvh, kpeh, at_hi, 15);
    mma_gemm<<<dim3(HID / 256, 8), 256, GSMEM, s2>>>(
        at_hi, O_COLS, wo_h, out, nullptr, pos, nullptr, HID, HID, O_COLS, 0);
    cudaEventRecord(evG6B, s2);

    // main: G6-high after flashA
    mma_gemm<<<dim3(HID / 256, 8), 256, GSMEM>>>(
        at_hi + (size_t)1024 * O_COLS, O_COLS, wo_h, out + (size_t)1024 * HID, nullptr,
        pos, nullptr, HID, HID, O_COLS, 0);

    cudaStreamWaitEvent(0, evG6B, 0);

    cudaEventDestroy(evFork);
    cudaEventDestroy(evW);
    cudaEventDestroy(evNorm);
    cudaEventDestroy(evKV);
    cudaEventDestroy(evQ);
    cudaEventDestroy(evG6B);
    cudaStreamDestroy(s2);
}